// round 2
// baseline (speedup 1.0000x reference)
#include <cuda_runtime.h>
#include <math.h>

#define BB    2
#define NSEQ  2048
#define CDIM  1024
#define HN    16
#define DH    64
#define MROWS (BB*NSEQ)     // 4096
#define QKVC  (3*CDIM)      // 3072

// ---------------- scratch (static device globals; no allocation) -------------
__device__ float g_q[(size_t)BB*HN*NSEQ*DH];
__device__ float g_k[(size_t)BB*HN*NSEQ*DH];
__device__ float g_v[(size_t)BB*HN*NSEQ*DH];
__device__ float g_att[(size_t)BB*NSEQ*CDIM];
__device__ unsigned char g_maskc[BB*NSEQ];
__device__ int g_causal_d;

// ---------------- prep: canonicalize mask dtype + causal_start ---------------
// A bool input may arrive as u8, i32, or f32. Sniff bytes:
//   i32 {0,1}: nonzero only at byte offset %4==0
//   f32 {0.0,1.0}: nonzero at %4==2 (0x80) and %4==3 (0x3F), never %4==1
//   u8 random {0,1}: nonzero at all offsets (incl %4==1) with overwhelming prob.
__global__ void prep_kernel(const void* __restrict__ mask_raw,
                            const int* __restrict__ cs_raw, int nmask) {
    __shared__ int sfmt;
    const unsigned char* mb = (const unsigned char*)mask_raw;
    if (threadIdx.x == 0) {
        bool nz1 = false, nz3 = false;
        int scan = nmask < 1024 ? nmask : 1024;  // safe: buffer >= nmask bytes
        for (int i = 0; i < scan; i++) {
            unsigned char v = mb[i];
            if (v) { int r = i & 3; if (r == 1) nz1 = true; else if (r == 3) nz3 = true; }
        }
        sfmt = nz1 ? 0 : (nz3 ? 2 : 1);  // 0=u8, 1=i32, 2=f32
        int cv = cs_raw[0];
        if (cv < 0 || cv > (1 << 24)) cv = (int)__int_as_float(cv);  // f32-encoded fallback
        g_causal_d = cv;
    }
    __syncthreads();
    int f = sfmt;
    for (int i = threadIdx.x; i < nmask; i += blockDim.x) {
        unsigned char m;
        if (f == 0)      m = mb[i] != 0;
        else if (f == 1) m = ((const int*)mask_raw)[i] != 0;
        else             m = ((const float*)mask_raw)[i] != 0.0f;
        g_maskc[i] = m;
    }
}

// ---------------- QKV GEMM: x(4096x1024) @ Wqkv(1024x3072) -------------------
// 64x64 tile, BK=16, 256 threads, 4x4 micro-tile. Scatters into (B,H,N,d).
__global__ void __launch_bounds__(256) gemm_qkv_kernel(const float* __restrict__ x,
                                                       const float* __restrict__ w) {
    __shared__ float As[64][20];   // [m][k], row stride 80B (16B aligned)
    __shared__ float Bs[16][68];   // [k][n], row stride 272B (16B aligned)
    const int tid = threadIdx.x;
    const int tx = tid & 15, ty = tid >> 4;
    const int m0 = blockIdx.y * 64;
    const int n0 = blockIdx.x * 64;
    float acc[4][4] = {};
    const int ar = tid >> 2, akq = (tid & 3) * 4;
    const int br = tid >> 4, bcq = (tid & 15) * 4;

    for (int k0 = 0; k0 < CDIM; k0 += 16) {
        float4 av = *(const float4*)(x + (size_t)(m0 + ar) * CDIM + k0 + akq);
        float4 bv = *(const float4*)(w + (size_t)(k0 + br) * QKVC + n0 + bcq);
        *(float4*)&As[ar][akq] = av;
        *(float4*)&Bs[br][bcq] = bv;
        __syncthreads();
#pragma unroll
        for (int kk = 0; kk < 16; kk++) {
            float a[4];
#pragma unroll
            for (int i = 0; i < 4; i++) a[i] = As[4 * ty + i][kk];
            float4 b4 = *(float4*)&Bs[kk][4 * tx];
            float bj[4] = {b4.x, b4.y, b4.z, b4.w};
#pragma unroll
            for (int i = 0; i < 4; i++)
#pragma unroll
                for (int j = 0; j < 4; j++) acc[i][j] += a[i] * bj[j];
        }
        __syncthreads();
    }
    // scatter: n0 is 64-aligned -> section & head constant per CTA
    const int sec = n0 >> 10;              // 0=Q,1=K,2=V
    const int h = (n0 & 1023) >> 6;        // head
    float* dst = sec == 0 ? g_q : (sec == 1 ? g_k : g_v);
#pragma unroll
    for (int i = 0; i < 4; i++) {
        int row = m0 + 4 * ty + i;         // token row in [0,4096)
        int b = row >> 11, n = row & (NSEQ - 1);
        float* dr = dst + (((size_t)b * HN + h) * NSEQ + n) * DH + 4 * tx;
#pragma unroll
        for (int j = 0; j < 4; j++) dr[j] = acc[i][j];
    }
}

// ---------------- Flash attention: 1 CTA per (b,h,64-query tile) -------------
#define FP 68
__global__ void __launch_bounds__(256) flash_kernel() {
    extern __shared__ float sm[];
    float* Qs = sm;                       // [64][FP]  Q[row][d]
    float* Kt = sm + 64 * FP;             // [64][FP]  K^T: [d][key]
    float* Vs = sm + 2 * 64 * FP;         // [64][FP]  V[key][d]
    float* Ps = sm + 3 * 64 * FP;         // [64][FP]  P[row][key]
    unsigned char* mrow = (unsigned char*)(sm + 4 * 64 * FP);  // [64]

    const int tid = threadIdx.x;
    const int tx = tid & 15, ty = tid >> 4;
    const int qt = blockIdx.x, h = blockIdx.y, b = blockIdx.z;
    const int q0 = qt * 64;
    const float scale = rsqrtf((float)DH);
    const int cstart = g_causal_d;

    const float* Qg = g_q + (((size_t)b * HN + h) * NSEQ) * DH;
    const float* Kg = g_k + (((size_t)b * HN + h) * NSEQ) * DH;
    const float* Vg = g_v + (((size_t)b * HN + h) * NSEQ) * DH;

    // load full Q tile: 64 rows x 64 cols (4 column-chunks per thread)
    {
        const int r = tid >> 2, cbase = (tid & 3) * 4;
#pragma unroll
        for (int c = 0; c < DH; c += 16) {
            float4 v = *(const float4*)(Qg + (size_t)(q0 + r) * DH + cbase + c);
            *(float4*)&Qs[r * FP + cbase + c] = v;
        }
    }

    float m_i[4], l_i[4], o[4][4];
#pragma unroll
    for (int i = 0; i < 4; i++) {
        m_i[i] = -1e30f; l_i[i] = 0.f;
#pragma unroll
        for (int j = 0; j < 4; j++) o[i][j] = 0.f;
    }

    int kmax = q0 + 63;
    if (cstart - 1 > kmax) kmax = cstart - 1;
    if (kmax > NSEQ - 1) kmax = NSEQ - 1;
    const int ntiles = kmax / 64 + 1;     // causal skip: tiles beyond kmax never visible

    for (int t = 0; t < ntiles; t++) {
        const int k0t = t * 64;
        __syncthreads();  // protect Kt/Vs/Ps reuse (also fences Qs store on t=0)
        {
            const int r = tid >> 2, cbase = (tid & 3) * 4;
#pragma unroll
            for (int c = 0; c < DH; c += 16) {
                const int cq = cbase + c;
                float4 kv = *(const float4*)(Kg + (size_t)(k0t + r) * DH + cq);
                Kt[(cq + 0) * FP + r] = kv.x;
                Kt[(cq + 1) * FP + r] = kv.y;
                Kt[(cq + 2) * FP + r] = kv.z;
                Kt[(cq + 3) * FP + r] = kv.w;
                float4 vv = *(const float4*)(Vg + (size_t)(k0t + r) * DH + cq);
                *(float4*)&Vs[r * FP + cq] = vv;
            }
        }
        if (tid < 64) mrow[tid] = g_maskc[(size_t)b * NSEQ + k0t + tid];
        __syncthreads();

        // S = Q @ K^T
        float s[4][4] = {};
#pragma unroll
        for (int kk = 0; kk < 64; kk++) {
            float a[4];
#pragma unroll
            for (int i = 0; i < 4; i++) a[i] = Qs[(4 * ty + i) * FP + kk];
            float4 b4 = *(float4*)&Kt[kk * FP + 4 * tx];
            float bj[4] = {b4.x, b4.y, b4.z, b4.w};
#pragma unroll
            for (int i = 0; i < 4; i++)
#pragma unroll
                for (int j = 0; j < 4; j++) s[i][j] += a[i] * bj[j];
        }

        // scale + masks + tile row-max
        float tmax[4];
#pragma unroll
        for (int i = 0; i < 4; i++) {
            int row = q0 + 4 * ty + i;
            float rm = -1e30f;
#pragma unroll
            for (int j = 0; j < 4; j++) {
                int col = k0t + 4 * tx + j;
                float sv = s[i][j] * scale;
                bool masked = (mrow[4 * tx + j] != 0) || (col > row && col >= cstart);
                sv = masked ? -1e30f : sv;
                s[i][j] = sv;
                rm = fmaxf(rm, sv);
            }
            tmax[i] = rm;
        }
#pragma unroll
        for (int off = 1; off < 16; off <<= 1)
#pragma unroll
            for (int i = 0; i < 4; i++)
                tmax[i] = fmaxf(tmax[i], __shfl_xor_sync(0xffffffffu, tmax[i], off));

        // online softmax update (m,l replicated across the 16 tx lanes of a row group)
        float rsum[4];
#pragma unroll
        for (int i = 0; i < 4; i++) {
            float mnew = fmaxf(m_i[i], tmax[i]);
            float corr = __expf(m_i[i] - mnew);   // underflows to 0 when jumping from -1e30
            m_i[i] = mnew;
            l_i[i] *= corr;
#pragma unroll
            for (int j = 0; j < 4; j++) o[i][j] *= corr;
            float rs = 0.f;
#pragma unroll
            for (int j = 0; j < 4; j++) { s[i][j] = __expf(s[i][j] - mnew); rs += s[i][j]; }
            rsum[i] = rs;
        }
#pragma unroll
        for (int off = 1; off < 16; off <<= 1)
#pragma unroll
            for (int i = 0; i < 4; i++)
                rsum[i] += __shfl_xor_sync(0xffffffffu, rsum[i], off);
#pragma unroll
        for (int i = 0; i < 4; i++) l_i[i] += rsum[i];

        // stage P
#pragma unroll
        for (int i = 0; i < 4; i++)
            *(float4*)&Ps[(4 * ty + i) * FP + 4 * tx] =
                make_float4(s[i][0], s[i][1], s[i][2], s[i][3]);
        __syncthreads();

        // O += P @ V
#pragma unroll
        for (int kk = 0; kk < 64; kk++) {
            float p[4];
#pragma unroll
            for (int i = 0; i < 4; i++) p[i] = Ps[(4 * ty + i) * FP + kk];
            float4 v4 = *(float4*)&Vs[kk * FP + 4 * tx];
            float vj[4] = {v4.x, v4.y, v4.z, v4.w};
#pragma unroll
            for (int i = 0; i < 4; i++)
#pragma unroll
                for (int j = 0; j < 4; j++) o[i][j] += p[i] * vj[j];
        }
    }

    // normalize + write to (B,N,C) layout for proj GEMM
    float* dst = g_att + (size_t)b * NSEQ * CDIM + (size_t)h * DH;
#pragma unroll
    for (int i = 0; i < 4; i++) {
        float inv = 1.0f / l_i[i];
        float* dr = dst + (size_t)(q0 + 4 * ty + i) * CDIM + 4 * tx;
#pragma unroll
        for (int j = 0; j < 4; j++) dr[j] = o[i][j] * inv;
    }
}
#define FLASH_SMEM (4 * 64 * FP * 4 + 64)

// ---------------- Proj GEMM: g_att(4096x1024) @ Wproj(1024x1024) + b ---------
__global__ void __launch_bounds__(256) gemm_proj_kernel(const float* __restrict__ w,
                                                        const float* __restrict__ bias,
                                                        float* __restrict__ out) {
    __shared__ float As[64][20];
    __shared__ float Bs[16][68];
    const int tid = threadIdx.x;
    const int tx = tid & 15, ty = tid >> 4;
    const int m0 = blockIdx.y * 64;
    const int n0 = blockIdx.x * 64;
    float acc[4][4] = {};
    const int ar = tid >> 2, akq = (tid & 3) * 4;
    const int br = tid >> 4, bcq = (tid & 15) * 4;

    for (int k0 = 0; k0 < CDIM; k0 += 16) {
        float4 av = *(const float4*)(g_att + (size_t)(m0 + ar) * CDIM + k0 + akq);
        float4 bv = *(const float4*)(w + (size_t)(k0 + br) * CDIM + n0 + bcq);
        *(float4*)&As[ar][akq] = av;
        *(float4*)&Bs[br][bcq] = bv;
        __syncthreads();
#pragma unroll
        for (int kk = 0; kk < 16; kk++) {
            float a[4];
#pragma unroll
            for (int i = 0; i < 4; i++) a[i] = As[4 * ty + i][kk];
            float4 b4 = *(float4*)&Bs[kk][4 * tx];
            float bj[4] = {b4.x, b4.y, b4.z, b4.w};
#pragma unroll
            for (int i = 0; i < 4; i++)
#pragma unroll
                for (int j = 0; j < 4; j++) acc[i][j] += a[i] * bj[j];
        }
        __syncthreads();
    }
#pragma unroll
    for (int i = 0; i < 4; i++) {
        int row = m0 + 4 * ty + i;
        float* dr = out + (size_t)row * CDIM + n0 + 4 * tx;
#pragma unroll
        for (int j = 0; j < 4; j++) dr[j] = acc[i][j] + bias[n0 + 4 * tx + j];
    }
}

// ---------------- launch ------------------------------------------------------
extern "C" void kernel_launch(void* const* d_in, const int* in_sizes, int n_in,
                              void* d_out, int out_size) {
    (void)n_in; (void)out_size;
    const float* x     = (const float*)d_in[0];
    const void*  mask  = d_in[1];
    const int*   cs    = (const int*)d_in[2];
    const float* wqkv  = (const float*)d_in[3];
    const float* wproj = (const float*)d_in[4];
    const float* bproj = (const float*)d_in[5];
    float* out = (float*)d_out;

    prep_kernel<<<1, 256>>>(mask, cs, in_sizes[1]);

    dim3 g1(QKVC / 64, MROWS / 64);
    gemm_qkv_kernel<<<g1, 256>>>(x, wqkv);

    cudaFuncSetAttribute(flash_kernel, cudaFuncAttributeMaxDynamicSharedMemorySize,
                         FLASH_SMEM);
    dim3 g2(NSEQ / 64, HN, BB);
    flash_kernel<<<g2, 256, FLASH_SMEM>>>();

    dim3 g3(CDIM / 64, MROWS / 64);
    gemm_proj_kernel<<<g3, 256>>>(wproj, bproj, out);
}

// round 3
// speedup vs baseline: 1.1211x; 1.1211x over previous
#include <cuda_runtime.h>
#include <math.h>

#define BB    2
#define NSEQ  2048
#define CDIM  1024
#define HN    16
#define DH    64
#define MROWS (BB*NSEQ)     // 4096
#define QKVC  (3*CDIM)      // 3072

// ---------------- scratch (static device globals; no allocation) -------------
__device__ float g_q[(size_t)BB*HN*NSEQ*DH];
__device__ float g_k[(size_t)BB*HN*NSEQ*DH];
__device__ float g_v[(size_t)BB*HN*NSEQ*DH];
__device__ float g_att[(size_t)BB*NSEQ*CDIM];
__device__ unsigned char g_maskc[BB*NSEQ];
__device__ int g_causal_d;

// ---------------- prep: canonicalize mask dtype + causal_start ---------------
__global__ void prep_kernel(const void* __restrict__ mask_raw,
                            const int* __restrict__ cs_raw, int nmask) {
    __shared__ int sfmt;
    const unsigned char* mb = (const unsigned char*)mask_raw;
    if (threadIdx.x == 0) {
        bool nz1 = false, nz3 = false;
        int scan = nmask < 1024 ? nmask : 1024;
        for (int i = 0; i < scan; i++) {
            unsigned char v = mb[i];
            if (v) { int r = i & 3; if (r == 1) nz1 = true; else if (r == 3) nz3 = true; }
        }
        sfmt = nz1 ? 0 : (nz3 ? 2 : 1);  // 0=u8, 1=i32, 2=f32
        int cv = cs_raw[0];
        if (cv < 0 || cv > (1 << 24)) cv = (int)__int_as_float(cv);
        g_causal_d = cv;
    }
    __syncthreads();
    int f = sfmt;
    for (int i = threadIdx.x; i < nmask; i += blockDim.x) {
        unsigned char m;
        if (f == 0)      m = mb[i] != 0;
        else if (f == 1) m = ((const int*)mask_raw)[i] != 0;
        else             m = ((const float*)mask_raw)[i] != 0.0f;
        g_maskc[i] = m;
    }
}

// =============== 128x128x16 SGEMM core (8x8 micro-tile, 256 thr) =============
// As: [16][132] A^T (k-major), Bs: [16][132]. Register prefetch of next tile.
#define GAPAD 132

__device__ __forceinline__ void gemm_core_compute(const float* As, const float* Bs,
                                                  int tx, int ty, float acc[8][8]) {
#pragma unroll
    for (int kk = 0; kk < 16; kk++) {
        float4 a0 = *(const float4*)&As[kk * GAPAD + ty * 4];
        float4 a1 = *(const float4*)&As[kk * GAPAD + 64 + ty * 4];
        float4 b0 = *(const float4*)&Bs[kk * GAPAD + tx * 4];
        float4 b1 = *(const float4*)&Bs[kk * GAPAD + 64 + tx * 4];
        float a[8] = {a0.x, a0.y, a0.z, a0.w, a1.x, a1.y, a1.z, a1.w};
        float b[8] = {b0.x, b0.y, b0.z, b0.w, b1.x, b1.y, b1.z, b1.w};
#pragma unroll
        for (int i = 0; i < 8; i++)
#pragma unroll
            for (int j = 0; j < 8; j++) acc[i][j] += a[i] * b[j];
    }
}

// ---------------- QKV GEMM: x(4096x1024) @ Wqkv(1024x3072) -> scatter --------
__global__ void __launch_bounds__(256) gemm_qkv_kernel(const float* __restrict__ x,
                                                       const float* __restrict__ w) {
    __shared__ float As[16 * GAPAD];
    __shared__ float Bs[16 * GAPAD];
    const int tid = threadIdx.x;
    const int tx = tid & 15, ty = tid >> 4;
    const int m0 = blockIdx.y * 128;
    const int n0 = blockIdx.x * 128;
    float acc[8][8] = {};

    const int ar = tid >> 1, akq = (tid & 1) * 8;      // A: row, k-offset
    const int br = tid >> 4, bnq = (tid & 15) * 8;     // B: k-row, n-offset

    float4 av0 = *(const float4*)(x + (size_t)(m0 + ar) * CDIM + akq);
    float4 av1 = *(const float4*)(x + (size_t)(m0 + ar) * CDIM + akq + 4);
    float4 bv0 = *(const float4*)(w + (size_t)br * QKVC + n0 + bnq);
    float4 bv1 = *(const float4*)(w + (size_t)br * QKVC + n0 + bnq + 4);

    for (int k0 = 0; k0 < CDIM; k0 += 16) {
        // stage to smem (A transposed)
        As[(akq + 0) * GAPAD + ar] = av0.x; As[(akq + 1) * GAPAD + ar] = av0.y;
        As[(akq + 2) * GAPAD + ar] = av0.z; As[(akq + 3) * GAPAD + ar] = av0.w;
        As[(akq + 4) * GAPAD + ar] = av1.x; As[(akq + 5) * GAPAD + ar] = av1.y;
        As[(akq + 6) * GAPAD + ar] = av1.z; As[(akq + 7) * GAPAD + ar] = av1.w;
        *(float4*)&Bs[br * GAPAD + bnq] = bv0;
        *(float4*)&Bs[br * GAPAD + bnq + 4] = bv1;
        __syncthreads();
        if (k0 + 16 < CDIM) {
            av0 = *(const float4*)(x + (size_t)(m0 + ar) * CDIM + k0 + 16 + akq);
            av1 = *(const float4*)(x + (size_t)(m0 + ar) * CDIM + k0 + 16 + akq + 4);
            bv0 = *(const float4*)(w + (size_t)(k0 + 16 + br) * QKVC + n0 + bnq);
            bv1 = *(const float4*)(w + (size_t)(k0 + 16 + br) * QKVC + n0 + bnq + 4);
        }
        gemm_core_compute(As, Bs, tx, ty, acc);
        __syncthreads();
    }

    // scatter into (B,H,N,d): cols n0 is 128-aligned; each 64-half = one head
#pragma unroll
    for (int jh = 0; jh < 2; jh++) {
        int col = n0 + jh * 64 + tx * 4;
        int sec = col >> 10;
        int h = (col & 1023) >> 6;
        int d = tx * 4;
        float* dst = sec == 0 ? g_q : (sec == 1 ? g_k : g_v);
#pragma unroll
        for (int ih = 0; ih < 2; ih++)
#pragma unroll
            for (int i = 0; i < 4; i++) {
                int row = m0 + ih * 64 + ty * 4 + i;
                int b = row >> 11, n = row & (NSEQ - 1);
                float* dr = dst + (((size_t)b * HN + h) * NSEQ + n) * DH + d;
                *(float4*)dr = make_float4(acc[ih * 4 + i][jh * 4 + 0],
                                           acc[ih * 4 + i][jh * 4 + 1],
                                           acc[ih * 4 + i][jh * 4 + 2],
                                           acc[ih * 4 + i][jh * 4 + 3]);
            }
    }
}

// ---------------- Proj GEMM: g_att(4096x1024) @ Wproj(1024x1024) + b ---------
__global__ void __launch_bounds__(256) gemm_proj_kernel(const float* __restrict__ w,
                                                        const float* __restrict__ bias,
                                                        float* __restrict__ out) {
    __shared__ float As[16 * GAPAD];
    __shared__ float Bs[16 * GAPAD];
    const int tid = threadIdx.x;
    const int tx = tid & 15, ty = tid >> 4;
    const int m0 = blockIdx.y * 128;
    const int n0 = blockIdx.x * 128;
    float acc[8][8] = {};

    const int ar = tid >> 1, akq = (tid & 1) * 8;
    const int br = tid >> 4, bnq = (tid & 15) * 8;

    float4 av0 = *(const float4*)(g_att + (size_t)(m0 + ar) * CDIM + akq);
    float4 av1 = *(const float4*)(g_att + (size_t)(m0 + ar) * CDIM + akq + 4);
    float4 bv0 = *(const float4*)(w + (size_t)br * CDIM + n0 + bnq);
    float4 bv1 = *(const float4*)(w + (size_t)br * CDIM + n0 + bnq + 4);

    for (int k0 = 0; k0 < CDIM; k0 += 16) {
        As[(akq + 0) * GAPAD + ar] = av0.x; As[(akq + 1) * GAPAD + ar] = av0.y;
        As[(akq + 2) * GAPAD + ar] = av0.z; As[(akq + 3) * GAPAD + ar] = av0.w;
        As[(akq + 4) * GAPAD + ar] = av1.x; As[(akq + 5) * GAPAD + ar] = av1.y;
        As[(akq + 6) * GAPAD + ar] = av1.z; As[(akq + 7) * GAPAD + ar] = av1.w;
        *(float4*)&Bs[br * GAPAD + bnq] = bv0;
        *(float4*)&Bs[br * GAPAD + bnq + 4] = bv1;
        __syncthreads();
        if (k0 + 16 < CDIM) {
            av0 = *(const float4*)(g_att + (size_t)(m0 + ar) * CDIM + k0 + 16 + akq);
            av1 = *(const float4*)(g_att + (size_t)(m0 + ar) * CDIM + k0 + 16 + akq + 4);
            bv0 = *(const float4*)(w + (size_t)(k0 + 16 + br) * CDIM + n0 + bnq);
            bv1 = *(const float4*)(w + (size_t)(k0 + 16 + br) * CDIM + n0 + bnq + 4);
        }
        gemm_core_compute(As, Bs, tx, ty, acc);
        __syncthreads();
    }

#pragma unroll
    for (int jh = 0; jh < 2; jh++) {
        int coln = n0 + jh * 64 + tx * 4;
        float4 bv = *(const float4*)(bias + coln);
#pragma unroll
        for (int ih = 0; ih < 2; ih++)
#pragma unroll
            for (int i = 0; i < 4; i++) {
                int row = m0 + ih * 64 + ty * 4 + i;
                float* dr = out + (size_t)row * CDIM + coln;
                *(float4*)dr = make_float4(acc[ih * 4 + i][jh * 4 + 0] + bv.x,
                                           acc[ih * 4 + i][jh * 4 + 1] + bv.y,
                                           acc[ih * 4 + i][jh * 4 + 2] + bv.z,
                                           acc[ih * 4 + i][jh * 4 + 3] + bv.w);
            }
    }
}

// ---------------- Flash attention: Br=128, Bc=64, 8x4 micro -------------------
#define FP 68
__global__ void __launch_bounds__(256) flash_kernel() {
    extern __shared__ float sm[];
    float* Qs = sm;                         // [128][FP] Q[row][d]
    float* Kt = sm + 128 * FP;              // [64][FP]  K^T: [d][key]
    float* Vs = sm + 128 * FP + 64 * FP;    // [64][FP]  V[key][d]
    float* Ps = sm + 128 * FP + 2 * 64 * FP;// [128][FP] P[row][key]
    unsigned char* mrow = (unsigned char*)(Ps + 128 * FP);  // [64]

    const int tid = threadIdx.x;
    const int tx = tid & 15, ty = tid >> 4;
    const int qt = blockIdx.x, h = blockIdx.y, b = blockIdx.z;
    const int q0 = qt * 128;
    const float scale = rsqrtf((float)DH);
    const int cstart = g_causal_d;

    const float* Qg = g_q + (((size_t)b * HN + h) * NSEQ) * DH;
    const float* Kg = g_k + (((size_t)b * HN + h) * NSEQ) * DH;
    const float* Vg = g_v + (((size_t)b * HN + h) * NSEQ) * DH;

    // load Q tile: 128x64 (each thread 8 float4)
    {
        const int r = tid >> 1, cb = (tid & 1) * 32;
#pragma unroll
        for (int c = 0; c < 32; c += 4) {
            float4 v = *(const float4*)(Qg + (size_t)(q0 + r) * DH + cb + c);
            *(float4*)&Qs[r * FP + cb + c] = v;
        }
    }

    int rowi[8];
#pragma unroll
    for (int i = 0; i < 8; i++) rowi[i] = (i < 4) ? (ty * 4 + i) : (64 + ty * 4 + i - 4);

    float m_i[8], l_i[8], o[8][4];
#pragma unroll
    for (int i = 0; i < 8; i++) {
        m_i[i] = -1e30f; l_i[i] = 0.f;
#pragma unroll
        for (int j = 0; j < 4; j++) o[i][j] = 0.f;
    }

    int kmax = q0 + 127;
    if (cstart - 1 > kmax) kmax = cstart - 1;
    if (kmax > NSEQ - 1) kmax = NSEQ - 1;
    const int ntiles = kmax / 64 + 1;

    for (int t = 0; t < ntiles; t++) {
        const int k0t = t * 64;
        __syncthreads();   // protect Kt/Vs/Ps reuse (also fences Qs on t=0)
        {
            const int r = tid >> 2, cb = (tid & 3) * 16;
#pragma unroll
            for (int c = 0; c < 16; c += 4) {
                const int cq = cb + c;
                float4 kv = *(const float4*)(Kg + (size_t)(k0t + r) * DH + cq);
                Kt[(cq + 0) * FP + r] = kv.x;
                Kt[(cq + 1) * FP + r] = kv.y;
                Kt[(cq + 2) * FP + r] = kv.z;
                Kt[(cq + 3) * FP + r] = kv.w;
                float4 vv = *(const float4*)(Vg + (size_t)(k0t + r) * DH + cq);
                *(float4*)&Vs[r * FP + cq] = vv;
            }
        }
        if (tid < 64) mrow[tid] = g_maskc[(size_t)b * NSEQ + k0t + tid];
        __syncthreads();

        // S = Q @ K^T  (8x4 per thread)
        float s[8][4] = {};
#pragma unroll
        for (int kk = 0; kk < 64; kk++) {
            float a[8];
#pragma unroll
            for (int i = 0; i < 8; i++) a[i] = Qs[rowi[i] * FP + kk];
            float4 b4 = *(float4*)&Kt[kk * FP + 4 * tx];
            float bj[4] = {b4.x, b4.y, b4.z, b4.w};
#pragma unroll
            for (int i = 0; i < 8; i++)
#pragma unroll
                for (int j = 0; j < 4; j++) s[i][j] += a[i] * bj[j];
        }

        // scale + masks + tile row-max
        float tmax[8];
#pragma unroll
        for (int i = 0; i < 8; i++) {
            int row = q0 + rowi[i];
            float rm = -1e30f;
#pragma unroll
            for (int j = 0; j < 4; j++) {
                int col = k0t + 4 * tx + j;
                float sv = s[i][j] * scale;
                bool masked = (mrow[4 * tx + j] != 0) || (col > row && col >= cstart);
                sv = masked ? -1e30f : sv;
                s[i][j] = sv;
                rm = fmaxf(rm, sv);
            }
            tmax[i] = rm;
        }
#pragma unroll
        for (int off = 1; off < 16; off <<= 1)
#pragma unroll
            for (int i = 0; i < 8; i++)
                tmax[i] = fmaxf(tmax[i], __shfl_xor_sync(0xffffffffu, tmax[i], off));

        // online softmax update
        float rsum[8];
#pragma unroll
        for (int i = 0; i < 8; i++) {
            float mnew = fmaxf(m_i[i], tmax[i]);
            float corr = __expf(m_i[i] - mnew);
            m_i[i] = mnew;
            l_i[i] *= corr;
#pragma unroll
            for (int j = 0; j < 4; j++) o[i][j] *= corr;
            float rs = 0.f;
#pragma unroll
            for (int j = 0; j < 4; j++) { s[i][j] = __expf(s[i][j] - mnew); rs += s[i][j]; }
            rsum[i] = rs;
        }
#pragma unroll
        for (int off = 1; off < 16; off <<= 1)
#pragma unroll
            for (int i = 0; i < 8; i++)
                rsum[i] += __shfl_xor_sync(0xffffffffu, rsum[i], off);
#pragma unroll
        for (int i = 0; i < 8; i++) l_i[i] += rsum[i];

        // stage P
#pragma unroll
        for (int i = 0; i < 8; i++)
            *(float4*)&Ps[rowi[i] * FP + 4 * tx] =
                make_float4(s[i][0], s[i][1], s[i][2], s[i][3]);
        __syncthreads();

        // O += P @ V
#pragma unroll
        for (int kk = 0; kk < 64; kk++) {
            float p[8];
#pragma unroll
            for (int i = 0; i < 8; i++) p[i] = Ps[rowi[i] * FP + kk];
            float4 v4 = *(float4*)&Vs[kk * FP + 4 * tx];
            float vj[4] = {v4.x, v4.y, v4.z, v4.w};
#pragma unroll
            for (int i = 0; i < 8; i++)
#pragma unroll
                for (int j = 0; j < 4; j++) o[i][j] += p[i] * vj[j];
        }
    }

    // normalize + write to (B,N,C) layout for proj GEMM
    float* dst = g_att + (size_t)b * NSEQ * CDIM + (size_t)h * DH;
#pragma unroll
    for (int i = 0; i < 8; i++) {
        float inv = 1.0f / l_i[i];
        float* dr = dst + (size_t)(q0 + rowi[i]) * CDIM + 4 * tx;
        *(float4*)dr = make_float4(o[i][0] * inv, o[i][1] * inv,
                                   o[i][2] * inv, o[i][3] * inv);
    }
}
#define FLASH_SMEM ((128 * FP + 64 * FP + 64 * FP + 128 * FP) * 4 + 64)

// ---------------- launch ------------------------------------------------------
extern "C" void kernel_launch(void* const* d_in, const int* in_sizes, int n_in,
                              void* d_out, int out_size) {
    (void)n_in; (void)out_size;
    const float* x     = (const float*)d_in[0];
    const void*  mask  = d_in[1];
    const int*   cs    = (const int*)d_in[2];
    const float* wqkv  = (const float*)d_in[3];
    const float* wproj = (const float*)d_in[4];
    const float* bproj = (const float*)d_in[5];
    float* out = (float*)d_out;

    prep_kernel<<<1, 256>>>(mask, cs, in_sizes[1]);

    dim3 g1(QKVC / 128, MROWS / 128);
    gemm_qkv_kernel<<<g1, 256>>>(x, wqkv);

    cudaFuncSetAttribute(flash_kernel, cudaFuncAttributeMaxDynamicSharedMemorySize,
                         FLASH_SMEM);
    dim3 g2(NSEQ / 128, HN, BB);
    flash_kernel<<<g2, 256, FLASH_SMEM>>>();

    dim3 g3(CDIM / 128, MROWS / 128);
    gemm_proj_kernel<<<g3, 256>>>(wproj, bproj, out);
}

// round 4
// speedup vs baseline: 1.5126x; 1.3493x over previous
#include <cuda_runtime.h>
#include <cuda_bf16.h>
#include <math.h>
#include <stdint.h>

#define BB    2
#define NSEQ  2048
#define CDIM  1024
#define HN    16
#define DH    64
#define MROWS (BB*NSEQ)     // 4096
#define QKVC  (3*CDIM)      // 3072

// ---------------- scratch (static device globals; no allocation) -------------
__device__ float g_q[(size_t)BB*HN*NSEQ*DH];
__device__ float g_k[(size_t)BB*HN*NSEQ*DH];
__device__ float g_v[(size_t)BB*HN*NSEQ*DH];
__device__ __nv_bfloat16 g_xhi[(size_t)MROWS*CDIM], g_xlo[(size_t)MROWS*CDIM];
__device__ __nv_bfloat16 g_wqhi[(size_t)CDIM*QKVC], g_wqlo[(size_t)CDIM*QKVC];
__device__ __nv_bfloat16 g_wphi[(size_t)CDIM*CDIM], g_wplo[(size_t)CDIM*CDIM];
__device__ __nv_bfloat16 g_ahi[(size_t)MROWS*CDIM], g_alo[(size_t)MROWS*CDIM];
__device__ unsigned char g_maskc[BB*NSEQ];
__device__ int g_causal_d;

// ---------------- prep: canonicalize mask dtype + causal_start ---------------
__global__ void prep_kernel(const void* __restrict__ mask_raw,
                            const int* __restrict__ cs_raw, int nmask) {
    __shared__ int sfmt;
    const unsigned char* mb = (const unsigned char*)mask_raw;
    if (threadIdx.x == 0) {
        bool nz1 = false, nz3 = false;
        int scan = nmask < 1024 ? nmask : 1024;
        for (int i = 0; i < scan; i++) {
            unsigned char v = mb[i];
            if (v) { int r = i & 3; if (r == 1) nz1 = true; else if (r == 3) nz3 = true; }
        }
        sfmt = nz1 ? 0 : (nz3 ? 2 : 1);  // 0=u8, 1=i32, 2=f32
        int cv = cs_raw[0];
        if (cv < 0 || cv > (1 << 24)) cv = (int)__int_as_float(cv);
        g_causal_d = cv;
    }
    __syncthreads();
    int f = sfmt;
    for (int i = threadIdx.x; i < nmask; i += blockDim.x) {
        unsigned char m;
        if (f == 0)      m = mb[i] != 0;
        else if (f == 1) m = ((const int*)mask_raw)[i] != 0;
        else             m = ((const float*)mask_raw)[i] != 0.0f;
        g_maskc[i] = m;
    }
}

// ---------------- split fp32 -> bf16 hi + lo ---------------------------------
__global__ void split_kernel(const float* __restrict__ src,
                             __nv_bfloat16* __restrict__ hi,
                             __nv_bfloat16* __restrict__ lo, int n) {
    int i = blockIdx.x * blockDim.x + threadIdx.x;
    if (i < n) {
        float v = src[i];
        __nv_bfloat16 h = __float2bfloat16(v);
        hi[i] = h;
        lo[i] = __float2bfloat16(v - __bfloat162float(h));
    }
}

// ---------------- mma.sync helpers -------------------------------------------
__device__ __forceinline__ uint32_t s2u(const void* p) {
    return (uint32_t)__cvta_generic_to_shared(p);
}
__device__ __forceinline__ void ldsm_x4(unsigned* r, uint32_t addr) {
    asm volatile("ldmatrix.sync.aligned.m8n8.x4.shared.b16 {%0,%1,%2,%3}, [%4];"
                 : "=r"(r[0]), "=r"(r[1]), "=r"(r[2]), "=r"(r[3]) : "r"(addr));
}
__device__ __forceinline__ void ldsm_x4t(unsigned* r, uint32_t addr) {
    asm volatile("ldmatrix.sync.aligned.m8n8.x4.trans.shared.b16 {%0,%1,%2,%3}, [%4];"
                 : "=r"(r[0]), "=r"(r[1]), "=r"(r[2]), "=r"(r[3]) : "r"(addr));
}
__device__ __forceinline__ void mma_bf16(float* d, const unsigned* a, const unsigned* b) {
    asm volatile("mma.sync.aligned.m16n8k16.row.col.f32.bf16.bf16.f32 "
                 "{%0,%1,%2,%3}, {%4,%5,%6,%7}, {%8,%9}, {%0,%1,%2,%3};"
                 : "+f"(d[0]), "+f"(d[1]), "+f"(d[2]), "+f"(d[3])
                 : "r"(a[0]), "r"(a[1]), "r"(a[2]), "r"(a[3]), "r"(b[0]), "r"(b[1]));
}

// =============== bf16x3 tensor-core GEMM: 128x128 CTA, 64x32 warp ============
// C = A(M x 1024) @ B(1024 x NTOT), bf16x3 (hi*hi + hi*lo + lo*hi), fp32 acc.
#define APAD 24    // A smem row stride (bf16) — conflict-free ldmatrix
#define BPAD 136   // B smem row stride (bf16)

template<int NTOT, bool QKV_EPI>
__global__ void __launch_bounds__(256, 1)
mma_gemm_kernel(const __nv_bfloat16* __restrict__ Ahi,
                const __nv_bfloat16* __restrict__ Alo,
                const __nv_bfloat16* __restrict__ Bhi,
                const __nv_bfloat16* __restrict__ Blo,
                const float* __restrict__ bias, float* __restrict__ out) {
    __shared__ __nv_bfloat16 sA[2][2][128 * APAD];  // [buf][hi/lo][row*APAD+k]
    __shared__ __nv_bfloat16 sB[2][2][16 * BPAD];   // [buf][hi/lo][k*BPAD+n]

    const int tid = threadIdx.x, lane = tid & 31, wid = tid >> 5;
    const int wm = wid >> 2, wn = wid & 3;          // warp grid 2x4
    const int m0 = blockIdx.y * 128, n0 = blockIdx.x * 128;

    // staging indices: A: 16B per thread (row, k-half); B: 16B (k-row, n-oct)
    const int ar = tid >> 1, ak = (tid & 1) * 8;
    const int br = tid >> 4, bn = (tid & 15) * 8;
    const size_t aoff = (size_t)(m0 + ar) * CDIM + ak;

    float acc[4][4][4];
#pragma unroll
    for (int i = 0; i < 4; i++)
#pragma unroll
        for (int j = 0; j < 4; j++)
#pragma unroll
            for (int q = 0; q < 4; q++) acc[i][j][q] = 0.f;

    // ldmatrix base addresses (within one [hi/lo] plane)
    const int a_ld = (wm * 64 + (lane & 15)) * APAD + (lane >> 4) * 8;
    const int b_ld = (lane & 15) * BPAD + wn * 32 + (lane >> 4) * 8;
    const uint32_t sA0 = s2u(&sA[0][0][0]);
    const uint32_t sB0 = s2u(&sB[0][0][0]);
    const uint32_t aplane = 128 * APAD * 2;  // bytes per [hi/lo] plane
    const uint32_t bplane = 16 * BPAD * 2;

    // preload k0 = 0
    uint4 vah = *(const uint4*)(Ahi + aoff);
    uint4 val = *(const uint4*)(Alo + aoff);
    uint4 vbh = *(const uint4*)(Bhi + (size_t)br * NTOT + n0 + bn);
    uint4 vbl = *(const uint4*)(Blo + (size_t)br * NTOT + n0 + bn);
    *(uint4*)&sA[0][0][ar * APAD + ak] = vah;
    *(uint4*)&sA[0][1][ar * APAD + ak] = val;
    *(uint4*)&sB[0][0][br * BPAD + bn] = vbh;
    *(uint4*)&sB[0][1][br * BPAD + bn] = vbl;
    __syncthreads();

    for (int k0 = 0, it = 0; k0 < CDIM; k0 += 16, it++) {
        const int cur = it & 1, nxt = cur ^ 1;
        const bool more = (k0 + 16 < CDIM);
        if (more) {
            vah = *(const uint4*)(Ahi + aoff + k0 + 16);
            val = *(const uint4*)(Alo + aoff + k0 + 16);
            vbh = *(const uint4*)(Bhi + (size_t)(k0 + 16 + br) * NTOT + n0 + bn);
            vbl = *(const uint4*)(Blo + (size_t)(k0 + 16 + br) * NTOT + n0 + bn);
        }

        // fragment loads
        unsigned ah[4][4], al[4][4], bh[4][2], bl[4][2];
        const uint32_t aBh = sA0 + (2 * cur + 0) * aplane + a_ld * 2;
        const uint32_t aBl = sA0 + (2 * cur + 1) * aplane + a_ld * 2;
        const uint32_t bBh = sB0 + (2 * cur + 0) * bplane + b_ld * 2;
        const uint32_t bBl = sB0 + (2 * cur + 1) * bplane + b_ld * 2;
#pragma unroll
        for (int mt = 0; mt < 4; mt++) {
            ldsm_x4(ah[mt], aBh + mt * 16 * APAD * 2);
            ldsm_x4(al[mt], aBl + mt * 16 * APAD * 2);
        }
#pragma unroll
        for (int ntp = 0; ntp < 2; ntp++) {
            unsigned t4[4];
            ldsm_x4t(t4, bBh + ntp * 16 * 2);
            bh[2 * ntp][0] = t4[0]; bh[2 * ntp][1] = t4[1];
            bh[2 * ntp + 1][0] = t4[2]; bh[2 * ntp + 1][1] = t4[3];
            ldsm_x4t(t4, bBl + ntp * 16 * 2);
            bl[2 * ntp][0] = t4[0]; bl[2 * ntp][1] = t4[1];
            bl[2 * ntp + 1][0] = t4[2]; bl[2 * ntp + 1][1] = t4[3];
        }
#pragma unroll
        for (int mt = 0; mt < 4; mt++)
#pragma unroll
            for (int nt = 0; nt < 4; nt++) {
                mma_bf16(acc[mt][nt], ah[mt], bh[nt]);
                mma_bf16(acc[mt][nt], ah[mt], bl[nt]);
                mma_bf16(acc[mt][nt], al[mt], bh[nt]);
            }

        if (more) {
            *(uint4*)&sA[nxt][0][ar * APAD + ak] = vah;
            *(uint4*)&sA[nxt][1][ar * APAD + ak] = val;
            *(uint4*)&sB[nxt][0][br * BPAD + bn] = vbh;
            *(uint4*)&sB[nxt][1][br * BPAD + bn] = vbl;
            __syncthreads();
        }
    }

    // epilogue: c-frag thread map: rows (lane>>2), (lane>>2)+8; cols (lane&3)*2,+1
    const int rb = m0 + wm * 64 + (lane >> 2);
    const int cb = n0 + wn * 32 + (lane & 3) * 2;
#pragma unroll
    for (int mt = 0; mt < 4; mt++)
#pragma unroll
        for (int nt = 0; nt < 4; nt++) {
            const int c = cb + nt * 8;
            if (QKV_EPI) {
                const int sec = c >> 10, h = (c & 1023) >> 6, d = c & 63;
                float* dst = sec == 0 ? g_q : (sec == 1 ? g_k : g_v);
#pragma unroll
                for (int half = 0; half < 2; half++) {
                    const int r = rb + mt * 16 + half * 8;
                    const int bidx = r >> 11, n = r & (NSEQ - 1);
                    float* p = dst + (((size_t)bidx * HN + h) * NSEQ + n) * DH + d;
                    *(float2*)p = make_float2(acc[mt][nt][2 * half],
                                              acc[mt][nt][2 * half + 1]);
                }
            } else {
                const float b0 = bias[c], b1 = bias[c + 1];
#pragma unroll
                for (int half = 0; half < 2; half++) {
                    const int r = rb + mt * 16 + half * 8;
                    float* p = out + (size_t)r * NTOT + c;
                    *(float2*)p = make_float2(acc[mt][nt][2 * half] + b0,
                                              acc[mt][nt][2 * half + 1] + b1);
                }
            }
        }
}

// ---------------- Flash attention: Br=128, Bc=64, 8x4 micro (fp32 SIMT) ------
#define FP 68
__global__ void __launch_bounds__(256) flash_kernel() {
    extern __shared__ float sm[];
    float* Qs = sm;                          // [128][FP]
    float* Kt = sm + 128 * FP;               // [64][FP] K^T
    float* Vs = sm + 128 * FP + 64 * FP;     // [64][FP]
    float* Ps = sm + 128 * FP + 2 * 64 * FP; // [128][FP]
    unsigned char* mrow = (unsigned char*)(Ps + 128 * FP);  // [64]

    const int tid = threadIdx.x;
    const int tx = tid & 15, ty = tid >> 4;
    const int qt = blockIdx.x, h = blockIdx.y, b = blockIdx.z;
    const int q0 = qt * 128;
    const float scale = rsqrtf((float)DH);
    const int cstart = g_causal_d;

    const float* Qg = g_q + (((size_t)b * HN + h) * NSEQ) * DH;
    const float* Kg = g_k + (((size_t)b * HN + h) * NSEQ) * DH;
    const float* Vg = g_v + (((size_t)b * HN + h) * NSEQ) * DH;

    {
        const int r = tid >> 1, cbse = (tid & 1) * 32;
#pragma unroll
        for (int c = 0; c < 32; c += 4) {
            float4 v = *(const float4*)(Qg + (size_t)(q0 + r) * DH + cbse + c);
            *(float4*)&Qs[r * FP + cbse + c] = v;
        }
    }

    int rowi[8];
#pragma unroll
    for (int i = 0; i < 8; i++) rowi[i] = (i < 4) ? (ty * 4 + i) : (64 + ty * 4 + i - 4);

    float m_i[8], l_i[8], o[8][4];
#pragma unroll
    for (int i = 0; i < 8; i++) {
        m_i[i] = -1e30f; l_i[i] = 0.f;
#pragma unroll
        for (int j = 0; j < 4; j++) o[i][j] = 0.f;
    }

    int kmax = q0 + 127;
    if (cstart - 1 > kmax) kmax = cstart - 1;
    if (kmax > NSEQ - 1) kmax = NSEQ - 1;
    const int ntiles = kmax / 64 + 1;

    for (int t = 0; t < ntiles; t++) {
        const int k0t = t * 64;
        __syncthreads();
        {
            const int r = tid >> 2, cbse = (tid & 3) * 16;
#pragma unroll
            for (int c = 0; c < 16; c += 4) {
                const int cq = cbse + c;
                float4 kv = *(const float4*)(Kg + (size_t)(k0t + r) * DH + cq);
                Kt[(cq + 0) * FP + r] = kv.x;
                Kt[(cq + 1) * FP + r] = kv.y;
                Kt[(cq + 2) * FP + r] = kv.z;
                Kt[(cq + 3) * FP + r] = kv.w;
                float4 vv = *(const float4*)(Vg + (size_t)(k0t + r) * DH + cq);
                *(float4*)&Vs[r * FP + cq] = vv;
            }
        }
        if (tid < 64) mrow[tid] = g_maskc[(size_t)b * NSEQ + k0t + tid];
        __syncthreads();

        float s[8][4] = {};
#pragma unroll
        for (int kk = 0; kk < 64; kk++) {
            float a[8];
#pragma unroll
            for (int i = 0; i < 8; i++) a[i] = Qs[rowi[i] * FP + kk];
            float4 b4 = *(float4*)&Kt[kk * FP + 4 * tx];
            float bj[4] = {b4.x, b4.y, b4.z, b4.w};
#pragma unroll
            for (int i = 0; i < 8; i++)
#pragma unroll
                for (int j = 0; j < 4; j++) s[i][j] += a[i] * bj[j];
        }

        float tmax[8];
#pragma unroll
        for (int i = 0; i < 8; i++) {
            int row = q0 + rowi[i];
            float rm = -1e30f;
#pragma unroll
            for (int j = 0; j < 4; j++) {
                int col = k0t + 4 * tx + j;
                float sv = s[i][j] * scale;
                bool masked = (mrow[4 * tx + j] != 0) || (col > row && col >= cstart);
                sv = masked ? -1e30f : sv;
                s[i][j] = sv;
                rm = fmaxf(rm, sv);
            }
            tmax[i] = rm;
        }
#pragma unroll
        for (int off = 1; off < 16; off <<= 1)
#pragma unroll
            for (int i = 0; i < 8; i++)
                tmax[i] = fmaxf(tmax[i], __shfl_xor_sync(0xffffffffu, tmax[i], off));

        float rsum[8];
#pragma unroll
        for (int i = 0; i < 8; i++) {
            float mnew = fmaxf(m_i[i], tmax[i]);
            float corr = __expf(m_i[i] - mnew);
            m_i[i] = mnew;
            l_i[i] *= corr;
#pragma unroll
            for (int j = 0; j < 4; j++) o[i][j] *= corr;
            float rs = 0.f;
#pragma unroll
            for (int j = 0; j < 4; j++) { s[i][j] = __expf(s[i][j] - mnew); rs += s[i][j]; }
            rsum[i] = rs;
        }
#pragma unroll
        for (int off = 1; off < 16; off <<= 1)
#pragma unroll
            for (int i = 0; i < 8; i++)
                rsum[i] += __shfl_xor_sync(0xffffffffu, rsum[i], off);
#pragma unroll
        for (int i = 0; i < 8; i++) l_i[i] += rsum[i];

#pragma unroll
        for (int i = 0; i < 8; i++)
            *(float4*)&Ps[rowi[i] * FP + 4 * tx] =
                make_float4(s[i][0], s[i][1], s[i][2], s[i][3]);
        __syncthreads();

#pragma unroll
        for (int kk = 0; kk < 64; kk++) {
            float p[8];
#pragma unroll
            for (int i = 0; i < 8; i++) p[i] = Ps[rowi[i] * FP + kk];
            float4 v4 = *(float4*)&Vs[kk * FP + 4 * tx];
            float vj[4] = {v4.x, v4.y, v4.z, v4.w};
#pragma unroll
            for (int i = 0; i < 8; i++)
#pragma unroll
                for (int j = 0; j < 4; j++) o[i][j] += p[i] * vj[j];
        }
    }

    // normalize + write bf16 hi/lo att (input of proj tensor GEMM)
#pragma unroll
    for (int i = 0; i < 8; i++) {
        float inv = 1.0f / l_i[i];
        size_t base = ((size_t)b * NSEQ + (q0 + rowi[i])) * CDIM + (size_t)h * DH + 4 * tx;
#pragma unroll
        for (int j = 0; j < 4; j++) {
            float v = o[i][j] * inv;
            __nv_bfloat16 hh = __float2bfloat16(v);
            g_ahi[base + j] = hh;
            g_alo[base + j] = __float2bfloat16(v - __bfloat162float(hh));
        }
    }
}
#define FLASH_SMEM ((128 * FP + 64 * FP + 64 * FP + 128 * FP) * 4 + 64)

// ---------------- launch ------------------------------------------------------
extern "C" void kernel_launch(void* const* d_in, const int* in_sizes, int n_in,
                              void* d_out, int out_size) {
    (void)n_in; (void)out_size;
    const float* x     = (const float*)d_in[0];
    const void*  mask  = d_in[1];
    const int*   cs    = (const int*)d_in[2];
    const float* wqkv  = (const float*)d_in[3];
    const float* wproj = (const float*)d_in[4];
    const float* bproj = (const float*)d_in[5];
    float* out = (float*)d_out;

    prep_kernel<<<1, 256>>>(mask, cs, in_sizes[1]);

    // resolve device-global scratch addresses (host-side, graph-capturable: no-op API? —
    // cudaGetSymbolAddress is not a stream op; it is allowed outside capture rules)
    __nv_bfloat16 *xhi, *xlo, *wqhi, *wqlo, *wphi, *wplo, *ahi, *alo;
    cudaGetSymbolAddress((void**)&xhi, g_xhi);   cudaGetSymbolAddress((void**)&xlo, g_xlo);
    cudaGetSymbolAddress((void**)&wqhi, g_wqhi); cudaGetSymbolAddress((void**)&wqlo, g_wqlo);
    cudaGetSymbolAddress((void**)&wphi, g_wphi); cudaGetSymbolAddress((void**)&wplo, g_wplo);
    cudaGetSymbolAddress((void**)&ahi, g_ahi);   cudaGetSymbolAddress((void**)&alo, g_alo);

    const int nx = MROWS * CDIM, nwq = CDIM * QKVC, nwp = CDIM * CDIM;
    split_kernel<<<(nx + 255) / 256, 256>>>(x, xhi, xlo, nx);
    split_kernel<<<(nwq + 255) / 256, 256>>>(wqkv, wqhi, wqlo, nwq);
    split_kernel<<<(nwp + 255) / 256, 256>>>(wproj, wphi, wplo, nwp);

    dim3 g1(QKVC / 128, MROWS / 128);
    mma_gemm_kernel<QKVC, true><<<g1, 256>>>(xhi, xlo, wqhi, wqlo, nullptr, nullptr);

    cudaFuncSetAttribute(flash_kernel, cudaFuncAttributeMaxDynamicSharedMemorySize,
                         FLASH_SMEM);
    dim3 g2(NSEQ / 128, HN, BB);
    flash_kernel<<<g2, 256, FLASH_SMEM>>>();

    dim3 g3(CDIM / 128, MROWS / 128);
    mma_gemm_kernel<CDIM, false><<<g3, 256>>>(ahi, alo, wphi, wplo, bproj, out);
}

// round 5
// speedup vs baseline: 2.4206x; 1.6003x over previous
#include <cuda_runtime.h>
#include <cuda_bf16.h>
#include <math.h>
#include <stdint.h>

#define BB    2
#define NSEQ  2048
#define CDIM  1024
#define HN    16
#define DH    64
#define MROWS (BB*NSEQ)     // 4096
#define QKVC  (3*CDIM)      // 3072

// ---------------- scratch (static device globals; no allocation) -------------
__device__ __align__(16) __nv_bfloat16 g_xhi[(size_t)MROWS*CDIM], g_xlo[(size_t)MROWS*CDIM];
__device__ __align__(16) __nv_bfloat16 g_wqhi[(size_t)CDIM*QKVC], g_wqlo[(size_t)CDIM*QKVC];
__device__ __align__(16) __nv_bfloat16 g_wphi[(size_t)CDIM*CDIM], g_wplo[(size_t)CDIM*CDIM];
__device__ __align__(16) __nv_bfloat16 g_ahi[(size_t)MROWS*CDIM], g_alo[(size_t)MROWS*CDIM];
__device__ __align__(16) __nv_bfloat16 g_qhi[(size_t)BB*HN*NSEQ*DH], g_qlo[(size_t)BB*HN*NSEQ*DH];
__device__ __align__(16) __nv_bfloat16 g_khi[(size_t)BB*HN*NSEQ*DH], g_klo[(size_t)BB*HN*NSEQ*DH];
__device__ __align__(16) __nv_bfloat16 g_vhi[(size_t)BB*HN*NSEQ*DH], g_vlo[(size_t)BB*HN*NSEQ*DH];
__device__ unsigned char g_maskc[BB*NSEQ];
__device__ int g_causal_d;

// ---------------- prep: canonicalize mask dtype + causal_start ---------------
__global__ void prep_kernel(const void* __restrict__ mask_raw,
                            const int* __restrict__ cs_raw, int nmask) {
    __shared__ int sfmt;
    const unsigned char* mb = (const unsigned char*)mask_raw;
    if (threadIdx.x == 0) {
        bool nz1 = false, nz3 = false;
        int scan = nmask < 1024 ? nmask : 1024;
        for (int i = 0; i < scan; i++) {
            unsigned char v = mb[i];
            if (v) { int r = i & 3; if (r == 1) nz1 = true; else if (r == 3) nz3 = true; }
        }
        sfmt = nz1 ? 0 : (nz3 ? 2 : 1);  // 0=u8, 1=i32, 2=f32
        int cv = cs_raw[0];
        if (cv < 0 || cv > (1 << 24)) cv = (int)__int_as_float(cv);
        g_causal_d = cv;
    }
    __syncthreads();
    int f = sfmt;
    for (int i = threadIdx.x; i < nmask; i += blockDim.x) {
        unsigned char m;
        if (f == 0)      m = mb[i] != 0;
        else if (f == 1) m = ((const int*)mask_raw)[i] != 0;
        else             m = ((const float*)mask_raw)[i] != 0.0f;
        g_maskc[i] = m;
    }
}

// ---------------- split fp32 -> bf16 hi + lo ---------------------------------
__global__ void split_kernel(const float* __restrict__ src,
                             __nv_bfloat16* __restrict__ hi,
                             __nv_bfloat16* __restrict__ lo, int n) {
    int i = blockIdx.x * blockDim.x + threadIdx.x;
    if (i < n) {
        float v = src[i];
        __nv_bfloat16 h = __float2bfloat16(v);
        hi[i] = h;
        lo[i] = __float2bfloat16(v - __bfloat162float(h));
    }
}

// ---------------- mma.sync helpers -------------------------------------------
__device__ __forceinline__ uint32_t s2u(const void* p) {
    return (uint32_t)__cvta_generic_to_shared(p);
}
__device__ __forceinline__ void ldsm_x4(unsigned* r, uint32_t addr) {
    asm volatile("ldmatrix.sync.aligned.m8n8.x4.shared.b16 {%0,%1,%2,%3}, [%4];"
                 : "=r"(r[0]), "=r"(r[1]), "=r"(r[2]), "=r"(r[3]) : "r"(addr));
}
__device__ __forceinline__ void ldsm_x4t(unsigned* r, uint32_t addr) {
    asm volatile("ldmatrix.sync.aligned.m8n8.x4.trans.shared.b16 {%0,%1,%2,%3}, [%4];"
                 : "=r"(r[0]), "=r"(r[1]), "=r"(r[2]), "=r"(r[3]) : "r"(addr));
}
__device__ __forceinline__ void mma_bf16(float* d, const unsigned* a, const unsigned* b) {
    asm volatile("mma.sync.aligned.m16n8k16.row.col.f32.bf16.bf16.f32 "
                 "{%0,%1,%2,%3}, {%4,%5,%6,%7}, {%8,%9}, {%0,%1,%2,%3};"
                 : "+f"(d[0]), "+f"(d[1]), "+f"(d[2]), "+f"(d[3])
                 : "r"(a[0]), "r"(a[1]), "r"(a[2]), "r"(a[3]), "r"(b[0]), "r"(b[1]));
}
__device__ __forceinline__ unsigned bf2u(__nv_bfloat162 x) { return *(unsigned*)&x; }

// =============== bf16x3 tensor-core GEMM: 128x128 CTA, 64x32 warp ============
#define APAD 24
#define BPAD 136

template<int NTOT, bool QKV_EPI>
__global__ void __launch_bounds__(256, 1)
mma_gemm_kernel(const __nv_bfloat16* __restrict__ Ahi,
                const __nv_bfloat16* __restrict__ Alo,
                const __nv_bfloat16* __restrict__ Bhi,
                const __nv_bfloat16* __restrict__ Blo,
                const float* __restrict__ bias, float* __restrict__ out) {
    __shared__ __nv_bfloat16 sA[2][2][128 * APAD];
    __shared__ __nv_bfloat16 sB[2][2][16 * BPAD];

    const int tid = threadIdx.x, lane = tid & 31, wid = tid >> 5;
    const int wm = wid >> 2, wn = wid & 3;
    const int m0 = blockIdx.y * 128, n0 = blockIdx.x * 128;

    const int ar = tid >> 1, ak = (tid & 1) * 8;
    const int br = tid >> 4, bn = (tid & 15) * 8;
    const size_t aoff = (size_t)(m0 + ar) * CDIM + ak;

    float acc[4][4][4];
#pragma unroll
    for (int i = 0; i < 4; i++)
#pragma unroll
        for (int j = 0; j < 4; j++)
#pragma unroll
            for (int q = 0; q < 4; q++) acc[i][j][q] = 0.f;

    const int a_ld = (wm * 64 + (lane & 15)) * APAD + (lane >> 4) * 8;
    const int b_ld = (lane & 15) * BPAD + wn * 32 + (lane >> 4) * 8;
    const uint32_t sA0 = s2u(&sA[0][0][0]);
    const uint32_t sB0 = s2u(&sB[0][0][0]);
    const uint32_t aplane = 128 * APAD * 2;
    const uint32_t bplane = 16 * BPAD * 2;

    uint4 vah = *(const uint4*)(Ahi + aoff);
    uint4 val = *(const uint4*)(Alo + aoff);
    uint4 vbh = *(const uint4*)(Bhi + (size_t)br * NTOT + n0 + bn);
    uint4 vbl = *(const uint4*)(Blo + (size_t)br * NTOT + n0 + bn);
    *(uint4*)&sA[0][0][ar * APAD + ak] = vah;
    *(uint4*)&sA[0][1][ar * APAD + ak] = val;
    *(uint4*)&sB[0][0][br * BPAD + bn] = vbh;
    *(uint4*)&sB[0][1][br * BPAD + bn] = vbl;
    __syncthreads();

    for (int k0 = 0, it = 0; k0 < CDIM; k0 += 16, it++) {
        const int cur = it & 1, nxt = cur ^ 1;
        const bool more = (k0 + 16 < CDIM);
        if (more) {
            vah = *(const uint4*)(Ahi + aoff + k0 + 16);
            val = *(const uint4*)(Alo + aoff + k0 + 16);
            vbh = *(const uint4*)(Bhi + (size_t)(k0 + 16 + br) * NTOT + n0 + bn);
            vbl = *(const uint4*)(Blo + (size_t)(k0 + 16 + br) * NTOT + n0 + bn);
        }

        unsigned ah[4][4], al[4][4], bh[4][2], bl[4][2];
        const uint32_t aBh = sA0 + (2 * cur + 0) * aplane + a_ld * 2;
        const uint32_t aBl = sA0 + (2 * cur + 1) * aplane + a_ld * 2;
        const uint32_t bBh = sB0 + (2 * cur + 0) * bplane + b_ld * 2;
        const uint32_t bBl = sB0 + (2 * cur + 1) * bplane + b_ld * 2;
#pragma unroll
        for (int mt = 0; mt < 4; mt++) {
            ldsm_x4(ah[mt], aBh + mt * 16 * APAD * 2);
            ldsm_x4(al[mt], aBl + mt * 16 * APAD * 2);
        }
#pragma unroll
        for (int ntp = 0; ntp < 2; ntp++) {
            unsigned t4[4];
            ldsm_x4t(t4, bBh + ntp * 16 * 2);
            bh[2 * ntp][0] = t4[0]; bh[2 * ntp][1] = t4[1];
            bh[2 * ntp + 1][0] = t4[2]; bh[2 * ntp + 1][1] = t4[3];
            ldsm_x4t(t4, bBl + ntp * 16 * 2);
            bl[2 * ntp][0] = t4[0]; bl[2 * ntp][1] = t4[1];
            bl[2 * ntp + 1][0] = t4[2]; bl[2 * ntp + 1][1] = t4[3];
        }
#pragma unroll
        for (int mt = 0; mt < 4; mt++)
#pragma unroll
            for (int nt = 0; nt < 4; nt++) {
                mma_bf16(acc[mt][nt], ah[mt], bh[nt]);
                mma_bf16(acc[mt][nt], ah[mt], bl[nt]);
                mma_bf16(acc[mt][nt], al[mt], bh[nt]);
            }

        if (more) {
            *(uint4*)&sA[nxt][0][ar * APAD + ak] = vah;
            *(uint4*)&sA[nxt][1][ar * APAD + ak] = val;
            *(uint4*)&sB[nxt][0][br * BPAD + bn] = vbh;
            *(uint4*)&sB[nxt][1][br * BPAD + bn] = vbl;
            __syncthreads();
        }
    }

    const int rb = m0 + wm * 64 + (lane >> 2);
    const int cb = n0 + wn * 32 + (lane & 3) * 2;
#pragma unroll
    for (int mt = 0; mt < 4; mt++)
#pragma unroll
        for (int nt = 0; nt < 4; nt++) {
            const int c = cb + nt * 8;
            if (QKV_EPI) {
                const int sec = c >> 10, h = (c & 1023) >> 6, d = c & 63;
                __nv_bfloat16 *dhi, *dlo;
                if (sec == 0)      { dhi = g_qhi; dlo = g_qlo; }
                else if (sec == 1) { dhi = g_khi; dlo = g_klo; }
                else               { dhi = g_vhi; dlo = g_vlo; }
#pragma unroll
                for (int half = 0; half < 2; half++) {
                    const int r = rb + mt * 16 + half * 8;
                    const int bidx = r >> 11, n = r & (NSEQ - 1);
                    size_t off = (((size_t)bidx * HN + h) * NSEQ + n) * DH + d;
                    float v0 = acc[mt][nt][2 * half], v1 = acc[mt][nt][2 * half + 1];
                    __nv_bfloat162 hh = __floats2bfloat162_rn(v0, v1);
                    __nv_bfloat162 ll = __floats2bfloat162_rn(
                        v0 - __bfloat162float(hh.x), v1 - __bfloat162float(hh.y));
                    *(__nv_bfloat162*)&dhi[off] = hh;
                    *(__nv_bfloat162*)&dlo[off] = ll;
                }
            } else {
                const float b0 = bias[c], b1 = bias[c + 1];
#pragma unroll
                for (int half = 0; half < 2; half++) {
                    const int r = rb + mt * 16 + half * 8;
                    float* p = out + (size_t)r * NTOT + c;
                    *(float2*)p = make_float2(acc[mt][nt][2 * half] + b0,
                                              acc[mt][nt][2 * half + 1] + b1);
                }
            }
        }
}

// =============== Flash attention on tensor cores (bf16x3) =====================
// 128 q-rows/CTA, 8 warps (16 rows each), 64-key tiles, mma.m16n8k16.
#define QP 72   // smem row stride in bf16 (144B) — conflict-free ldmatrix
#define FLASH_MMA_SMEM (512 * QP * 2 + 64)

__global__ void __launch_bounds__(256, 1) flash_mma_kernel() {
    extern __shared__ __align__(16) char smraw[];
    __nv_bfloat16* smb = (__nv_bfloat16*)smraw;
    __nv_bfloat16* sQh = smb;
    __nv_bfloat16* sQl = smb + 128 * QP;
    __nv_bfloat16* sKh = smb + 256 * QP;
    __nv_bfloat16* sKl = smb + 320 * QP;
    __nv_bfloat16* sVh = smb + 384 * QP;
    __nv_bfloat16* sVl = smb + 448 * QP;
    unsigned char* mrow = (unsigned char*)(smb + 512 * QP);

    const int tid = threadIdx.x, lane = tid & 31, wid = tid >> 5;
    const int qt = blockIdx.x, h = blockIdx.y, b = blockIdx.z;
    const int q0 = qt * 128;
    const int cstart = g_causal_d;
    const size_t hoff = ((size_t)b * HN + h) * NSEQ * DH;

    const __nv_bfloat16 *Qh = g_qhi + hoff, *Ql = g_qlo + hoff;
    const __nv_bfloat16 *Kh = g_khi + hoff, *Kl = g_klo + hoff;
    const __nv_bfloat16 *Vh = g_vhi + hoff, *Vl = g_vlo + hoff;

    // stage Q tile (128 x 64, hi+lo)
    {
        const int r = tid >> 1, c0 = (tid & 1) * 32;
#pragma unroll
        for (int c = 0; c < 32; c += 8) {
            *(uint4*)&sQh[r * QP + c0 + c] = *(const uint4*)&Qh[(size_t)(q0 + r) * DH + c0 + c];
            *(uint4*)&sQl[r * QP + c0 + c] = *(const uint4*)&Ql[(size_t)(q0 + r) * DH + c0 + c];
        }
    }
    __syncthreads();

    // Q fragments (invariant over key tiles): 4 k-steps x (hi,lo)
    unsigned qfh[4][4], qfl[4][4];
#pragma unroll
    for (int ks = 0; ks < 4; ks++) {
        const int qa = (wid * 16 + (lane & 15)) * QP + ks * 16 + (lane >> 4) * 8;
        ldsm_x4(qfh[ks], s2u(&sQh[qa]));
        ldsm_x4(qfl[ks], s2u(&sQl[qa]));
    }

    float m0v = -1e30f, m1v = -1e30f, l0v = 0.f, l1v = 0.f;
    float oacc[8][4] = {};

    int kmaxi = q0 + 127;
    if (cstart - 1 > kmaxi) kmaxi = cstart - 1;
    if (kmaxi > NSEQ - 1) kmaxi = NSEQ - 1;
    const int ntiles = kmaxi / 64 + 1;

    const int grow0 = q0 + wid * 16 + (lane >> 2);
    const int grow1 = grow0 + 8;

    for (int t = 0; t < ntiles; t++) {
        const int k0t = t * 64;
        __syncthreads();
        {
            const int r = tid >> 2, c0 = (tid & 3) * 16;
#pragma unroll
            for (int c = 0; c < 16; c += 8) {
                *(uint4*)&sKh[r * QP + c0 + c] = *(const uint4*)&Kh[(size_t)(k0t + r) * DH + c0 + c];
                *(uint4*)&sKl[r * QP + c0 + c] = *(const uint4*)&Kl[(size_t)(k0t + r) * DH + c0 + c];
                *(uint4*)&sVh[r * QP + c0 + c] = *(const uint4*)&Vh[(size_t)(k0t + r) * DH + c0 + c];
                *(uint4*)&sVl[r * QP + c0 + c] = *(const uint4*)&Vl[(size_t)(k0t + r) * DH + c0 + c];
            }
        }
        if (tid < 64) mrow[tid] = g_maskc[(size_t)b * NSEQ + k0t + tid];
        __syncthreads();

        // ---- S = Q K^T (bf16x3, fp32 acc) ----
        float sacc[8][4] = {};
#pragma unroll
        for (int ks = 0; ks < 4; ks++) {
            unsigned kbh[8][2], kbl[8][2];
#pragma unroll
            for (int np = 0; np < 4; np++) {
                const int row = np * 16 + ((lane >> 4) & 1) * 8 + (lane & 7);
                const int col = ks * 16 + ((lane >> 3) & 1) * 8;
                unsigned t4[4];
                ldsm_x4(t4, s2u(&sKh[row * QP + col]));
                kbh[2 * np][0] = t4[0]; kbh[2 * np][1] = t4[1];
                kbh[2 * np + 1][0] = t4[2]; kbh[2 * np + 1][1] = t4[3];
                ldsm_x4(t4, s2u(&sKl[row * QP + col]));
                kbl[2 * np][0] = t4[0]; kbl[2 * np][1] = t4[1];
                kbl[2 * np + 1][0] = t4[2]; kbl[2 * np + 1][1] = t4[3];
            }
#pragma unroll
            for (int nt = 0; nt < 8; nt++) {
                mma_bf16(sacc[nt], qfh[ks], kbh[nt]);
                mma_bf16(sacc[nt], qfh[ks], kbl[nt]);
                mma_bf16(sacc[nt], qfl[ks], kbh[nt]);
            }
        }

        // ---- scale + masks + row max ----
        float tmax0 = -INFINITY, tmax1 = -INFINITY;
#pragma unroll
        for (int nt = 0; nt < 8; nt++) {
#pragma unroll
            for (int j = 0; j < 2; j++) {
                const int lc = nt * 8 + (lane & 3) * 2 + j;
                const int col = k0t + lc;
                const bool pad = mrow[lc] != 0;
                float v0 = sacc[nt][j] * 0.125f;
                float v1 = sacc[nt][2 + j] * 0.125f;
                v0 = (pad || (col > grow0 && col >= cstart)) ? -INFINITY : v0;
                v1 = (pad || (col > grow1 && col >= cstart)) ? -INFINITY : v1;
                sacc[nt][j] = v0; sacc[nt][2 + j] = v1;
                tmax0 = fmaxf(tmax0, v0); tmax1 = fmaxf(tmax1, v1);
            }
        }
#pragma unroll
        for (int off = 1; off < 4; off <<= 1) {
            tmax0 = fmaxf(tmax0, __shfl_xor_sync(0xffffffffu, tmax0, off));
            tmax1 = fmaxf(tmax1, __shfl_xor_sync(0xffffffffu, tmax1, off));
        }

        // ---- online softmax update ----
        const float mn0 = fmaxf(m0v, tmax0), mn1 = fmaxf(m1v, tmax1);
        const float cr0 = __expf(m0v - mn0), cr1 = __expf(m1v - mn1);
        m0v = mn0; m1v = mn1;
        l0v *= cr0; l1v *= cr1;
#pragma unroll
        for (int nt = 0; nt < 8; nt++) {
            oacc[nt][0] *= cr0; oacc[nt][1] *= cr0;
            oacc[nt][2] *= cr1; oacc[nt][3] *= cr1;
        }
        float rs0 = 0.f, rs1 = 0.f;
#pragma unroll
        for (int nt = 0; nt < 8; nt++) {
            float p0 = __expf(sacc[nt][0] - mn0), p1 = __expf(sacc[nt][1] - mn0);
            float p2 = __expf(sacc[nt][2] - mn1), p3 = __expf(sacc[nt][3] - mn1);
            sacc[nt][0] = p0; sacc[nt][1] = p1; sacc[nt][2] = p2; sacc[nt][3] = p3;
            rs0 += p0 + p1; rs1 += p2 + p3;
        }
#pragma unroll
        for (int off = 1; off < 4; off <<= 1) {
            rs0 += __shfl_xor_sync(0xffffffffu, rs0, off);
            rs1 += __shfl_xor_sync(0xffffffffu, rs1, off);
        }
        l0v += rs0; l1v += rs1;

        // ---- O += P V (P split hi/lo in registers; V hi/lo from smem) ----
#pragma unroll
        for (int ks = 0; ks < 4; ks++) {
            unsigned ah[4], al[4];
            {
                const float v0 = sacc[2 * ks][0], v1 = sacc[2 * ks][1];
                const float v2 = sacc[2 * ks][2], v3 = sacc[2 * ks][3];
                const float w0 = sacc[2 * ks + 1][0], w1 = sacc[2 * ks + 1][1];
                const float w2 = sacc[2 * ks + 1][2], w3 = sacc[2 * ks + 1][3];
                __nv_bfloat162 h0 = __floats2bfloat162_rn(v0, v1);
                __nv_bfloat162 h1 = __floats2bfloat162_rn(v2, v3);
                __nv_bfloat162 h2 = __floats2bfloat162_rn(w0, w1);
                __nv_bfloat162 h3 = __floats2bfloat162_rn(w2, w3);
                ah[0] = bf2u(h0); ah[1] = bf2u(h1); ah[2] = bf2u(h2); ah[3] = bf2u(h3);
                al[0] = bf2u(__floats2bfloat162_rn(v0 - __bfloat162float(h0.x),
                                                   v1 - __bfloat162float(h0.y)));
                al[1] = bf2u(__floats2bfloat162_rn(v2 - __bfloat162float(h1.x),
                                                   v3 - __bfloat162float(h1.y)));
                al[2] = bf2u(__floats2bfloat162_rn(w0 - __bfloat162float(h2.x),
                                                   w1 - __bfloat162float(h2.y)));
                al[3] = bf2u(__floats2bfloat162_rn(w2 - __bfloat162float(h3.x),
                                                   w3 - __bfloat162float(h3.y)));
            }
#pragma unroll
            for (int np = 0; np < 4; np++) {
                const int va = (ks * 16 + (lane & 15)) * QP + np * 16 + (lane >> 4) * 8;
                unsigned t4[4], t4l[4];
                ldsm_x4t(t4, s2u(&sVh[va]));
                ldsm_x4t(t4l, s2u(&sVl[va]));
                unsigned vb0[2] = {t4[0], t4[1]}, vb1[2] = {t4[2], t4[3]};
                unsigned vl0[2] = {t4l[0], t4l[1]}, vl1[2] = {t4l[2], t4l[3]};
                mma_bf16(oacc[2 * np], ah, vb0);
                mma_bf16(oacc[2 * np], ah, vl0);
                mma_bf16(oacc[2 * np], al, vb0);
                mma_bf16(oacc[2 * np + 1], ah, vb1);
                mma_bf16(oacc[2 * np + 1], ah, vl1);
                mma_bf16(oacc[2 * np + 1], al, vb1);
            }
        }
    }

    // ---- normalize + write bf16 hi/lo att (input of proj GEMM) ----
    const float inv0 = 1.f / l0v, inv1 = 1.f / l1v;
#pragma unroll
    for (int nt = 0; nt < 8; nt++) {
        const int d = nt * 8 + (lane & 3) * 2;
        const size_t o0 = ((size_t)b * NSEQ + grow0) * CDIM + h * DH + d;
        const size_t o1 = ((size_t)b * NSEQ + grow1) * CDIM + h * DH + d;
        const float v0 = oacc[nt][0] * inv0, v1 = oacc[nt][1] * inv0;
        const float w0 = oacc[nt][2] * inv1, w1 = oacc[nt][3] * inv1;
        __nv_bfloat162 h0 = __floats2bfloat162_rn(v0, v1);
        *(__nv_bfloat162*)&g_ahi[o0] = h0;
        *(__nv_bfloat162*)&g_alo[o0] = __floats2bfloat162_rn(
            v0 - __bfloat162float(h0.x), v1 - __bfloat162float(h0.y));
        __nv_bfloat162 h1 = __floats2bfloat162_rn(w0, w1);
        *(__nv_bfloat162*)&g_ahi[o1] = h1;
        *(__nv_bfloat162*)&g_alo[o1] = __floats2bfloat162_rn(
            w0 - __bfloat162float(h1.x), w1 - __bfloat162float(h1.y));
    }
}

// ---------------- launch ------------------------------------------------------
extern "C" void kernel_launch(void* const* d_in, const int* in_sizes, int n_in,
                              void* d_out, int out_size) {
    (void)n_in; (void)out_size;
    const float* x     = (const float*)d_in[0];
    const void*  mask  = d_in[1];
    const int*   cs    = (const int*)d_in[2];
    const float* wqkv  = (const float*)d_in[3];
    const float* wproj = (const float*)d_in[4];
    const float* bproj = (const float*)d_in[5];
    float* out = (float*)d_out;

    prep_kernel<<<1, 256>>>(mask, cs, in_sizes[1]);

    __nv_bfloat16 *xhi, *xlo, *wqhi, *wqlo, *wphi, *wplo, *ahi, *alo;
    cudaGetSymbolAddress((void**)&xhi, g_xhi);   cudaGetSymbolAddress((void**)&xlo, g_xlo);
    cudaGetSymbolAddress((void**)&wqhi, g_wqhi); cudaGetSymbolAddress((void**)&wqlo, g_wqlo);
    cudaGetSymbolAddress((void**)&wphi, g_wphi); cudaGetSymbolAddress((void**)&wplo, g_wplo);
    cudaGetSymbolAddress((void**)&ahi, g_ahi);   cudaGetSymbolAddress((void**)&alo, g_alo);

    const int nx = MROWS * CDIM, nwq = CDIM * QKVC, nwp = CDIM * CDIM;
    split_kernel<<<(nx + 255) / 256, 256>>>(x, xhi, xlo, nx);
    split_kernel<<<(nwq + 255) / 256, 256>>>(wqkv, wqhi, wqlo, nwq);
    split_kernel<<<(nwp + 255) / 256, 256>>>(wproj, wphi, wplo, nwp);

    dim3 g1(QKVC / 128, MROWS / 128);
    mma_gemm_kernel<QKVC, true><<<g1, 256>>>(xhi, xlo, wqhi, wqlo, nullptr, nullptr);

    cudaFuncSetAttribute(flash_mma_kernel, cudaFuncAttributeMaxDynamicSharedMemorySize,
                         FLASH_MMA_SMEM);
    dim3 g2(NSEQ / 128, HN, BB);
    flash_mma_kernel<<<g2, 256, FLASH_MMA_SMEM>>>();

    dim3 g3(CDIM / 128, MROWS / 128);
    mma_gemm_kernel<CDIM, false><<<g3, 256>>>(ahi, alo, wphi, wplo, bproj, out);
}

// round 6
// speedup vs baseline: 2.5404x; 1.0495x over previous
#include <cuda_runtime.h>
#include <cuda_bf16.h>
#include <math.h>
#include <stdint.h>

#define BB    2
#define NSEQ  2048
#define CDIM  1024
#define HN    16
#define DH    64
#define MROWS (BB*NSEQ)     // 4096
#define QKVC  (3*CDIM)      // 3072

// ---------------- scratch (static device globals; no allocation) -------------
__device__ __align__(16) __nv_bfloat16 g_xhi[(size_t)MROWS*CDIM], g_xlo[(size_t)MROWS*CDIM];
__device__ __align__(16) __nv_bfloat16 g_wqhi[(size_t)CDIM*QKVC], g_wqlo[(size_t)CDIM*QKVC];
__device__ __align__(16) __nv_bfloat16 g_wphi[(size_t)CDIM*CDIM], g_wplo[(size_t)CDIM*CDIM];
__device__ __align__(16) __nv_bfloat16 g_ahi[(size_t)MROWS*CDIM], g_alo[(size_t)MROWS*CDIM];
__device__ __align__(16) __nv_bfloat16 g_qhi[(size_t)BB*HN*NSEQ*DH], g_qlo[(size_t)BB*HN*NSEQ*DH];
__device__ __align__(16) __nv_bfloat16 g_khi[(size_t)BB*HN*NSEQ*DH], g_klo[(size_t)BB*HN*NSEQ*DH];
__device__ __align__(16) __nv_bfloat16 g_vhi[(size_t)BB*HN*NSEQ*DH], g_vlo[(size_t)BB*HN*NSEQ*DH];
__device__ unsigned char g_maskc[BB*NSEQ];
__device__ int g_causal_d;

// ---------------- prep: canonicalize mask dtype + causal_start ---------------
__global__ void prep_kernel(const void* __restrict__ mask_raw,
                            const int* __restrict__ cs_raw, int nmask) {
    __shared__ int sfmt;
    const unsigned char* mb = (const unsigned char*)mask_raw;
    if (threadIdx.x == 0) {
        bool nz1 = false, nz3 = false;
        int scan = nmask < 1024 ? nmask : 1024;
        for (int i = 0; i < scan; i++) {
            unsigned char v = mb[i];
            if (v) { int r = i & 3; if (r == 1) nz1 = true; else if (r == 3) nz3 = true; }
        }
        sfmt = nz1 ? 0 : (nz3 ? 2 : 1);  // 0=u8, 1=i32, 2=f32
        int cv = cs_raw[0];
        if (cv < 0 || cv > (1 << 24)) cv = (int)__int_as_float(cv);
        g_causal_d = cv;
    }
    __syncthreads();
    int f = sfmt;
    for (int i = threadIdx.x; i < nmask; i += blockDim.x) {
        unsigned char m;
        if (f == 0)      m = mb[i] != 0;
        else if (f == 1) m = ((const int*)mask_raw)[i] != 0;
        else             m = ((const float*)mask_raw)[i] != 0.0f;
        g_maskc[i] = m;
    }
}

// ---------------- split fp32 -> bf16 hi + lo ---------------------------------
__global__ void split_kernel(const float* __restrict__ src,
                             __nv_bfloat16* __restrict__ hi,
                             __nv_bfloat16* __restrict__ lo, int n) {
    int i = blockIdx.x * blockDim.x + threadIdx.x;
    if (i < n) {
        float v = src[i];
        __nv_bfloat16 h = __float2bfloat16(v);
        hi[i] = h;
        lo[i] = __float2bfloat16(v - __bfloat162float(h));
    }
}

// ---------------- PTX helpers -------------------------------------------------
__device__ __forceinline__ uint32_t s2u(const void* p) {
    return (uint32_t)__cvta_generic_to_shared(p);
}
__device__ __forceinline__ void ldsm_x4(unsigned* r, uint32_t addr) {
    asm volatile("ldmatrix.sync.aligned.m8n8.x4.shared.b16 {%0,%1,%2,%3}, [%4];"
                 : "=r"(r[0]), "=r"(r[1]), "=r"(r[2]), "=r"(r[3]) : "r"(addr));
}
__device__ __forceinline__ void ldsm_x4t(unsigned* r, uint32_t addr) {
    asm volatile("ldmatrix.sync.aligned.m8n8.x4.trans.shared.b16 {%0,%1,%2,%3}, [%4];"
                 : "=r"(r[0]), "=r"(r[1]), "=r"(r[2]), "=r"(r[3]) : "r"(addr));
}
__device__ __forceinline__ void mma_bf16(float* d, const unsigned* a, const unsigned* b) {
    asm volatile("mma.sync.aligned.m16n8k16.row.col.f32.bf16.bf16.f32 "
                 "{%0,%1,%2,%3}, {%4,%5,%6,%7}, {%8,%9}, {%0,%1,%2,%3};"
                 : "+f"(d[0]), "+f"(d[1]), "+f"(d[2]), "+f"(d[3])
                 : "r"(a[0]), "r"(a[1]), "r"(a[2]), "r"(a[3]), "r"(b[0]), "r"(b[1]));
}
__device__ __forceinline__ unsigned bf2u(__nv_bfloat162 x) { return *(unsigned*)&x; }
__device__ __forceinline__ void cp16(uint32_t smem, const void* g) {
    asm volatile("cp.async.cg.shared.global [%0], [%1], 16;"
                 :: "r"(smem), "l"(__cvta_generic_to_global(g)) : "memory");
}
__device__ __forceinline__ void cp_commit() {
    asm volatile("cp.async.commit_group;" ::: "memory");
}
template<int N> __device__ __forceinline__ void cp_wait() {
    asm volatile("cp.async.wait_group %0;" :: "n"(N) : "memory");
}

// =============== bf16x3 tensor-core GEMM, BK=32, 3-stage cp.async ============
// smem stage layout (bf16 elems): Ahi[128*40]=0, Alo=5120, Bhi[32*136]=10240,
// Blo=14592; stage size 18944 elems (37888 B); 3 stages = 113664 B.
#define G_STG   18944
#define G_ALO   5120
#define G_BHI   10240
#define G_BLO   14592
#define G_SMEM  (3 * G_STG * 2)
#define G_NT    (CDIM / 32)   // 32

template<int NTOT, bool QKV_EPI>
__global__ void __launch_bounds__(256, 1)
mma_gemm_kernel(const __nv_bfloat16* __restrict__ Ahi,
                const __nv_bfloat16* __restrict__ Alo,
                const __nv_bfloat16* __restrict__ Bhi,
                const __nv_bfloat16* __restrict__ Blo,
                const float* __restrict__ bias, float* __restrict__ out) {
    extern __shared__ __align__(16) char smraw[];
    const uint32_t smu = s2u(smraw);

    const int tid = threadIdx.x, lane = tid & 31, wid = tid >> 5;
    const int wm = wid >> 2, wn = wid & 3;
    const int m0 = blockIdx.y * 128, n0 = blockIdx.x * 128;

    // staging maps
    const int s_ar = tid >> 2, s_ak = (tid & 3) * 8;       // + 64 rows on it=1
    const int s_br = tid >> 4, s_bn = (tid & 15) * 8;      // + 16 rows on it=1

    auto stage = [&](int kt, int s) {
        const int k0 = kt * 32;
        const uint32_t sb = smu + s * G_STG * 2;
#pragma unroll
        for (int it = 0; it < 2; it++) {
            const int r = s_ar + it * 64;
            cp16(sb + (r * 40 + s_ak) * 2, Ahi + (size_t)(m0 + r) * CDIM + k0 + s_ak);
            cp16(sb + (G_ALO + r * 40 + s_ak) * 2, Alo + (size_t)(m0 + r) * CDIM + k0 + s_ak);
            const int rb = s_br + it * 16;
            cp16(sb + (G_BHI + rb * 136 + s_bn) * 2, Bhi + (size_t)(k0 + rb) * NTOT + n0 + s_bn);
            cp16(sb + (G_BLO + rb * 136 + s_bn) * 2, Blo + (size_t)(k0 + rb) * NTOT + n0 + s_bn);
        }
    };

    float acc[4][4][4];
#pragma unroll
    for (int i = 0; i < 4; i++)
#pragma unroll
        for (int j = 0; j < 4; j++)
#pragma unroll
            for (int q = 0; q < 4; q++) acc[i][j][q] = 0.f;

    const int a_ld = (wm * 64 + (lane & 15)) * 40 + (lane >> 4) * 8;
    const int b_ld = (lane & 15) * 136 + wn * 32 + (lane >> 4) * 8;

    stage(0, 0); cp_commit();
    stage(1, 1); cp_commit();

    for (int kt = 0; kt < G_NT; kt++) {
        if (kt < G_NT - 1) cp_wait<1>(); else cp_wait<0>();
        __syncthreads();
        if (kt + 2 < G_NT) { stage(kt + 2, (kt + 2) % 3); cp_commit(); }

        const uint32_t sb = smu + (kt % 3) * G_STG * 2;
#pragma unroll
        for (int ks = 0; ks < 2; ks++) {
            unsigned ah[4][4], al[4][4], bh[4][2], bl[4][2];
            const uint32_t aBh = sb + (a_ld + ks * 16) * 2;
            const uint32_t aBl = aBh + G_ALO * 2;
            const uint32_t bBh = sb + (G_BHI + b_ld + ks * 16 * 136) * 2;
            const uint32_t bBl = bBh + (G_BLO - G_BHI) * 2;
#pragma unroll
            for (int mt = 0; mt < 4; mt++) {
                ldsm_x4(ah[mt], aBh + mt * 16 * 40 * 2);
                ldsm_x4(al[mt], aBl + mt * 16 * 40 * 2);
            }
#pragma unroll
            for (int ntp = 0; ntp < 2; ntp++) {
                unsigned t4[4];
                ldsm_x4t(t4, bBh + ntp * 16 * 2);
                bh[2 * ntp][0] = t4[0]; bh[2 * ntp][1] = t4[1];
                bh[2 * ntp + 1][0] = t4[2]; bh[2 * ntp + 1][1] = t4[3];
                ldsm_x4t(t4, bBl + ntp * 16 * 2);
                bl[2 * ntp][0] = t4[0]; bl[2 * ntp][1] = t4[1];
                bl[2 * ntp + 1][0] = t4[2]; bl[2 * ntp + 1][1] = t4[3];
            }
#pragma unroll
            for (int mt = 0; mt < 4; mt++)
#pragma unroll
                for (int nt = 0; nt < 4; nt++) {
                    mma_bf16(acc[mt][nt], ah[mt], bh[nt]);
                    mma_bf16(acc[mt][nt], ah[mt], bl[nt]);
                    mma_bf16(acc[mt][nt], al[mt], bh[nt]);
                }
        }
    }

    // epilogue
    const int rb = m0 + wm * 64 + (lane >> 2);
    const int cb = n0 + wn * 32 + (lane & 3) * 2;
#pragma unroll
    for (int mt = 0; mt < 4; mt++)
#pragma unroll
        for (int nt = 0; nt < 4; nt++) {
            const int c = cb + nt * 8;
            if (QKV_EPI) {
                const int sec = c >> 10, h = (c & 1023) >> 6, d = c & 63;
                __nv_bfloat16 *dhi, *dlo;
                if (sec == 0)      { dhi = g_qhi; dlo = g_qlo; }
                else if (sec == 1) { dhi = g_khi; dlo = g_klo; }
                else               { dhi = g_vhi; dlo = g_vlo; }
#pragma unroll
                for (int half = 0; half < 2; half++) {
                    const int r = rb + mt * 16 + half * 8;
                    const int bidx = r >> 11, n = r & (NSEQ - 1);
                    size_t off = (((size_t)bidx * HN + h) * NSEQ + n) * DH + d;
                    float v0 = acc[mt][nt][2 * half], v1 = acc[mt][nt][2 * half + 1];
                    __nv_bfloat162 hh = __floats2bfloat162_rn(v0, v1);
                    __nv_bfloat162 ll = __floats2bfloat162_rn(
                        v0 - __bfloat162float(hh.x), v1 - __bfloat162float(hh.y));
                    *(__nv_bfloat162*)&dhi[off] = hh;
                    *(__nv_bfloat162*)&dlo[off] = ll;
                }
            } else {
                const float b0 = bias[c], b1 = bias[c + 1];
#pragma unroll
                for (int half = 0; half < 2; half++) {
                    const int r = rb + mt * 16 + half * 8;
                    float* p = out + (size_t)r * NTOT + c;
                    *(float2*)p = make_float2(acc[mt][nt][2 * half] + b0,
                                              acc[mt][nt][2 * half + 1] + b1);
                }
            }
        }
}

// =============== Flash attention, tensor cores + cp.async double-buffer ======
// smem (bf16 elems): Qh=0 (128*72), Ql=9216, KV[2] at 18432 + buf*18432
// (per buf: Kh=0, Kl=4608, Vh=9216, Vl=13824); mrow[2][64] bytes at end.
#define QP 72
#define F_KV0   18432
#define F_KVSZ  18432
#define F_MROWB (55296 * 2)
#define FLASH_MMA_SMEM (F_MROWB + 128)

__global__ void __launch_bounds__(256, 1) flash_mma_kernel() {
    extern __shared__ __align__(16) char smraw[];
    __nv_bfloat16* smb = (__nv_bfloat16*)smraw;
    const uint32_t smu = s2u(smraw);
    __nv_bfloat16* sQh = smb;
    __nv_bfloat16* sQl = smb + 9216;
    unsigned char* mrow = (unsigned char*)(smraw + F_MROWB);  // [2][64]

    const int tid = threadIdx.x, lane = tid & 31, wid = tid >> 5;
    const int qt = blockIdx.x, h = blockIdx.y, b = blockIdx.z;
    const int q0 = qt * 128;
    const int cstart = g_causal_d;
    const size_t hoff = ((size_t)b * HN + h) * NSEQ * DH;

    const __nv_bfloat16 *Qh = g_qhi + hoff, *Ql = g_qlo + hoff;
    const __nv_bfloat16* kvsrc[4] = {g_khi + hoff, g_klo + hoff,
                                     g_vhi + hoff, g_vlo + hoff};

    // stage Q tile (128 x 64, hi+lo) — regular stores, covered by first sync
    {
        const int r = tid >> 1, c0 = (tid & 1) * 32;
#pragma unroll
        for (int c = 0; c < 32; c += 8) {
            *(uint4*)&sQh[r * QP + c0 + c] = *(const uint4*)&Qh[(size_t)(q0 + r) * DH + c0 + c];
            *(uint4*)&sQl[r * QP + c0 + c] = *(const uint4*)&Ql[(size_t)(q0 + r) * DH + c0 + c];
        }
    }

    const int kv_r = tid >> 3, kv_c = (tid & 7) * 8;   // + 32 rows on half=1
    auto stageKV = [&](int t) {
        const int k0t = t * 64;
        const uint32_t base = smu + (F_KV0 + (t & 1) * F_KVSZ) * 2;
#pragma unroll
        for (int pl = 0; pl < 4; pl++)
#pragma unroll
            for (int half = 0; half < 2; half++) {
                const int r = kv_r + half * 32;
                cp16(base + (pl * 4608 + r * QP + kv_c) * 2,
                     kvsrc[pl] + (size_t)(k0t + r) * DH + kv_c);
            }
    };

    int kmaxi = q0 + 127;
    if (cstart - 1 > kmaxi) kmaxi = cstart - 1;
    if (kmaxi > NSEQ - 1) kmaxi = NSEQ - 1;
    const int ntiles = kmaxi / 64 + 1;

    stageKV(0); cp_commit();
    if (tid < 64) mrow[tid] = g_maskc[(size_t)b * NSEQ + tid];

    unsigned qfh[4][4], qfl[4][4];
    float m0v = -1e30f, m1v = -1e30f, l0v = 0.f, l1v = 0.f;
    float oacc[8][4] = {};

    const int grow0 = q0 + wid * 16 + (lane >> 2);
    const int grow1 = grow0 + 8;

    for (int t = 0; t < ntiles; t++) {
        const int k0t = t * 64;
        __syncthreads();                 // Q visible (t=0); frees buffer (t+1)&1
        if (t == 0) {
#pragma unroll
            for (int ks = 0; ks < 4; ks++) {
                const int qa = (wid * 16 + (lane & 15)) * QP + ks * 16 + (lane >> 4) * 8;
                ldsm_x4(qfh[ks], s2u(&sQh[qa]));
                ldsm_x4(qfl[ks], s2u(&sQl[qa]));
            }
        }
        if (t + 1 < ntiles) {
            stageKV(t + 1);
            if (tid < 64)
                mrow[((t + 1) & 1) * 64 + tid] = g_maskc[(size_t)b * NSEQ + (t + 1) * 64 + tid];
            cp_commit();
            cp_wait<1>();
        } else {
            cp_wait<0>();
        }
        __syncthreads();                 // KV tile t visible to all warps

        const __nv_bfloat16* kb = smb + F_KV0 + (t & 1) * F_KVSZ;
        const __nv_bfloat16* sKh = kb;
        const __nv_bfloat16* sKl = kb + 4608;
        const __nv_bfloat16* sVh = kb + 9216;
        const __nv_bfloat16* sVl = kb + 13824;
        const unsigned char* mr = mrow + (t & 1) * 64;

        // ---- S = Q K^T ----
        float sacc[8][4] = {};
#pragma unroll
        for (int ks = 0; ks < 4; ks++) {
            unsigned kbh[8][2], kbl[8][2];
#pragma unroll
            for (int np = 0; np < 4; np++) {
                const int row = np * 16 + ((lane >> 4) & 1) * 8 + (lane & 7);
                const int col = ks * 16 + ((lane >> 3) & 1) * 8;
                unsigned t4[4];
                ldsm_x4(t4, s2u(&sKh[row * QP + col]));
                kbh[2 * np][0] = t4[0]; kbh[2 * np][1] = t4[1];
                kbh[2 * np + 1][0] = t4[2]; kbh[2 * np + 1][1] = t4[3];
                ldsm_x4(t4, s2u(&sKl[row * QP + col]));
                kbl[2 * np][0] = t4[0]; kbl[2 * np][1] = t4[1];
                kbl[2 * np + 1][0] = t4[2]; kbl[2 * np + 1][1] = t4[3];
            }
#pragma unroll
            for (int nt = 0; nt < 8; nt++) {
                mma_bf16(sacc[nt], qfh[ks], kbh[nt]);
                mma_bf16(sacc[nt], qfh[ks], kbl[nt]);
                mma_bf16(sacc[nt], qfl[ks], kbh[nt]);
            }
        }

        // ---- scale + masks + row max ----
        float tmax0 = -INFINITY, tmax1 = -INFINITY;
#pragma unroll
        for (int nt = 0; nt < 8; nt++) {
#pragma unroll
            for (int j = 0; j < 2; j++) {
                const int lc = nt * 8 + (lane & 3) * 2 + j;
                const int col = k0t + lc;
                const bool pad = mr[lc] != 0;
                float v0 = sacc[nt][j] * 0.125f;
                float v1 = sacc[nt][2 + j] * 0.125f;
                v0 = (pad || (col > grow0 && col >= cstart)) ? -INFINITY : v0;
                v1 = (pad || (col > grow1 && col >= cstart)) ? -INFINITY : v1;
                sacc[nt][j] = v0; sacc[nt][2 + j] = v1;
                tmax0 = fmaxf(tmax0, v0); tmax1 = fmaxf(tmax1, v1);
            }
        }
#pragma unroll
        for (int off = 1; off < 4; off <<= 1) {
            tmax0 = fmaxf(tmax0, __shfl_xor_sync(0xffffffffu, tmax0, off));
            tmax1 = fmaxf(tmax1, __shfl_xor_sync(0xffffffffu, tmax1, off));
        }

        // ---- online softmax update ----
        const float mn0 = fmaxf(m0v, tmax0), mn1 = fmaxf(m1v, tmax1);
        const float cr0 = __expf(m0v - mn0), cr1 = __expf(m1v - mn1);
        m0v = mn0; m1v = mn1;
        l0v *= cr0; l1v *= cr1;
#pragma unroll
        for (int nt = 0; nt < 8; nt++) {
            oacc[nt][0] *= cr0; oacc[nt][1] *= cr0;
            oacc[nt][2] *= cr1; oacc[nt][3] *= cr1;
        }
        float rs0 = 0.f, rs1 = 0.f;
#pragma unroll
        for (int nt = 0; nt < 8; nt++) {
            float p0 = __expf(sacc[nt][0] - mn0), p1 = __expf(sacc[nt][1] - mn0);
            float p2 = __expf(sacc[nt][2] - mn1), p3 = __expf(sacc[nt][3] - mn1);
            sacc[nt][0] = p0; sacc[nt][1] = p1; sacc[nt][2] = p2; sacc[nt][3] = p3;
            rs0 += p0 + p1; rs1 += p2 + p3;
        }
#pragma unroll
        for (int off = 1; off < 4; off <<= 1) {
            rs0 += __shfl_xor_sync(0xffffffffu, rs0, off);
            rs1 += __shfl_xor_sync(0xffffffffu, rs1, off);
        }
        l0v += rs0; l1v += rs1;

        // ---- O += P V ----
#pragma unroll
        for (int ks = 0; ks < 4; ks++) {
            unsigned ah[4], al[4];
            {
                const float v0 = sacc[2 * ks][0], v1 = sacc[2 * ks][1];
                const float v2 = sacc[2 * ks][2], v3 = sacc[2 * ks][3];
                const float w0 = sacc[2 * ks + 1][0], w1 = sacc[2 * ks + 1][1];
                const float w2 = sacc[2 * ks + 1][2], w3 = sacc[2 * ks + 1][3];
                __nv_bfloat162 h0 = __floats2bfloat162_rn(v0, v1);
                __nv_bfloat162 h1 = __floats2bfloat162_rn(v2, v3);
                __nv_bfloat162 h2 = __floats2bfloat162_rn(w0, w1);
                __nv_bfloat162 h3 = __floats2bfloat162_rn(w2, w3);
                ah[0] = bf2u(h0); ah[1] = bf2u(h1); ah[2] = bf2u(h2); ah[3] = bf2u(h3);
                al[0] = bf2u(__floats2bfloat162_rn(v0 - __bfloat162float(h0.x),
                                                   v1 - __bfloat162float(h0.y)));
                al[1] = bf2u(__floats2bfloat162_rn(v2 - __bfloat162float(h1.x),
                                                   v3 - __bfloat162float(h1.y)));
                al[2] = bf2u(__floats2bfloat162_rn(w0 - __bfloat162float(h2.x),
                                                   w1 - __bfloat162float(h2.y)));
                al[3] = bf2u(__floats2bfloat162_rn(w2 - __bfloat162float(h3.x),
                                                   w3 - __bfloat162float(h3.y)));
            }
#pragma unroll
            for (int np = 0; np < 4; np++) {
                const int va = (ks * 16 + (lane & 15)) * QP + np * 16 + (lane >> 4) * 8;
                unsigned t4[4], t4l[4];
                ldsm_x4t(t4, s2u(&sVh[va]));
                ldsm_x4t(t4l, s2u(&sVl[va]));
                unsigned vb0[2] = {t4[0], t4[1]}, vb1[2] = {t4[2], t4[3]};
                unsigned vl0[2] = {t4l[0], t4l[1]}, vl1[2] = {t4l[2], t4l[3]};
                mma_bf16(oacc[2 * np], ah, vb0);
                mma_bf16(oacc[2 * np], ah, vl0);
                mma_bf16(oacc[2 * np], al, vb0);
                mma_bf16(oacc[2 * np + 1], ah, vb1);
                mma_bf16(oacc[2 * np + 1], ah, vl1);
                mma_bf16(oacc[2 * np + 1], al, vb1);
            }
        }
    }

    // ---- normalize + write bf16 hi/lo att ----
    const float inv0 = 1.f / l0v, inv1 = 1.f / l1v;
#pragma unroll
    for (int nt = 0; nt < 8; nt++) {
        const int d = nt * 8 + (lane & 3) * 2;
        const size_t o0 = ((size_t)b * NSEQ + grow0) * CDIM + h * DH + d;
        const size_t o1 = ((size_t)b * NSEQ + grow1) * CDIM + h * DH + d;
        const float v0 = oacc[nt][0] * inv0, v1 = oacc[nt][1] * inv0;
        const float w0 = oacc[nt][2] * inv1, w1 = oacc[nt][3] * inv1;
        __nv_bfloat162 h0 = __floats2bfloat162_rn(v0, v1);
        *(__nv_bfloat162*)&g_ahi[o0] = h0;
        *(__nv_bfloat162*)&g_alo[o0] = __floats2bfloat162_rn(
            v0 - __bfloat162float(h0.x), v1 - __bfloat162float(h0.y));
        __nv_bfloat162 h1 = __floats2bfloat162_rn(w0, w1);
        *(__nv_bfloat162*)&g_ahi[o1] = h1;
        *(__nv_bfloat162*)&g_alo[o1] = __floats2bfloat162_rn(
            w0 - __bfloat162float(h1.x), w1 - __bfloat162float(h1.y));
    }
}

// ---------------- launch ------------------------------------------------------
extern "C" void kernel_launch(void* const* d_in, const int* in_sizes, int n_in,
                              void* d_out, int out_size) {
    (void)n_in; (void)out_size;
    const float* x     = (const float*)d_in[0];
    const void*  mask  = d_in[1];
    const int*   cs    = (const int*)d_in[2];
    const float* wqkv  = (const float*)d_in[3];
    const float* wproj = (const float*)d_in[4];
    const float* bproj = (const float*)d_in[5];
    float* out = (float*)d_out;

    prep_kernel<<<1, 256>>>(mask, cs, in_sizes[1]);

    __nv_bfloat16 *xhi, *xlo, *wqhi, *wqlo, *wphi, *wplo, *ahi, *alo;
    cudaGetSymbolAddress((void**)&xhi, g_xhi);   cudaGetSymbolAddress((void**)&xlo, g_xlo);
    cudaGetSymbolAddress((void**)&wqhi, g_wqhi); cudaGetSymbolAddress((void**)&wqlo, g_wqlo);
    cudaGetSymbolAddress((void**)&wphi, g_wphi); cudaGetSymbolAddress((void**)&wplo, g_wplo);
    cudaGetSymbolAddress((void**)&ahi, g_ahi);   cudaGetSymbolAddress((void**)&alo, g_alo);

    const int nx = MROWS * CDIM, nwq = CDIM * QKVC, nwp = CDIM * CDIM;
    split_kernel<<<(nx + 255) / 256, 256>>>(x, xhi, xlo, nx);
    split_kernel<<<(nwq + 255) / 256, 256>>>(wqkv, wqhi, wqlo, nwq);
    split_kernel<<<(nwp + 255) / 256, 256>>>(wproj, wphi, wplo, nwp);

    cudaFuncSetAttribute(mma_gemm_kernel<QKVC, true>,
                         cudaFuncAttributeMaxDynamicSharedMemorySize, G_SMEM);
    cudaFuncSetAttribute(mma_gemm_kernel<CDIM, false>,
                         cudaFuncAttributeMaxDynamicSharedMemorySize, G_SMEM);
    cudaFuncSetAttribute(flash_mma_kernel,
                         cudaFuncAttributeMaxDynamicSharedMemorySize, FLASH_MMA_SMEM);

    dim3 g1(QKVC / 128, MROWS / 128);
    mma_gemm_kernel<QKVC, true><<<g1, 256, G_SMEM>>>(xhi, xlo, wqhi, wqlo, nullptr, nullptr);

    dim3 g2(NSEQ / 128, HN, BB);
    flash_mma_kernel<<<g2, 256, FLASH_MMA_SMEM>>>();

    dim3 g3(CDIM / 128, MROWS / 128);
    mma_gemm_kernel<CDIM, false><<<g3, 256, G_SMEM>>>(ahi, alo, wphi, wplo, bproj, out);
}

// round 8
// speedup vs baseline: 2.7528x; 1.0836x over previous
#include <cuda_runtime.h>
#include <cuda_bf16.h>
#include <math.h>
#include <stdint.h>

#define BB    2
#define NSEQ  2048
#define CDIM  1024
#define HN    16
#define DH    64
#define MROWS (BB*NSEQ)     // 4096
#define QKVC  (3*CDIM)      // 3072

// ---------------- scratch (static device globals; no allocation) -------------
__device__ __align__(16) __nv_bfloat16 g_xhi[(size_t)MROWS*CDIM], g_xlo[(size_t)MROWS*CDIM];
__device__ __align__(16) __nv_bfloat16 g_wqhi[(size_t)CDIM*QKVC], g_wqlo[(size_t)CDIM*QKVC];
__device__ __align__(16) __nv_bfloat16 g_wphi[(size_t)CDIM*CDIM], g_wplo[(size_t)CDIM*CDIM];
__device__ __align__(16) __nv_bfloat16 g_ahi[(size_t)MROWS*CDIM], g_alo[(size_t)MROWS*CDIM];
__device__ __align__(16) __nv_bfloat16 g_qhi[(size_t)BB*HN*NSEQ*DH], g_qlo[(size_t)BB*HN*NSEQ*DH];
__device__ __align__(16) __nv_bfloat16 g_khi[(size_t)BB*HN*NSEQ*DH], g_klo[(size_t)BB*HN*NSEQ*DH];
__device__ __align__(16) __nv_bfloat16 g_vhi[(size_t)BB*HN*NSEQ*DH], g_vlo[(size_t)BB*HN*NSEQ*DH];
__device__ unsigned char g_maskc[BB*NSEQ];
__device__ int g_causal_d;

// ---------------- prep: canonicalize mask dtype + causal_start ---------------
__global__ void prep_kernel(const void* __restrict__ mask_raw,
                            const int* __restrict__ cs_raw, int nmask) {
    __shared__ int sfmt;
    const unsigned char* mb = (const unsigned char*)mask_raw;
    if (threadIdx.x == 0) {
        bool nz1 = false, nz3 = false;
        int scan = nmask < 1024 ? nmask : 1024;
        for (int i = 0; i < scan; i++) {
            unsigned char v = mb[i];
            if (v) { int r = i & 3; if (r == 1) nz1 = true; else if (r == 3) nz3 = true; }
        }
        sfmt = nz1 ? 0 : (nz3 ? 2 : 1);  // 0=u8, 1=i32, 2=f32
        int cv = cs_raw[0];
        if (cv < 0 || cv > (1 << 24)) cv = (int)__int_as_float(cv);
        g_causal_d = cv;
    }
    __syncthreads();
    int f = sfmt;
    for (int i = threadIdx.x; i < nmask; i += blockDim.x) {
        unsigned char m;
        if (f == 0)      m = mb[i] != 0;
        else if (f == 1) m = ((const int*)mask_raw)[i] != 0;
        else             m = ((const float*)mask_raw)[i] != 0.0f;
        g_maskc[i] = m;
    }
}

// ---------------- split fp32 -> bf16 hi + lo ---------------------------------
__global__ void split_kernel(const float* __restrict__ src,
                             __nv_bfloat16* __restrict__ hi,
                             __nv_bfloat16* __restrict__ lo, int n) {
    int i = blockIdx.x * blockDim.x + threadIdx.x;
    if (i < n) {
        float v = src[i];
        __nv_bfloat16 h = __float2bfloat16(v);
        hi[i] = h;
        lo[i] = __float2bfloat16(v - __bfloat162float(h));
    }
}

// ---------------- PTX helpers -------------------------------------------------
__device__ __forceinline__ uint32_t s2u(const void* p) {
    return (uint32_t)__cvta_generic_to_shared(p);
}
__device__ __forceinline__ void ldsm_x4(unsigned* r, uint32_t addr) {
    asm volatile("ldmatrix.sync.aligned.m8n8.x4.shared.b16 {%0,%1,%2,%3}, [%4];"
                 : "=r"(r[0]), "=r"(r[1]), "=r"(r[2]), "=r"(r[3]) : "r"(addr));
}
__device__ __forceinline__ void ldsm_x4t(unsigned* r, uint32_t addr) {
    asm volatile("ldmatrix.sync.aligned.m8n8.x4.trans.shared.b16 {%0,%1,%2,%3}, [%4];"
                 : "=r"(r[0]), "=r"(r[1]), "=r"(r[2]), "=r"(r[3]) : "r"(addr));
}
__device__ __forceinline__ void mma_bf16(float* d, const unsigned* a, const unsigned* b) {
    asm volatile("mma.sync.aligned.m16n8k16.row.col.f32.bf16.bf16.f32 "
                 "{%0,%1,%2,%3}, {%4,%5,%6,%7}, {%8,%9}, {%0,%1,%2,%3};"
                 : "+f"(d[0]), "+f"(d[1]), "+f"(d[2]), "+f"(d[3])
                 : "r"(a[0]), "r"(a[1]), "r"(a[2]), "r"(a[3]), "r"(b[0]), "r"(b[1]));
}
__device__ __forceinline__ unsigned bf2u(__nv_bfloat162 x) { return *(unsigned*)&x; }
__device__ __forceinline__ void cp16(uint32_t smem, const void* g) {
    asm volatile("cp.async.cg.shared.global [%0], [%1], 16;"
                 :: "r"(smem), "l"(__cvta_generic_to_global(g)) : "memory");
}
__device__ __forceinline__ void cp_commit() {
    asm volatile("cp.async.commit_group;" ::: "memory");
}
template<int N> __device__ __forceinline__ void cp_wait() {
    asm volatile("cp.async.wait_group %0;" :: "n"(N) : "memory");
}

// =============== bf16x3 tensor-core GEMM, BK=32, 2-stage, 2 CTAs/SM ==========
// smem stage (bf16 elems): Ahi[128*40]=0, Alo=5120, Bhi[32*136]=10240, Blo=14592
#define G_STG   18944
#define G_ALO   5120
#define G_BHI   10240
#define G_BLO   14592
#define G_SMEM  (2 * G_STG * 2)       // 75776 B
#define G_NT    (CDIM / 32)           // 32

template<int NTOT, bool QKV_EPI>
__global__ void __launch_bounds__(256, 2)
mma_gemm_kernel(const __nv_bfloat16* __restrict__ Ahi,
                const __nv_bfloat16* __restrict__ Alo,
                const __nv_bfloat16* __restrict__ Bhi,
                const __nv_bfloat16* __restrict__ Blo,
                const float* __restrict__ bias, float* __restrict__ out) {
    extern __shared__ __align__(16) char smraw[];
    const uint32_t smu = s2u(smraw);

    const int tid = threadIdx.x, lane = tid & 31, wid = tid >> 5;
    const int wm = wid >> 2, wn = wid & 3;
    const int m0 = blockIdx.y * 128, n0 = blockIdx.x * 128;

    const int s_ar = tid >> 2, s_ak = (tid & 3) * 8;
    const int s_br = tid >> 4, s_bn = (tid & 15) * 8;

    auto stage = [&](int kt, int s) {
        const int k0 = kt * 32;
        const uint32_t sb = smu + s * G_STG * 2;
#pragma unroll
        for (int it = 0; it < 2; it++) {
            const int r = s_ar + it * 64;
            cp16(sb + (r * 40 + s_ak) * 2, Ahi + (size_t)(m0 + r) * CDIM + k0 + s_ak);
            cp16(sb + (G_ALO + r * 40 + s_ak) * 2, Alo + (size_t)(m0 + r) * CDIM + k0 + s_ak);
            const int rb = s_br + it * 16;
            cp16(sb + (G_BHI + rb * 136 + s_bn) * 2, Bhi + (size_t)(k0 + rb) * NTOT + n0 + s_bn);
            cp16(sb + (G_BLO + rb * 136 + s_bn) * 2, Blo + (size_t)(k0 + rb) * NTOT + n0 + s_bn);
        }
    };

    float acc[4][4][4];
#pragma unroll
    for (int i = 0; i < 4; i++)
#pragma unroll
        for (int j = 0; j < 4; j++)
#pragma unroll
            for (int q = 0; q < 4; q++) acc[i][j][q] = 0.f;

    const int a_ld = (wm * 64 + (lane & 15)) * 40 + (lane >> 4) * 8;
    const int b_ld = (lane & 15) * 136 + wn * 32 + (lane >> 4) * 8;

    stage(0, 0); cp_commit();
    stage(1, 1); cp_commit();

    for (int kt = 0; kt < G_NT; kt++) {
        if (kt == G_NT - 1) cp_wait<0>(); else cp_wait<1>();
        __syncthreads();

        const uint32_t sb = smu + (kt & 1) * G_STG * 2;
#pragma unroll
        for (int ks = 0; ks < 2; ks++) {
            unsigned ah[4][4], al[4][4], bh[4][2], bl[4][2];
            const uint32_t aBh = sb + (a_ld + ks * 16) * 2;
            const uint32_t aBl = aBh + G_ALO * 2;
            const uint32_t bBh = sb + (G_BHI + b_ld + ks * 16 * 136) * 2;
            const uint32_t bBl = bBh + (G_BLO - G_BHI) * 2;
#pragma unroll
            for (int mt = 0; mt < 4; mt++) {
                ldsm_x4(ah[mt], aBh + mt * 16 * 40 * 2);
                ldsm_x4(al[mt], aBl + mt * 16 * 40 * 2);
            }
#pragma unroll
            for (int ntp = 0; ntp < 2; ntp++) {
                unsigned t4[4];
                ldsm_x4t(t4, bBh + ntp * 16 * 2);
                bh[2 * ntp][0] = t4[0]; bh[2 * ntp][1] = t4[1];
                bh[2 * ntp + 1][0] = t4[2]; bh[2 * ntp + 1][1] = t4[3];
                ldsm_x4t(t4, bBl + ntp * 16 * 2);
                bl[2 * ntp][0] = t4[0]; bl[2 * ntp][1] = t4[1];
                bl[2 * ntp + 1][0] = t4[2]; bl[2 * ntp + 1][1] = t4[3];
            }
#pragma unroll
            for (int mt = 0; mt < 4; mt++)
#pragma unroll
                for (int nt = 0; nt < 4; nt++) {
                    mma_bf16(acc[mt][nt], ah[mt], bh[nt]);
                    mma_bf16(acc[mt][nt], ah[mt], bl[nt]);
                    mma_bf16(acc[mt][nt], al[mt], bh[nt]);
                }
        }
        __syncthreads();
        if (kt + 2 < G_NT) { stage(kt + 2, kt & 1); cp_commit(); }
    }

    // epilogue
    const int rb = m0 + wm * 64 + (lane >> 2);
    const int cb = n0 + wn * 32 + (lane & 3) * 2;
#pragma unroll
    for (int mt = 0; mt < 4; mt++)
#pragma unroll
        for (int nt = 0; nt < 4; nt++) {
            const int c = cb + nt * 8;
            if (QKV_EPI) {
                const int sec = c >> 10, h = (c & 1023) >> 6, d = c & 63;
                const float scl = (sec == 0) ? 0.125f : 1.0f;  // pre-scale Q by 1/sqrt(d)/... (1/8)
                __nv_bfloat16 *dhi, *dlo;
                if (sec == 0)      { dhi = g_qhi; dlo = g_qlo; }
                else if (sec == 1) { dhi = g_khi; dlo = g_klo; }
                else               { dhi = g_vhi; dlo = g_vlo; }
#pragma unroll
                for (int half = 0; half < 2; half++) {
                    const int r = rb + mt * 16 + half * 8;
                    const int bidx = r >> 11, n = r & (NSEQ - 1);
                    size_t off = (((size_t)bidx * HN + h) * NSEQ + n) * DH + d;
                    float v0 = acc[mt][nt][2 * half] * scl, v1 = acc[mt][nt][2 * half + 1] * scl;
                    __nv_bfloat162 hh = __floats2bfloat162_rn(v0, v1);
                    __nv_bfloat162 ll = __floats2bfloat162_rn(
                        v0 - __bfloat162float(hh.x), v1 - __bfloat162float(hh.y));
                    *(__nv_bfloat162*)&dhi[off] = hh;
                    *(__nv_bfloat162*)&dlo[off] = ll;
                }
            } else {
                const float b0 = bias[c], b1 = bias[c + 1];
#pragma unroll
                for (int half = 0; half < 2; half++) {
                    const int r = rb + mt * 16 + half * 8;
                    float* p = out + (size_t)r * NTOT + c;
                    *(float2*)p = make_float2(acc[mt][nt][2 * half] + b0,
                                              acc[mt][nt][2 * half + 1] + b1);
                }
            }
        }
}

// =============== Flash attention: Br=128, Bc=128, bf16x3 mma.sync ============
// smem (bf16 elems): Qh=0 (128*72), Ql=9216, KV bufs at 18432 + buf*36864
// (per buf: Kh=0, Kl=9216, Vh=18432, Vl=27648); mrow[2][128] bytes at 184320.
#define QP 72
#define F_KV0   18432
#define F_BUF   36864
#define F_MROWB 184320
#define FLASH_MMA_SMEM (F_MROWB + 256)

__global__ void __launch_bounds__(256, 1) flash_mma_kernel() {
    extern __shared__ __align__(16) char smraw[];
    __nv_bfloat16* smb = (__nv_bfloat16*)smraw;
    const uint32_t smu = s2u(smraw);
    __nv_bfloat16* sQh = smb;
    __nv_bfloat16* sQl = smb + 9216;
    unsigned char* mrow = (unsigned char*)(smraw + F_MROWB);  // [2][128]

    const int tid = threadIdx.x, lane = tid & 31, wid = tid >> 5;
    const int qt = gridDim.x - 1 - blockIdx.x;   // heavy tiles first
    const int h = blockIdx.y, b = blockIdx.z;
    const int q0 = qt * 128;
    const int cstart = g_causal_d;
    const size_t hoff = ((size_t)b * HN + h) * NSEQ * DH;

    const __nv_bfloat16 *Qh = g_qhi + hoff, *Ql = g_qlo + hoff;
    const __nv_bfloat16* kvsrc[4] = {g_khi + hoff, g_klo + hoff,
                                     g_vhi + hoff, g_vlo + hoff};

    // stage Q tile (128 x 64, hi+lo) — plain stores, covered by first sync
    {
        const int r = tid >> 1, c0 = (tid & 1) * 32;
#pragma unroll
        for (int c = 0; c < 32; c += 8) {
            *(uint4*)&sQh[r * QP + c0 + c] = *(const uint4*)&Qh[(size_t)(q0 + r) * DH + c0 + c];
            *(uint4*)&sQl[r * QP + c0 + c] = *(const uint4*)&Ql[(size_t)(q0 + r) * DH + c0 + c];
        }
    }

    // KV staging: 128 rows x 64 cols x 4 planes per buffer (16 cp16 / thread)
    const int kv_r = tid >> 1, kv_c0 = (tid & 1) * 32;
    auto stageKV = [&](int t) {
        const int k0t = t * 128;
        const uint32_t base = smu + (F_KV0 + (t & 1) * F_BUF) * 2;
#pragma unroll
        for (int pl = 0; pl < 4; pl++)
#pragma unroll
            for (int j = 0; j < 4; j++)
                cp16(base + (pl * 9216 + kv_r * QP + kv_c0 + j * 8) * 2,
                     kvsrc[pl] + (size_t)(k0t + kv_r) * DH + kv_c0 + j * 8);
    };

    int kmaxi = q0 + 127;
    if (cstart - 1 > kmaxi) kmaxi = cstart - 1;
    if (kmaxi > NSEQ - 1) kmaxi = NSEQ - 1;
    const int ntiles = kmaxi / 128 + 1;

    stageKV(0); cp_commit();
    if (tid < 128) mrow[tid] = g_maskc[(size_t)b * NSEQ + tid];

    unsigned qfh[4][4], qfl[4][4];
    float m0v = -1e30f, m1v = -1e30f, l0v = 0.f, l1v = 0.f;
    float oacc[8][4] = {};

    const int grow0 = q0 + wid * 16 + (lane >> 2);
    const int grow1 = grow0 + 8;

    for (int t = 0; t < ntiles; t++) {
        const int k0t = t * 128;
        __syncthreads();
        if (t == 0) {
#pragma unroll
            for (int ks = 0; ks < 4; ks++) {
                const int qa = (wid * 16 + (lane & 15)) * QP + ks * 16 + (lane >> 4) * 8;
                ldsm_x4(qfh[ks], s2u(&sQh[qa]));
                ldsm_x4(qfl[ks], s2u(&sQl[qa]));
            }
        }
        if (t + 1 < ntiles) {
            stageKV(t + 1);
            if (tid < 128)
                mrow[((t + 1) & 1) * 128 + tid] = g_maskc[(size_t)b * NSEQ + (t + 1) * 128 + tid];
            cp_commit();
            cp_wait<1>();
        } else {
            cp_wait<0>();
        }
        __syncthreads();

        const __nv_bfloat16* kb = smb + F_KV0 + (t & 1) * F_BUF;
        const __nv_bfloat16* sKh = kb;
        const __nv_bfloat16* sKl = kb + 9216;
        const __nv_bfloat16* sVh = kb + 18432;
        const __nv_bfloat16* sVl = kb + 27648;
        const unsigned char* mr = mrow + (t & 1) * 128;

        // ---- S = Q K^T (128 q x 128 k; Q pre-scaled by 0.125) ----
        float sacc[16][4] = {};
#pragma unroll
        for (int ks = 0; ks < 4; ks++) {
#pragma unroll
            for (int np = 0; np < 8; np++) {
                const int row = np * 16 + ((lane >> 4) & 1) * 8 + (lane & 7);
                const int col = ks * 16 + ((lane >> 3) & 1) * 8;
                unsigned t4[4], t4l[4];
                ldsm_x4(t4, s2u(&sKh[row * QP + col]));
                ldsm_x4(t4l, s2u(&sKl[row * QP + col]));
                unsigned b0h[2] = {t4[0], t4[1]}, b1h[2] = {t4[2], t4[3]};
                unsigned b0l[2] = {t4l[0], t4l[1]}, b1l[2] = {t4l[2], t4l[3]};
                mma_bf16(sacc[2 * np], qfh[ks], b0h);
                mma_bf16(sacc[2 * np], qfh[ks], b0l);
                mma_bf16(sacc[2 * np], qfl[ks], b0h);
                mma_bf16(sacc[2 * np + 1], qfh[ks], b1h);
                mma_bf16(sacc[2 * np + 1], qfh[ks], b1l);
                mma_bf16(sacc[2 * np + 1], qfl[ks], b1h);
            }
        }

        // ---- masks + row max ----
        float tmax0 = -INFINITY, tmax1 = -INFINITY;
#pragma unroll
        for (int nt = 0; nt < 16; nt++) {
#pragma unroll
            for (int j = 0; j < 2; j++) {
                const int lc = nt * 8 + (lane & 3) * 2 + j;
                const int col = k0t + lc;
                const bool pad = mr[lc] != 0;
                float v0 = sacc[nt][j];
                float v1 = sacc[nt][2 + j];
                v0 = (pad || (col > grow0 && col >= cstart)) ? -INFINITY : v0;
                v1 = (pad || (col > grow1 && col >= cstart)) ? -INFINITY : v1;
                sacc[nt][j] = v0; sacc[nt][2 + j] = v1;
                tmax0 = fmaxf(tmax0, v0); tmax1 = fmaxf(tmax1, v1);
            }
        }
#pragma unroll
        for (int off = 1; off < 4; off <<= 1) {
            tmax0 = fmaxf(tmax0, __shfl_xor_sync(0xffffffffu, tmax0, off));
            tmax1 = fmaxf(tmax1, __shfl_xor_sync(0xffffffffu, tmax1, off));
        }

        // ---- online softmax update ----
        const float mn0 = fmaxf(m0v, tmax0), mn1 = fmaxf(m1v, tmax1);
        const float cr0 = __expf(m0v - mn0), cr1 = __expf(m1v - mn1);
        m0v = mn0; m1v = mn1;
        l0v *= cr0; l1v *= cr1;
#pragma unroll
        for (int nt = 0; nt < 8; nt++) {
            oacc[nt][0] *= cr0; oacc[nt][1] *= cr0;
            oacc[nt][2] *= cr1; oacc[nt][3] *= cr1;
        }
        float rs0 = 0.f, rs1 = 0.f;
#pragma unroll
        for (int nt = 0; nt < 16; nt++) {
            float p0 = __expf(sacc[nt][0] - mn0), p1 = __expf(sacc[nt][1] - mn0);
            float p2 = __expf(sacc[nt][2] - mn1), p3 = __expf(sacc[nt][3] - mn1);
            sacc[nt][0] = p0; sacc[nt][1] = p1; sacc[nt][2] = p2; sacc[nt][3] = p3;
            rs0 += p0 + p1; rs1 += p2 + p3;
        }
#pragma unroll
        for (int off = 1; off < 4; off <<= 1) {
            rs0 += __shfl_xor_sync(0xffffffffu, rs0, off);
            rs1 += __shfl_xor_sync(0xffffffffu, rs1, off);
        }
        l0v += rs0; l1v += rs1;

        // ---- O += P V (8 k-steps over 128 keys) ----
#pragma unroll
        for (int ks = 0; ks < 8; ks++) {
            unsigned ah[4], al[4];
            {
                const float v0 = sacc[2 * ks][0], v1 = sacc[2 * ks][1];
                const float v2 = sacc[2 * ks][2], v3 = sacc[2 * ks][3];
                const float w0 = sacc[2 * ks + 1][0], w1 = sacc[2 * ks + 1][1];
                const float w2 = sacc[2 * ks + 1][2], w3 = sacc[2 * ks + 1][3];
                __nv_bfloat162 h0 = __floats2bfloat162_rn(v0, v1);
                __nv_bfloat162 h1 = __floats2bfloat162_rn(v2, v3);
                __nv_bfloat162 h2 = __floats2bfloat162_rn(w0, w1);
                __nv_bfloat162 h3 = __floats2bfloat162_rn(w2, w3);
                ah[0] = bf2u(h0); ah[1] = bf2u(h1); ah[2] = bf2u(h2); ah[3] = bf2u(h3);
                al[0] = bf2u(__floats2bfloat162_rn(v0 - __bfloat162float(h0.x),
                                                   v1 - __bfloat162float(h0.y)));
                al[1] = bf2u(__floats2bfloat162_rn(v2 - __bfloat162float(h1.x),
                                                   v3 - __bfloat162float(h1.y)));
                al[2] = bf2u(__floats2bfloat162_rn(w0 - __bfloat162float(h2.x),
                                                   w1 - __bfloat162float(h2.y)));
                al[3] = bf2u(__floats2bfloat162_rn(w2 - __bfloat162float(h3.x),
                                                   w3 - __bfloat162float(h3.y)));
            }
#pragma unroll
            for (int np = 0; np < 4; np++) {
                const int va = (ks * 16 + (lane & 15)) * QP + np * 16 + (lane >> 4) * 8;
                unsigned t4[4], t4l[4];
                ldsm_x4t(t4, s2u(&sVh[va]));
                ldsm_x4t(t4l, s2u(&sVl[va]));
                unsigned vb0[2] = {t4[0], t4[1]}, vb1[2] = {t4[2], t4[3]};
                unsigned vl0[2] = {t4l[0], t4l[1]}, vl1[2] = {t4l[2], t4l[3]};
                mma_bf16(oacc[2 * np], ah, vb0);
                mma_bf16(oacc[2 * np], ah, vl0);
                mma_bf16(oacc[2 * np], al, vb0);
                mma_bf16(oacc[2 * np + 1], ah, vb1);
                mma_bf16(oacc[2 * np + 1], ah, vl1);
                mma_bf16(oacc[2 * np + 1], al, vb1);
            }
        }
    }

    // ---- normalize + write bf16 hi/lo att (input of proj GEMM) ----
    const float inv0 = 1.f / l0v, inv1 = 1.f / l1v;
#pragma unroll
    for (int nt = 0; nt < 8; nt++) {
        const int d = nt * 8 + (lane & 3) * 2;
        const size_t o0 = ((size_t)b * NSEQ + grow0) * CDIM + h * DH + d;
        const size_t o1 = ((size_t)b * NSEQ + grow1) * CDIM + h * DH + d;
        const float v0 = oacc[nt][0] * inv0, v1 = oacc[nt][1] * inv0;
        const float w0 = oacc[nt][2] * inv1, w1 = oacc[nt][3] * inv1;
        __nv_bfloat162 h0 = __floats2bfloat162_rn(v0, v1);
        *(__nv_bfloat162*)&g_ahi[o0] = h0;
        *(__nv_bfloat162*)&g_alo[o0] = __floats2bfloat162_rn(
            v0 - __bfloat162float(h0.x), v1 - __bfloat162float(h0.y));
        __nv_bfloat162 h1 = __floats2bfloat162_rn(w0, w1);
        *(__nv_bfloat162*)&g_ahi[o1] = h1;
        *(__nv_bfloat162*)&g_alo[o1] = __floats2bfloat162_rn(
            w0 - __bfloat162float(h1.x), w1 - __bfloat162float(h1.y));
    }
}

// ---------------- launch ------------------------------------------------------
extern "C" void kernel_launch(void* const* d_in, const int* in_sizes, int n_in,
                              void* d_out, int out_size) {
    (void)n_in; (void)out_size;
    const float* x     = (const float*)d_in[0];
    const void*  mask  = d_in[1];
    const int*   cs    = (const int*)d_in[2];
    const float* wqkv  = (const float*)d_in[3];
    const float* wproj = (const float*)d_in[4];
    const float* bproj = (const float*)d_in[5];
    float* out = (float*)d_out;

    prep_kernel<<<1, 256>>>(mask, cs, in_sizes[1]);

    __nv_bfloat16 *xhi, *xlo, *wqhi, *wqlo, *wphi, *wplo, *ahi, *alo;
    cudaGetSymbolAddress((void**)&xhi, g_xhi);   cudaGetSymbolAddress((void**)&xlo, g_xlo);
    cudaGetSymbolAddress((void**)&wqhi, g_wqhi); cudaGetSymbolAddress((void**)&wqlo, g_wqlo);
    cudaGetSymbolAddress((void**)&wphi, g_wphi); cudaGetSymbolAddress((void**)&wplo, g_wplo);
    cudaGetSymbolAddress((void**)&ahi, g_ahi);   cudaGetSymbolAddress((void**)&alo, g_alo);

    const int nx = MROWS * CDIM, nwq = CDIM * QKVC, nwp = CDIM * CDIM;
    split_kernel<<<(nx + 255) / 256, 256>>>(x, xhi, xlo, nx);
    split_kernel<<<(nwq + 255) / 256, 256>>>(wqkv, wqhi, wqlo, nwq);
    split_kernel<<<(nwp + 255) / 256, 256>>>(wproj, wphi, wplo, nwp);

    cudaFuncSetAttribute(mma_gemm_kernel<QKVC, true>,
                         cudaFuncAttributeMaxDynamicSharedMemorySize, G_SMEM);
    cudaFuncSetAttribute(mma_gemm_kernel<CDIM, false>,
                         cudaFuncAttributeMaxDynamicSharedMemorySize, G_SMEM);
    cudaFuncSetAttribute(flash_mma_kernel,
                         cudaFuncAttributeMaxDynamicSharedMemorySize, FLASH_MMA_SMEM);

    dim3 g1(QKVC / 128, MROWS / 128);
    mma_gemm_kernel<QKVC, true><<<g1, 256, G_SMEM>>>(xhi, xlo, wqhi, wqlo, nullptr, nullptr);

    dim3 g2(NSEQ / 128, HN, BB);
    flash_mma_kernel<<<g2, 256, FLASH_MMA_SMEM>>>();

    dim3 g3(CDIM / 128, MROWS / 128);
    mma_gemm_kernel<CDIM, false><<<g3, 256, G_SMEM>>>(ahi, alo, wphi, wplo, bproj, out);
}

// round 9
// speedup vs baseline: 2.7576x; 1.0017x over previous
#include <cuda_runtime.h>
#include <cuda_bf16.h>
#include <math.h>
#include <stdint.h>

#define BB    2
#define NSEQ  2048
#define CDIM  1024
#define HN    16
#define DH    64
#define MROWS (BB*NSEQ)     // 4096
#define QKVC  (3*CDIM)      // 3072

// ---------------- scratch (static device globals; no allocation) -------------
__device__ __align__(16) __nv_bfloat16 g_xhi[(size_t)MROWS*CDIM], g_xlo[(size_t)MROWS*CDIM];
__device__ __align__(16) __nv_bfloat16 g_wqhi[(size_t)CDIM*QKVC], g_wqlo[(size_t)CDIM*QKVC];
__device__ __align__(16) __nv_bfloat16 g_wphi[(size_t)CDIM*CDIM], g_wplo[(size_t)CDIM*CDIM];
__device__ __align__(16) __nv_bfloat16 g_ahi[(size_t)MROWS*CDIM], g_alo[(size_t)MROWS*CDIM];
__device__ __align__(16) __nv_bfloat16 g_qhi[(size_t)BB*HN*NSEQ*DH], g_qlo[(size_t)BB*HN*NSEQ*DH];
__device__ __align__(16) __nv_bfloat16 g_khi[(size_t)BB*HN*NSEQ*DH], g_klo[(size_t)BB*HN*NSEQ*DH];
__device__ __align__(16) __nv_bfloat16 g_vhi[(size_t)BB*HN*NSEQ*DH], g_vlo[(size_t)BB*HN*NSEQ*DH];
__device__ unsigned char g_maskc[BB*NSEQ];
__device__ int g_causal_d;

// ---------------- prep: canonicalize mask dtype + causal_start ---------------
__global__ void prep_kernel(const void* __restrict__ mask_raw,
                            const int* __restrict__ cs_raw, int nmask) {
    __shared__ int sfmt;
    const unsigned char* mb = (const unsigned char*)mask_raw;
    if (threadIdx.x == 0) {
        bool nz1 = false, nz3 = false;
        int scan = nmask < 1024 ? nmask : 1024;
        for (int i = 0; i < scan; i++) {
            unsigned char v = mb[i];
            if (v) { int r = i & 3; if (r == 1) nz1 = true; else if (r == 3) nz3 = true; }
        }
        sfmt = nz1 ? 0 : (nz3 ? 2 : 1);  // 0=u8, 1=i32, 2=f32
        int cv = cs_raw[0];
        if (cv < 0 || cv > (1 << 24)) cv = (int)__int_as_float(cv);
        g_causal_d = cv;
    }
    __syncthreads();
    int f = sfmt;
    for (int i = threadIdx.x; i < nmask; i += blockDim.x) {
        unsigned char m;
        if (f == 0)      m = mb[i] != 0;
        else if (f == 1) m = ((const int*)mask_raw)[i] != 0;
        else             m = ((const float*)mask_raw)[i] != 0.0f;
        g_maskc[i] = m;
    }
}

// ---------------- split fp32 -> bf16 hi + lo ---------------------------------
__global__ void split_kernel(const float* __restrict__ src,
                             __nv_bfloat16* __restrict__ hi,
                             __nv_bfloat16* __restrict__ lo, int n) {
    int i = blockIdx.x * blockDim.x + threadIdx.x;
    if (i < n) {
        float v = src[i];
        __nv_bfloat16 h = __float2bfloat16(v);
        hi[i] = h;
        lo[i] = __float2bfloat16(v - __bfloat162float(h));
    }
}

// ---------------- PTX helpers -------------------------------------------------
__device__ __forceinline__ uint32_t s2u(const void* p) {
    return (uint32_t)__cvta_generic_to_shared(p);
}
__device__ __forceinline__ void ldsm_x4(unsigned* r, uint32_t addr) {
    asm volatile("ldmatrix.sync.aligned.m8n8.x4.shared.b16 {%0,%1,%2,%3}, [%4];"
                 : "=r"(r[0]), "=r"(r[1]), "=r"(r[2]), "=r"(r[3]) : "r"(addr));
}
__device__ __forceinline__ void ldsm_x4t(unsigned* r, uint32_t addr) {
    asm volatile("ldmatrix.sync.aligned.m8n8.x4.trans.shared.b16 {%0,%1,%2,%3}, [%4];"
                 : "=r"(r[0]), "=r"(r[1]), "=r"(r[2]), "=r"(r[3]) : "r"(addr));
}
__device__ __forceinline__ void mma_bf16(float* d, const unsigned* a, const unsigned* b) {
    asm volatile("mma.sync.aligned.m16n8k16.row.col.f32.bf16.bf16.f32 "
                 "{%0,%1,%2,%3}, {%4,%5,%6,%7}, {%8,%9}, {%0,%1,%2,%3};"
                 : "+f"(d[0]), "+f"(d[1]), "+f"(d[2]), "+f"(d[3])
                 : "r"(a[0]), "r"(a[1]), "r"(a[2]), "r"(a[3]), "r"(b[0]), "r"(b[1]));
}
__device__ __forceinline__ unsigned bf2u(__nv_bfloat162 x) { return *(unsigned*)&x; }
__device__ __forceinline__ void cp16(uint32_t smem, const void* g) {
    asm volatile("cp.async.cg.shared.global [%0], [%1], 16;"
                 :: "r"(smem), "l"(__cvta_generic_to_global(g)) : "memory");
}
__device__ __forceinline__ void cp_commit() {
    asm volatile("cp.async.commit_group;" ::: "memory");
}
template<int N> __device__ __forceinline__ void cp_wait() {
    asm volatile("cp.async.wait_group %0;" :: "n"(N) : "memory");
}

// =============== bf16x3 tensor-core GEMM, BK=32, 2-stage, 2 CTAs/SM ==========
#define G_STG   18944
#define G_ALO   5120
#define G_BHI   10240
#define G_BLO   14592
#define G_SMEM  (2 * G_STG * 2)       // 75776 B
#define G_NT    (CDIM / 32)           // 32

template<int NTOT, bool QKV_EPI>
__global__ void __launch_bounds__(256, 2)
mma_gemm_kernel(const __nv_bfloat16* __restrict__ Ahi,
                const __nv_bfloat16* __restrict__ Alo,
                const __nv_bfloat16* __restrict__ Bhi,
                const __nv_bfloat16* __restrict__ Blo,
                const float* __restrict__ bias, float* __restrict__ out) {
    extern __shared__ __align__(16) char smraw[];
    const uint32_t smu = s2u(smraw);

    const int tid = threadIdx.x, lane = tid & 31, wid = tid >> 5;
    const int wm = wid >> 2, wn = wid & 3;
    const int m0 = blockIdx.y * 128, n0 = blockIdx.x * 128;

    const int s_ar = tid >> 2, s_ak = (tid & 3) * 8;
    const int s_br = tid >> 4, s_bn = (tid & 15) * 8;

    auto stage = [&](int kt, int s) {
        const int k0 = kt * 32;
        const uint32_t sb = smu + s * G_STG * 2;
#pragma unroll
        for (int it = 0; it < 2; it++) {
            const int r = s_ar + it * 64;
            cp16(sb + (r * 40 + s_ak) * 2, Ahi + (size_t)(m0 + r) * CDIM + k0 + s_ak);
            cp16(sb + (G_ALO + r * 40 + s_ak) * 2, Alo + (size_t)(m0 + r) * CDIM + k0 + s_ak);
            const int rb = s_br + it * 16;
            cp16(sb + (G_BHI + rb * 136 + s_bn) * 2, Bhi + (size_t)(k0 + rb) * NTOT + n0 + s_bn);
            cp16(sb + (G_BLO + rb * 136 + s_bn) * 2, Blo + (size_t)(k0 + rb) * NTOT + n0 + s_bn);
        }
    };

    float acc[4][4][4];
#pragma unroll
    for (int i = 0; i < 4; i++)
#pragma unroll
        for (int j = 0; j < 4; j++)
#pragma unroll
            for (int q = 0; q < 4; q++) acc[i][j][q] = 0.f;

    const int a_ld = (wm * 64 + (lane & 15)) * 40 + (lane >> 4) * 8;
    const int b_ld = (lane & 15) * 136 + wn * 32 + (lane >> 4) * 8;

    stage(0, 0); cp_commit();
    stage(1, 1); cp_commit();

    for (int kt = 0; kt < G_NT; kt++) {
        if (kt == G_NT - 1) cp_wait<0>(); else cp_wait<1>();
        __syncthreads();

        const uint32_t sb = smu + (kt & 1) * G_STG * 2;
#pragma unroll
        for (int ks = 0; ks < 2; ks++) {
            unsigned ah[4][4], al[4][4], bh[4][2], bl[4][2];
            const uint32_t aBh = sb + (a_ld + ks * 16) * 2;
            const uint32_t aBl = aBh + G_ALO * 2;
            const uint32_t bBh = sb + (G_BHI + b_ld + ks * 16 * 136) * 2;
            const uint32_t bBl = bBh + (G_BLO - G_BHI) * 2;
#pragma unroll
            for (int mt = 0; mt < 4; mt++) {
                ldsm_x4(ah[mt], aBh + mt * 16 * 40 * 2);
                ldsm_x4(al[mt], aBl + mt * 16 * 40 * 2);
            }
#pragma unroll
            for (int ntp = 0; ntp < 2; ntp++) {
                unsigned t4[4];
                ldsm_x4t(t4, bBh + ntp * 16 * 2);
                bh[2 * ntp][0] = t4[0]; bh[2 * ntp][1] = t4[1];
                bh[2 * ntp + 1][0] = t4[2]; bh[2 * ntp + 1][1] = t4[3];
                ldsm_x4t(t4, bBl + ntp * 16 * 2);
                bl[2 * ntp][0] = t4[0]; bl[2 * ntp][1] = t4[1];
                bl[2 * ntp + 1][0] = t4[2]; bl[2 * ntp + 1][1] = t4[3];
            }
#pragma unroll
            for (int mt = 0; mt < 4; mt++)
#pragma unroll
                for (int nt = 0; nt < 4; nt++) {
                    mma_bf16(acc[mt][nt], ah[mt], bh[nt]);
                    mma_bf16(acc[mt][nt], ah[mt], bl[nt]);
                    mma_bf16(acc[mt][nt], al[mt], bh[nt]);
                }
        }
        __syncthreads();
        if (kt + 2 < G_NT) { stage(kt + 2, kt & 1); cp_commit(); }
    }

    // epilogue
    const int rb = m0 + wm * 64 + (lane >> 2);
    const int cb = n0 + wn * 32 + (lane & 3) * 2;
#pragma unroll
    for (int mt = 0; mt < 4; mt++)
#pragma unroll
        for (int nt = 0; nt < 4; nt++) {
            const int c = cb + nt * 8;
            if (QKV_EPI) {
                const int sec = c >> 10, h = (c & 1023) >> 6, d = c & 63;
                const float scl = (sec == 0) ? 0.125f : 1.0f;  // pre-scale Q by 1/sqrt(64)
                __nv_bfloat16 *dhi, *dlo;
                if (sec == 0)      { dhi = g_qhi; dlo = g_qlo; }
                else if (sec == 1) { dhi = g_khi; dlo = g_klo; }
                else               { dhi = g_vhi; dlo = g_vlo; }
#pragma unroll
                for (int half = 0; half < 2; half++) {
                    const int r = rb + mt * 16 + half * 8;
                    const int bidx = r >> 11, n = r & (NSEQ - 1);
                    size_t off = (((size_t)bidx * HN + h) * NSEQ + n) * DH + d;
                    float v0 = acc[mt][nt][2 * half] * scl, v1 = acc[mt][nt][2 * half + 1] * scl;
                    __nv_bfloat162 hh = __floats2bfloat162_rn(v0, v1);
                    __nv_bfloat162 ll = __floats2bfloat162_rn(
                        v0 - __bfloat162float(hh.x), v1 - __bfloat162float(hh.y));
                    *(__nv_bfloat162*)&dhi[off] = hh;
                    *(__nv_bfloat162*)&dlo[off] = ll;
                }
            } else {
                const float b0 = bias[c], b1 = bias[c + 1];
#pragma unroll
                for (int half = 0; half < 2; half++) {
                    const int r = rb + mt * 16 + half * 8;
                    float* p = out + (size_t)r * NTOT + c;
                    *(float2*)p = make_float2(acc[mt][nt][2 * half] + b0,
                                              acc[mt][nt][2 * half + 1] + b1);
                }
            }
        }
}

// =============== Flash attention: Br=128, Bc=64, 2 CTAs/SM ===================
// smem (bf16 elems): Qh=0 (128*72=9216), Ql=9216, KV bufs at 18432 + buf*18432
// (per buf: Kh=0, Kl=4608, Vh=9216, Vl=13824); mrow[2][64] bytes at 110592.
#define QP 72
#define F_KV0   18432
#define F_KVSZ  18432
#define F_MROWB (55296 * 2)
#define FLASH_MMA_SMEM (F_MROWB + 256)   // 110848 B -> 2 CTAs/SM

__global__ void __launch_bounds__(256, 2) flash_mma_kernel() {
    extern __shared__ __align__(16) char smraw[];
    __nv_bfloat16* smb = (__nv_bfloat16*)smraw;
    const uint32_t smu = s2u(smraw);
    __nv_bfloat16* sQh = smb;
    __nv_bfloat16* sQl = smb + 9216;
    unsigned char* mrow = (unsigned char*)(smraw + F_MROWB);  // [2][64]

    const int tid = threadIdx.x, lane = tid & 31, wid = tid >> 5;
    const int qt = gridDim.x - 1 - blockIdx.x;   // heavy causal tiles first
    const int h = blockIdx.y, b = blockIdx.z;
    const int q0 = qt * 128;
    const int cstart = g_causal_d;
    const size_t hoff = ((size_t)b * HN + h) * NSEQ * DH;

    const __nv_bfloat16 *Qh = g_qhi + hoff, *Ql = g_qlo + hoff;
    const __nv_bfloat16* kvsrc[4] = {g_khi + hoff, g_klo + hoff,
                                     g_vhi + hoff, g_vlo + hoff};

    // stage Q tile (128 x 64, hi+lo) — plain stores, covered by first sync
    {
        const int r = tid >> 1, c0 = (tid & 1) * 32;
#pragma unroll
        for (int c = 0; c < 32; c += 8) {
            *(uint4*)&sQh[r * QP + c0 + c] = *(const uint4*)&Qh[(size_t)(q0 + r) * DH + c0 + c];
            *(uint4*)&sQl[r * QP + c0 + c] = *(const uint4*)&Ql[(size_t)(q0 + r) * DH + c0 + c];
        }
    }

    const int kv_r = tid >> 3, kv_c = (tid & 7) * 8;
    auto stageKV = [&](int t) {
        const int k0t = t * 64;
        const uint32_t base = smu + (F_KV0 + (t & 1) * F_KVSZ) * 2;
#pragma unroll
        for (int pl = 0; pl < 4; pl++)
#pragma unroll
            for (int half = 0; half < 2; half++) {
                const int r = kv_r + half * 32;
                cp16(base + (pl * 4608 + r * QP + kv_c) * 2,
                     kvsrc[pl] + (size_t)(k0t + r) * DH + kv_c);
            }
    };

    int kmaxi = q0 + 127;
    if (cstart - 1 > kmaxi) kmaxi = cstart - 1;
    if (kmaxi > NSEQ - 1) kmaxi = NSEQ - 1;
    const int ntiles = kmaxi / 64 + 1;

    stageKV(0); cp_commit();
    if (tid < 64) mrow[tid] = g_maskc[(size_t)b * NSEQ + tid];

    unsigned qfh[4][4], qfl[4][4];
    float m0v = -1e30f, m1v = -1e30f, l0v = 0.f, l1v = 0.f;
    float oacc[8][4] = {};

    const int grow0 = q0 + wid * 16 + (lane >> 2);
    const int grow1 = grow0 + 8;

    for (int t = 0; t < ntiles; t++) {
        const int k0t = t * 64;
        __syncthreads();
        if (t == 0) {
#pragma unroll
            for (int ks = 0; ks < 4; ks++) {
                const int qa = (wid * 16 + (lane & 15)) * QP + ks * 16 + (lane >> 4) * 8;
                ldsm_x4(qfh[ks], s2u(&sQh[qa]));
                ldsm_x4(qfl[ks], s2u(&sQl[qa]));
            }
        }
        if (t + 1 < ntiles) {
            stageKV(t + 1);
            if (tid < 64)
                mrow[((t + 1) & 1) * 64 + tid] = g_maskc[(size_t)b * NSEQ + (t + 1) * 64 + tid];
            cp_commit();
            cp_wait<1>();
        } else {
            cp_wait<0>();
        }
        __syncthreads();

        const __nv_bfloat16* kb = smb + F_KV0 + (t & 1) * F_KVSZ;
        const __nv_bfloat16* sKh = kb;
        const __nv_bfloat16* sKl = kb + 4608;
        const __nv_bfloat16* sVh = kb + 9216;
        const __nv_bfloat16* sVl = kb + 13824;
        const unsigned char* mr = mrow + (t & 1) * 64;

        // ---- S = Q K^T (Q pre-scaled by 0.125 in QKV epilogue) ----
        float sacc[8][4] = {};
#pragma unroll
        for (int ks = 0; ks < 4; ks++) {
            unsigned kbh[8][2], kbl[8][2];
#pragma unroll
            for (int np = 0; np < 4; np++) {
                const int row = np * 16 + ((lane >> 4) & 1) * 8 + (lane & 7);
                const int col = ks * 16 + ((lane >> 3) & 1) * 8;
                unsigned t4[4];
                ldsm_x4(t4, s2u(&sKh[row * QP + col]));
                kbh[2 * np][0] = t4[0]; kbh[2 * np][1] = t4[1];
                kbh[2 * np + 1][0] = t4[2]; kbh[2 * np + 1][1] = t4[3];
                ldsm_x4(t4, s2u(&sKl[row * QP + col]));
                kbl[2 * np][0] = t4[0]; kbl[2 * np][1] = t4[1];
                kbl[2 * np + 1][0] = t4[2]; kbl[2 * np + 1][1] = t4[3];
            }
#pragma unroll
            for (int nt = 0; nt < 8; nt++) {
                mma_bf16(sacc[nt], qfh[ks], kbh[nt]);
                mma_bf16(sacc[nt], qfh[ks], kbl[nt]);
                mma_bf16(sacc[nt], qfl[ks], kbh[nt]);
            }
        }

        // ---- masks + row max ----
        float tmax0 = -INFINITY, tmax1 = -INFINITY;
#pragma unroll
        for (int nt = 0; nt < 8; nt++) {
#pragma unroll
            for (int j = 0; j < 2; j++) {
                const int lc = nt * 8 + (lane & 3) * 2 + j;
                const int col = k0t + lc;
                const bool pad = mr[lc] != 0;
                float v0 = sacc[nt][j];
                float v1 = sacc[nt][2 + j];
                v0 = (pad || (col > grow0 && col >= cstart)) ? -INFINITY : v0;
                v1 = (pad || (col > grow1 && col >= cstart)) ? -INFINITY : v1;
                sacc[nt][j] = v0; sacc[nt][2 + j] = v1;
                tmax0 = fmaxf(tmax0, v0); tmax1 = fmaxf(tmax1, v1);
            }
        }
#pragma unroll
        for (int off = 1; off < 4; off <<= 1) {
            tmax0 = fmaxf(tmax0, __shfl_xor_sync(0xffffffffu, tmax0, off));
            tmax1 = fmaxf(tmax1, __shfl_xor_sync(0xffffffffu, tmax1, off));
        }

        // ---- online softmax update ----
        const float mn0 = fmaxf(m0v, tmax0), mn1 = fmaxf(m1v, tmax1);
        const float cr0 = __expf(m0v - mn0), cr1 = __expf(m1v - mn1);
        m0v = mn0; m1v = mn1;
        l0v *= cr0; l1v *= cr1;
#pragma unroll
        for (int nt = 0; nt < 8; nt++) {
            oacc[nt][0] *= cr0; oacc[nt][1] *= cr0;
            oacc[nt][2] *= cr1; oacc[nt][3] *= cr1;
        }
        float rs0 = 0.f, rs1 = 0.f;
#pragma unroll
        for (int nt = 0; nt < 8; nt++) {
            float p0 = __expf(sacc[nt][0] - mn0), p1 = __expf(sacc[nt][1] - mn0);
            float p2 = __expf(sacc[nt][2] - mn1), p3 = __expf(sacc[nt][3] - mn1);
            sacc[nt][0] = p0; sacc[nt][1] = p1; sacc[nt][2] = p2; sacc[nt][3] = p3;
            rs0 += p0 + p1; rs1 += p2 + p3;
        }
#pragma unroll
        for (int off = 1; off < 4; off <<= 1) {
            rs0 += __shfl_xor_sync(0xffffffffu, rs0, off);
            rs1 += __shfl_xor_sync(0xffffffffu, rs1, off);
        }
        l0v += rs0; l1v += rs1;

        // ---- O += P V ----
#pragma unroll
        for (int ks = 0; ks < 4; ks++) {
            unsigned ah[4], al[4];
            {
                const float v0 = sacc[2 * ks][0], v1 = sacc[2 * ks][1];
                const float v2 = sacc[2 * ks][2], v3 = sacc[2 * ks][3];
                const float w0 = sacc[2 * ks + 1][0], w1 = sacc[2 * ks + 1][1];
                const float w2 = sacc[2 * ks + 1][2], w3 = sacc[2 * ks + 1][3];
                __nv_bfloat162 h0 = __floats2bfloat162_rn(v0, v1);
                __nv_bfloat162 h1 = __floats2bfloat162_rn(v2, v3);
                __nv_bfloat162 h2 = __floats2bfloat162_rn(w0, w1);
                __nv_bfloat162 h3 = __floats2bfloat162_rn(w2, w3);
                ah[0] = bf2u(h0); ah[1] = bf2u(h1); ah[2] = bf2u(h2); ah[3] = bf2u(h3);
                al[0] = bf2u(__floats2bfloat162_rn(v0 - __bfloat162float(h0.x),
                                                   v1 - __bfloat162float(h0.y)));
                al[1] = bf2u(__floats2bfloat162_rn(v2 - __bfloat162float(h1.x),
                                                   v3 - __bfloat162float(h1.y)));
                al[2] = bf2u(__floats2bfloat162_rn(w0 - __bfloat162float(h2.x),
                                                   w1 - __bfloat162float(h2.y)));
                al[3] = bf2u(__floats2bfloat162_rn(w2 - __bfloat162float(h3.x),
                                                   w3 - __bfloat162float(h3.y)));
            }
#pragma unroll
            for (int np = 0; np < 4; np++) {
                const int va = (ks * 16 + (lane & 15)) * QP + np * 16 + (lane >> 4) * 8;
                unsigned t4[4], t4l[4];
                ldsm_x4t(t4, s2u(&sVh[va]));
                ldsm_x4t(t4l, s2u(&sVl[va]));
                unsigned vb0[2] = {t4[0], t4[1]}, vb1[2] = {t4[2], t4[3]};
                unsigned vl0[2] = {t4l[0], t4l[1]}, vl1[2] = {t4l[2], t4l[3]};
                mma_bf16(oacc[2 * np], ah, vb0);
                mma_bf16(oacc[2 * np], ah, vl0);
                mma_bf16(oacc[2 * np], al, vb0);
                mma_bf16(oacc[2 * np + 1], ah, vb1);
                mma_bf16(oacc[2 * np + 1], ah, vl1);
                mma_bf16(oacc[2 * np + 1], al, vb1);
            }
        }
    }

    // ---- normalize + write bf16 hi/lo att (input of proj GEMM) ----
    const float inv0 = 1.f / l0v, inv1 = 1.f / l1v;
#pragma unroll
    for (int nt = 0; nt < 8; nt++) {
        const int d = nt * 8 + (lane & 3) * 2;
        const size_t o0 = ((size_t)b * NSEQ + grow0) * CDIM + h * DH + d;
        const size_t o1 = ((size_t)b * NSEQ + grow1) * CDIM + h * DH + d;
        const float v0 = oacc[nt][0] * inv0, v1 = oacc[nt][1] * inv0;
        const float w0 = oacc[nt][2] * inv1, w1 = oacc[nt][3] * inv1;
        __nv_bfloat162 h0 = __floats2bfloat162_rn(v0, v1);
        *(__nv_bfloat162*)&g_ahi[o0] = h0;
        *(__nv_bfloat162*)&g_alo[o0] = __floats2bfloat162_rn(
            v0 - __bfloat162float(h0.x), v1 - __bfloat162float(h0.y));
        __nv_bfloat162 h1 = __floats2bfloat162_rn(w0, w1);
        *(__nv_bfloat162*)&g_ahi[o1] = h1;
        *(__nv_bfloat162*)&g_alo[o1] = __floats2bfloat162_rn(
            w0 - __bfloat162float(h1.x), w1 - __bfloat162float(h1.y));
    }
}

// ---------------- launch ------------------------------------------------------
extern "C" void kernel_launch(void* const* d_in, const int* in_sizes, int n_in,
                              void* d_out, int out_size) {
    (void)n_in; (void)out_size;
    const float* x     = (const float*)d_in[0];
    const void*  mask  = d_in[1];
    const int*   cs    = (const int*)d_in[2];
    const float* wqkv  = (const float*)d_in[3];
    const float* wproj = (const float*)d_in[4];
    const float* bproj = (const float*)d_in[5];
    float* out = (float*)d_out;

    prep_kernel<<<1, 256>>>(mask, cs, in_sizes[1]);

    __nv_bfloat16 *xhi, *xlo, *wqhi, *wqlo, *wphi, *wplo, *ahi, *alo;
    cudaGetSymbolAddress((void**)&xhi, g_xhi);   cudaGetSymbolAddress((void**)&xlo, g_xlo);
    cudaGetSymbolAddress((void**)&wqhi, g_wqhi); cudaGetSymbolAddress((void**)&wqlo, g_wqlo);
    cudaGetSymbolAddress((void**)&wphi, g_wphi); cudaGetSymbolAddress((void**)&wplo, g_wplo);
    cudaGetSymbolAddress((void**)&ahi, g_ahi);   cudaGetSymbolAddress((void**)&alo, g_alo);

    const int nx = MROWS * CDIM, nwq = CDIM * QKVC, nwp = CDIM * CDIM;
    split_kernel<<<(nx + 255) / 256, 256>>>(x, xhi, xlo, nx);
    split_kernel<<<(nwq + 255) / 256, 256>>>(wqkv, wqhi, wqlo, nwq);
    split_kernel<<<(nwp + 255) / 256, 256>>>(wproj, wphi, wplo, nwp);

    cudaFuncSetAttribute(mma_gemm_kernel<QKVC, true>,
                         cudaFuncAttributeMaxDynamicSharedMemorySize, G_SMEM);
    cudaFuncSetAttribute(mma_gemm_kernel<CDIM, false>,
                         cudaFuncAttributeMaxDynamicSharedMemorySize, G_SMEM);
    cudaFuncSetAttribute(flash_mma_kernel,
                         cudaFuncAttributeMaxDynamicSharedMemorySize, FLASH_MMA_SMEM);

    dim3 g1(QKVC / 128, MROWS / 128);
    mma_gemm_kernel<QKVC, true><<<g1, 256, G_SMEM>>>(xhi, xlo, wqhi, wqlo, nullptr, nullptr);

    dim3 g2(NSEQ / 128, HN, BB);
    flash_mma_kernel<<<g2, 256, FLASH_MMA_SMEM>>>();

    dim3 g3(CDIM / 128, MROWS / 128);
    mma_gemm_kernel<CDIM, false><<<g3, 256, G_SMEM>>>(ahi, alo, wphi, wplo, bproj, out);
}

// round 10
// speedup vs baseline: 3.3215x; 1.2045x over previous
#include <cuda_runtime.h>
#include <cuda_bf16.h>
#include <math.h>
#include <stdint.h>

#define BB    2
#define NSEQ  2048
#define CDIM  1024
#define HN    16
#define DH    64
#define MROWS (BB*NSEQ)     // 4096
#define QKVC  (3*CDIM)      // 3072

// ---------------- scratch (static device globals; no allocation) -------------
__device__ __align__(16) __nv_bfloat16 g_xhi[(size_t)MROWS*CDIM], g_xlo[(size_t)MROWS*CDIM];
__device__ __align__(16) __nv_bfloat16 g_wqhi[(size_t)CDIM*QKVC], g_wqlo[(size_t)CDIM*QKVC];
__device__ __align__(16) __nv_bfloat16 g_wphi[(size_t)CDIM*CDIM], g_wplo[(size_t)CDIM*CDIM];
__device__ __align__(16) __nv_bfloat16 g_ahi[(size_t)MROWS*CDIM], g_alo[(size_t)MROWS*CDIM];
__device__ __align__(16) __nv_bfloat16 g_qhi[(size_t)BB*HN*NSEQ*DH], g_qlo[(size_t)BB*HN*NSEQ*DH];
__device__ __align__(16) __nv_bfloat16 g_khi[(size_t)BB*HN*NSEQ*DH], g_klo[(size_t)BB*HN*NSEQ*DH];
__device__ __align__(16) __nv_bfloat16 g_vhi[(size_t)BB*HN*NSEQ*DH], g_vlo[(size_t)BB*HN*NSEQ*DH];
// gathered (padding-compacted) K/V
__device__ __align__(16) __nv_bfloat16 g_kghi[(size_t)BB*HN*NSEQ*DH], g_kglo[(size_t)BB*HN*NSEQ*DH];
__device__ __align__(16) __nv_bfloat16 g_vghi[(size_t)BB*HN*NSEQ*DH], g_vglo[(size_t)BB*HN*NSEQ*DH];
__device__ unsigned char g_maskc[BB*NSEQ];
__device__ int g_kidx[BB*NSEQ];          // ascending orig cols of unmasked keys (pad 0x7FFFFFFF)
__device__ int g_pcnt[BB*(NSEQ+1)];      // exclusive prefix count of unmasked
__device__ int g_kcnt[BB];
__device__ int g_causal_d;

// ---------------- prep: mask canon + causal + per-batch key compaction -------
__global__ void prep_kernel(const void* __restrict__ mask_raw,
                            const int* __restrict__ cs_raw, int nmask) {
    __shared__ int sfmt;
    __shared__ int tsum[257];
    const unsigned char* mb = (const unsigned char*)mask_raw;
    const int tid = threadIdx.x;
    if (tid == 0) {
        bool nz1 = false, nz3 = false;
        int scan = nmask < 1024 ? nmask : 1024;
        for (int i = 0; i < scan; i++) {
            unsigned char v = mb[i];
            if (v) { int r = i & 3; if (r == 1) nz1 = true; else if (r == 3) nz3 = true; }
        }
        sfmt = nz1 ? 0 : (nz3 ? 2 : 1);  // 0=u8, 1=i32, 2=f32
        int cv = cs_raw[0];
        if (cv < 0 || cv > (1 << 24)) cv = (int)__int_as_float(cv);
        g_causal_d = cv;
    }
    __syncthreads();
    int f = sfmt;
    for (int i = tid; i < nmask; i += 256) {
        unsigned char m;
        if (f == 0)      m = mb[i] != 0;
        else if (f == 1) m = ((const int*)mask_raw)[i] != 0;
        else             m = ((const float*)mask_raw)[i] != 0.0f;
        g_maskc[i] = m;
    }
    __syncthreads();
    // per-batch compaction scan (2048 = 256 threads x 8)
    for (int b = 0; b < BB; b++) {
        int flags[8], s = 0;
        const int base = b * NSEQ + tid * 8;
#pragma unroll
        for (int j = 0; j < 8; j++) { flags[j] = g_maskc[base + j] ? 0 : 1; s += flags[j]; }
        tsum[tid] = s;
        __syncthreads();
        if (tid == 0) {
            int acc = 0;
            for (int i = 0; i < 256; i++) { int t = tsum[i]; tsum[i] = acc; acc += t; }
            tsum[256] = acc;
            g_kcnt[b] = acc;
        }
        __syncthreads();
        int run = tsum[tid];
#pragma unroll
        for (int j = 0; j < 8; j++) {
            const int n = tid * 8 + j;
            g_pcnt[b * (NSEQ + 1) + n] = run;
            if (flags[j]) { g_kidx[b * NSEQ + run] = n; run++; }
        }
        if (tid == 255) g_pcnt[b * (NSEQ + 1) + NSEQ] = run;
        __syncthreads();
        const int cnt = tsum[256];
        for (int i = cnt + tid; i < NSEQ; i += 256) g_kidx[b * NSEQ + i] = 0x7FFFFFFF;
        __syncthreads();
    }
}

// ---------------- split fp32 -> bf16 hi + lo ---------------------------------
__global__ void split_kernel(const float* __restrict__ src,
                             __nv_bfloat16* __restrict__ hi,
                             __nv_bfloat16* __restrict__ lo, int n) {
    int i = blockIdx.x * blockDim.x + threadIdx.x;
    if (i < n) {
        float v = src[i];
        __nv_bfloat16 h = __float2bfloat16(v);
        hi[i] = h;
        lo[i] = __float2bfloat16(v - __bfloat162float(h));
    }
}

// ---------------- gather: compact unmasked K/V rows per (b,h) ----------------
// grid (NSEQ/8, HN, BB), block 256: 8 rows/block, one warp per row, 1 uint/lane.
__global__ void gather_kv_kernel() {
    const int b = blockIdx.z, h = blockIdx.y;
    const int j = blockIdx.x * 8 + (threadIdx.x >> 5);
    const int lane = threadIdx.x & 31;
    const int cnt = g_kcnt[b];
    const int cntp = (cnt + 63) & ~63;
    if (j >= cntp) return;
    const size_t dst = (((size_t)b * HN + h) * NSEQ + j) * DH;
    if (j < cnt) {
        const int n = g_kidx[b * NSEQ + j];
        const size_t src = (((size_t)b * HN + h) * NSEQ + n) * DH;
        ((unsigned*)(g_kghi + dst))[lane] = ((const unsigned*)(g_khi + src))[lane];
        ((unsigned*)(g_kglo + dst))[lane] = ((const unsigned*)(g_klo + src))[lane];
        ((unsigned*)(g_vghi + dst))[lane] = ((const unsigned*)(g_vhi + src))[lane];
        ((unsigned*)(g_vglo + dst))[lane] = ((const unsigned*)(g_vlo + src))[lane];
    } else {
        ((unsigned*)(g_kghi + dst))[lane] = 0;
        ((unsigned*)(g_kglo + dst))[lane] = 0;
        ((unsigned*)(g_vghi + dst))[lane] = 0;
        ((unsigned*)(g_vglo + dst))[lane] = 0;
    }
}

// ---------------- PTX helpers -------------------------------------------------
__device__ __forceinline__ uint32_t s2u(const void* p) {
    return (uint32_t)__cvta_generic_to_shared(p);
}
__device__ __forceinline__ void ldsm_x4(unsigned* r, uint32_t addr) {
    asm volatile("ldmatrix.sync.aligned.m8n8.x4.shared.b16 {%0,%1,%2,%3}, [%4];"
                 : "=r"(r[0]), "=r"(r[1]), "=r"(r[2]), "=r"(r[3]) : "r"(addr));
}
__device__ __forceinline__ void ldsm_x4t(unsigned* r, uint32_t addr) {
    asm volatile("ldmatrix.sync.aligned.m8n8.x4.trans.shared.b16 {%0,%1,%2,%3}, [%4];"
                 : "=r"(r[0]), "=r"(r[1]), "=r"(r[2]), "=r"(r[3]) : "r"(addr));
}
__device__ __forceinline__ void mma_bf16(float* d, const unsigned* a, const unsigned* b) {
    asm volatile("mma.sync.aligned.m16n8k16.row.col.f32.bf16.bf16.f32 "
                 "{%0,%1,%2,%3}, {%4,%5,%6,%7}, {%8,%9}, {%0,%1,%2,%3};"
                 : "+f"(d[0]), "+f"(d[1]), "+f"(d[2]), "+f"(d[3])
                 : "r"(a[0]), "r"(a[1]), "r"(a[2]), "r"(a[3]), "r"(b[0]), "r"(b[1]));
}
__device__ __forceinline__ unsigned bf2u(__nv_bfloat162 x) { return *(unsigned*)&x; }
__device__ __forceinline__ void cp16(uint32_t smem, const void* g) {
    asm volatile("cp.async.cg.shared.global [%0], [%1], 16;"
                 :: "r"(smem), "l"(__cvta_generic_to_global(g)) : "memory");
}
__device__ __forceinline__ void cp_commit() {
    asm volatile("cp.async.commit_group;" ::: "memory");
}
template<int N> __device__ __forceinline__ void cp_wait() {
    asm volatile("cp.async.wait_group %0;" :: "n"(N) : "memory");
}

// =============== bf16x3 tensor-core GEMM, BK=32, 2-stage, 2 CTAs/SM ==========
#define G_STG   18944
#define G_ALO   5120
#define G_BHI   10240
#define G_BLO   14592
#define G_SMEM  (2 * G_STG * 2)       // 75776 B
#define G_NT    (CDIM / 32)           // 32

template<int NTOT, bool QKV_EPI>
__global__ void __launch_bounds__(256, 2)
mma_gemm_kernel(const __nv_bfloat16* __restrict__ Ahi,
                const __nv_bfloat16* __restrict__ Alo,
                const __nv_bfloat16* __restrict__ Bhi,
                const __nv_bfloat16* __restrict__ Blo,
                const float* __restrict__ bias, float* __restrict__ out) {
    extern __shared__ __align__(16) char smraw[];
    const uint32_t smu = s2u(smraw);

    const int tid = threadIdx.x, lane = tid & 31, wid = tid >> 5;
    const int wm = wid >> 2, wn = wid & 3;
    const int m0 = blockIdx.y * 128, n0 = blockIdx.x * 128;

    const int s_ar = tid >> 2, s_ak = (tid & 3) * 8;
    const int s_br = tid >> 4, s_bn = (tid & 15) * 8;

    auto stage = [&](int kt, int s) {
        const int k0 = kt * 32;
        const uint32_t sb = smu + s * G_STG * 2;
#pragma unroll
        for (int it = 0; it < 2; it++) {
            const int r = s_ar + it * 64;
            cp16(sb + (r * 40 + s_ak) * 2, Ahi + (size_t)(m0 + r) * CDIM + k0 + s_ak);
            cp16(sb + (G_ALO + r * 40 + s_ak) * 2, Alo + (size_t)(m0 + r) * CDIM + k0 + s_ak);
            const int rb = s_br + it * 16;
            cp16(sb + (G_BHI + rb * 136 + s_bn) * 2, Bhi + (size_t)(k0 + rb) * NTOT + n0 + s_bn);
            cp16(sb + (G_BLO + rb * 136 + s_bn) * 2, Blo + (size_t)(k0 + rb) * NTOT + n0 + s_bn);
        }
    };

    float acc[4][4][4];
#pragma unroll
    for (int i = 0; i < 4; i++)
#pragma unroll
        for (int j = 0; j < 4; j++)
#pragma unroll
            for (int q = 0; q < 4; q++) acc[i][j][q] = 0.f;

    const int a_ld = (wm * 64 + (lane & 15)) * 40 + (lane >> 4) * 8;
    const int b_ld = (lane & 15) * 136 + wn * 32 + (lane >> 4) * 8;

    stage(0, 0); cp_commit();
    stage(1, 1); cp_commit();

    for (int kt = 0; kt < G_NT; kt++) {
        if (kt == G_NT - 1) cp_wait<0>(); else cp_wait<1>();
        __syncthreads();

        const uint32_t sb = smu + (kt & 1) * G_STG * 2;
#pragma unroll
        for (int ks = 0; ks < 2; ks++) {
            unsigned ah[4][4], al[4][4], bh[4][2], bl[4][2];
            const uint32_t aBh = sb + (a_ld + ks * 16) * 2;
            const uint32_t aBl = aBh + G_ALO * 2;
            const uint32_t bBh = sb + (G_BHI + b_ld + ks * 16 * 136) * 2;
            const uint32_t bBl = bBh + (G_BLO - G_BHI) * 2;
#pragma unroll
            for (int mt = 0; mt < 4; mt++) {
                ldsm_x4(ah[mt], aBh + mt * 16 * 40 * 2);
                ldsm_x4(al[mt], aBl + mt * 16 * 40 * 2);
            }
#pragma unroll
            for (int ntp = 0; ntp < 2; ntp++) {
                unsigned t4[4];
                ldsm_x4t(t4, bBh + ntp * 16 * 2);
                bh[2 * ntp][0] = t4[0]; bh[2 * ntp][1] = t4[1];
                bh[2 * ntp + 1][0] = t4[2]; bh[2 * ntp + 1][1] = t4[3];
                ldsm_x4t(t4, bBl + ntp * 16 * 2);
                bl[2 * ntp][0] = t4[0]; bl[2 * ntp][1] = t4[1];
                bl[2 * ntp + 1][0] = t4[2]; bl[2 * ntp + 1][1] = t4[3];
            }
#pragma unroll
            for (int mt = 0; mt < 4; mt++)
#pragma unroll
                for (int nt = 0; nt < 4; nt++) {
                    mma_bf16(acc[mt][nt], ah[mt], bh[nt]);
                    mma_bf16(acc[mt][nt], ah[mt], bl[nt]);
                    mma_bf16(acc[mt][nt], al[mt], bh[nt]);
                }
        }
        __syncthreads();
        if (kt + 2 < G_NT) { stage(kt + 2, kt & 1); cp_commit(); }
    }

    // epilogue
    const int rb = m0 + wm * 64 + (lane >> 2);
    const int cb = n0 + wn * 32 + (lane & 3) * 2;
#pragma unroll
    for (int mt = 0; mt < 4; mt++)
#pragma unroll
        for (int nt = 0; nt < 4; nt++) {
            const int c = cb + nt * 8;
            if (QKV_EPI) {
                const int sec = c >> 10, h = (c & 1023) >> 6, d = c & 63;
                const float scl = (sec == 0) ? 0.125f : 1.0f;  // pre-scale Q by 1/sqrt(64)
                __nv_bfloat16 *dhi, *dlo;
                if (sec == 0)      { dhi = g_qhi; dlo = g_qlo; }
                else if (sec == 1) { dhi = g_khi; dlo = g_klo; }
                else               { dhi = g_vhi; dlo = g_vlo; }
#pragma unroll
                for (int half = 0; half < 2; half++) {
                    const int r = rb + mt * 16 + half * 8;
                    const int bidx = r >> 11, n = r & (NSEQ - 1);
                    size_t off = (((size_t)bidx * HN + h) * NSEQ + n) * DH + d;
                    float v0 = acc[mt][nt][2 * half] * scl, v1 = acc[mt][nt][2 * half + 1] * scl;
                    __nv_bfloat162 hh = __floats2bfloat162_rn(v0, v1);
                    __nv_bfloat162 ll = __floats2bfloat162_rn(
                        v0 - __bfloat162float(hh.x), v1 - __bfloat162float(hh.y));
                    *(__nv_bfloat162*)&dhi[off] = hh;
                    *(__nv_bfloat162*)&dlo[off] = ll;
                }
            } else {
                const float b0 = bias[c], b1 = bias[c + 1];
#pragma unroll
                for (int half = 0; half < 2; half++) {
                    const int r = rb + mt * 16 + half * 8;
                    float* p = out + (size_t)r * NTOT + c;
                    *(float2*)p = make_float2(acc[mt][nt][2 * half] + b0,
                                              acc[mt][nt][2 * half + 1] + b1);
                }
            }
        }
}

// =============== Flash attention: Br=128, compacted keys, Bc=64 ==============
// smem (bf16 elems): Qh=0 (128*72=9216), Ql=9216, KV bufs at 18432 + buf*18432
// (per buf: Kh=0, Kl=4608, Vh=9216, Vl=13824); scol int[2][64] at 110592 B.
#define QP 72
#define F_KV0   18432
#define F_KVSZ  18432
#define F_SCOLB (55296 * 2)
#define FLASH_MMA_SMEM (F_SCOLB + 512)   // 111104 B -> 2 CTAs/SM

__global__ void __launch_bounds__(256, 2) flash_mma_kernel() {
    extern __shared__ __align__(16) char smraw[];
    __nv_bfloat16* smb = (__nv_bfloat16*)smraw;
    const uint32_t smu = s2u(smraw);
    __nv_bfloat16* sQh = smb;
    __nv_bfloat16* sQl = smb + 9216;
    int* scol = (int*)(smraw + F_SCOLB);   // [2][64] gathered orig column ids

    const int tid = threadIdx.x, lane = tid & 31, wid = tid >> 5;
    const int qt = gridDim.x - 1 - blockIdx.x;   // heavy causal tiles first
    const int h = blockIdx.y, b = blockIdx.z;
    const int q0 = qt * 128;
    const int cstart = g_causal_d;
    const size_t hoff = ((size_t)b * HN + h) * NSEQ * DH;

    const __nv_bfloat16 *Qh = g_qhi + hoff, *Ql = g_qlo + hoff;
    const __nv_bfloat16* kvsrc[4] = {g_kghi + hoff, g_kglo + hoff,
                                     g_vghi + hoff, g_vglo + hoff};

    // stage Q tile (128 x 64, hi+lo) — plain stores, covered by first sync
    {
        const int r = tid >> 1, c0 = (tid & 1) * 32;
#pragma unroll
        for (int c = 0; c < 32; c += 8) {
            *(uint4*)&sQh[r * QP + c0 + c] = *(const uint4*)&Qh[(size_t)(q0 + r) * DH + c0 + c];
            *(uint4*)&sQl[r * QP + c0 + c] = *(const uint4*)&Ql[(size_t)(q0 + r) * DH + c0 + c];
        }
    }

    const int kv_r = tid >> 3, kv_c = (tid & 7) * 8;
    auto stageKV = [&](int t) {
        const int k0t = t * 64;
        const uint32_t base = smu + (F_KV0 + (t & 1) * F_KVSZ) * 2;
#pragma unroll
        for (int pl = 0; pl < 4; pl++)
#pragma unroll
            for (int half = 0; half < 2; half++) {
                const int r = kv_r + half * 32;
                cp16(base + (pl * 4608 + r * QP + kv_c) * 2,
                     kvsrc[pl] + (size_t)(k0t + r) * DH + kv_c);
            }
    };

    int kmaxi = q0 + 127;
    if (cstart - 1 > kmaxi) kmaxi = cstart - 1;
    if (kmaxi > NSEQ - 1) kmaxi = NSEQ - 1;
    const int kcnt = g_pcnt[b * (NSEQ + 1) + kmaxi + 1];  // unmasked keys visible
    const int ntiles = (kcnt + 63) >> 6;

    stageKV(0); cp_commit();
    if (tid < 64) scol[tid] = g_kidx[b * NSEQ + tid];

    unsigned qfh[4][4], qfl[4][4];
    float m0v = -1e30f, m1v = -1e30f, l0v = 0.f, l1v = 0.f;
    float oacc[8][4] = {};

    const int grow0 = q0 + wid * 16 + (lane >> 2);
    const int grow1 = grow0 + 8;

    for (int t = 0; t < ntiles; t++) {
        __syncthreads();
        if (t == 0) {
#pragma unroll
            for (int ks = 0; ks < 4; ks++) {
                const int qa = (wid * 16 + (lane & 15)) * QP + ks * 16 + (lane >> 4) * 8;
                ldsm_x4(qfh[ks], s2u(&sQh[qa]));
                ldsm_x4(qfl[ks], s2u(&sQl[qa]));
            }
        }
        if (t + 1 < ntiles) {
            stageKV(t + 1);
            if (tid < 64)
                scol[((t + 1) & 1) * 64 + tid] = g_kidx[b * NSEQ + (t + 1) * 64 + tid];
            cp_commit();
            cp_wait<1>();
        } else {
            cp_wait<0>();
        }
        __syncthreads();

        const __nv_bfloat16* kb = smb + F_KV0 + (t & 1) * F_KVSZ;
        const __nv_bfloat16* sKh = kb;
        const __nv_bfloat16* sKl = kb + 4608;
        const __nv_bfloat16* sVh = kb + 9216;
        const __nv_bfloat16* sVl = kb + 13824;
        const int* sc = scol + (t & 1) * 64;

        // ---- S = Q K^T (Q pre-scaled by 0.125 in QKV epilogue) ----
        float sacc[8][4] = {};
#pragma unroll
        for (int ks = 0; ks < 4; ks++) {
            unsigned kbh[8][2], kbl[8][2];
#pragma unroll
            for (int np = 0; np < 4; np++) {
                const int row = np * 16 + ((lane >> 4) & 1) * 8 + (lane & 7);
                const int col = ks * 16 + ((lane >> 3) & 1) * 8;
                unsigned t4[4];
                ldsm_x4(t4, s2u(&sKh[row * QP + col]));
                kbh[2 * np][0] = t4[0]; kbh[2 * np][1] = t4[1];
                kbh[2 * np + 1][0] = t4[2]; kbh[2 * np + 1][1] = t4[3];
                ldsm_x4(t4, s2u(&sKl[row * QP + col]));
                kbl[2 * np][0] = t4[0]; kbl[2 * np][1] = t4[1];
                kbl[2 * np + 1][0] = t4[2]; kbl[2 * np + 1][1] = t4[3];
            }
#pragma unroll
            for (int nt = 0; nt < 8; nt++) {
                mma_bf16(sacc[nt], qfh[ks], kbh[nt]);
                mma_bf16(sacc[nt], qfh[ks], kbl[nt]);
                mma_bf16(sacc[nt], qfl[ks], kbh[nt]);
            }
        }

        // ---- causal mask on ORIGINAL column ids + row max ----
        float tmax0 = -INFINITY, tmax1 = -INFINITY;
#pragma unroll
        for (int nt = 0; nt < 8; nt++) {
#pragma unroll
            for (int j = 0; j < 2; j++) {
                const int lc = nt * 8 + (lane & 3) * 2 + j;
                const int col = sc[lc];               // orig col (INT_MAX pad -> masked)
                float v0 = sacc[nt][j];
                float v1 = sacc[nt][2 + j];
                v0 = (col > grow0 && col >= cstart) ? -INFINITY : v0;
                v1 = (col > grow1 && col >= cstart) ? -INFINITY : v1;
                sacc[nt][j] = v0; sacc[nt][2 + j] = v1;
                tmax0 = fmaxf(tmax0, v0); tmax1 = fmaxf(tmax1, v1);
            }
        }
#pragma unroll
        for (int off = 1; off < 4; off <<= 1) {
            tmax0 = fmaxf(tmax0, __shfl_xor_sync(0xffffffffu, tmax0, off));
            tmax1 = fmaxf(tmax1, __shfl_xor_sync(0xffffffffu, tmax1, off));
        }

        // ---- online softmax update ----
        const float mn0 = fmaxf(m0v, tmax0), mn1 = fmaxf(m1v, tmax1);
        const float cr0 = __expf(m0v - mn0), cr1 = __expf(m1v - mn1);
        m0v = mn0; m1v = mn1;
        l0v *= cr0; l1v *= cr1;
#pragma unroll
        for (int nt = 0; nt < 8; nt++) {
            oacc[nt][0] *= cr0; oacc[nt][1] *= cr0;
            oacc[nt][2] *= cr1; oacc[nt][3] *= cr1;
        }
        float rs0 = 0.f, rs1 = 0.f;
#pragma unroll
        for (int nt = 0; nt < 8; nt++) {
            float p0 = __expf(sacc[nt][0] - mn0), p1 = __expf(sacc[nt][1] - mn0);
            float p2 = __expf(sacc[nt][2] - mn1), p3 = __expf(sacc[nt][3] - mn1);
            sacc[nt][0] = p0; sacc[nt][1] = p1; sacc[nt][2] = p2; sacc[nt][3] = p3;
            rs0 += p0 + p1; rs1 += p2 + p3;
        }
#pragma unroll
        for (int off = 1; off < 4; off <<= 1) {
            rs0 += __shfl_xor_sync(0xffffffffu, rs0, off);
            rs1 += __shfl_xor_sync(0xffffffffu, rs1, off);
        }
        l0v += rs0; l1v += rs1;

        // ---- O += P V ----
#pragma unroll
        for (int ks = 0; ks < 4; ks++) {
            unsigned ah[4], al[4];
            {
                const float v0 = sacc[2 * ks][0], v1 = sacc[2 * ks][1];
                const float v2 = sacc[2 * ks][2], v3 = sacc[2 * ks][3];
                const float w0 = sacc[2 * ks + 1][0], w1 = sacc[2 * ks + 1][1];
                const float w2 = sacc[2 * ks + 1][2], w3 = sacc[2 * ks + 1][3];
                __nv_bfloat162 h0 = __floats2bfloat162_rn(v0, v1);
                __nv_bfloat162 h1 = __floats2bfloat162_rn(v2, v3);
                __nv_bfloat162 h2 = __floats2bfloat162_rn(w0, w1);
                __nv_bfloat162 h3 = __floats2bfloat162_rn(w2, w3);
                ah[0] = bf2u(h0); ah[1] = bf2u(h1); ah[2] = bf2u(h2); ah[3] = bf2u(h3);
                al[0] = bf2u(__floats2bfloat162_rn(v0 - __bfloat162float(h0.x),
                                                   v1 - __bfloat162float(h0.y)));
                al[1] = bf2u(__floats2bfloat162_rn(v2 - __bfloat162float(h1.x),
                                                   v3 - __bfloat162float(h1.y)));
                al[2] = bf2u(__floats2bfloat162_rn(w0 - __bfloat162float(h2.x),
                                                   w1 - __bfloat162float(h2.y)));
                al[3] = bf2u(__floats2bfloat162_rn(w2 - __bfloat162float(h3.x),
                                                   w3 - __bfloat162float(h3.y)));
            }
#pragma unroll
            for (int np = 0; np < 4; np++) {
                const int va = (ks * 16 + (lane & 15)) * QP + np * 16 + (lane >> 4) * 8;
                unsigned t4[4], t4l[4];
                ldsm_x4t(t4, s2u(&sVh[va]));
                ldsm_x4t(t4l, s2u(&sVl[va]));
                unsigned vb0[2] = {t4[0], t4[1]}, vb1[2] = {t4[2], t4[3]};
                unsigned vl0[2] = {t4l[0], t4l[1]}, vl1[2] = {t4l[2], t4l[3]};
                mma_bf16(oacc[2 * np], ah, vb0);
                mma_bf16(oacc[2 * np], ah, vl0);
                mma_bf16(oacc[2 * np], al, vb0);
                mma_bf16(oacc[2 * np + 1], ah, vb1);
                mma_bf16(oacc[2 * np + 1], ah, vl1);
                mma_bf16(oacc[2 * np + 1], al, vb1);
            }
        }
    }

    // ---- normalize + write bf16 hi/lo att (input of proj GEMM) ----
    const float inv0 = 1.f / l0v, inv1 = 1.f / l1v;
#pragma unroll
    for (int nt = 0; nt < 8; nt++) {
        const int d = nt * 8 + (lane & 3) * 2;
        const size_t o0 = ((size_t)b * NSEQ + grow0) * CDIM + h * DH + d;
        const size_t o1 = ((size_t)b * NSEQ + grow1) * CDIM + h * DH + d;
        const float v0 = oacc[nt][0] * inv0, v1 = oacc[nt][1] * inv0;
        const float w0 = oacc[nt][2] * inv1, w1 = oacc[nt][3] * inv1;
        __nv_bfloat162 h0 = __floats2bfloat162_rn(v0, v1);
        *(__nv_bfloat162*)&g_ahi[o0] = h0;
        *(__nv_bfloat162*)&g_alo[o0] = __floats2bfloat162_rn(
            v0 - __bfloat162float(h0.x), v1 - __bfloat162float(h0.y));
        __nv_bfloat162 h1 = __floats2bfloat162_rn(w0, w1);
        *(__nv_bfloat162*)&g_ahi[o1] = h1;
        *(__nv_bfloat162*)&g_alo[o1] = __floats2bfloat162_rn(
            w0 - __bfloat162float(h1.x), w1 - __bfloat162float(h1.y));
    }
}

// ---------------- launch ------------------------------------------------------
extern "C" void kernel_launch(void* const* d_in, const int* in_sizes, int n_in,
                              void* d_out, int out_size) {
    (void)n_in; (void)out_size;
    const float* x     = (const float*)d_in[0];
    const void*  mask  = d_in[1];
    const int*   cs    = (const int*)d_in[2];
    const float* wqkv  = (const float*)d_in[3];
    const float* wproj = (const float*)d_in[4];
    const float* bproj = (const float*)d_in[5];
    float* out = (float*)d_out;

    prep_kernel<<<1, 256>>>(mask, cs, in_sizes[1]);

    __nv_bfloat16 *xhi, *xlo, *wqhi, *wqlo, *wphi, *wplo, *ahi, *alo;
    cudaGetSymbolAddress((void**)&xhi, g_xhi);   cudaGetSymbolAddress((void**)&xlo, g_xlo);
    cudaGetSymbolAddress((void**)&wqhi, g_wqhi); cudaGetSymbolAddress((void**)&wqlo, g_wqlo);
    cudaGetSymbolAddress((void**)&wphi, g_wphi); cudaGetSymbolAddress((void**)&wplo, g_wplo);
    cudaGetSymbolAddress((void**)&ahi, g_ahi);   cudaGetSymbolAddress((void**)&alo, g_alo);

    const int nx = MROWS * CDIM, nwq = CDIM * QKVC, nwp = CDIM * CDIM;
    split_kernel<<<(nx + 255) / 256, 256>>>(x, xhi, xlo, nx);
    split_kernel<<<(nwq + 255) / 256, 256>>>(wqkv, wqhi, wqlo, nwq);
    split_kernel<<<(nwp + 255) / 256, 256>>>(wproj, wphi, wplo, nwp);

    cudaFuncSetAttribute(mma_gemm_kernel<QKVC, true>,
                         cudaFuncAttributeMaxDynamicSharedMemorySize, G_SMEM);
    cudaFuncSetAttribute(mma_gemm_kernel<CDIM, false>,
                         cudaFuncAttributeMaxDynamicSharedMemorySize, G_SMEM);
    cudaFuncSetAttribute(flash_mma_kernel,
                         cudaFuncAttributeMaxDynamicSharedMemorySize, FLASH_MMA_SMEM);

    dim3 g1(QKVC / 128, MROWS / 128);
    mma_gemm_kernel<QKVC, true><<<g1, 256, G_SMEM>>>(xhi, xlo, wqhi, wqlo, nullptr, nullptr);

    dim3 gg(NSEQ / 8, HN, BB);
    gather_kv_kernel<<<gg, 256>>>();

    dim3 g2(NSEQ / 128, HN, BB);
    flash_mma_kernel<<<g2, 256, FLASH_MMA_SMEM>>>();

    dim3 g3(CDIM / 128, MROWS / 128);
    mma_gemm_kernel<CDIM, false><<<g3, 256, G_SMEM>>>(ahi, alo, wphi, wplo, bproj, out);
}

// round 11
// speedup vs baseline: 3.4476x; 1.0380x over previous
#include <cuda_runtime.h>
#include <cuda_bf16.h>
#include <math.h>
#include <stdint.h>

#define BB    2
#define NSEQ  2048
#define CDIM  1024
#define HN    16
#define DH    64
#define MROWS (BB*NSEQ)     // 4096
#define QKVC  (3*CDIM)      // 3072

// ---------------- scratch (static device globals; no allocation) -------------
__device__ __align__(16) __nv_bfloat16 g_xhi[(size_t)MROWS*CDIM], g_xlo[(size_t)MROWS*CDIM];
__device__ __align__(16) __nv_bfloat16 g_wqhi[(size_t)CDIM*QKVC], g_wqlo[(size_t)CDIM*QKVC];
__device__ __align__(16) __nv_bfloat16 g_wphi[(size_t)CDIM*CDIM], g_wplo[(size_t)CDIM*CDIM];
__device__ __align__(16) __nv_bfloat16 g_ahi[(size_t)MROWS*CDIM], g_alo[(size_t)MROWS*CDIM];
__device__ __align__(16) __nv_bfloat16 g_qhi[(size_t)BB*HN*NSEQ*DH], g_qlo[(size_t)BB*HN*NSEQ*DH];
__device__ __align__(16) __nv_bfloat16 g_khi[(size_t)BB*HN*NSEQ*DH], g_klo[(size_t)BB*HN*NSEQ*DH];
__device__ __align__(16) __nv_bfloat16 g_vhi[(size_t)BB*HN*NSEQ*DH], g_vlo[(size_t)BB*HN*NSEQ*DH];
// gathered (padding-compacted) K/V
__device__ __align__(16) __nv_bfloat16 g_kghi[(size_t)BB*HN*NSEQ*DH], g_kglo[(size_t)BB*HN*NSEQ*DH];
__device__ __align__(16) __nv_bfloat16 g_vghi[(size_t)BB*HN*NSEQ*DH], g_vglo[(size_t)BB*HN*NSEQ*DH];
__device__ unsigned char g_maskc[BB*NSEQ];
__device__ int g_kidx[BB*NSEQ];          // ascending orig cols of unmasked keys (pad 0x7FFFFFFF)
__device__ int g_pcnt[BB*(NSEQ+1)];      // exclusive prefix count of unmasked
__device__ int g_kcnt[BB];
__device__ int g_causal_d;

// ---------------- prep: mask canon + causal + per-batch key compaction -------
__global__ void prep_kernel(const void* __restrict__ mask_raw,
                            const int* __restrict__ cs_raw, int nmask) {
    __shared__ int sfmt;
    __shared__ int snz1, snz3;
    __shared__ int tsum[257];
    const unsigned char* mb = (const unsigned char*)mask_raw;
    const int tid = threadIdx.x;
    if (tid == 0) { snz1 = 0; snz3 = 0; }
    __syncthreads();
    {   // parallel dtype sniff over first 1024 bytes
        int scan = nmask < 1024 ? nmask : 1024;
        for (int i = tid; i < scan; i += 256) {
            unsigned char v = mb[i];
            if (v) { int r = i & 3; if (r == 1) snz1 = 1; else if (r == 3) snz3 = 1; }
        }
    }
    __syncthreads();
    if (tid == 0) {
        sfmt = snz1 ? 0 : (snz3 ? 2 : 1);  // 0=u8, 1=i32, 2=f32
        int cv = cs_raw[0];
        if (cv < 0 || cv > (1 << 24)) cv = (int)__int_as_float(cv);
        g_causal_d = cv;
    }
    __syncthreads();
    int f = sfmt;
    for (int i = tid; i < nmask; i += 256) {
        unsigned char m;
        if (f == 0)      m = mb[i] != 0;
        else if (f == 1) m = ((const int*)mask_raw)[i] != 0;
        else             m = ((const float*)mask_raw)[i] != 0.0f;
        g_maskc[i] = m;
    }
    __syncthreads();
    // per-batch compaction scan (2048 = 256 threads x 8)
    for (int b = 0; b < BB; b++) {
        int flags[8], s = 0;
        const int base = b * NSEQ + tid * 8;
#pragma unroll
        for (int j = 0; j < 8; j++) { flags[j] = g_maskc[base + j] ? 0 : 1; s += flags[j]; }
        tsum[tid] = s;
        __syncthreads();
        if (tid == 0) {
            int acc = 0;
            for (int i = 0; i < 256; i++) { int t = tsum[i]; tsum[i] = acc; acc += t; }
            tsum[256] = acc;
            g_kcnt[b] = acc;
        }
        __syncthreads();
        int run = tsum[tid];
#pragma unroll
        for (int j = 0; j < 8; j++) {
            const int n = tid * 8 + j;
            g_pcnt[b * (NSEQ + 1) + n] = run;
            if (flags[j]) { g_kidx[b * NSEQ + run] = n; run++; }
        }
        if (tid == 255) g_pcnt[b * (NSEQ + 1) + NSEQ] = run;
        __syncthreads();
        const int cnt = tsum[256];
        for (int i = cnt + tid; i < NSEQ; i += 256) g_kidx[b * NSEQ + i] = 0x7FFFFFFF;
        __syncthreads();
    }
}

// ---------------- vectorized split fp32 -> bf16 hi + lo ----------------------
__global__ void split4_kernel(const float4* __restrict__ src,
                              __nv_bfloat162* __restrict__ hi,
                              __nv_bfloat162* __restrict__ lo, int n4) {
    int i = blockIdx.x * blockDim.x + threadIdx.x;
    if (i < n4) {
        float4 v = src[i];
        __nv_bfloat162 h0 = __floats2bfloat162_rn(v.x, v.y);
        __nv_bfloat162 h1 = __floats2bfloat162_rn(v.z, v.w);
        __nv_bfloat162 l0 = __floats2bfloat162_rn(v.x - __bfloat162float(h0.x),
                                                  v.y - __bfloat162float(h0.y));
        __nv_bfloat162 l1 = __floats2bfloat162_rn(v.z - __bfloat162float(h1.x),
                                                  v.w - __bfloat162float(h1.y));
        hi[2 * i] = h0; hi[2 * i + 1] = h1;
        lo[2 * i] = l0; lo[2 * i + 1] = l1;
    }
}

// ---------------- gather: compact unmasked K/V rows per (b,h) ----------------
__global__ void gather_kv_kernel() {
    const int b = blockIdx.z, h = blockIdx.y;
    const int j = blockIdx.x * 8 + (threadIdx.x >> 5);
    const int lane = threadIdx.x & 31;
    const int cnt = g_kcnt[b];
    const int cntp = (cnt + 63) & ~63;
    if (j >= cntp) return;
    const size_t dst = (((size_t)b * HN + h) * NSEQ + j) * DH;
    if (j < cnt) {
        const int n = g_kidx[b * NSEQ + j];
        const size_t src = (((size_t)b * HN + h) * NSEQ + n) * DH;
        ((unsigned*)(g_kghi + dst))[lane] = ((const unsigned*)(g_khi + src))[lane];
        ((unsigned*)(g_kglo + dst))[lane] = ((const unsigned*)(g_klo + src))[lane];
        ((unsigned*)(g_vghi + dst))[lane] = ((const unsigned*)(g_vhi + src))[lane];
        ((unsigned*)(g_vglo + dst))[lane] = ((const unsigned*)(g_vlo + src))[lane];
    } else {
        ((unsigned*)(g_kghi + dst))[lane] = 0;
        ((unsigned*)(g_kglo + dst))[lane] = 0;
        ((unsigned*)(g_vghi + dst))[lane] = 0;
        ((unsigned*)(g_vglo + dst))[lane] = 0;
    }
}

// ---------------- PTX helpers -------------------------------------------------
__device__ __forceinline__ uint32_t s2u(const void* p) {
    return (uint32_t)__cvta_generic_to_shared(p);
}
__device__ __forceinline__ void ldsm_x4(unsigned* r, uint32_t addr) {
    asm volatile("ldmatrix.sync.aligned.m8n8.x4.shared.b16 {%0,%1,%2,%3}, [%4];"
                 : "=r"(r[0]), "=r"(r[1]), "=r"(r[2]), "=r"(r[3]) : "r"(addr));
}
__device__ __forceinline__ void ldsm_x4t(unsigned* r, uint32_t addr) {
    asm volatile("ldmatrix.sync.aligned.m8n8.x4.trans.shared.b16 {%0,%1,%2,%3}, [%4];"
                 : "=r"(r[0]), "=r"(r[1]), "=r"(r[2]), "=r"(r[3]) : "r"(addr));
}
__device__ __forceinline__ void mma_bf16(float* d, const unsigned* a, const unsigned* b) {
    asm volatile("mma.sync.aligned.m16n8k16.row.col.f32.bf16.bf16.f32 "
                 "{%0,%1,%2,%3}, {%4,%5,%6,%7}, {%8,%9}, {%0,%1,%2,%3};"
                 : "+f"(d[0]), "+f"(d[1]), "+f"(d[2]), "+f"(d[3])
                 : "r"(a[0]), "r"(a[1]), "r"(a[2]), "r"(a[3]), "r"(b[0]), "r"(b[1]));
}
__device__ __forceinline__ unsigned bf2u(__nv_bfloat162 x) { return *(unsigned*)&x; }
__device__ __forceinline__ void cp16(uint32_t smem, const void* g) {
    asm volatile("cp.async.cg.shared.global [%0], [%1], 16;"
                 :: "r"(smem), "l"(__cvta_generic_to_global(g)) : "memory");
}
__device__ __forceinline__ void cp_commit() {
    asm volatile("cp.async.commit_group;" ::: "memory");
}
template<int N> __device__ __forceinline__ void cp_wait() {
    asm volatile("cp.async.wait_group %0;" :: "n"(N) : "memory");
}

// ====== bf16x3 tensor-core GEMM, BK=32, 3-stage ring, 2 CTAs/SM, 1 sync/iter =
#define G_STG   18944
#define G_ALO   5120
#define G_BHI   10240
#define G_BLO   14592
#define G_SMEM  (3 * G_STG * 2)       // 113664 B; x2 CTAs = 227.3KB <= 228KB
#define G_NT    (CDIM / 32)           // 32

template<int NTOT, bool QKV_EPI>
__global__ void __launch_bounds__(256, 2)
mma_gemm_kernel(const __nv_bfloat16* __restrict__ Ahi,
                const __nv_bfloat16* __restrict__ Alo,
                const __nv_bfloat16* __restrict__ Bhi,
                const __nv_bfloat16* __restrict__ Blo,
                const float* __restrict__ bias, float* __restrict__ out) {
    extern __shared__ __align__(16) char smraw[];
    const uint32_t smu = s2u(smraw);

    const int tid = threadIdx.x, lane = tid & 31, wid = tid >> 5;
    const int wm = wid >> 2, wn = wid & 3;
    const int m0 = blockIdx.y * 128, n0 = blockIdx.x * 128;

    const int s_ar = tid >> 2, s_ak = (tid & 3) * 8;
    const int s_br = tid >> 4, s_bn = (tid & 15) * 8;

    auto stage = [&](int kt, int s) {
        const int k0 = kt * 32;
        const uint32_t sb = smu + s * G_STG * 2;
#pragma unroll
        for (int it = 0; it < 2; it++) {
            const int r = s_ar + it * 64;
            cp16(sb + (r * 40 + s_ak) * 2, Ahi + (size_t)(m0 + r) * CDIM + k0 + s_ak);
            cp16(sb + (G_ALO + r * 40 + s_ak) * 2, Alo + (size_t)(m0 + r) * CDIM + k0 + s_ak);
            const int rb = s_br + it * 16;
            cp16(sb + (G_BHI + rb * 136 + s_bn) * 2, Bhi + (size_t)(k0 + rb) * NTOT + n0 + s_bn);
            cp16(sb + (G_BLO + rb * 136 + s_bn) * 2, Blo + (size_t)(k0 + rb) * NTOT + n0 + s_bn);
        }
    };

    float acc[4][4][4];
#pragma unroll
    for (int i = 0; i < 4; i++)
#pragma unroll
        for (int j = 0; j < 4; j++)
#pragma unroll
            for (int q = 0; q < 4; q++) acc[i][j][q] = 0.f;

    const int a_ld = (wm * 64 + (lane & 15)) * 40 + (lane >> 4) * 8;
    const int b_ld = (lane & 15) * 136 + wn * 32 + (lane >> 4) * 8;

    stage(0, 0); cp_commit();
    stage(1, 1); cp_commit();

    for (int kt = 0; kt < G_NT; kt++) {
        if (kt == G_NT - 1) cp_wait<0>(); else cp_wait<1>();
        __syncthreads();   // buffer kt ready for all; all warps done with (kt+2)%3's prior use
        if (kt + 2 < G_NT) { stage(kt + 2, (kt + 2) % 3); cp_commit(); }

        const uint32_t sb = smu + (kt % 3) * G_STG * 2;
#pragma unroll
        for (int ks = 0; ks < 2; ks++) {
            unsigned ah[4][4], al[4][4], bh[4][2], bl[4][2];
            const uint32_t aBh = sb + (a_ld + ks * 16) * 2;
            const uint32_t aBl = aBh + G_ALO * 2;
            const uint32_t bBh = sb + (G_BHI + b_ld + ks * 16 * 136) * 2;
            const uint32_t bBl = bBh + (G_BLO - G_BHI) * 2;
#pragma unroll
            for (int mt = 0; mt < 4; mt++) {
                ldsm_x4(ah[mt], aBh + mt * 16 * 40 * 2);
                ldsm_x4(al[mt], aBl + mt * 16 * 40 * 2);
            }
#pragma unroll
            for (int ntp = 0; ntp < 2; ntp++) {
                unsigned t4[4];
                ldsm_x4t(t4, bBh + ntp * 16 * 2);
                bh[2 * ntp][0] = t4[0]; bh[2 * ntp][1] = t4[1];
                bh[2 * ntp + 1][0] = t4[2]; bh[2 * ntp + 1][1] = t4[3];
                ldsm_x4t(t4, bBl + ntp * 16 * 2);
                bl[2 * ntp][0] = t4[0]; bl[2 * ntp][1] = t4[1];
                bl[2 * ntp + 1][0] = t4[2]; bl[2 * ntp + 1][1] = t4[3];
            }
#pragma unroll
            for (int mt = 0; mt < 4; mt++)
#pragma unroll
                for (int nt = 0; nt < 4; nt++) {
                    mma_bf16(acc[mt][nt], ah[mt], bh[nt]);
                    mma_bf16(acc[mt][nt], ah[mt], bl[nt]);
                    mma_bf16(acc[mt][nt], al[mt], bh[nt]);
                }
        }
    }

    // epilogue
    const int rb = m0 + wm * 64 + (lane >> 2);
    const int cb = n0 + wn * 32 + (lane & 3) * 2;
#pragma unroll
    for (int mt = 0; mt < 4; mt++)
#pragma unroll
        for (int nt = 0; nt < 4; nt++) {
            const int c = cb + nt * 8;
            if (QKV_EPI) {
                const int sec = c >> 10, h = (c & 1023) >> 6, d = c & 63;
                const float scl = (sec == 0) ? 0.125f : 1.0f;  // pre-scale Q by 1/sqrt(64)
                __nv_bfloat16 *dhi, *dlo;
                if (sec == 0)      { dhi = g_qhi; dlo = g_qlo; }
                else if (sec == 1) { dhi = g_khi; dlo = g_klo; }
                else               { dhi = g_vhi; dlo = g_vlo; }
#pragma unroll
                for (int half = 0; half < 2; half++) {
                    const int r = rb + mt * 16 + half * 8;
                    const int bidx = r >> 11, n = r & (NSEQ - 1);
                    size_t off = (((size_t)bidx * HN + h) * NSEQ + n) * DH + d;
                    float v0 = acc[mt][nt][2 * half] * scl, v1 = acc[mt][nt][2 * half + 1] * scl;
                    __nv_bfloat162 hh = __floats2bfloat162_rn(v0, v1);
                    __nv_bfloat162 ll = __floats2bfloat162_rn(
                        v0 - __bfloat162float(hh.x), v1 - __bfloat162float(hh.y));
                    *(__nv_bfloat162*)&dhi[off] = hh;
                    *(__nv_bfloat162*)&dlo[off] = ll;
                }
            } else {
                const float b0 = bias[c], b1 = bias[c + 1];
#pragma unroll
                for (int half = 0; half < 2; half++) {
                    const int r = rb + mt * 16 + half * 8;
                    float* p = out + (size_t)r * NTOT + c;
                    *(float2*)p = make_float2(acc[mt][nt][2 * half] + b0,
                                              acc[mt][nt][2 * half + 1] + b1);
                }
            }
        }
}

// =============== Flash attention: Br=128, compacted keys, Bc=64 ==============
#define QP 72
#define F_KV0   18432
#define F_KVSZ  18432
#define F_SCOLB (55296 * 2)
#define FLASH_MMA_SMEM (F_SCOLB + 512)   // 111104 B -> 2 CTAs/SM

__global__ void __launch_bounds__(256, 2) flash_mma_kernel() {
    extern __shared__ __align__(16) char smraw[];
    __nv_bfloat16* smb = (__nv_bfloat16*)smraw;
    const uint32_t smu = s2u(smraw);
    __nv_bfloat16* sQh = smb;
    __nv_bfloat16* sQl = smb + 9216;
    int* scol = (int*)(smraw + F_SCOLB);   // [2][64] gathered orig column ids

    const int tid = threadIdx.x, lane = tid & 31, wid = tid >> 5;
    const int qt = gridDim.x - 1 - blockIdx.x;   // heavy causal tiles first
    const int h = blockIdx.y, b = blockIdx.z;
    const int q0 = qt * 128;
    const int cstart = g_causal_d;
    const size_t hoff = ((size_t)b * HN + h) * NSEQ * DH;

    const __nv_bfloat16 *Qh = g_qhi + hoff, *Ql = g_qlo + hoff;
    const __nv_bfloat16* kvsrc[4] = {g_kghi + hoff, g_kglo + hoff,
                                     g_vghi + hoff, g_vglo + hoff};

    {
        const int r = tid >> 1, c0 = (tid & 1) * 32;
#pragma unroll
        for (int c = 0; c < 32; c += 8) {
            *(uint4*)&sQh[r * QP + c0 + c] = *(const uint4*)&Qh[(size_t)(q0 + r) * DH + c0 + c];
            *(uint4*)&sQl[r * QP + c0 + c] = *(const uint4*)&Ql[(size_t)(q0 + r) * DH + c0 + c];
        }
    }

    const int kv_r = tid >> 3, kv_c = (tid & 7) * 8;
    auto stageKV = [&](int t) {
        const int k0t = t * 64;
        const uint32_t base = smu + (F_KV0 + (t & 1) * F_KVSZ) * 2;
#pragma unroll
        for (int pl = 0; pl < 4; pl++)
#pragma unroll
            for (int half = 0; half < 2; half++) {
                const int r = kv_r + half * 32;
                cp16(base + (pl * 4608 + r * QP + kv_c) * 2,
                     kvsrc[pl] + (size_t)(k0t + r) * DH + kv_c);
            }
    };

    int kmaxi = q0 + 127;
    if (cstart - 1 > kmaxi) kmaxi = cstart - 1;
    if (kmaxi > NSEQ - 1) kmaxi = NSEQ - 1;
    const int kcnt = g_pcnt[b * (NSEQ + 1) + kmaxi + 1];  // unmasked keys visible
    const int ntiles = (kcnt + 63) >> 6;

    stageKV(0); cp_commit();
    if (tid < 64) scol[tid] = g_kidx[b * NSEQ + tid];

    unsigned qfh[4][4], qfl[4][4];
    float m0v = -1e30f, m1v = -1e30f, l0v = 0.f, l1v = 0.f;
    float oacc[8][4] = {};

    const int grow0 = q0 + wid * 16 + (lane >> 2);
    const int grow1 = grow0 + 8;

    for (int t = 0; t < ntiles; t++) {
        __syncthreads();
        if (t == 0) {
#pragma unroll
            for (int ks = 0; ks < 4; ks++) {
                const int qa = (wid * 16 + (lane & 15)) * QP + ks * 16 + (lane >> 4) * 8;
                ldsm_x4(qfh[ks], s2u(&sQh[qa]));
                ldsm_x4(qfl[ks], s2u(&sQl[qa]));
            }
        }
        if (t + 1 < ntiles) {
            stageKV(t + 1);
            if (tid < 64)
                scol[((t + 1) & 1) * 64 + tid] = g_kidx[b * NSEQ + (t + 1) * 64 + tid];
            cp_commit();
            cp_wait<1>();
        } else {
            cp_wait<0>();
        }
        __syncthreads();

        const __nv_bfloat16* kb = smb + F_KV0 + (t & 1) * F_KVSZ;
        const __nv_bfloat16* sKh = kb;
        const __nv_bfloat16* sKl = kb + 4608;
        const __nv_bfloat16* sVh = kb + 9216;
        const __nv_bfloat16* sVl = kb + 13824;
        const int* sc = scol + (t & 1) * 64;

        // ---- S = Q K^T (Q pre-scaled by 0.125 in QKV epilogue) ----
        float sacc[8][4] = {};
#pragma unroll
        for (int ks = 0; ks < 4; ks++) {
            unsigned kbh[8][2], kbl[8][2];
#pragma unroll
            for (int np = 0; np < 4; np++) {
                const int row = np * 16 + ((lane >> 4) & 1) * 8 + (lane & 7);
                const int col = ks * 16 + ((lane >> 3) & 1) * 8;
                unsigned t4[4];
                ldsm_x4(t4, s2u(&sKh[row * QP + col]));
                kbh[2 * np][0] = t4[0]; kbh[2 * np][1] = t4[1];
                kbh[2 * np + 1][0] = t4[2]; kbh[2 * np + 1][1] = t4[3];
                ldsm_x4(t4, s2u(&sKl[row * QP + col]));
                kbl[2 * np][0] = t4[0]; kbl[2 * np][1] = t4[1];
                kbl[2 * np + 1][0] = t4[2]; kbl[2 * np + 1][1] = t4[3];
            }
#pragma unroll
            for (int nt = 0; nt < 8; nt++) {
                mma_bf16(sacc[nt], qfh[ks], kbh[nt]);
                mma_bf16(sacc[nt], qfh[ks], kbl[nt]);
                mma_bf16(sacc[nt], qfl[ks], kbh[nt]);
            }
        }

        // ---- causal mask on ORIGINAL column ids + row max ----
        float tmax0 = -INFINITY, tmax1 = -INFINITY;
#pragma unroll
        for (int nt = 0; nt < 8; nt++) {
#pragma unroll
            for (int j = 0; j < 2; j++) {
                const int lc = nt * 8 + (lane & 3) * 2 + j;
                const int col = sc[lc];               // orig col (INT_MAX pad -> masked)
                float v0 = sacc[nt][j];
                float v1 = sacc[nt][2 + j];
                v0 = (col > grow0 && col >= cstart) ? -INFINITY : v0;
                v1 = (col > grow1 && col >= cstart) ? -INFINITY : v1;
                sacc[nt][j] = v0; sacc[nt][2 + j] = v1;
                tmax0 = fmaxf(tmax0, v0); tmax1 = fmaxf(tmax1, v1);
            }
        }
#pragma unroll
        for (int off = 1; off < 4; off <<= 1) {
            tmax0 = fmaxf(tmax0, __shfl_xor_sync(0xffffffffu, tmax0, off));
            tmax1 = fmaxf(tmax1, __shfl_xor_sync(0xffffffffu, tmax1, off));
        }

        // ---- online softmax update ----
        const float mn0 = fmaxf(m0v, tmax0), mn1 = fmaxf(m1v, tmax1);
        const float cr0 = __expf(m0v - mn0), cr1 = __expf(m1v - mn1);
        m0v = mn0; m1v = mn1;
        l0v *= cr0; l1v *= cr1;
#pragma unroll
        for (int nt = 0; nt < 8; nt++) {
            oacc[nt][0] *= cr0; oacc[nt][1] *= cr0;
            oacc[nt][2] *= cr1; oacc[nt][3] *= cr1;
        }
        float rs0 = 0.f, rs1 = 0.f;
#pragma unroll
        for (int nt = 0; nt < 8; nt++) {
            float p0 = __expf(sacc[nt][0] - mn0), p1 = __expf(sacc[nt][1] - mn0);
            float p2 = __expf(sacc[nt][2] - mn1), p3 = __expf(sacc[nt][3] - mn1);
            sacc[nt][0] = p0; sacc[nt][1] = p1; sacc[nt][2] = p2; sacc[nt][3] = p3;
            rs0 += p0 + p1; rs1 += p2 + p3;
        }
#pragma unroll
        for (int off = 1; off < 4; off <<= 1) {
            rs0 += __shfl_xor_sync(0xffffffffu, rs0, off);
            rs1 += __shfl_xor_sync(0xffffffffu, rs1, off);
        }
        l0v += rs0; l1v += rs1;

        // ---- O += P V ----
#pragma unroll
        for (int ks = 0; ks < 4; ks++) {
            unsigned ah[4], al[4];
            {
                const float v0 = sacc[2 * ks][0], v1 = sacc[2 * ks][1];
                const float v2 = sacc[2 * ks][2], v3 = sacc[2 * ks][3];
                const float w0 = sacc[2 * ks + 1][0], w1 = sacc[2 * ks + 1][1];
                const float w2 = sacc[2 * ks + 1][2], w3 = sacc[2 * ks + 1][3];
                __nv_bfloat162 h0 = __floats2bfloat162_rn(v0, v1);
                __nv_bfloat162 h1 = __floats2bfloat162_rn(v2, v3);
                __nv_bfloat162 h2 = __floats2bfloat162_rn(w0, w1);
                __nv_bfloat162 h3 = __floats2bfloat162_rn(w2, w3);
                ah[0] = bf2u(h0); ah[1] = bf2u(h1); ah[2] = bf2u(h2); ah[3] = bf2u(h3);
                al[0] = bf2u(__floats2bfloat162_rn(v0 - __bfloat162float(h0.x),
                                                   v1 - __bfloat162float(h0.y)));
                al[1] = bf2u(__floats2bfloat162_rn(v2 - __bfloat162float(h1.x),
                                                   v3 - __bfloat162float(h1.y)));
                al[2] = bf2u(__floats2bfloat162_rn(w0 - __bfloat162float(h2.x),
                                                   w1 - __bfloat162float(h2.y)));
                al[3] = bf2u(__floats2bfloat162_rn(w2 - __bfloat162float(h3.x),
                                                   w3 - __bfloat162float(h3.y)));
            }
#pragma unroll
            for (int np = 0; np < 4; np++) {
                const int va = (ks * 16 + (lane & 15)) * QP + np * 16 + (lane >> 4) * 8;
                unsigned t4[4], t4l[4];
                ldsm_x4t(t4, s2u(&sVh[va]));
                ldsm_x4t(t4l, s2u(&sVl[va]));
                unsigned vb0[2] = {t4[0], t4[1]}, vb1[2] = {t4[2], t4[3]};
                unsigned vl0[2] = {t4l[0], t4l[1]}, vl1[2] = {t4l[2], t4l[3]};
                mma_bf16(oacc[2 * np], ah, vb0);
                mma_bf16(oacc[2 * np], ah, vl0);
                mma_bf16(oacc[2 * np], al, vb0);
                mma_bf16(oacc[2 * np + 1], ah, vb1);
                mma_bf16(oacc[2 * np + 1], ah, vl1);
                mma_bf16(oacc[2 * np + 1], al, vb1);
            }
        }
    }

    // ---- normalize + write bf16 hi/lo att (input of proj GEMM) ----
    const float inv0 = 1.f / l0v, inv1 = 1.f / l1v;
#pragma unroll
    for (int nt = 0; nt < 8; nt++) {
        const int d = nt * 8 + (lane & 3) * 2;
        const size_t o0 = ((size_t)b * NSEQ + grow0) * CDIM + h * DH + d;
        const size_t o1 = ((size_t)b * NSEQ + grow1) * CDIM + h * DH + d;
        const float v0 = oacc[nt][0] * inv0, v1 = oacc[nt][1] * inv0;
        const float w0 = oacc[nt][2] * inv1, w1 = oacc[nt][3] * inv1;
        __nv_bfloat162 h0 = __floats2bfloat162_rn(v0, v1);
        *(__nv_bfloat162*)&g_ahi[o0] = h0;
        *(__nv_bfloat162*)&g_alo[o0] = __floats2bfloat162_rn(
            v0 - __bfloat162float(h0.x), v1 - __bfloat162float(h0.y));
        __nv_bfloat162 h1 = __floats2bfloat162_rn(w0, w1);
        *(__nv_bfloat162*)&g_ahi[o1] = h1;
        *(__nv_bfloat162*)&g_alo[o1] = __floats2bfloat162_rn(
            w0 - __bfloat162float(h1.x), w1 - __bfloat162float(h1.y));
    }
}

// ---------------- launch ------------------------------------------------------
extern "C" void kernel_launch(void* const* d_in, const int* in_sizes, int n_in,
                              void* d_out, int out_size) {
    (void)n_in; (void)out_size;
    const float* x     = (const float*)d_in[0];
    const void*  mask  = d_in[1];
    const int*   cs    = (const int*)d_in[2];
    const float* wqkv  = (const float*)d_in[3];
    const float* wproj = (const float*)d_in[4];
    const float* bproj = (const float*)d_in[5];
    float* out = (float*)d_out;

    prep_kernel<<<1, 256>>>(mask, cs, in_sizes[1]);

    __nv_bfloat16 *xhi, *xlo, *wqhi, *wqlo, *wphi, *wplo, *ahi, *alo;
    cudaGetSymbolAddress((void**)&xhi, g_xhi);   cudaGetSymbolAddress((void**)&xlo, g_xlo);
    cudaGetSymbolAddress((void**)&wqhi, g_wqhi); cudaGetSymbolAddress((void**)&wqlo, g_wqlo);
    cudaGetSymbolAddress((void**)&wphi, g_wphi); cudaGetSymbolAddress((void**)&wplo, g_wplo);
    cudaGetSymbolAddress((void**)&ahi, g_ahi);   cudaGetSymbolAddress((void**)&alo, g_alo);

    const int nx4 = MROWS * CDIM / 4, nwq4 = CDIM * QKVC / 4, nwp4 = CDIM * CDIM / 4;
    split4_kernel<<<(nx4 + 255) / 256, 256>>>((const float4*)x,
        (__nv_bfloat162*)xhi, (__nv_bfloat162*)xlo, nx4);
    split4_kernel<<<(nwq4 + 255) / 256, 256>>>((const float4*)wqkv,
        (__nv_bfloat162*)wqhi, (__nv_bfloat162*)wqlo, nwq4);
    split4_kernel<<<(nwp4 + 255) / 256, 256>>>((const float4*)wproj,
        (__nv_bfloat162*)wphi, (__nv_bfloat162*)wplo, nwp4);

    cudaFuncSetAttribute(mma_gemm_kernel<QKVC, true>,
                         cudaFuncAttributeMaxDynamicSharedMemorySize, G_SMEM);
    cudaFuncSetAttribute(mma_gemm_kernel<CDIM, false>,
                         cudaFuncAttributeMaxDynamicSharedMemorySize, G_SMEM);
    cudaFuncSetAttribute(flash_mma_kernel,
                         cudaFuncAttributeMaxDynamicSharedMemorySize, FLASH_MMA_SMEM);

    dim3 g1(QKVC / 128, MROWS / 128);
    mma_gemm_kernel<QKVC, true><<<g1, 256, G_SMEM>>>(xhi, xlo, wqhi, wqlo, nullptr, nullptr);

    dim3 gg(NSEQ / 8, HN, BB);
    gather_kv_kernel<<<gg, 256>>>();

    dim3 g2(NSEQ / 128, HN, BB);
    flash_mma_kernel<<<g2, 256, FLASH_MMA_SMEM>>>();

    dim3 g3(CDIM / 128, MROWS / 128);
    mma_gemm_kernel<CDIM, false><<<g3, 256, G_SMEM>>>(ahi, alo, wphi, wplo, bproj, out);
}

// round 12
// speedup vs baseline: 3.6126x; 1.0479x over previous
#include <cuda_runtime.h>
#include <cuda_bf16.h>
#include <math.h>
#include <stdint.h>

#define BB    2
#define NSEQ  2048
#define CDIM  1024
#define HN    16
#define DH    64
#define MROWS (BB*NSEQ)     // 4096
#define QKVC  (3*CDIM)      // 3072

// ---------------- scratch (static device globals; no allocation) -------------
__device__ __align__(16) __nv_bfloat16 g_xhi[(size_t)MROWS*CDIM], g_xlo[(size_t)MROWS*CDIM];
__device__ __align__(16) __nv_bfloat16 g_wqhi[(size_t)CDIM*QKVC], g_wqlo[(size_t)CDIM*QKVC];
__device__ __align__(16) __nv_bfloat16 g_wphi[(size_t)CDIM*CDIM], g_wplo[(size_t)CDIM*CDIM];
__device__ __align__(16) __nv_bfloat16 g_ahi[(size_t)MROWS*CDIM], g_alo[(size_t)MROWS*CDIM];
__device__ __align__(16) __nv_bfloat16 g_qhi[(size_t)BB*HN*NSEQ*DH], g_qlo[(size_t)BB*HN*NSEQ*DH];
__device__ __align__(16) __nv_bfloat16 g_khi[(size_t)BB*HN*NSEQ*DH], g_klo[(size_t)BB*HN*NSEQ*DH];
__device__ __align__(16) __nv_bfloat16 g_vhi[(size_t)BB*HN*NSEQ*DH], g_vlo[(size_t)BB*HN*NSEQ*DH];
// gathered (padding-compacted) K/V
__device__ __align__(16) __nv_bfloat16 g_kghi[(size_t)BB*HN*NSEQ*DH], g_kglo[(size_t)BB*HN*NSEQ*DH];
__device__ __align__(16) __nv_bfloat16 g_vghi[(size_t)BB*HN*NSEQ*DH], g_vglo[(size_t)BB*HN*NSEQ*DH];
__device__ unsigned char g_maskc[BB*NSEQ];
__device__ int g_kidx[BB*NSEQ];
__device__ int g_pcnt[BB*(NSEQ+1)];
__device__ int g_kcnt[BB];
__device__ int g_causal_d;

// ---------------- prep: mask canon + causal + per-batch key compaction -------
__global__ void prep_kernel(const void* __restrict__ mask_raw,
                            const int* __restrict__ cs_raw, int nmask) {
    __shared__ int sfmt;
    __shared__ int snz1, snz3;
    __shared__ int tsum[257];
    const unsigned char* mb = (const unsigned char*)mask_raw;
    const int tid = threadIdx.x;
    if (tid == 0) { snz1 = 0; snz3 = 0; }
    __syncthreads();
    {
        int scan = nmask < 1024 ? nmask : 1024;
        for (int i = tid; i < scan; i += 256) {
            unsigned char v = mb[i];
            if (v) { int r = i & 3; if (r == 1) snz1 = 1; else if (r == 3) snz3 = 1; }
        }
    }
    __syncthreads();
    if (tid == 0) {
        sfmt = snz1 ? 0 : (snz3 ? 2 : 1);
        int cv = cs_raw[0];
        if (cv < 0 || cv > (1 << 24)) cv = (int)__int_as_float(cv);
        g_causal_d = cv;
    }
    __syncthreads();
    int f = sfmt;
    for (int i = tid; i < nmask; i += 256) {
        unsigned char m;
        if (f == 0)      m = mb[i] != 0;
        else if (f == 1) m = ((const int*)mask_raw)[i] != 0;
        else             m = ((const float*)mask_raw)[i] != 0.0f;
        g_maskc[i] = m;
    }
    __syncthreads();
    for (int b = 0; b < BB; b++) {
        int flags[8], s = 0;
        const int base = b * NSEQ + tid * 8;
#pragma unroll
        for (int j = 0; j < 8; j++) { flags[j] = g_maskc[base + j] ? 0 : 1; s += flags[j]; }
        tsum[tid] = s;
        __syncthreads();
        if (tid == 0) {
            int acc = 0;
            for (int i = 0; i < 256; i++) { int t = tsum[i]; tsum[i] = acc; acc += t; }
            tsum[256] = acc;
            g_kcnt[b] = acc;
        }
        __syncthreads();
        int run = tsum[tid];
#pragma unroll
        for (int j = 0; j < 8; j++) {
            const int n = tid * 8 + j;
            g_pcnt[b * (NSEQ + 1) + n] = run;
            if (flags[j]) { g_kidx[b * NSEQ + run] = n; run++; }
        }
        if (tid == 255) g_pcnt[b * (NSEQ + 1) + NSEQ] = run;
        __syncthreads();
        const int cnt = tsum[256];
        for (int i = cnt + tid; i < NSEQ; i += 256) g_kidx[b * NSEQ + i] = 0x7FFFFFFF;
        __syncthreads();
    }
}

// ---------------- fused vectorized splits (x, wqkv, wproj) -------------------
#define NX4  (MROWS * CDIM / 4)
#define NWQ4 (CDIM * QKVC / 4)
#define NWP4 (CDIM * CDIM / 4)
__global__ void split_all_kernel(const float4* __restrict__ x,
                                 const float4* __restrict__ wq,
                                 const float4* __restrict__ wp) {
    int i = blockIdx.x * blockDim.x + threadIdx.x;
    const float4* src;
    __nv_bfloat162 *hi, *lo;
    if (i < NX4) {
        src = x + i; hi = (__nv_bfloat162*)g_xhi + 2 * i; lo = (__nv_bfloat162*)g_xlo + 2 * i;
    } else if (i < NX4 + NWQ4) {
        int j = i - NX4;
        src = wq + j; hi = (__nv_bfloat162*)g_wqhi + 2 * j; lo = (__nv_bfloat162*)g_wqlo + 2 * j;
    } else if (i < NX4 + NWQ4 + NWP4) {
        int j = i - NX4 - NWQ4;
        src = wp + j; hi = (__nv_bfloat162*)g_wphi + 2 * j; lo = (__nv_bfloat162*)g_wplo + 2 * j;
    } else return;
    float4 v = *src;
    __nv_bfloat162 h0 = __floats2bfloat162_rn(v.x, v.y);
    __nv_bfloat162 h1 = __floats2bfloat162_rn(v.z, v.w);
    hi[0] = h0; hi[1] = h1;
    lo[0] = __floats2bfloat162_rn(v.x - __bfloat162float(h0.x), v.y - __bfloat162float(h0.y));
    lo[1] = __floats2bfloat162_rn(v.z - __bfloat162float(h1.x), v.w - __bfloat162float(h1.y));
}

// ---------------- gather: compact unmasked K/V rows per (b,h) ----------------
__global__ void gather_kv_kernel() {
    const int b = blockIdx.z, h = blockIdx.y;
    const int j = blockIdx.x * 8 + (threadIdx.x >> 5);
    const int lane = threadIdx.x & 31;
    const int cnt = g_kcnt[b];
    const int cntp = (cnt + 63) & ~63;
    if (j >= cntp) return;
    const size_t dst = (((size_t)b * HN + h) * NSEQ + j) * DH;
    if (j < cnt) {
        const int n = g_kidx[b * NSEQ + j];
        const size_t src = (((size_t)b * HN + h) * NSEQ + n) * DH;
        ((unsigned*)(g_kghi + dst))[lane] = ((const unsigned*)(g_khi + src))[lane];
        ((unsigned*)(g_kglo + dst))[lane] = ((const unsigned*)(g_klo + src))[lane];
        ((unsigned*)(g_vghi + dst))[lane] = ((const unsigned*)(g_vhi + src))[lane];
        ((unsigned*)(g_vglo + dst))[lane] = ((const unsigned*)(g_vlo + src))[lane];
    } else {
        ((unsigned*)(g_kghi + dst))[lane] = 0;
        ((unsigned*)(g_kglo + dst))[lane] = 0;
        ((unsigned*)(g_vghi + dst))[lane] = 0;
        ((unsigned*)(g_vglo + dst))[lane] = 0;
    }
}

// ---------------- PTX helpers -------------------------------------------------
__device__ __forceinline__ uint32_t s2u(const void* p) {
    return (uint32_t)__cvta_generic_to_shared(p);
}
__device__ __forceinline__ void ldsm_x4(unsigned* r, uint32_t addr) {
    asm volatile("ldmatrix.sync.aligned.m8n8.x4.shared.b16 {%0,%1,%2,%3}, [%4];"
                 : "=r"(r[0]), "=r"(r[1]), "=r"(r[2]), "=r"(r[3]) : "r"(addr));
}
__device__ __forceinline__ void ldsm_x4t(unsigned* r, uint32_t addr) {
    asm volatile("ldmatrix.sync.aligned.m8n8.x4.trans.shared.b16 {%0,%1,%2,%3}, [%4];"
                 : "=r"(r[0]), "=r"(r[1]), "=r"(r[2]), "=r"(r[3]) : "r"(addr));
}
__device__ __forceinline__ void mma_bf16(float* d, const unsigned* a, const unsigned* b) {
    asm volatile("mma.sync.aligned.m16n8k16.row.col.f32.bf16.bf16.f32 "
                 "{%0,%1,%2,%3}, {%4,%5,%6,%7}, {%8,%9}, {%0,%1,%2,%3};"
                 : "+f"(d[0]), "+f"(d[1]), "+f"(d[2]), "+f"(d[3])
                 : "r"(a[0]), "r"(a[1]), "r"(a[2]), "r"(a[3]), "r"(b[0]), "r"(b[1]));
}
__device__ __forceinline__ unsigned bf2u(__nv_bfloat162 x) { return *(unsigned*)&x; }
__device__ __forceinline__ void cp16(uint32_t smem, const void* g) {
    asm volatile("cp.async.cg.shared.global [%0], [%1], 16;"
                 :: "r"(smem), "l"(__cvta_generic_to_global(g)) : "memory");
}
__device__ __forceinline__ void cp_commit() {
    asm volatile("cp.async.commit_group;" ::: "memory");
}
template<int N> __device__ __forceinline__ void cp_wait() {
    asm volatile("cp.async.wait_group %0;" :: "n"(N) : "memory");
}

// == bf16x3 GEMM: 128x128 CTA, 4 warps x 64x64 warp tile, BK=32, 3-stage ring =
#define G_STG   18944
#define G_ALO   5120
#define G_BHI   10240
#define G_BLO   14592
#define G_SMEM  (3 * G_STG * 2)       // 113664 B; x2 CTAs = 227.3KB <= 228KB
#define G_NT    (CDIM / 32)           // 32

template<int NTOT, bool QKV_EPI>
__global__ void __launch_bounds__(128)
mma_gemm_kernel(const __nv_bfloat16* __restrict__ Ahi,
                const __nv_bfloat16* __restrict__ Alo,
                const __nv_bfloat16* __restrict__ Bhi,
                const __nv_bfloat16* __restrict__ Blo,
                const float* __restrict__ bias, float* __restrict__ out) {
    extern __shared__ __align__(16) char smraw[];
    const uint32_t smu = s2u(smraw);

    const int tid = threadIdx.x, lane = tid & 31, wid = tid >> 5;
    const int wm = wid >> 1, wn = wid & 1;          // 2x2 warp grid, 64x64 tiles
    const int m0 = blockIdx.y * 128, n0 = blockIdx.x * 128;

    auto stage = [&](int kt, int s) {
        const int k0 = kt * 32;
        const uint32_t sb = smu + s * G_STG * 2;
        const int arow = tid >> 2, acol = (tid & 3) * 8;     // +32 rows per it (4 its)
        const int brow = tid >> 4, bcol = (tid & 15) * 8;    // +8 rows per it (4 its)
#pragma unroll
        for (int it = 0; it < 4; it++) {
            const int r = arow + it * 32;
            cp16(sb + (r * 40 + acol) * 2, Ahi + (size_t)(m0 + r) * CDIM + k0 + acol);
            cp16(sb + (G_ALO + r * 40 + acol) * 2, Alo + (size_t)(m0 + r) * CDIM + k0 + acol);
            const int rb = brow + it * 8;
            cp16(sb + (G_BHI + rb * 136 + bcol) * 2, Bhi + (size_t)(k0 + rb) * NTOT + n0 + bcol);
            cp16(sb + (G_BLO + rb * 136 + bcol) * 2, Blo + (size_t)(k0 + rb) * NTOT + n0 + bcol);
        }
    };

    float acc[4][8][4];
#pragma unroll
    for (int i = 0; i < 4; i++)
#pragma unroll
        for (int j = 0; j < 8; j++)
#pragma unroll
            for (int q = 0; q < 4; q++) acc[i][j][q] = 0.f;

    const int a_ld = (wm * 64 + (lane & 15)) * 40 + (lane >> 4) * 8;
    const int b_ld = (lane & 15) * 136 + wn * 64 + (lane >> 4) * 8;

    stage(0, 0); cp_commit();
    stage(1, 1); cp_commit();

    for (int kt = 0; kt < G_NT; kt++) {
        if (kt == G_NT - 1) cp_wait<0>(); else cp_wait<1>();
        __syncthreads();
        if (kt + 2 < G_NT) { stage(kt + 2, (kt + 2) % 3); cp_commit(); }

        const uint32_t sb = smu + (kt % 3) * G_STG * 2;
#pragma unroll
        for (int ks = 0; ks < 2; ks++) {
            unsigned ah[4][4], al[4][4], bh[8][2], bl[8][2];
            const uint32_t aBh = sb + (a_ld + ks * 16) * 2;
            const uint32_t aBl = aBh + G_ALO * 2;
            const uint32_t bBh = sb + (G_BHI + b_ld + ks * 16 * 136) * 2;
            const uint32_t bBl = bBh + (G_BLO - G_BHI) * 2;
#pragma unroll
            for (int mt = 0; mt < 4; mt++) {
                ldsm_x4(ah[mt], aBh + mt * 16 * 40 * 2);
                ldsm_x4(al[mt], aBl + mt * 16 * 40 * 2);
            }
#pragma unroll
            for (int ntp = 0; ntp < 4; ntp++) {
                unsigned t4[4];
                ldsm_x4t(t4, bBh + ntp * 16 * 2);
                bh[2 * ntp][0] = t4[0]; bh[2 * ntp][1] = t4[1];
                bh[2 * ntp + 1][0] = t4[2]; bh[2 * ntp + 1][1] = t4[3];
                ldsm_x4t(t4, bBl + ntp * 16 * 2);
                bl[2 * ntp][0] = t4[0]; bl[2 * ntp][1] = t4[1];
                bl[2 * ntp + 1][0] = t4[2]; bl[2 * ntp + 1][1] = t4[3];
            }
#pragma unroll
            for (int mt = 0; mt < 4; mt++)
#pragma unroll
                for (int nt = 0; nt < 8; nt++) {
                    mma_bf16(acc[mt][nt], ah[mt], bh[nt]);
                    mma_bf16(acc[mt][nt], ah[mt], bl[nt]);
                    mma_bf16(acc[mt][nt], al[mt], bh[nt]);
                }
        }
    }

    // epilogue
    const int rb = m0 + wm * 64 + (lane >> 2);
    const int cb = n0 + wn * 64 + (lane & 3) * 2;
#pragma unroll
    for (int mt = 0; mt < 4; mt++)
#pragma unroll
        for (int nt = 0; nt < 8; nt++) {
            const int c = cb + nt * 8;
            if (QKV_EPI) {
                const int sec = c >> 10, h = (c & 1023) >> 6, d = c & 63;
                const float scl = (sec == 0) ? 0.125f : 1.0f;
                __nv_bfloat16 *dhi, *dlo;
                if (sec == 0)      { dhi = g_qhi; dlo = g_qlo; }
                else if (sec == 1) { dhi = g_khi; dlo = g_klo; }
                else               { dhi = g_vhi; dlo = g_vlo; }
#pragma unroll
                for (int half = 0; half < 2; half++) {
                    const int r = rb + mt * 16 + half * 8;
                    const int bidx = r >> 11, n = r & (NSEQ - 1);
                    size_t off = (((size_t)bidx * HN + h) * NSEQ + n) * DH + d;
                    float v0 = acc[mt][nt][2 * half] * scl, v1 = acc[mt][nt][2 * half + 1] * scl;
                    __nv_bfloat162 hh = __floats2bfloat162_rn(v0, v1);
                    __nv_bfloat162 ll = __floats2bfloat162_rn(
                        v0 - __bfloat162float(hh.x), v1 - __bfloat162float(hh.y));
                    *(__nv_bfloat162*)&dhi[off] = hh;
                    *(__nv_bfloat162*)&dlo[off] = ll;
                }
            } else {
                const float b0 = bias[c], b1 = bias[c + 1];
#pragma unroll
                for (int half = 0; half < 2; half++) {
                    const int r = rb + mt * 16 + half * 8;
                    float* p = out + (size_t)r * NTOT + c;
                    *(float2*)p = make_float2(acc[mt][nt][2 * half] + b0,
                                              acc[mt][nt][2 * half + 1] + b1);
                }
            }
        }
}

// =============== Flash attention: Br=128, compacted keys, Bc=64 ==============
#define QP 72
#define F_KV0   18432
#define F_KVSZ  18432
#define F_SCOLB (55296 * 2)
#define FLASH_MMA_SMEM (F_SCOLB + 512)   // 111104 B -> 2 CTAs/SM

__global__ void __launch_bounds__(256, 2) flash_mma_kernel() {
    extern __shared__ __align__(16) char smraw[];
    __nv_bfloat16* smb = (__nv_bfloat16*)smraw;
    const uint32_t smu = s2u(smraw);
    __nv_bfloat16* sQh = smb;
    __nv_bfloat16* sQl = smb + 9216;
    int* scol = (int*)(smraw + F_SCOLB);

    const int tid = threadIdx.x, lane = tid & 31, wid = tid >> 5;
    const int qt = gridDim.x - 1 - blockIdx.x;
    const int h = blockIdx.y, b = blockIdx.z;
    const int q0 = qt * 128;
    const int cstart = g_causal_d;
    const size_t hoff = ((size_t)b * HN + h) * NSEQ * DH;

    const __nv_bfloat16 *Qh = g_qhi + hoff, *Ql = g_qlo + hoff;
    const __nv_bfloat16* kvsrc[4] = {g_kghi + hoff, g_kglo + hoff,
                                     g_vghi + hoff, g_vglo + hoff};

    {
        const int r = tid >> 1, c0 = (tid & 1) * 32;
#pragma unroll
        for (int c = 0; c < 32; c += 8) {
            *(uint4*)&sQh[r * QP + c0 + c] = *(const uint4*)&Qh[(size_t)(q0 + r) * DH + c0 + c];
            *(uint4*)&sQl[r * QP + c0 + c] = *(const uint4*)&Ql[(size_t)(q0 + r) * DH + c0 + c];
        }
    }

    const int kv_r = tid >> 3, kv_c = (tid & 7) * 8;
    auto stageKV = [&](int t) {
        const int k0t = t * 64;
        const uint32_t base = smu + (F_KV0 + (t & 1) * F_KVSZ) * 2;
#pragma unroll
        for (int pl = 0; pl < 4; pl++)
#pragma unroll
            for (int half = 0; half < 2; half++) {
                const int r = kv_r + half * 32;
                cp16(base + (pl * 4608 + r * QP + kv_c) * 2,
                     kvsrc[pl] + (size_t)(k0t + r) * DH + kv_c);
            }
    };

    int kmaxi = q0 + 127;
    if (cstart - 1 > kmaxi) kmaxi = cstart - 1;
    if (kmaxi > NSEQ - 1) kmaxi = NSEQ - 1;
    const int kcnt = g_pcnt[b * (NSEQ + 1) + kmaxi + 1];
    const int ntiles = (kcnt + 63) >> 6;

    stageKV(0); cp_commit();
    if (tid < 64) scol[tid] = g_kidx[b * NSEQ + tid];

    unsigned qfh[4][4], qfl[4][4];
    float m0v = -1e30f, m1v = -1e30f, l0v = 0.f, l1v = 0.f;
    float oacc[8][4] = {};

    const int grow0 = q0 + wid * 16 + (lane >> 2);
    const int grow1 = grow0 + 8;

    for (int t = 0; t < ntiles; t++) {
        __syncthreads();
        if (t == 0) {
#pragma unroll
            for (int ks = 0; ks < 4; ks++) {
                const int qa = (wid * 16 + (lane & 15)) * QP + ks * 16 + (lane >> 4) * 8;
                ldsm_x4(qfh[ks], s2u(&sQh[qa]));
                ldsm_x4(qfl[ks], s2u(&sQl[qa]));
            }
        }
        if (t + 1 < ntiles) {
            stageKV(t + 1);
            if (tid < 64)
                scol[((t + 1) & 1) * 64 + tid] = g_kidx[b * NSEQ + (t + 1) * 64 + tid];
            cp_commit();
            cp_wait<1>();
        } else {
            cp_wait<0>();
        }
        __syncthreads();

        const __nv_bfloat16* kb = smb + F_KV0 + (t & 1) * F_KVSZ;
        const __nv_bfloat16* sKh = kb;
        const __nv_bfloat16* sKl = kb + 4608;
        const __nv_bfloat16* sVh = kb + 9216;
        const __nv_bfloat16* sVl = kb + 13824;
        const int* sc = scol + (t & 1) * 64;

        float sacc[8][4] = {};
#pragma unroll
        for (int ks = 0; ks < 4; ks++) {
            unsigned kbh[8][2], kbl[8][2];
#pragma unroll
            for (int np = 0; np < 4; np++) {
                const int row = np * 16 + ((lane >> 4) & 1) * 8 + (lane & 7);
                const int col = ks * 16 + ((lane >> 3) & 1) * 8;
                unsigned t4[4];
                ldsm_x4(t4, s2u(&sKh[row * QP + col]));
                kbh[2 * np][0] = t4[0]; kbh[2 * np][1] = t4[1];
                kbh[2 * np + 1][0] = t4[2]; kbh[2 * np + 1][1] = t4[3];
                ldsm_x4(t4, s2u(&sKl[row * QP + col]));
                kbl[2 * np][0] = t4[0]; kbl[2 * np][1] = t4[1];
                kbl[2 * np + 1][0] = t4[2]; kbl[2 * np + 1][1] = t4[3];
            }
#pragma unroll
            for (int nt = 0; nt < 8; nt++) {
                mma_bf16(sacc[nt], qfh[ks], kbh[nt]);
                mma_bf16(sacc[nt], qfh[ks], kbl[nt]);
                mma_bf16(sacc[nt], qfl[ks], kbh[nt]);
            }
        }

        float tmax0 = -INFINITY, tmax1 = -INFINITY;
#pragma unroll
        for (int nt = 0; nt < 8; nt++) {
#pragma unroll
            for (int j = 0; j < 2; j++) {
                const int lc = nt * 8 + (lane & 3) * 2 + j;
                const int col = sc[lc];
                float v0 = sacc[nt][j];
                float v1 = sacc[nt][2 + j];
                v0 = (col > grow0 && col >= cstart) ? -INFINITY : v0;
                v1 = (col > grow1 && col >= cstart) ? -INFINITY : v1;
                sacc[nt][j] = v0; sacc[nt][2 + j] = v1;
                tmax0 = fmaxf(tmax0, v0); tmax1 = fmaxf(tmax1, v1);
            }
        }
#pragma unroll
        for (int off = 1; off < 4; off <<= 1) {
            tmax0 = fmaxf(tmax0, __shfl_xor_sync(0xffffffffu, tmax0, off));
            tmax1 = fmaxf(tmax1, __shfl_xor_sync(0xffffffffu, tmax1, off));
        }

        const float mn0 = fmaxf(m0v, tmax0), mn1 = fmaxf(m1v, tmax1);
        const float cr0 = __expf(m0v - mn0), cr1 = __expf(m1v - mn1);
        m0v = mn0; m1v = mn1;
        l0v *= cr0; l1v *= cr1;
#pragma unroll
        for (int nt = 0; nt < 8; nt++) {
            oacc[nt][0] *= cr0; oacc[nt][1] *= cr0;
            oacc[nt][2] *= cr1; oacc[nt][3] *= cr1;
        }
        float rs0 = 0.f, rs1 = 0.f;
#pragma unroll
        for (int nt = 0; nt < 8; nt++) {
            float p0 = __expf(sacc[nt][0] - mn0), p1 = __expf(sacc[nt][1] - mn0);
            float p2 = __expf(sacc[nt][2] - mn1), p3 = __expf(sacc[nt][3] - mn1);
            sacc[nt][0] = p0; sacc[nt][1] = p1; sacc[nt][2] = p2; sacc[nt][3] = p3;
            rs0 += p0 + p1; rs1 += p2 + p3;
        }
#pragma unroll
        for (int off = 1; off < 4; off <<= 1) {
            rs0 += __shfl_xor_sync(0xffffffffu, rs0, off);
            rs1 += __shfl_xor_sync(0xffffffffu, rs1, off);
        }
        l0v += rs0; l1v += rs1;

#pragma unroll
        for (int ks = 0; ks < 4; ks++) {
            unsigned ah[4], al[4];
            {
                const float v0 = sacc[2 * ks][0], v1 = sacc[2 * ks][1];
                const float v2 = sacc[2 * ks][2], v3 = sacc[2 * ks][3];
                const float w0 = sacc[2 * ks + 1][0], w1 = sacc[2 * ks + 1][1];
                const float w2 = sacc[2 * ks + 1][2], w3 = sacc[2 * ks + 1][3];
                __nv_bfloat162 h0 = __floats2bfloat162_rn(v0, v1);
                __nv_bfloat162 h1 = __floats2bfloat162_rn(v2, v3);
                __nv_bfloat162 h2 = __floats2bfloat162_rn(w0, w1);
                __nv_bfloat162 h3 = __floats2bfloat162_rn(w2, w3);
                ah[0] = bf2u(h0); ah[1] = bf2u(h1); ah[2] = bf2u(h2); ah[3] = bf2u(h3);
                al[0] = bf2u(__floats2bfloat162_rn(v0 - __bfloat162float(h0.x),
                                                   v1 - __bfloat162float(h0.y)));
                al[1] = bf2u(__floats2bfloat162_rn(v2 - __bfloat162float(h1.x),
                                                   v3 - __bfloat162float(h1.y)));
                al[2] = bf2u(__floats2bfloat162_rn(w0 - __bfloat162float(h2.x),
                                                   w1 - __bfloat162float(h2.y)));
                al[3] = bf2u(__floats2bfloat162_rn(w2 - __bfloat162float(h3.x),
                                                   w3 - __bfloat162float(h3.y)));
            }
#pragma unroll
            for (int np = 0; np < 4; np++) {
                const int va = (ks * 16 + (lane & 15)) * QP + np * 16 + (lane >> 4) * 8;
                unsigned t4[4], t4l[4];
                ldsm_x4t(t4, s2u(&sVh[va]));
                ldsm_x4t(t4l, s2u(&sVl[va]));
                unsigned vb0[2] = {t4[0], t4[1]}, vb1[2] = {t4[2], t4[3]};
                unsigned vl0[2] = {t4l[0], t4l[1]}, vl1[2] = {t4l[2], t4l[3]};
                mma_bf16(oacc[2 * np], ah, vb0);
                mma_bf16(oacc[2 * np], ah, vl0);
                mma_bf16(oacc[2 * np], al, vb0);
                mma_bf16(oacc[2 * np + 1], ah, vb1);
                mma_bf16(oacc[2 * np + 1], ah, vl1);
                mma_bf16(oacc[2 * np + 1], al, vb1);
            }
        }
    }

    const float inv0 = 1.f / l0v, inv1 = 1.f / l1v;
#pragma unroll
    for (int nt = 0; nt < 8; nt++) {
        const int d = nt * 8 + (lane & 3) * 2;
        const size_t o0 = ((size_t)b * NSEQ + grow0) * CDIM + h * DH + d;
        const size_t o1 = ((size_t)b * NSEQ + grow1) * CDIM + h * DH + d;
        const float v0 = oacc[nt][0] * inv0, v1 = oacc[nt][1] * inv0;
        const float w0 = oacc[nt][2] * inv1, w1 = oacc[nt][3] * inv1;
        __nv_bfloat162 h0 = __floats2bfloat162_rn(v0, v1);
        *(__nv_bfloat162*)&g_ahi[o0] = h0;
        *(__nv_bfloat162*)&g_alo[o0] = __floats2bfloat162_rn(
            v0 - __bfloat162float(h0.x), v1 - __bfloat162float(h0.y));
        __nv_bfloat162 h1 = __floats2bfloat162_rn(w0, w1);
        *(__nv_bfloat162*)&g_ahi[o1] = h1;
        *(__nv_bfloat162*)&g_alo[o1] = __floats2bfloat162_rn(
            w0 - __bfloat162float(h1.x), w1 - __bfloat162float(h1.y));
    }
}

// ---------------- launch ------------------------------------------------------
extern "C" void kernel_launch(void* const* d_in, const int* in_sizes, int n_in,
                              void* d_out, int out_size) {
    (void)n_in; (void)out_size;
    const float* x     = (const float*)d_in[0];
    const void*  mask  = d_in[1];
    const int*   cs    = (const int*)d_in[2];
    const float* wqkv  = (const float*)d_in[3];
    const float* wproj = (const float*)d_in[4];
    const float* bproj = (const float*)d_in[5];
    float* out = (float*)d_out;

    prep_kernel<<<1, 256>>>(mask, cs, in_sizes[1]);

    __nv_bfloat16 *xhi, *xlo, *wqhi, *wqlo, *wphi, *wplo, *ahi, *alo;
    cudaGetSymbolAddress((void**)&xhi, g_xhi);   cudaGetSymbolAddress((void**)&xlo, g_xlo);
    cudaGetSymbolAddress((void**)&wqhi, g_wqhi); cudaGetSymbolAddress((void**)&wqlo, g_wqlo);
    cudaGetSymbolAddress((void**)&wphi, g_wphi); cudaGetSymbolAddress((void**)&wplo, g_wplo);
    cudaGetSymbolAddress((void**)&ahi, g_ahi);   cudaGetSymbolAddress((void**)&alo, g_alo);

    const int ntot4 = NX4 + NWQ4 + NWP4;
    split_all_kernel<<<(ntot4 + 255) / 256, 256>>>((const float4*)x,
        (const float4*)wqkv, (const float4*)wproj);

    cudaFuncSetAttribute(mma_gemm_kernel<QKVC, true>,
                         cudaFuncAttributeMaxDynamicSharedMemorySize, G_SMEM);
    cudaFuncSetAttribute(mma_gemm_kernel<CDIM, false>,
                         cudaFuncAttributeMaxDynamicSharedMemorySize, G_SMEM);
    cudaFuncSetAttribute(flash_mma_kernel,
                         cudaFuncAttributeMaxDynamicSharedMemorySize, FLASH_MMA_SMEM);

    dim3 g1(QKVC / 128, MROWS / 128);
    mma_gemm_kernel<QKVC, true><<<g1, 128, G_SMEM>>>(xhi, xlo, wqhi, wqlo, nullptr, nullptr);

    dim3 gg(NSEQ / 8, HN, BB);
    gather_kv_kernel<<<gg, 256>>>();

    dim3 g2(NSEQ / 128, HN, BB);
    flash_mma_kernel<<<g2, 256, FLASH_MMA_SMEM>>>();

    dim3 g3(CDIM / 128, MROWS / 128);
    mma_gemm_kernel<CDIM, false><<<g3, 128, G_SMEM>>>(ahi, alo, wphi, wplo, bproj, out);
}

// round 13
// speedup vs baseline: 4.1937x; 1.1609x over previous
#include <cuda_runtime.h>
#include <cuda_bf16.h>
#include <math.h>
#include <stdint.h>

#define BB    2
#define NSEQ  2048
#define CDIM  1024
#define HN    16
#define DH    64
#define MROWS (BB*NSEQ)     // 4096
#define QKVC  (3*CDIM)      // 3072

// ---------------- scratch (static device globals; no allocation) -------------
__device__ __align__(16) __nv_bfloat16 g_xhi[(size_t)MROWS*CDIM], g_xlo[(size_t)MROWS*CDIM];
__device__ __align__(16) __nv_bfloat16 g_xghi[(size_t)MROWS*CDIM], g_xglo[(size_t)MROWS*CDIM];
__device__ __align__(16) __nv_bfloat16 g_wqhi[(size_t)CDIM*QKVC], g_wqlo[(size_t)CDIM*QKVC];
__device__ __align__(16) __nv_bfloat16 g_wphi[(size_t)CDIM*CDIM], g_wplo[(size_t)CDIM*CDIM];
__device__ __align__(16) __nv_bfloat16 g_ahi[(size_t)MROWS*CDIM], g_alo[(size_t)MROWS*CDIM];
__device__ __align__(16) __nv_bfloat16 g_qhi[(size_t)BB*HN*NSEQ*DH], g_qlo[(size_t)BB*HN*NSEQ*DH];
__device__ __align__(16) __nv_bfloat16 g_khi[(size_t)BB*HN*NSEQ*DH], g_klo[(size_t)BB*HN*NSEQ*DH];
__device__ __align__(16) __nv_bfloat16 g_vhi[(size_t)BB*HN*NSEQ*DH], g_vlo[(size_t)BB*HN*NSEQ*DH];
__device__ unsigned char g_maskc[BB*NSEQ];
__device__ int g_kidx[BB*NSEQ];          // gathered j -> orig col (pad 0x7FFFFFFF)
__device__ int g_pcnt[BB*(NSEQ+1)];
__device__ int g_kcnt[BB];
__device__ int g_causal_d;

// ---------------- prep: mask canon + causal + per-batch key compaction -------
__global__ void prep_kernel(const void* __restrict__ mask_raw,
                            const int* __restrict__ cs_raw, int nmask) {
    __shared__ int sfmt;
    __shared__ int snz1, snz3;
    __shared__ int tsum[257];
    const unsigned char* mb = (const unsigned char*)mask_raw;
    const int tid = threadIdx.x;
    if (tid == 0) { snz1 = 0; snz3 = 0; }
    __syncthreads();
    {
        int scan = nmask < 1024 ? nmask : 1024;
        for (int i = tid; i < scan; i += 256) {
            unsigned char v = mb[i];
            if (v) { int r = i & 3; if (r == 1) snz1 = 1; else if (r == 3) snz3 = 1; }
        }
    }
    __syncthreads();
    if (tid == 0) {
        sfmt = snz1 ? 0 : (snz3 ? 2 : 1);
        int cv = cs_raw[0];
        if (cv < 0 || cv > (1 << 24)) cv = (int)__int_as_float(cv);
        g_causal_d = cv;
    }
    __syncthreads();
    int f = sfmt;
    for (int i = tid; i < nmask; i += 256) {
        unsigned char m;
        if (f == 0)      m = mb[i] != 0;
        else if (f == 1) m = ((const int*)mask_raw)[i] != 0;
        else             m = ((const float*)mask_raw)[i] != 0.0f;
        g_maskc[i] = m;
    }
    __syncthreads();
    for (int b = 0; b < BB; b++) {
        int flags[8], s = 0;
        const int base = b * NSEQ + tid * 8;
#pragma unroll
        for (int j = 0; j < 8; j++) { flags[j] = g_maskc[base + j] ? 0 : 1; s += flags[j]; }
        tsum[tid] = s;
        __syncthreads();
        if (tid == 0) {
            int acc = 0;
            for (int i = 0; i < 256; i++) { int t = tsum[i]; tsum[i] = acc; acc += t; }
            tsum[256] = acc;
            g_kcnt[b] = acc;
        }
        __syncthreads();
        int run = tsum[tid];
#pragma unroll
        for (int j = 0; j < 8; j++) {
            const int n = tid * 8 + j;
            g_pcnt[b * (NSEQ + 1) + n] = run;
            if (flags[j]) { g_kidx[b * NSEQ + run] = n; run++; }
        }
        if (tid == 255) g_pcnt[b * (NSEQ + 1) + NSEQ] = run;
        __syncthreads();
        const int cnt = tsum[256];
        for (int i = cnt + tid; i < NSEQ; i += 256) g_kidx[b * NSEQ + i] = 0x7FFFFFFF;
        __syncthreads();
    }
}

// ---------------- fused vectorized splits (x, wqkv, wproj) -------------------
#define NX4  (MROWS * CDIM / 4)
#define NWQ4 (CDIM * QKVC / 4)
#define NWP4 (CDIM * CDIM / 4)
__global__ void split_all_kernel(const float4* __restrict__ x,
                                 const float4* __restrict__ wq,
                                 const float4* __restrict__ wp) {
    int i = blockIdx.x * blockDim.x + threadIdx.x;
    const float4* src;
    __nv_bfloat162 *hi, *lo;
    if (i < NX4) {
        src = x + i; hi = (__nv_bfloat162*)g_xhi + 2 * i; lo = (__nv_bfloat162*)g_xlo + 2 * i;
    } else if (i < NX4 + NWQ4) {
        int j = i - NX4;
        src = wq + j; hi = (__nv_bfloat162*)g_wqhi + 2 * j; lo = (__nv_bfloat162*)g_wqlo + 2 * j;
    } else if (i < NX4 + NWQ4 + NWP4) {
        int j = i - NX4 - NWQ4;
        src = wp + j; hi = (__nv_bfloat162*)g_wphi + 2 * j; lo = (__nv_bfloat162*)g_wplo + 2 * j;
    } else return;
    float4 v = *src;
    __nv_bfloat162 h0 = __floats2bfloat162_rn(v.x, v.y);
    __nv_bfloat162 h1 = __floats2bfloat162_rn(v.z, v.w);
    hi[0] = h0; hi[1] = h1;
    lo[0] = __floats2bfloat162_rn(v.x - __bfloat162float(h0.x), v.y - __bfloat162float(h0.y));
    lo[1] = __floats2bfloat162_rn(v.z - __bfloat162float(h1.x), v.w - __bfloat162float(h1.y));
}

// ---------------- gather x rows by mask compaction (zero pad) ----------------
// grid (NSEQ, BB), 128 threads: row = 1024 bf16 = 128 uint4 per plane.
__global__ void gather_x_kernel() {
    const int j = blockIdx.x, b = blockIdx.y, t = threadIdx.x;
    const int cnt = g_kcnt[b];
    const size_t dst = ((size_t)b * NSEQ + j) * CDIM;
    uint4* dh = (uint4*)(g_xghi + dst);
    uint4* dl = (uint4*)(g_xglo + dst);
    if (j < cnt) {
        const int n = g_kidx[b * NSEQ + j];
        const size_t src = ((size_t)b * NSEQ + n) * CDIM;
        dh[t] = ((const uint4*)(g_xhi + src))[t];
        dl[t] = ((const uint4*)(g_xlo + src))[t];
    } else {
        uint4 z = make_uint4(0, 0, 0, 0);
        dh[t] = z; dl[t] = z;
    }
}

// ---------------- PTX helpers -------------------------------------------------
__device__ __forceinline__ uint32_t s2u(const void* p) {
    return (uint32_t)__cvta_generic_to_shared(p);
}
__device__ __forceinline__ void ldsm_x4(unsigned* r, uint32_t addr) {
    asm volatile("ldmatrix.sync.aligned.m8n8.x4.shared.b16 {%0,%1,%2,%3}, [%4];"
                 : "=r"(r[0]), "=r"(r[1]), "=r"(r[2]), "=r"(r[3]) : "r"(addr));
}
__device__ __forceinline__ void ldsm_x4t(unsigned* r, uint32_t addr) {
    asm volatile("ldmatrix.sync.aligned.m8n8.x4.trans.shared.b16 {%0,%1,%2,%3}, [%4];"
                 : "=r"(r[0]), "=r"(r[1]), "=r"(r[2]), "=r"(r[3]) : "r"(addr));
}
__device__ __forceinline__ void mma_bf16(float* d, const unsigned* a, const unsigned* b) {
    asm volatile("mma.sync.aligned.m16n8k16.row.col.f32.bf16.bf16.f32 "
                 "{%0,%1,%2,%3}, {%4,%5,%6,%7}, {%8,%9}, {%0,%1,%2,%3};"
                 : "+f"(d[0]), "+f"(d[1]), "+f"(d[2]), "+f"(d[3])
                 : "r"(a[0]), "r"(a[1]), "r"(a[2]), "r"(a[3]), "r"(b[0]), "r"(b[1]));
}
__device__ __forceinline__ unsigned bf2u(__nv_bfloat162 x) { return *(unsigned*)&x; }
__device__ __forceinline__ void cp16(uint32_t smem, const void* g) {
    asm volatile("cp.async.cg.shared.global [%0], [%1], 16;"
                 :: "r"(smem), "l"(__cvta_generic_to_global(g)) : "memory");
}
__device__ __forceinline__ void cp_commit() {
    asm volatile("cp.async.commit_group;" ::: "memory");
}
template<int N> __device__ __forceinline__ void cp_wait() {
    asm volatile("cp.async.wait_group %0;" :: "n"(N) : "memory");
}

// == bf16x3 GEMM: 128x128 CTA, 4 warps x 64x64 tiles, BK=32, 3-stage ring =====
// MODE: 0 = Q-GEMM (x rows, write Q scaled), 1 = KV-GEMM (gathered x rows,
// early-exit, write K/V at gathered rows), 2 = proj (write out + bias).
#define G_STG   18944
#define G_ALO   5120
#define G_BHI   10240
#define G_BLO   14592
#define G_SMEM  (3 * G_STG * 2)       // 113664 B; x2 CTAs = 227.3KB
#define G_NT    (CDIM / 32)           // 32

template<int MODE, int NTOT, int NOFF>
__global__ void __launch_bounds__(128)
mma_gemm_kernel(const __nv_bfloat16* __restrict__ Ahi,
                const __nv_bfloat16* __restrict__ Alo,
                const __nv_bfloat16* __restrict__ Bhi,
                const __nv_bfloat16* __restrict__ Blo,
                const float* __restrict__ bias, float* __restrict__ out) {
    extern __shared__ __align__(16) char smraw[];
    const uint32_t smu = s2u(smraw);

    const int tid = threadIdx.x, lane = tid & 31, wid = tid >> 5;
    const int wm = wid >> 1, wn = wid & 1;
    const int m0 = blockIdx.y * 128, n0 = NOFF + blockIdx.x * 128;

    if (MODE == 1) {   // early exit: tile fully beyond padded key count
        const int b = m0 >> 11, j0 = m0 & (NSEQ - 1);
        if (j0 >= ((g_kcnt[b] + 63) & ~63)) return;
    }

    auto stage = [&](int kt, int s) {
        const int k0 = kt * 32;
        const uint32_t sb = smu + s * G_STG * 2;
        const int arow = tid >> 2, acol = (tid & 3) * 8;
        const int brow = tid >> 4, bcol = (tid & 15) * 8;
#pragma unroll
        for (int it = 0; it < 4; it++) {
            const int r = arow + it * 32;
            cp16(sb + (r * 40 + acol) * 2, Ahi + (size_t)(m0 + r) * CDIM + k0 + acol);
            cp16(sb + (G_ALO + r * 40 + acol) * 2, Alo + (size_t)(m0 + r) * CDIM + k0 + acol);
            const int rb = brow + it * 8;
            cp16(sb + (G_BHI + rb * 136 + bcol) * 2, Bhi + (size_t)(k0 + rb) * NTOT + n0 + bcol);
            cp16(sb + (G_BLO + rb * 136 + bcol) * 2, Blo + (size_t)(k0 + rb) * NTOT + n0 + bcol);
        }
    };

    float acc[4][8][4];
#pragma unroll
    for (int i = 0; i < 4; i++)
#pragma unroll
        for (int j = 0; j < 8; j++)
#pragma unroll
            for (int q = 0; q < 4; q++) acc[i][j][q] = 0.f;

    const int a_ld = (wm * 64 + (lane & 15)) * 40 + (lane >> 4) * 8;
    const int b_ld = (lane & 15) * 136 + wn * 64 + (lane >> 4) * 8;

    stage(0, 0); cp_commit();
    stage(1, 1); cp_commit();

    for (int kt = 0; kt < G_NT; kt++) {
        if (kt == G_NT - 1) cp_wait<0>(); else cp_wait<1>();
        __syncthreads();
        if (kt + 2 < G_NT) { stage(kt + 2, (kt + 2) % 3); cp_commit(); }

        const uint32_t sb = smu + (kt % 3) * G_STG * 2;
#pragma unroll
        for (int ks = 0; ks < 2; ks++) {
            unsigned ah[4][4], al[4][4], bh[8][2], bl[8][2];
            const uint32_t aBh = sb + (a_ld + ks * 16) * 2;
            const uint32_t aBl = aBh + G_ALO * 2;
            const uint32_t bBh = sb + (G_BHI + b_ld + ks * 16 * 136) * 2;
            const uint32_t bBl = bBh + (G_BLO - G_BHI) * 2;
#pragma unroll
            for (int mt = 0; mt < 4; mt++) {
                ldsm_x4(ah[mt], aBh + mt * 16 * 40 * 2);
                ldsm_x4(al[mt], aBl + mt * 16 * 40 * 2);
            }
#pragma unroll
            for (int ntp = 0; ntp < 4; ntp++) {
                unsigned t4[4];
                ldsm_x4t(t4, bBh + ntp * 16 * 2);
                bh[2 * ntp][0] = t4[0]; bh[2 * ntp][1] = t4[1];
                bh[2 * ntp + 1][0] = t4[2]; bh[2 * ntp + 1][1] = t4[3];
                ldsm_x4t(t4, bBl + ntp * 16 * 2);
                bl[2 * ntp][0] = t4[0]; bl[2 * ntp][1] = t4[1];
                bl[2 * ntp + 1][0] = t4[2]; bl[2 * ntp + 1][1] = t4[3];
            }
#pragma unroll
            for (int mt = 0; mt < 4; mt++)
#pragma unroll
                for (int nt = 0; nt < 8; nt++) {
                    mma_bf16(acc[mt][nt], ah[mt], bh[nt]);
                    mma_bf16(acc[mt][nt], ah[mt], bl[nt]);
                    mma_bf16(acc[mt][nt], al[mt], bh[nt]);
                }
        }
    }

    // epilogue
    const int rb = m0 + wm * 64 + (lane >> 2);
    const int cb = n0 + wn * 64 + (lane & 3) * 2;
#pragma unroll
    for (int mt = 0; mt < 4; mt++)
#pragma unroll
        for (int nt = 0; nt < 8; nt++) {
            const int c = cb + nt * 8;
            if (MODE == 0) {
                // Q section: c in [0,1024): h=(c>>6), d=c&63; scale 0.125
                const int h = c >> 6, d = c & 63;
#pragma unroll
                for (int half = 0; half < 2; half++) {
                    const int r = rb + mt * 16 + half * 8;
                    const int bidx = r >> 11, n = r & (NSEQ - 1);
                    size_t off = (((size_t)bidx * HN + h) * NSEQ + n) * DH + d;
                    float v0 = acc[mt][nt][2 * half] * 0.125f;
                    float v1 = acc[mt][nt][2 * half + 1] * 0.125f;
                    __nv_bfloat162 hh = __floats2bfloat162_rn(v0, v1);
                    *(__nv_bfloat162*)&g_qhi[off] = hh;
                    *(__nv_bfloat162*)&g_qlo[off] = __floats2bfloat162_rn(
                        v0 - __bfloat162float(hh.x), v1 - __bfloat162float(hh.y));
                }
            } else if (MODE == 1) {
                // K/V section: c in [1024,3072); rows are GATHERED positions j
                const int sec = c >> 10, h = (c & 1023) >> 6, d = c & 63;
                __nv_bfloat16* dhi = (sec == 1) ? g_khi : g_vhi;
                __nv_bfloat16* dlo = (sec == 1) ? g_klo : g_vlo;
#pragma unroll
                for (int half = 0; half < 2; half++) {
                    const int r = rb + mt * 16 + half * 8;
                    const int bidx = r >> 11, j = r & (NSEQ - 1);
                    size_t off = (((size_t)bidx * HN + h) * NSEQ + j) * DH + d;
                    float v0 = acc[mt][nt][2 * half], v1 = acc[mt][nt][2 * half + 1];
                    __nv_bfloat162 hh = __floats2bfloat162_rn(v0, v1);
                    *(__nv_bfloat162*)&dhi[off] = hh;
                    *(__nv_bfloat162*)&dlo[off] = __floats2bfloat162_rn(
                        v0 - __bfloat162float(hh.x), v1 - __bfloat162float(hh.y));
                }
            } else {
                const float b0 = bias[c], b1 = bias[c + 1];
#pragma unroll
                for (int half = 0; half < 2; half++) {
                    const int r = rb + mt * 16 + half * 8;
                    float* p = out + (size_t)r * NTOT + c;
                    *(float2*)p = make_float2(acc[mt][nt][2 * half] + b0,
                                              acc[mt][nt][2 * half + 1] + b1);
                }
            }
        }
}

// =============== Flash attention: Br=128, compacted keys, Bc=64 ==============
#define QP 72
#define F_KV0   18432
#define F_KVSZ  18432
#define F_SCOLB (55296 * 2)
#define FLASH_MMA_SMEM (F_SCOLB + 512)   // 111104 B -> 2 CTAs/SM

__global__ void __launch_bounds__(256, 2) flash_mma_kernel() {
    extern __shared__ __align__(16) char smraw[];
    __nv_bfloat16* smb = (__nv_bfloat16*)smraw;
    const uint32_t smu = s2u(smraw);
    __nv_bfloat16* sQh = smb;
    __nv_bfloat16* sQl = smb + 9216;
    int* scol = (int*)(smraw + F_SCOLB);

    const int tid = threadIdx.x, lane = tid & 31, wid = tid >> 5;
    const int qt = gridDim.x - 1 - blockIdx.x;
    const int h = blockIdx.y, b = blockIdx.z;
    const int q0 = qt * 128;
    const int cstart = g_causal_d;
    const size_t hoff = ((size_t)b * HN + h) * NSEQ * DH;

    const __nv_bfloat16 *Qh = g_qhi + hoff, *Ql = g_qlo + hoff;
    const __nv_bfloat16* kvsrc[4] = {g_khi + hoff, g_klo + hoff,
                                     g_vhi + hoff, g_vlo + hoff};

    {
        const int r = tid >> 1, c0 = (tid & 1) * 32;
#pragma unroll
        for (int c = 0; c < 32; c += 8) {
            *(uint4*)&sQh[r * QP + c0 + c] = *(const uint4*)&Qh[(size_t)(q0 + r) * DH + c0 + c];
            *(uint4*)&sQl[r * QP + c0 + c] = *(const uint4*)&Ql[(size_t)(q0 + r) * DH + c0 + c];
        }
    }

    const int kv_r = tid >> 3, kv_c = (tid & 7) * 8;
    auto stageKV = [&](int t) {
        const int k0t = t * 64;
        const uint32_t base = smu + (F_KV0 + (t & 1) * F_KVSZ) * 2;
#pragma unroll
        for (int pl = 0; pl < 4; pl++)
#pragma unroll
            for (int half = 0; half < 2; half++) {
                const int r = kv_r + half * 32;
                cp16(base + (pl * 4608 + r * QP + kv_c) * 2,
                     kvsrc[pl] + (size_t)(k0t + r) * DH + kv_c);
            }
    };

    int kmaxi = q0 + 127;
    if (cstart - 1 > kmaxi) kmaxi = cstart - 1;
    if (kmaxi > NSEQ - 1) kmaxi = NSEQ - 1;
    const int kcnt = g_pcnt[b * (NSEQ + 1) + kmaxi + 1];
    const int ntiles = (kcnt + 63) >> 6;

    stageKV(0); cp_commit();
    if (tid < 64) scol[tid] = g_kidx[b * NSEQ + tid];

    unsigned qfh[4][4], qfl[4][4];
    float m0v = -1e30f, m1v = -1e30f, l0v = 0.f, l1v = 0.f;
    float oacc[8][4] = {};

    const int grow0 = q0 + wid * 16 + (lane >> 2);
    const int grow1 = grow0 + 8;

    for (int t = 0; t < ntiles; t++) {
        __syncthreads();
        if (t == 0) {
#pragma unroll
            for (int ks = 0; ks < 4; ks++) {
                const int qa = (wid * 16 + (lane & 15)) * QP + ks * 16 + (lane >> 4) * 8;
                ldsm_x4(qfh[ks], s2u(&sQh[qa]));
                ldsm_x4(qfl[ks], s2u(&sQl[qa]));
            }
        }
        if (t + 1 < ntiles) {
            stageKV(t + 1);
            if (tid < 64)
                scol[((t + 1) & 1) * 64 + tid] = g_kidx[b * NSEQ + (t + 1) * 64 + tid];
            cp_commit();
            cp_wait<1>();
        } else {
            cp_wait<0>();
        }
        __syncthreads();

        const __nv_bfloat16* kb = smb + F_KV0 + (t & 1) * F_KVSZ;
        const __nv_bfloat16* sKh = kb;
        const __nv_bfloat16* sKl = kb + 4608;
        const __nv_bfloat16* sVh = kb + 9216;
        const __nv_bfloat16* sVl = kb + 13824;
        const int* sc = scol + (t & 1) * 64;

        float sacc[8][4] = {};
#pragma unroll
        for (int ks = 0; ks < 4; ks++) {
            unsigned kbh[8][2], kbl[8][2];
#pragma unroll
            for (int np = 0; np < 4; np++) {
                const int row = np * 16 + ((lane >> 4) & 1) * 8 + (lane & 7);
                const int col = ks * 16 + ((lane >> 3) & 1) * 8;
                unsigned t4[4];
                ldsm_x4(t4, s2u(&sKh[row * QP + col]));
                kbh[2 * np][0] = t4[0]; kbh[2 * np][1] = t4[1];
                kbh[2 * np + 1][0] = t4[2]; kbh[2 * np + 1][1] = t4[3];
                ldsm_x4(t4, s2u(&sKl[row * QP + col]));
                kbl[2 * np][0] = t4[0]; kbl[2 * np][1] = t4[1];
                kbl[2 * np + 1][0] = t4[2]; kbl[2 * np + 1][1] = t4[3];
            }
#pragma unroll
            for (int nt = 0; nt < 8; nt++) {
                mma_bf16(sacc[nt], qfh[ks], kbh[nt]);
                mma_bf16(sacc[nt], qfh[ks], kbl[nt]);
                mma_bf16(sacc[nt], qfl[ks], kbh[nt]);
            }
        }

        float tmax0 = -INFINITY, tmax1 = -INFINITY;
#pragma unroll
        for (int nt = 0; nt < 8; nt++) {
#pragma unroll
            for (int j = 0; j < 2; j++) {
                const int lc = nt * 8 + (lane & 3) * 2 + j;
                const int col = sc[lc];
                float v0 = sacc[nt][j];
                float v1 = sacc[nt][2 + j];
                v0 = (col > grow0 && col >= cstart) ? -INFINITY : v0;
                v1 = (col > grow1 && col >= cstart) ? -INFINITY : v1;
                sacc[nt][j] = v0; sacc[nt][2 + j] = v1;
                tmax0 = fmaxf(tmax0, v0); tmax1 = fmaxf(tmax1, v1);
            }
        }
#pragma unroll
        for (int off = 1; off < 4; off <<= 1) {
            tmax0 = fmaxf(tmax0, __shfl_xor_sync(0xffffffffu, tmax0, off));
            tmax1 = fmaxf(tmax1, __shfl_xor_sync(0xffffffffu, tmax1, off));
        }

        const float mn0 = fmaxf(m0v, tmax0), mn1 = fmaxf(m1v, tmax1);
        const float cr0 = __expf(m0v - mn0), cr1 = __expf(m1v - mn1);
        m0v = mn0; m1v = mn1;
        l0v *= cr0; l1v *= cr1;
#pragma unroll
        for (int nt = 0; nt < 8; nt++) {
            oacc[nt][0] *= cr0; oacc[nt][1] *= cr0;
            oacc[nt][2] *= cr1; oacc[nt][3] *= cr1;
        }
        float rs0 = 0.f, rs1 = 0.f;
#pragma unroll
        for (int nt = 0; nt < 8; nt++) {
            float p0 = __expf(sacc[nt][0] - mn0), p1 = __expf(sacc[nt][1] - mn0);
            float p2 = __expf(sacc[nt][2] - mn1), p3 = __expf(sacc[nt][3] - mn1);
            sacc[nt][0] = p0; sacc[nt][1] = p1; sacc[nt][2] = p2; sacc[nt][3] = p3;
            rs0 += p0 + p1; rs1 += p2 + p3;
        }
#pragma unroll
        for (int off = 1; off < 4; off <<= 1) {
            rs0 += __shfl_xor_sync(0xffffffffu, rs0, off);
            rs1 += __shfl_xor_sync(0xffffffffu, rs1, off);
        }
        l0v += rs0; l1v += rs1;

#pragma unroll
        for (int ks = 0; ks < 4; ks++) {
            unsigned ah[4], al[4];
            {
                const float v0 = sacc[2 * ks][0], v1 = sacc[2 * ks][1];
                const float v2 = sacc[2 * ks][2], v3 = sacc[2 * ks][3];
                const float w0 = sacc[2 * ks + 1][0], w1 = sacc[2 * ks + 1][1];
                const float w2 = sacc[2 * ks + 1][2], w3 = sacc[2 * ks + 1][3];
                __nv_bfloat162 h0 = __floats2bfloat162_rn(v0, v1);
                __nv_bfloat162 h1 = __floats2bfloat162_rn(v2, v3);
                __nv_bfloat162 h2 = __floats2bfloat162_rn(w0, w1);
                __nv_bfloat162 h3 = __floats2bfloat162_rn(w2, w3);
                ah[0] = bf2u(h0); ah[1] = bf2u(h1); ah[2] = bf2u(h2); ah[3] = bf2u(h3);
                al[0] = bf2u(__floats2bfloat162_rn(v0 - __bfloat162float(h0.x),
                                                   v1 - __bfloat162float(h0.y)));
                al[1] = bf2u(__floats2bfloat162_rn(v2 - __bfloat162float(h1.x),
                                                   v3 - __bfloat162float(h1.y)));
                al[2] = bf2u(__floats2bfloat162_rn(w0 - __bfloat162float(h2.x),
                                                   w1 - __bfloat162float(h2.y)));
                al[3] = bf2u(__floats2bfloat162_rn(w2 - __bfloat162float(h3.x),
                                                   w3 - __bfloat162float(h3.y)));
            }
#pragma unroll
            for (int np = 0; np < 4; np++) {
                const int va = (ks * 16 + (lane & 15)) * QP + np * 16 + (lane >> 4) * 8;
                unsigned t4[4], t4l[4];
                ldsm_x4t(t4, s2u(&sVh[va]));
                ldsm_x4t(t4l, s2u(&sVl[va]));
                unsigned vb0[2] = {t4[0], t4[1]}, vb1[2] = {t4[2], t4[3]};
                unsigned vl0[2] = {t4l[0], t4l[1]}, vl1[2] = {t4l[2], t4l[3]};
                mma_bf16(oacc[2 * np], ah, vb0);
                mma_bf16(oacc[2 * np], ah, vl0);
                mma_bf16(oacc[2 * np], al, vb0);
                mma_bf16(oacc[2 * np + 1], ah, vb1);
                mma_bf16(oacc[2 * np + 1], ah, vl1);
                mma_bf16(oacc[2 * np + 1], al, vb1);
            }
        }
    }

    const float inv0 = 1.f / l0v, inv1 = 1.f / l1v;
#pragma unroll
    for (int nt = 0; nt < 8; nt++) {
        const int d = nt * 8 + (lane & 3) * 2;
        const size_t o0 = ((size_t)b * NSEQ + grow0) * CDIM + h * DH + d;
        const size_t o1 = ((size_t)b * NSEQ + grow1) * CDIM + h * DH + d;
        const float v0 = oacc[nt][0] * inv0, v1 = oacc[nt][1] * inv0;
        const float w0 = oacc[nt][2] * inv1, w1 = oacc[nt][3] * inv1;
        __nv_bfloat162 h0 = __floats2bfloat162_rn(v0, v1);
        *(__nv_bfloat162*)&g_ahi[o0] = h0;
        *(__nv_bfloat162*)&g_alo[o0] = __floats2bfloat162_rn(
            v0 - __bfloat162float(h0.x), v1 - __bfloat162float(h0.y));
        __nv_bfloat162 h1 = __floats2bfloat162_rn(w0, w1);
        *(__nv_bfloat162*)&g_ahi[o1] = h1;
        *(__nv_bfloat162*)&g_alo[o1] = __floats2bfloat162_rn(
            w0 - __bfloat162float(h1.x), w1 - __bfloat162float(h1.y));
    }
}

// ---------------- launch ------------------------------------------------------
extern "C" void kernel_launch(void* const* d_in, const int* in_sizes, int n_in,
                              void* d_out, int out_size) {
    (void)n_in; (void)out_size;
    const float* x     = (const float*)d_in[0];
    const void*  mask  = d_in[1];
    const int*   cs    = (const int*)d_in[2];
    const float* wqkv  = (const float*)d_in[3];
    const float* wproj = (const float*)d_in[4];
    const float* bproj = (const float*)d_in[5];
    float* out = (float*)d_out;

    prep_kernel<<<1, 256>>>(mask, cs, in_sizes[1]);

    __nv_bfloat16 *xhi, *xlo, *xghi, *xglo, *wqhi, *wqlo, *wphi, *wplo, *ahi, *alo;
    cudaGetSymbolAddress((void**)&xhi, g_xhi);   cudaGetSymbolAddress((void**)&xlo, g_xlo);
    cudaGetSymbolAddress((void**)&xghi, g_xghi); cudaGetSymbolAddress((void**)&xglo, g_xglo);
    cudaGetSymbolAddress((void**)&wqhi, g_wqhi); cudaGetSymbolAddress((void**)&wqlo, g_wqlo);
    cudaGetSymbolAddress((void**)&wphi, g_wphi); cudaGetSymbolAddress((void**)&wplo, g_wplo);
    cudaGetSymbolAddress((void**)&ahi, g_ahi);   cudaGetSymbolAddress((void**)&alo, g_alo);

    const int ntot4 = NX4 + NWQ4 + NWP4;
    split_all_kernel<<<(ntot4 + 255) / 256, 256>>>((const float4*)x,
        (const float4*)wqkv, (const float4*)wproj);

    gather_x_kernel<<<dim3(NSEQ, BB), 128>>>();

    cudaFuncSetAttribute(mma_gemm_kernel<0, QKVC, 0>,
                         cudaFuncAttributeMaxDynamicSharedMemorySize, G_SMEM);
    cudaFuncSetAttribute(mma_gemm_kernel<1, QKVC, 1024>,
                         cudaFuncAttributeMaxDynamicSharedMemorySize, G_SMEM);
    cudaFuncSetAttribute(mma_gemm_kernel<2, CDIM, 0>,
                         cudaFuncAttributeMaxDynamicSharedMemorySize, G_SMEM);
    cudaFuncSetAttribute(flash_mma_kernel,
                         cudaFuncAttributeMaxDynamicSharedMemorySize, FLASH_MMA_SMEM);

    // Q-GEMM: all token rows x Wq (cols 0..1023)
    dim3 gq(CDIM / 128, MROWS / 128);
    mma_gemm_kernel<0, QKVC, 0><<<gq, 128, G_SMEM>>>(xhi, xlo, wqhi, wqlo, nullptr, nullptr);

    // KV-GEMM: gathered rows x Wkv (cols 1024..3071), early-exit beyond kcnt
    dim3 gkv((QKVC - CDIM) / 128, MROWS / 128);
    mma_gemm_kernel<1, QKVC, 1024><<<gkv, 128, G_SMEM>>>(xghi, xglo, wqhi, wqlo, nullptr, nullptr);

    dim3 g2(NSEQ / 128, HN, BB);
    flash_mma_kernel<<<g2, 256, FLASH_MMA_SMEM>>>();

    dim3 g3(CDIM / 128, MROWS / 128);
    mma_gemm_kernel<2, CDIM, 0><<<g3, 128, G_SMEM>>>(ahi, alo, wphi, wplo, bproj, out);
}

// round 14
// speedup vs baseline: 4.3329x; 1.0332x over previous
#include <cuda_runtime.h>
#include <cuda_bf16.h>
#include <math.h>
#include <stdint.h>

#define BB    2
#define NSEQ  2048
#define CDIM  1024
#define HN    16
#define DH    64
#define MROWS (BB*NSEQ)     // 4096
#define QKVC  (3*CDIM)      // 3072

// ---------------- scratch (static device globals; no allocation) -------------
__device__ __align__(16) __nv_bfloat16 g_xhi[(size_t)MROWS*CDIM], g_xlo[(size_t)MROWS*CDIM];
__device__ __align__(16) __nv_bfloat16 g_xghi[(size_t)MROWS*CDIM], g_xglo[(size_t)MROWS*CDIM];
__device__ __align__(16) __nv_bfloat16 g_wqhi[(size_t)CDIM*QKVC], g_wqlo[(size_t)CDIM*QKVC];
__device__ __align__(16) __nv_bfloat16 g_wphi[(size_t)CDIM*CDIM], g_wplo[(size_t)CDIM*CDIM];
__device__ __align__(16) __nv_bfloat16 g_ahi[(size_t)MROWS*CDIM], g_alo[(size_t)MROWS*CDIM];
__device__ __align__(16) __nv_bfloat16 g_qhi[(size_t)BB*HN*NSEQ*DH], g_qlo[(size_t)BB*HN*NSEQ*DH];
__device__ __align__(16) __nv_bfloat16 g_khi[(size_t)BB*HN*NSEQ*DH], g_klo[(size_t)BB*HN*NSEQ*DH];
__device__ __align__(16) __nv_bfloat16 g_vhi[(size_t)BB*HN*NSEQ*DH], g_vlo[(size_t)BB*HN*NSEQ*DH];
__device__ unsigned char g_maskc[BB*NSEQ];
__device__ int g_kidx[BB*NSEQ];          // gathered j -> orig col (pad 0x7FFFFFFF), ASCENDING
__device__ int g_pcnt[BB*(NSEQ+1)];
__device__ int g_kcnt[BB];
__device__ int g_causal_d;

// ---------------- prep: mask canon + causal + per-batch key compaction -------
__global__ void prep_kernel(const void* __restrict__ mask_raw,
                            const int* __restrict__ cs_raw, int nmask) {
    __shared__ int sfmt;
    __shared__ int snz1, snz3;
    __shared__ int tsum[257];
    const unsigned char* mb = (const unsigned char*)mask_raw;
    const int tid = threadIdx.x;
    if (tid == 0) { snz1 = 0; snz3 = 0; }
    __syncthreads();
    {
        int scan = nmask < 1024 ? nmask : 1024;
        for (int i = tid; i < scan; i += 256) {
            unsigned char v = mb[i];
            if (v) { int r = i & 3; if (r == 1) snz1 = 1; else if (r == 3) snz3 = 1; }
        }
    }
    __syncthreads();
    if (tid == 0) {
        sfmt = snz1 ? 0 : (snz3 ? 2 : 1);
        int cv = cs_raw[0];
        if (cv < 0 || cv > (1 << 24)) cv = (int)__int_as_float(cv);
        g_causal_d = cv;
    }
    __syncthreads();
    int f = sfmt;
    for (int i = tid; i < nmask; i += 256) {
        unsigned char m;
        if (f == 0)      m = mb[i] != 0;
        else if (f == 1) m = ((const int*)mask_raw)[i] != 0;
        else             m = ((const float*)mask_raw)[i] != 0.0f;
        g_maskc[i] = m;
    }
    __syncthreads();
    for (int b = 0; b < BB; b++) {
        int flags[8], s = 0;
        const int base = b * NSEQ + tid * 8;
#pragma unroll
        for (int j = 0; j < 8; j++) { flags[j] = g_maskc[base + j] ? 0 : 1; s += flags[j]; }
        tsum[tid] = s;
        __syncthreads();
        if (tid == 0) {
            int acc = 0;
            for (int i = 0; i < 256; i++) { int t = tsum[i]; tsum[i] = acc; acc += t; }
            tsum[256] = acc;
            g_kcnt[b] = acc;
        }
        __syncthreads();
        int run = tsum[tid];
#pragma unroll
        for (int j = 0; j < 8; j++) {
            const int n = tid * 8 + j;
            g_pcnt[b * (NSEQ + 1) + n] = run;
            if (flags[j]) { g_kidx[b * NSEQ + run] = n; run++; }
        }
        if (tid == 255) g_pcnt[b * (NSEQ + 1) + NSEQ] = run;
        __syncthreads();
        const int cnt = tsum[256];
        for (int i = cnt + tid; i < NSEQ; i += 256) g_kidx[b * NSEQ + i] = 0x7FFFFFFF;
        __syncthreads();
    }
}

// ---------------- fused vectorized splits (x, wqkv, wproj) -------------------
#define NX4  (MROWS * CDIM / 4)
#define NWQ4 (CDIM * QKVC / 4)
#define NWP4 (CDIM * CDIM / 4)
__global__ void split_all_kernel(const float4* __restrict__ x,
                                 const float4* __restrict__ wq,
                                 const float4* __restrict__ wp) {
    int i = blockIdx.x * blockDim.x + threadIdx.x;
    const float4* src;
    __nv_bfloat162 *hi, *lo;
    if (i < NX4) {
        src = x + i; hi = (__nv_bfloat162*)g_xhi + 2 * i; lo = (__nv_bfloat162*)g_xlo + 2 * i;
    } else if (i < NX4 + NWQ4) {
        int j = i - NX4;
        src = wq + j; hi = (__nv_bfloat162*)g_wqhi + 2 * j; lo = (__nv_bfloat162*)g_wqlo + 2 * j;
    } else if (i < NX4 + NWQ4 + NWP4) {
        int j = i - NX4 - NWQ4;
        src = wp + j; hi = (__nv_bfloat162*)g_wphi + 2 * j; lo = (__nv_bfloat162*)g_wplo + 2 * j;
    } else return;
    float4 v = *src;
    __nv_bfloat162 h0 = __floats2bfloat162_rn(v.x, v.y);
    __nv_bfloat162 h1 = __floats2bfloat162_rn(v.z, v.w);
    hi[0] = h0; hi[1] = h1;
    lo[0] = __floats2bfloat162_rn(v.x - __bfloat162float(h0.x), v.y - __bfloat162float(h0.y));
    lo[1] = __floats2bfloat162_rn(v.z - __bfloat162float(h1.x), v.w - __bfloat162float(h1.y));
}

// ---------------- gather x rows by mask compaction (zero pad) ----------------
__global__ void gather_x_kernel() {
    const int j = blockIdx.x, b = blockIdx.y, t = threadIdx.x;
    const int cnt = g_kcnt[b];
    const size_t dst = ((size_t)b * NSEQ + j) * CDIM;
    uint4* dh = (uint4*)(g_xghi + dst);
    uint4* dl = (uint4*)(g_xglo + dst);
    if (j < cnt) {
        const int n = g_kidx[b * NSEQ + j];
        const size_t src = ((size_t)b * NSEQ + n) * CDIM;
        dh[t] = ((const uint4*)(g_xhi + src))[t];
        dl[t] = ((const uint4*)(g_xlo + src))[t];
    } else {
        uint4 z = make_uint4(0, 0, 0, 0);
        dh[t] = z; dl[t] = z;
    }
}

// ---------------- PTX helpers -------------------------------------------------
__device__ __forceinline__ uint32_t s2u(const void* p) {
    return (uint32_t)__cvta_generic_to_shared(p);
}
__device__ __forceinline__ void ldsm_x4(unsigned* r, uint32_t addr) {
    asm volatile("ldmatrix.sync.aligned.m8n8.x4.shared.b16 {%0,%1,%2,%3}, [%4];"
                 : "=r"(r[0]), "=r"(r[1]), "=r"(r[2]), "=r"(r[3]) : "r"(addr));
}
__device__ __forceinline__ void ldsm_x4t(unsigned* r, uint32_t addr) {
    asm volatile("ldmatrix.sync.aligned.m8n8.x4.trans.shared.b16 {%0,%1,%2,%3}, [%4];"
                 : "=r"(r[0]), "=r"(r[1]), "=r"(r[2]), "=r"(r[3]) : "r"(addr));
}
__device__ __forceinline__ void mma_bf16(float* d, const unsigned* a, const unsigned* b) {
    asm volatile("mma.sync.aligned.m16n8k16.row.col.f32.bf16.bf16.f32 "
                 "{%0,%1,%2,%3}, {%4,%5,%6,%7}, {%8,%9}, {%0,%1,%2,%3};"
                 : "+f"(d[0]), "+f"(d[1]), "+f"(d[2]), "+f"(d[3])
                 : "r"(a[0]), "r"(a[1]), "r"(a[2]), "r"(a[3]), "r"(b[0]), "r"(b[1]));
}
__device__ __forceinline__ unsigned bf2u(__nv_bfloat162 x) { return *(unsigned*)&x; }
__device__ __forceinline__ void cp16(uint32_t smem, const void* g) {
    asm volatile("cp.async.cg.shared.global [%0], [%1], 16;"
                 :: "r"(smem), "l"(__cvta_generic_to_global(g)) : "memory");
}
__device__ __forceinline__ void cp_commit() {
    asm volatile("cp.async.commit_group;" ::: "memory");
}
template<int N> __device__ __forceinline__ void cp_wait() {
    asm volatile("cp.async.wait_group %0;" :: "n"(N) : "memory");
}

// == bf16x3 GEMM core: 128x128 CTA, 4 warps x 64x64 tiles, BK=32, 3-stage ring
#define G_STG   18944
#define G_ALO   5120
#define G_BHI   10240
#define G_BLO   14592
#define G_SMEM  (3 * G_STG * 2)       // 113664 B
#define G_NT    (CDIM / 32)           // 32

// --------- merged QKV GEMM: grid (24, 32); ntile<8 -> Q, else KV -------------
__global__ void __launch_bounds__(128)
qkv_gemm_kernel() {
    extern __shared__ __align__(16) char smraw[];
    const uint32_t smu = s2u(smraw);

    const int tid = threadIdx.x, lane = tid & 31, wid = tid >> 5;
    const int wm = wid >> 1, wn = wid & 1;
    const bool isQ = blockIdx.x < 8;
    const int n0 = isQ ? blockIdx.x * 128 : CDIM + (blockIdx.x - 8) * 128;
    const int m0 = blockIdx.y * 128;

    if (!isQ) {   // early exit: tile fully beyond padded key count
        const int b = m0 >> 11, j0 = m0 & (NSEQ - 1);
        if (j0 >= ((g_kcnt[b] + 63) & ~63)) return;
    }
    const __nv_bfloat16* Ahi = isQ ? g_xhi : g_xghi;
    const __nv_bfloat16* Alo = isQ ? g_xlo : g_xglo;

    auto stage = [&](int kt, int s) {
        const int k0 = kt * 32;
        const uint32_t sb = smu + s * G_STG * 2;
        const int arow = tid >> 2, acol = (tid & 3) * 8;
        const int brow = tid >> 4, bcol = (tid & 15) * 8;
#pragma unroll
        for (int it = 0; it < 4; it++) {
            const int r = arow + it * 32;
            cp16(sb + (r * 40 + acol) * 2, Ahi + (size_t)(m0 + r) * CDIM + k0 + acol);
            cp16(sb + (G_ALO + r * 40 + acol) * 2, Alo + (size_t)(m0 + r) * CDIM + k0 + acol);
            const int rb = brow + it * 8;
            cp16(sb + (G_BHI + rb * 136 + bcol) * 2, g_wqhi + (size_t)(k0 + rb) * QKVC + n0 + bcol);
            cp16(sb + (G_BLO + rb * 136 + bcol) * 2, g_wqlo + (size_t)(k0 + rb) * QKVC + n0 + bcol);
        }
    };

    float acc[4][8][4];
#pragma unroll
    for (int i = 0; i < 4; i++)
#pragma unroll
        for (int j = 0; j < 8; j++)
#pragma unroll
            for (int q = 0; q < 4; q++) acc[i][j][q] = 0.f;

    const int a_ld = (wm * 64 + (lane & 15)) * 40 + (lane >> 4) * 8;
    const int b_ld = (lane & 15) * 136 + wn * 64 + (lane >> 4) * 8;

    stage(0, 0); cp_commit();
    stage(1, 1); cp_commit();

    for (int kt = 0; kt < G_NT; kt++) {
        if (kt == G_NT - 1) cp_wait<0>(); else cp_wait<1>();
        __syncthreads();
        if (kt + 2 < G_NT) { stage(kt + 2, (kt + 2) % 3); cp_commit(); }

        const uint32_t sb = smu + (kt % 3) * G_STG * 2;
#pragma unroll
        for (int ks = 0; ks < 2; ks++) {
            unsigned ah[4][4], al[4][4], bh[8][2], bl[8][2];
            const uint32_t aBh = sb + (a_ld + ks * 16) * 2;
            const uint32_t aBl = aBh + G_ALO * 2;
            const uint32_t bBh = sb + (G_BHI + b_ld + ks * 16 * 136) * 2;
            const uint32_t bBl = bBh + (G_BLO - G_BHI) * 2;
#pragma unroll
            for (int mt = 0; mt < 4; mt++) {
                ldsm_x4(ah[mt], aBh + mt * 16 * 40 * 2);
                ldsm_x4(al[mt], aBl + mt * 16 * 40 * 2);
            }
#pragma unroll
            for (int ntp = 0; ntp < 4; ntp++) {
                unsigned t4[4];
                ldsm_x4t(t4, bBh + ntp * 16 * 2);
                bh[2 * ntp][0] = t4[0]; bh[2 * ntp][1] = t4[1];
                bh[2 * ntp + 1][0] = t4[2]; bh[2 * ntp + 1][1] = t4[3];
                ldsm_x4t(t4, bBl + ntp * 16 * 2);
                bl[2 * ntp][0] = t4[0]; bl[2 * ntp][1] = t4[1];
                bl[2 * ntp + 1][0] = t4[2]; bl[2 * ntp + 1][1] = t4[3];
            }
#pragma unroll
            for (int mt = 0; mt < 4; mt++)
#pragma unroll
                for (int nt = 0; nt < 8; nt++) {
                    mma_bf16(acc[mt][nt], ah[mt], bh[nt]);
                    mma_bf16(acc[mt][nt], ah[mt], bl[nt]);
                    mma_bf16(acc[mt][nt], al[mt], bh[nt]);
                }
        }
    }

    const int rb = m0 + wm * 64 + (lane >> 2);
    const int cb = n0 + wn * 64 + (lane & 3) * 2;
#pragma unroll
    for (int mt = 0; mt < 4; mt++)
#pragma unroll
        for (int nt = 0; nt < 8; nt++) {
            const int c = cb + nt * 8;
            if (isQ) {
                const int h = c >> 6, d = c & 63;
#pragma unroll
                for (int half = 0; half < 2; half++) {
                    const int r = rb + mt * 16 + half * 8;
                    const int bidx = r >> 11, n = r & (NSEQ - 1);
                    size_t off = (((size_t)bidx * HN + h) * NSEQ + n) * DH + d;
                    float v0 = acc[mt][nt][2 * half] * 0.125f;
                    float v1 = acc[mt][nt][2 * half + 1] * 0.125f;
                    __nv_bfloat162 hh = __floats2bfloat162_rn(v0, v1);
                    *(__nv_bfloat162*)&g_qhi[off] = hh;
                    *(__nv_bfloat162*)&g_qlo[off] = __floats2bfloat162_rn(
                        v0 - __bfloat162float(hh.x), v1 - __bfloat162float(hh.y));
                }
            } else {
                const int sec = c >> 10, h = (c & 1023) >> 6, d = c & 63;
                __nv_bfloat16* dhi = (sec == 1) ? g_khi : g_vhi;
                __nv_bfloat16* dlo = (sec == 1) ? g_klo : g_vlo;
#pragma unroll
                for (int half = 0; half < 2; half++) {
                    const int r = rb + mt * 16 + half * 8;
                    const int bidx = r >> 11, j = r & (NSEQ - 1);
                    size_t off = (((size_t)bidx * HN + h) * NSEQ + j) * DH + d;
                    float v0 = acc[mt][nt][2 * half], v1 = acc[mt][nt][2 * half + 1];
                    __nv_bfloat162 hh = __floats2bfloat162_rn(v0, v1);
                    *(__nv_bfloat162*)&dhi[off] = hh;
                    *(__nv_bfloat162*)&dlo[off] = __floats2bfloat162_rn(
                        v0 - __bfloat162float(hh.x), v1 - __bfloat162float(hh.y));
                }
            }
        }
}

// --------- proj GEMM: att(4096x1024) @ Wp + bias -> out ----------------------
__global__ void __launch_bounds__(128)
proj_gemm_kernel(const float* __restrict__ bias, float* __restrict__ out) {
    extern __shared__ __align__(16) char smraw[];
    const uint32_t smu = s2u(smraw);

    const int tid = threadIdx.x, lane = tid & 31, wid = tid >> 5;
    const int wm = wid >> 1, wn = wid & 1;
    const int m0 = blockIdx.y * 128, n0 = blockIdx.x * 128;

    auto stage = [&](int kt, int s) {
        const int k0 = kt * 32;
        const uint32_t sb = smu + s * G_STG * 2;
        const int arow = tid >> 2, acol = (tid & 3) * 8;
        const int brow = tid >> 4, bcol = (tid & 15) * 8;
#pragma unroll
        for (int it = 0; it < 4; it++) {
            const int r = arow + it * 32;
            cp16(sb + (r * 40 + acol) * 2, g_ahi + (size_t)(m0 + r) * CDIM + k0 + acol);
            cp16(sb + (G_ALO + r * 40 + acol) * 2, g_alo + (size_t)(m0 + r) * CDIM + k0 + acol);
            const int rb = brow + it * 8;
            cp16(sb + (G_BHI + rb * 136 + bcol) * 2, g_wphi + (size_t)(k0 + rb) * CDIM + n0 + bcol);
            cp16(sb + (G_BLO + rb * 136 + bcol) * 2, g_wplo + (size_t)(k0 + rb) * CDIM + n0 + bcol);
        }
    };

    float acc[4][8][4];
#pragma unroll
    for (int i = 0; i < 4; i++)
#pragma unroll
        for (int j = 0; j < 8; j++)
#pragma unroll
            for (int q = 0; q < 4; q++) acc[i][j][q] = 0.f;

    const int a_ld = (wm * 64 + (lane & 15)) * 40 + (lane >> 4) * 8;
    const int b_ld = (lane & 15) * 136 + wn * 64 + (lane >> 4) * 8;

    stage(0, 0); cp_commit();
    stage(1, 1); cp_commit();

    for (int kt = 0; kt < G_NT; kt++) {
        if (kt == G_NT - 1) cp_wait<0>(); else cp_wait<1>();
        __syncthreads();
        if (kt + 2 < G_NT) { stage(kt + 2, (kt + 2) % 3); cp_commit(); }

        const uint32_t sb = smu + (kt % 3) * G_STG * 2;
#pragma unroll
        for (int ks = 0; ks < 2; ks++) {
            unsigned ah[4][4], al[4][4], bh[8][2], bl[8][2];
            const uint32_t aBh = sb + (a_ld + ks * 16) * 2;
            const uint32_t aBl = aBh + G_ALO * 2;
            const uint32_t bBh = sb + (G_BHI + b_ld + ks * 16 * 136) * 2;
            const uint32_t bBl = bBh + (G_BLO - G_BHI) * 2;
#pragma unroll
            for (int mt = 0; mt < 4; mt++) {
                ldsm_x4(ah[mt], aBh + mt * 16 * 40 * 2);
                ldsm_x4(al[mt], aBl + mt * 16 * 40 * 2);
            }
#pragma unroll
            for (int ntp = 0; ntp < 4; ntp++) {
                unsigned t4[4];
                ldsm_x4t(t4, bBh + ntp * 16 * 2);
                bh[2 * ntp][0] = t4[0]; bh[2 * ntp][1] = t4[1];
                bh[2 * ntp + 1][0] = t4[2]; bh[2 * ntp + 1][1] = t4[3];
                ldsm_x4t(t4, bBl + ntp * 16 * 2);
                bl[2 * ntp][0] = t4[0]; bl[2 * ntp][1] = t4[1];
                bl[2 * ntp + 1][0] = t4[2]; bl[2 * ntp + 1][1] = t4[3];
            }
#pragma unroll
            for (int mt = 0; mt < 4; mt++)
#pragma unroll
                for (int nt = 0; nt < 8; nt++) {
                    mma_bf16(acc[mt][nt], ah[mt], bh[nt]);
                    mma_bf16(acc[mt][nt], ah[mt], bl[nt]);
                    mma_bf16(acc[mt][nt], al[mt], bh[nt]);
                }
        }
    }

    const int rb = m0 + wm * 64 + (lane >> 2);
    const int cb = n0 + wn * 64 + (lane & 3) * 2;
#pragma unroll
    for (int mt = 0; mt < 4; mt++)
#pragma unroll
        for (int nt = 0; nt < 8; nt++) {
            const int c = cb + nt * 8;
            const float b0 = bias[c], b1 = bias[c + 1];
#pragma unroll
            for (int half = 0; half < 2; half++) {
                const int r = rb + mt * 16 + half * 8;
                float* p = out + (size_t)r * CDIM + c;
                *(float2*)p = make_float2(acc[mt][nt][2 * half] + b0,
                                          acc[mt][nt][2 * half + 1] + b1);
            }
        }
}

// =============== Flash attention: Br=128, compacted keys, Bc=64 ==============
#define QP 72
#define F_KV0   18432
#define F_KVSZ  18432
#define F_SCOLB (55296 * 2)
#define FLASH_MMA_SMEM (F_SCOLB + 512)   // 111104 B -> 2 CTAs/SM

__global__ void __launch_bounds__(256, 2) flash_mma_kernel() {
    extern __shared__ __align__(16) char smraw[];
    __nv_bfloat16* smb = (__nv_bfloat16*)smraw;
    const uint32_t smu = s2u(smraw);
    __nv_bfloat16* sQh = smb;
    __nv_bfloat16* sQl = smb + 9216;
    int* scol = (int*)(smraw + F_SCOLB);

    const int tid = threadIdx.x, lane = tid & 31, wid = tid >> 5;
    const int qt = gridDim.x - 1 - blockIdx.x;
    const int h = blockIdx.y, b = blockIdx.z;
    const int q0 = qt * 128;
    const int cstart = g_causal_d;
    const size_t hoff = ((size_t)b * HN + h) * NSEQ * DH;

    const __nv_bfloat16 *Qh = g_qhi + hoff, *Ql = g_qlo + hoff;
    const __nv_bfloat16* kvsrc[4] = {g_khi + hoff, g_klo + hoff,
                                     g_vhi + hoff, g_vlo + hoff};

    {
        const int r = tid >> 1, c0 = (tid & 1) * 32;
#pragma unroll
        for (int c = 0; c < 32; c += 8) {
            *(uint4*)&sQh[r * QP + c0 + c] = *(const uint4*)&Qh[(size_t)(q0 + r) * DH + c0 + c];
            *(uint4*)&sQl[r * QP + c0 + c] = *(const uint4*)&Ql[(size_t)(q0 + r) * DH + c0 + c];
        }
    }

    const int kv_r = tid >> 3, kv_c = (tid & 7) * 8;
    auto stageKV = [&](int t) {
        const int k0t = t * 64;
        const uint32_t base = smu + (F_KV0 + (t & 1) * F_KVSZ) * 2;
#pragma unroll
        for (int pl = 0; pl < 4; pl++)
#pragma unroll
            for (int half = 0; half < 2; half++) {
                const int r = kv_r + half * 32;
                cp16(base + (pl * 4608 + r * QP + kv_c) * 2,
                     kvsrc[pl] + (size_t)(k0t + r) * DH + kv_c);
            }
    };

    int kmaxi = q0 + 127;
    if (cstart - 1 > kmaxi) kmaxi = cstart - 1;
    if (kmaxi > NSEQ - 1) kmaxi = NSEQ - 1;
    const int kcnt = g_pcnt[b * (NSEQ + 1) + kmaxi + 1];
    const int ntiles = (kcnt + 63) >> 6;

    stageKV(0); cp_commit();
    if (tid < 64) scol[tid] = g_kidx[b * NSEQ + tid];

    unsigned qfh[4][4], qfl[4][4];
    float m0v = -1e30f, m1v = -1e30f, l0v = 0.f, l1v = 0.f;
    float oacc[8][4] = {};

    const int grow0 = q0 + wid * 16 + (lane >> 2);
    const int grow1 = grow0 + 8;
    // tile fully visible iff max orig col <= max(q0, cstart-1)
    const int visthr = (q0 > cstart - 1) ? q0 : (cstart - 1);

    for (int t = 0; t < ntiles; t++) {
        __syncthreads();
        if (t == 0) {
#pragma unroll
            for (int ks = 0; ks < 4; ks++) {
                const int qa = (wid * 16 + (lane & 15)) * QP + ks * 16 + (lane >> 4) * 8;
                ldsm_x4(qfh[ks], s2u(&sQh[qa]));
                ldsm_x4(qfl[ks], s2u(&sQl[qa]));
            }
        }
        if (t + 1 < ntiles) {
            stageKV(t + 1);
            if (tid < 64)
                scol[((t + 1) & 1) * 64 + tid] = g_kidx[b * NSEQ + (t + 1) * 64 + tid];
            cp_commit();
            cp_wait<1>();
        } else {
            cp_wait<0>();
        }
        __syncthreads();

        const __nv_bfloat16* kb = smb + F_KV0 + (t & 1) * F_KVSZ;
        const __nv_bfloat16* sKh = kb;
        const __nv_bfloat16* sKl = kb + 4608;
        const __nv_bfloat16* sVh = kb + 9216;
        const __nv_bfloat16* sVl = kb + 13824;
        const int* sc = scol + (t & 1) * 64;

        // ---- S = Q K^T ----
        float sacc[8][4] = {};
#pragma unroll
        for (int ks = 0; ks < 4; ks++) {
            unsigned kbh[8][2], kbl[8][2];
#pragma unroll
            for (int np = 0; np < 4; np++) {
                const int row = np * 16 + ((lane >> 4) & 1) * 8 + (lane & 7);
                const int col = ks * 16 + ((lane >> 3) & 1) * 8;
                unsigned t4[4];
                ldsm_x4(t4, s2u(&sKh[row * QP + col]));
                kbh[2 * np][0] = t4[0]; kbh[2 * np][1] = t4[1];
                kbh[2 * np + 1][0] = t4[2]; kbh[2 * np + 1][1] = t4[3];
                ldsm_x4(t4, s2u(&sKl[row * QP + col]));
                kbl[2 * np][0] = t4[0]; kbl[2 * np][1] = t4[1];
                kbl[2 * np + 1][0] = t4[2]; kbl[2 * np + 1][1] = t4[3];
            }
#pragma unroll
            for (int nt = 0; nt < 8; nt++) {
                mma_bf16(sacc[nt], qfh[ks], kbh[nt]);
                mma_bf16(sacc[nt], qfh[ks], kbl[nt]);
                mma_bf16(sacc[nt], qfl[ks], kbh[nt]);
            }
        }

        // ---- mask (slow path only) + row max ----
        const bool fullvis = sc[63] <= visthr;   // keys ascending within tile
        float tmax0 = -INFINITY, tmax1 = -INFINITY;
        if (fullvis) {
#pragma unroll
            for (int nt = 0; nt < 8; nt++) {
#pragma unroll
                for (int j = 0; j < 2; j++) {
                    tmax0 = fmaxf(tmax0, sacc[nt][j]);
                    tmax1 = fmaxf(tmax1, sacc[nt][2 + j]);
                }
            }
        } else {
#pragma unroll
            for (int nt = 0; nt < 8; nt++) {
#pragma unroll
                for (int j = 0; j < 2; j++) {
                    const int lc = nt * 8 + (lane & 3) * 2 + j;
                    const int col = sc[lc];
                    float v0 = sacc[nt][j];
                    float v1 = sacc[nt][2 + j];
                    v0 = (col > grow0 && col >= cstart) ? -INFINITY : v0;
                    v1 = (col > grow1 && col >= cstart) ? -INFINITY : v1;
                    sacc[nt][j] = v0; sacc[nt][2 + j] = v1;
                    tmax0 = fmaxf(tmax0, v0); tmax1 = fmaxf(tmax1, v1);
                }
            }
        }
#pragma unroll
        for (int off = 1; off < 4; off <<= 1) {
            tmax0 = fmaxf(tmax0, __shfl_xor_sync(0xffffffffu, tmax0, off));
            tmax1 = fmaxf(tmax1, __shfl_xor_sync(0xffffffffu, tmax1, off));
        }

        // ---- online softmax update ----
        const float mn0 = fmaxf(m0v, tmax0), mn1 = fmaxf(m1v, tmax1);
        const float cr0 = __expf(m0v - mn0), cr1 = __expf(m1v - mn1);
        m0v = mn0; m1v = mn1;
        l0v *= cr0; l1v *= cr1;
#pragma unroll
        for (int nt = 0; nt < 8; nt++) {
            oacc[nt][0] *= cr0; oacc[nt][1] *= cr0;
            oacc[nt][2] *= cr1; oacc[nt][3] *= cr1;
        }
        float rs0 = 0.f, rs1 = 0.f;
#pragma unroll
        for (int nt = 0; nt < 8; nt++) {
            float p0 = __expf(sacc[nt][0] - mn0), p1 = __expf(sacc[nt][1] - mn0);
            float p2 = __expf(sacc[nt][2] - mn1), p3 = __expf(sacc[nt][3] - mn1);
            sacc[nt][0] = p0; sacc[nt][1] = p1; sacc[nt][2] = p2; sacc[nt][3] = p3;
            rs0 += p0 + p1; rs1 += p2 + p3;
        }
#pragma unroll
        for (int off = 1; off < 4; off <<= 1) {
            rs0 += __shfl_xor_sync(0xffffffffu, rs0, off);
            rs1 += __shfl_xor_sync(0xffffffffu, rs1, off);
        }
        l0v += rs0; l1v += rs1;

        // ---- O += P V ----
#pragma unroll
        for (int ks = 0; ks < 4; ks++) {
            unsigned ah[4], al[4];
            {
                const float v0 = sacc[2 * ks][0], v1 = sacc[2 * ks][1];
                const float v2 = sacc[2 * ks][2], v3 = sacc[2 * ks][3];
                const float w0 = sacc[2 * ks + 1][0], w1 = sacc[2 * ks + 1][1];
                const float w2 = sacc[2 * ks + 1][2], w3 = sacc[2 * ks + 1][3];
                __nv_bfloat162 h0 = __floats2bfloat162_rn(v0, v1);
                __nv_bfloat162 h1 = __floats2bfloat162_rn(v2, v3);
                __nv_bfloat162 h2 = __floats2bfloat162_rn(w0, w1);
                __nv_bfloat162 h3 = __floats2bfloat162_rn(w2, w3);
                ah[0] = bf2u(h0); ah[1] = bf2u(h1); ah[2] = bf2u(h2); ah[3] = bf2u(h3);
                al[0] = bf2u(__floats2bfloat162_rn(v0 - __bfloat162float(h0.x),
                                                   v1 - __bfloat162float(h0.y)));
                al[1] = bf2u(__floats2bfloat162_rn(v2 - __bfloat162float(h1.x),
                                                   v3 - __bfloat162float(h1.y)));
                al[2] = bf2u(__floats2bfloat162_rn(w0 - __bfloat162float(h2.x),
                                                   w1 - __bfloat162float(h2.y)));
                al[3] = bf2u(__floats2bfloat162_rn(w2 - __bfloat162float(h3.x),
                                                   w3 - __bfloat162float(h3.y)));
            }
#pragma unroll
            for (int np = 0; np < 4; np++) {
                const int va = (ks * 16 + (lane & 15)) * QP + np * 16 + (lane >> 4) * 8;
                unsigned t4[4], t4l[4];
                ldsm_x4t(t4, s2u(&sVh[va]));
                ldsm_x4t(t4l, s2u(&sVl[va]));
                unsigned vb0[2] = {t4[0], t4[1]}, vb1[2] = {t4[2], t4[3]};
                unsigned vl0[2] = {t4l[0], t4l[1]}, vl1[2] = {t4l[2], t4l[3]};
                mma_bf16(oacc[2 * np], ah, vb0);
                mma_bf16(oacc[2 * np], ah, vl0);
                mma_bf16(oacc[2 * np], al, vb0);
                mma_bf16(oacc[2 * np + 1], ah, vb1);
                mma_bf16(oacc[2 * np + 1], ah, vl1);
                mma_bf16(oacc[2 * np + 1], al, vb1);
            }
        }
    }

    const float inv0 = 1.f / l0v, inv1 = 1.f / l1v;
#pragma unroll
    for (int nt = 0; nt < 8; nt++) {
        const int d = nt * 8 + (lane & 3) * 2;
        const size_t o0 = ((size_t)b * NSEQ + grow0) * CDIM + h * DH + d;
        const size_t o1 = ((size_t)b * NSEQ + grow1) * CDIM + h * DH + d;
        const float v0 = oacc[nt][0] * inv0, v1 = oacc[nt][1] * inv0;
        const float w0 = oacc[nt][2] * inv1, w1 = oacc[nt][3] * inv1;
        __nv_bfloat162 h0 = __floats2bfloat162_rn(v0, v1);
        *(__nv_bfloat162*)&g_ahi[o0] = h0;
        *(__nv_bfloat162*)&g_alo[o0] = __floats2bfloat162_rn(
            v0 - __bfloat162float(h0.x), v1 - __bfloat162float(h0.y));
        __nv_bfloat162 h1 = __floats2bfloat162_rn(w0, w1);
        *(__nv_bfloat162*)&g_ahi[o1] = h1;
        *(__nv_bfloat162*)&g_alo[o1] = __floats2bfloat162_rn(
            w0 - __bfloat162float(h1.x), w1 - __bfloat162float(h1.y));
    }
}

// ---------------- launch ------------------------------------------------------
extern "C" void kernel_launch(void* const* d_in, const int* in_sizes, int n_in,
                              void* d_out, int out_size) {
    (void)n_in; (void)out_size;
    const float* x     = (const float*)d_in[0];
    const void*  mask  = d_in[1];
    const int*   cs    = (const int*)d_in[2];
    const float* wqkv  = (const float*)d_in[3];
    const float* wproj = (const float*)d_in[4];
    const float* bproj = (const float*)d_in[5];
    float* out = (float*)d_out;

    prep_kernel<<<1, 256>>>(mask, cs, in_sizes[1]);

    const int ntot4 = NX4 + NWQ4 + NWP4;
    split_all_kernel<<<(ntot4 + 255) / 256, 256>>>((const float4*)x,
        (const float4*)wqkv, (const float4*)wproj);

    gather_x_kernel<<<dim3(NSEQ, BB), 128>>>();

    cudaFuncSetAttribute(qkv_gemm_kernel,
                         cudaFuncAttributeMaxDynamicSharedMemorySize, G_SMEM);
    cudaFuncSetAttribute(proj_gemm_kernel,
                         cudaFuncAttributeMaxDynamicSharedMemorySize, G_SMEM);
    cudaFuncSetAttribute(flash_mma_kernel,
                         cudaFuncAttributeMaxDynamicSharedMemorySize, FLASH_MMA_SMEM);

    // merged Q + KV GEMM (ntile<8 -> Q; else KV with early exit)
    dim3 g1(QKVC / 128, MROWS / 128);
    qkv_gemm_kernel<<<g1, 128, G_SMEM>>>();

    dim3 g2(NSEQ / 128, HN, BB);
    flash_mma_kernel<<<g2, 256, FLASH_MMA_SMEM>>>();

    dim3 g3(CDIM / 128, MROWS / 128);
    proj_gemm_kernel<<<g3, 128, G_SMEM>>>(bproj, out);
}

// round 15
// speedup vs baseline: 4.4528x; 1.0277x over previous
#include <cuda_runtime.h>
#include <cuda_bf16.h>
#include <math.h>
#include <stdint.h>

#define BB    2
#define NSEQ  2048
#define CDIM  1024
#define HN    16
#define DH    64
#define MROWS (BB*NSEQ)     // 4096
#define QKVC  (3*CDIM)      // 3072

// ---------------- scratch (static device globals; no allocation) -------------
__device__ __align__(16) __nv_bfloat16 g_xhi[(size_t)MROWS*CDIM], g_xlo[(size_t)MROWS*CDIM];
__device__ __align__(16) __nv_bfloat16 g_wqhi[(size_t)CDIM*QKVC], g_wqlo[(size_t)CDIM*QKVC];
__device__ __align__(16) __nv_bfloat16 g_wphi[(size_t)CDIM*CDIM], g_wplo[(size_t)CDIM*CDIM];
__device__ __align__(16) __nv_bfloat16 g_ahi[(size_t)MROWS*CDIM], g_alo[(size_t)MROWS*CDIM];
__device__ __align__(16) __nv_bfloat16 g_qhi[(size_t)BB*HN*NSEQ*DH], g_qlo[(size_t)BB*HN*NSEQ*DH];
__device__ __align__(16) __nv_bfloat16 g_khi[(size_t)BB*HN*NSEQ*DH], g_klo[(size_t)BB*HN*NSEQ*DH];
__device__ __align__(16) __nv_bfloat16 g_vhi[(size_t)BB*HN*NSEQ*DH], g_vlo[(size_t)BB*HN*NSEQ*DH];
__device__ __align__(16) __nv_bfloat16 g_zrow[CDIM];   // zero-initialized pad row
__device__ unsigned char g_maskc[BB*NSEQ];
__device__ int g_kidx[BB*NSEQ];          // gathered j -> orig col (pad 0x7FFFFFFF), ASCENDING
__device__ int g_pcnt[BB*(NSEQ+1)];
__device__ int g_kcnt[BB];
__device__ int g_causal_d;

// ---------------- prep: mask canon + causal + per-batch key compaction -------
__global__ void prep_kernel(const void* __restrict__ mask_raw,
                            const int* __restrict__ cs_raw, int nmask) {
    __shared__ int sfmt;
    __shared__ int snz1, snz3;
    __shared__ int tsum[257];
    const unsigned char* mb = (const unsigned char*)mask_raw;
    const int tid = threadIdx.x;
    if (tid == 0) { snz1 = 0; snz3 = 0; }
    __syncthreads();
    {
        int scan = nmask < 1024 ? nmask : 1024;
        for (int i = tid; i < scan; i += 256) {
            unsigned char v = mb[i];
            if (v) { int r = i & 3; if (r == 1) snz1 = 1; else if (r == 3) snz3 = 1; }
        }
    }
    __syncthreads();
    if (tid == 0) {
        sfmt = snz1 ? 0 : (snz3 ? 2 : 1);
        int cv = cs_raw[0];
        if (cv < 0 || cv > (1 << 24)) cv = (int)__int_as_float(cv);
        g_causal_d = cv;
    }
    __syncthreads();
    int f = sfmt;
    for (int i = tid; i < nmask; i += 256) {
        unsigned char m;
        if (f == 0)      m = mb[i] != 0;
        else if (f == 1) m = ((const int*)mask_raw)[i] != 0;
        else             m = ((const float*)mask_raw)[i] != 0.0f;
        g_maskc[i] = m;
    }
    __syncthreads();
    for (int b = 0; b < BB; b++) {
        int flags[8], s = 0;
        const int base = b * NSEQ + tid * 8;
#pragma unroll
        for (int j = 0; j < 8; j++) { flags[j] = g_maskc[base + j] ? 0 : 1; s += flags[j]; }
        tsum[tid] = s;
        __syncthreads();
        if (tid == 0) {
            int acc = 0;
            for (int i = 0; i < 256; i++) { int t = tsum[i]; tsum[i] = acc; acc += t; }
            tsum[256] = acc;
            g_kcnt[b] = acc;
        }
        __syncthreads();
        int run = tsum[tid];
#pragma unroll
        for (int j = 0; j < 8; j++) {
            const int n = tid * 8 + j;
            g_pcnt[b * (NSEQ + 1) + n] = run;
            if (flags[j]) { g_kidx[b * NSEQ + run] = n; run++; }
        }
        if (tid == 255) g_pcnt[b * (NSEQ + 1) + NSEQ] = run;
        __syncthreads();
        const int cnt = tsum[256];
        for (int i = cnt + tid; i < NSEQ; i += 256) g_kidx[b * NSEQ + i] = 0x7FFFFFFF;
        __syncthreads();
    }
}

// ---------------- fused vectorized splits (x, wqkv, wproj) -------------------
#define NX4  (MROWS * CDIM / 4)
#define NWQ4 (CDIM * QKVC / 4)
#define NWP4 (CDIM * CDIM / 4)
__global__ void split_all_kernel(const float4* __restrict__ x,
                                 const float4* __restrict__ wq,
                                 const float4* __restrict__ wp) {
    int i = blockIdx.x * blockDim.x + threadIdx.x;
    const float4* src;
    __nv_bfloat162 *hi, *lo;
    if (i < NX4) {
        src = x + i; hi = (__nv_bfloat162*)g_xhi + 2 * i; lo = (__nv_bfloat162*)g_xlo + 2 * i;
    } else if (i < NX4 + NWQ4) {
        int j = i - NX4;
        src = wq + j; hi = (__nv_bfloat162*)g_wqhi + 2 * j; lo = (__nv_bfloat162*)g_wqlo + 2 * j;
    } else if (i < NX4 + NWQ4 + NWP4) {
        int j = i - NX4 - NWQ4;
        src = wp + j; hi = (__nv_bfloat162*)g_wphi + 2 * j; lo = (__nv_bfloat162*)g_wplo + 2 * j;
    } else return;
    float4 v = *src;
    __nv_bfloat162 h0 = __floats2bfloat162_rn(v.x, v.y);
    __nv_bfloat162 h1 = __floats2bfloat162_rn(v.z, v.w);
    hi[0] = h0; hi[1] = h1;
    lo[0] = __floats2bfloat162_rn(v.x - __bfloat162float(h0.x), v.y - __bfloat162float(h0.y));
    lo[1] = __floats2bfloat162_rn(v.z - __bfloat162float(h1.x), v.w - __bfloat162float(h1.y));
}

// ---------------- PTX helpers -------------------------------------------------
__device__ __forceinline__ uint32_t s2u(const void* p) {
    return (uint32_t)__cvta_generic_to_shared(p);
}
__device__ __forceinline__ void ldsm_x4(unsigned* r, uint32_t addr) {
    asm volatile("ldmatrix.sync.aligned.m8n8.x4.shared.b16 {%0,%1,%2,%3}, [%4];"
                 : "=r"(r[0]), "=r"(r[1]), "=r"(r[2]), "=r"(r[3]) : "r"(addr));
}
__device__ __forceinline__ void ldsm_x4t(unsigned* r, uint32_t addr) {
    asm volatile("ldmatrix.sync.aligned.m8n8.x4.trans.shared.b16 {%0,%1,%2,%3}, [%4];"
                 : "=r"(r[0]), "=r"(r[1]), "=r"(r[2]), "=r"(r[3]) : "r"(addr));
}
__device__ __forceinline__ void mma_bf16(float* d, const unsigned* a, const unsigned* b) {
    asm volatile("mma.sync.aligned.m16n8k16.row.col.f32.bf16.bf16.f32 "
                 "{%0,%1,%2,%3}, {%4,%5,%6,%7}, {%8,%9}, {%0,%1,%2,%3};"
                 : "+f"(d[0]), "+f"(d[1]), "+f"(d[2]), "+f"(d[3])
                 : "r"(a[0]), "r"(a[1]), "r"(a[2]), "r"(a[3]), "r"(b[0]), "r"(b[1]));
}
__device__ __forceinline__ unsigned bf2u(__nv_bfloat162 x) { return *(unsigned*)&x; }
__device__ __forceinline__ void cp16(uint32_t smem, const void* g) {
    asm volatile("cp.async.cg.shared.global [%0], [%1], 16;"
                 :: "r"(smem), "l"(__cvta_generic_to_global(g)) : "memory");
}
__device__ __forceinline__ void cp_commit() {
    asm volatile("cp.async.commit_group;" ::: "memory");
}
template<int N> __device__ __forceinline__ void cp_wait() {
    asm volatile("cp.async.wait_group %0;" :: "n"(N) : "memory");
}

// == bf16x3 GEMM core: 128x128 CTA, 4 warps x 64x64 tiles, BK=32, 3-stage ring
#define G_STG   18944
#define G_ALO   5120
#define G_BHI   10240
#define G_BLO   14592
#define G_SMEM  (3 * G_STG * 2)       // 113664 B
#define G_NT    (CDIM / 32)           // 32

// --------- merged QKV GEMM: grid (24, 32); ntile<8 -> Q, else KV -------------
// KV path gathers x rows on the fly via g_kidx (zero-row padding).
__global__ void __launch_bounds__(128)
qkv_gemm_kernel() {
    extern __shared__ __align__(16) char smraw[];
    const uint32_t smu = s2u(smraw);

    const int tid = threadIdx.x, lane = tid & 31, wid = tid >> 5;
    const int wm = wid >> 1, wn = wid & 1;
    const bool isQ = blockIdx.x < 8;
    const int n0 = isQ ? blockIdx.x * 128 : CDIM + (blockIdx.x - 8) * 128;
    const int m0 = blockIdx.y * 128;
    const int bb = m0 >> 11;

    if (!isQ) {   // early exit: tile fully beyond padded key count
        const int j0 = m0 & (NSEQ - 1);
        if (j0 >= ((g_kcnt[bb] + 63) & ~63)) return;
    }

    // per-thread A source row pointers (4 rows: arow + it*32)
    const int arow = tid >> 2, acol = (tid & 3) * 8;
    const __nv_bfloat16 *pAh[4], *pAl[4];
#pragma unroll
    for (int it = 0; it < 4; it++) {
        const int r = m0 + arow + it * 32;
        if (isQ) {
            pAh[it] = g_xhi + (size_t)r * CDIM;
            pAl[it] = g_xlo + (size_t)r * CDIM;
        } else {
            const int j = r & (NSEQ - 1);
            if (j < g_kcnt[bb]) {
                const int n = g_kidx[bb * NSEQ + j];
                pAh[it] = g_xhi + ((size_t)bb * NSEQ + n) * CDIM;
                pAl[it] = g_xlo + ((size_t)bb * NSEQ + n) * CDIM;
            } else {
                pAh[it] = g_zrow;  // zero row (k-offset < CDIM always valid)
                pAl[it] = g_zrow;
            }
        }
    }

    auto stage = [&](int kt, int s) {
        const int k0 = kt * 32;
        const uint32_t sb = smu + s * G_STG * 2;
        const int brow = tid >> 4, bcol = (tid & 15) * 8;
#pragma unroll
        for (int it = 0; it < 4; it++) {
            const int r = arow + it * 32;
            cp16(sb + (r * 40 + acol) * 2, pAh[it] + k0 + acol);
            cp16(sb + (G_ALO + r * 40 + acol) * 2, pAl[it] + k0 + acol);
            const int rb = brow + it * 8;
            cp16(sb + (G_BHI + rb * 136 + bcol) * 2, g_wqhi + (size_t)(k0 + rb) * QKVC + n0 + bcol);
            cp16(sb + (G_BLO + rb * 136 + bcol) * 2, g_wqlo + (size_t)(k0 + rb) * QKVC + n0 + bcol);
        }
    };

    float acc[4][8][4];
#pragma unroll
    for (int i = 0; i < 4; i++)
#pragma unroll
        for (int j = 0; j < 8; j++)
#pragma unroll
            for (int q = 0; q < 4; q++) acc[i][j][q] = 0.f;

    const int a_ld = (wm * 64 + (lane & 15)) * 40 + (lane >> 4) * 8;
    const int b_ld = (lane & 15) * 136 + wn * 64 + (lane >> 4) * 8;

    stage(0, 0); cp_commit();
    stage(1, 1); cp_commit();

    for (int kt = 0; kt < G_NT; kt++) {
        if (kt == G_NT - 1) cp_wait<0>(); else cp_wait<1>();
        __syncthreads();
        if (kt + 2 < G_NT) { stage(kt + 2, (kt + 2) % 3); cp_commit(); }

        const uint32_t sb = smu + (kt % 3) * G_STG * 2;
#pragma unroll
        for (int ks = 0; ks < 2; ks++) {
            unsigned ah[4][4], al[4][4], bh[8][2], bl[8][2];
            const uint32_t aBh = sb + (a_ld + ks * 16) * 2;
            const uint32_t aBl = aBh + G_ALO * 2;
            const uint32_t bBh = sb + (G_BHI + b_ld + ks * 16 * 136) * 2;
            const uint32_t bBl = bBh + (G_BLO - G_BHI) * 2;
#pragma unroll
            for (int mt = 0; mt < 4; mt++) {
                ldsm_x4(ah[mt], aBh + mt * 16 * 40 * 2);
                ldsm_x4(al[mt], aBl + mt * 16 * 40 * 2);
            }
#pragma unroll
            for (int ntp = 0; ntp < 4; ntp++) {
                unsigned t4[4];
                ldsm_x4t(t4, bBh + ntp * 16 * 2);
                bh[2 * ntp][0] = t4[0]; bh[2 * ntp][1] = t4[1];
                bh[2 * ntp + 1][0] = t4[2]; bh[2 * ntp + 1][1] = t4[3];
                ldsm_x4t(t4, bBl + ntp * 16 * 2);
                bl[2 * ntp][0] = t4[0]; bl[2 * ntp][1] = t4[1];
                bl[2 * ntp + 1][0] = t4[2]; bl[2 * ntp + 1][1] = t4[3];
            }
#pragma unroll
            for (int mt = 0; mt < 4; mt++)
#pragma unroll
                for (int nt = 0; nt < 8; nt++) {
                    mma_bf16(acc[mt][nt], ah[mt], bh[nt]);
                    mma_bf16(acc[mt][nt], ah[mt], bl[nt]);
                    mma_bf16(acc[mt][nt], al[mt], bh[nt]);
                }
        }
    }

    const int rb = m0 + wm * 64 + (lane >> 2);
    const int cb = n0 + wn * 64 + (lane & 3) * 2;
#pragma unroll
    for (int mt = 0; mt < 4; mt++)
#pragma unroll
        for (int nt = 0; nt < 8; nt++) {
            const int c = cb + nt * 8;
            if (isQ) {
                const int h = c >> 6, d = c & 63;
#pragma unroll
                for (int half = 0; half < 2; half++) {
                    const int r = rb + mt * 16 + half * 8;
                    const int bidx = r >> 11, n = r & (NSEQ - 1);
                    size_t off = (((size_t)bidx * HN + h) * NSEQ + n) * DH + d;
                    float v0 = acc[mt][nt][2 * half] * 0.125f;
                    float v1 = acc[mt][nt][2 * half + 1] * 0.125f;
                    __nv_bfloat162 hh = __floats2bfloat162_rn(v0, v1);
                    *(__nv_bfloat162*)&g_qhi[off] = hh;
                    *(__nv_bfloat162*)&g_qlo[off] = __floats2bfloat162_rn(
                        v0 - __bfloat162float(hh.x), v1 - __bfloat162float(hh.y));
                }
            } else {
                const int sec = c >> 10, h = (c & 1023) >> 6, d = c & 63;
                __nv_bfloat16* dhi = (sec == 1) ? g_khi : g_vhi;
                __nv_bfloat16* dlo = (sec == 1) ? g_klo : g_vlo;
#pragma unroll
                for (int half = 0; half < 2; half++) {
                    const int r = rb + mt * 16 + half * 8;
                    const int bidx = r >> 11, j = r & (NSEQ - 1);
                    size_t off = (((size_t)bidx * HN + h) * NSEQ + j) * DH + d;
                    float v0 = acc[mt][nt][2 * half], v1 = acc[mt][nt][2 * half + 1];
                    __nv_bfloat162 hh = __floats2bfloat162_rn(v0, v1);
                    *(__nv_bfloat162*)&dhi[off] = hh;
                    *(__nv_bfloat162*)&dlo[off] = __floats2bfloat162_rn(
                        v0 - __bfloat162float(hh.x), v1 - __bfloat162float(hh.y));
                }
            }
        }
}

// --------- proj GEMM: att(4096x1024) @ Wp + bias -> out ----------------------
__global__ void __launch_bounds__(128)
proj_gemm_kernel(const float* __restrict__ bias, float* __restrict__ out) {
    extern __shared__ __align__(16) char smraw[];
    const uint32_t smu = s2u(smraw);

    const int tid = threadIdx.x, lane = tid & 31, wid = tid >> 5;
    const int wm = wid >> 1, wn = wid & 1;
    const int m0 = blockIdx.y * 128, n0 = blockIdx.x * 128;

    auto stage = [&](int kt, int s) {
        const int k0 = kt * 32;
        const uint32_t sb = smu + s * G_STG * 2;
        const int arow = tid >> 2, acol = (tid & 3) * 8;
        const int brow = tid >> 4, bcol = (tid & 15) * 8;
#pragma unroll
        for (int it = 0; it < 4; it++) {
            const int r = arow + it * 32;
            cp16(sb + (r * 40 + acol) * 2, g_ahi + (size_t)(m0 + r) * CDIM + k0 + acol);
            cp16(sb + (G_ALO + r * 40 + acol) * 2, g_alo + (size_t)(m0 + r) * CDIM + k0 + acol);
            const int rb = brow + it * 8;
            cp16(sb + (G_BHI + rb * 136 + bcol) * 2, g_wphi + (size_t)(k0 + rb) * CDIM + n0 + bcol);
            cp16(sb + (G_BLO + rb * 136 + bcol) * 2, g_wplo + (size_t)(k0 + rb) * CDIM + n0 + bcol);
        }
    };

    float acc[4][8][4];
#pragma unroll
    for (int i = 0; i < 4; i++)
#pragma unroll
        for (int j = 0; j < 8; j++)
#pragma unroll
            for (int q = 0; q < 4; q++) acc[i][j][q] = 0.f;

    const int a_ld = (wm * 64 + (lane & 15)) * 40 + (lane >> 4) * 8;
    const int b_ld = (lane & 15) * 136 + wn * 64 + (lane >> 4) * 8;

    stage(0, 0); cp_commit();
    stage(1, 1); cp_commit();

    for (int kt = 0; kt < G_NT; kt++) {
        if (kt == G_NT - 1) cp_wait<0>(); else cp_wait<1>();
        __syncthreads();
        if (kt + 2 < G_NT) { stage(kt + 2, (kt + 2) % 3); cp_commit(); }

        const uint32_t sb = smu + (kt % 3) * G_STG * 2;
#pragma unroll
        for (int ks = 0; ks < 2; ks++) {
            unsigned ah[4][4], al[4][4], bh[8][2], bl[8][2];
            const uint32_t aBh = sb + (a_ld + ks * 16) * 2;
            const uint32_t aBl = aBh + G_ALO * 2;
            const uint32_t bBh = sb + (G_BHI + b_ld + ks * 16 * 136) * 2;
            const uint32_t bBl = bBh + (G_BLO - G_BHI) * 2;
#pragma unroll
            for (int mt = 0; mt < 4; mt++) {
                ldsm_x4(ah[mt], aBh + mt * 16 * 40 * 2);
                ldsm_x4(al[mt], aBl + mt * 16 * 40 * 2);
            }
#pragma unroll
            for (int ntp = 0; ntp < 4; ntp++) {
                unsigned t4[4];
                ldsm_x4t(t4, bBh + ntp * 16 * 2);
                bh[2 * ntp][0] = t4[0]; bh[2 * ntp][1] = t4[1];
                bh[2 * ntp + 1][0] = t4[2]; bh[2 * ntp + 1][1] = t4[3];
                ldsm_x4t(t4, bBl + ntp * 16 * 2);
                bl[2 * ntp][0] = t4[0]; bl[2 * ntp][1] = t4[1];
                bl[2 * ntp + 1][0] = t4[2]; bl[2 * ntp + 1][1] = t4[3];
            }
#pragma unroll
            for (int mt = 0; mt < 4; mt++)
#pragma unroll
                for (int nt = 0; nt < 8; nt++) {
                    mma_bf16(acc[mt][nt], ah[mt], bh[nt]);
                    mma_bf16(acc[mt][nt], ah[mt], bl[nt]);
                    mma_bf16(acc[mt][nt], al[mt], bh[nt]);
                }
        }
    }

    const int rb = m0 + wm * 64 + (lane >> 2);
    const int cb = n0 + wn * 64 + (lane & 3) * 2;
#pragma unroll
    for (int mt = 0; mt < 4; mt++)
#pragma unroll
        for (int nt = 0; nt < 8; nt++) {
            const int c = cb + nt * 8;
            const float b0 = bias[c], b1 = bias[c + 1];
#pragma unroll
            for (int half = 0; half < 2; half++) {
                const int r = rb + mt * 16 + half * 8;
                float* p = out + (size_t)r * CDIM + c;
                *(float2*)p = make_float2(acc[mt][nt][2 * half] + b0,
                                          acc[mt][nt][2 * half + 1] + b1);
            }
        }
}

// =============== Flash attention: Br=128, compacted keys, Bc=64 ==============
// Q fragments re-loaded from smem each tile (keeps live regs < 128 -> no spills
// under __launch_bounds__(256,2)).
#define QP 72
#define F_KV0   18432
#define F_KVSZ  18432
#define F_SCOLB (55296 * 2)
#define FLASH_MMA_SMEM (F_SCOLB + 512)   // 111104 B -> 2 CTAs/SM

__global__ void __launch_bounds__(256, 2) flash_mma_kernel() {
    extern __shared__ __align__(16) char smraw[];
    __nv_bfloat16* smb = (__nv_bfloat16*)smraw;
    const uint32_t smu = s2u(smraw);
    __nv_bfloat16* sQh = smb;
    __nv_bfloat16* sQl = smb + 9216;
    int* scol = (int*)(smraw + F_SCOLB);

    const int tid = threadIdx.x, lane = tid & 31, wid = tid >> 5;
    const int qt = gridDim.x - 1 - blockIdx.x;
    const int h = blockIdx.y, b = blockIdx.z;
    const int q0 = qt * 128;
    const int cstart = g_causal_d;
    const size_t hoff = ((size_t)b * HN + h) * NSEQ * DH;

    const __nv_bfloat16 *Qh = g_qhi + hoff, *Ql = g_qlo + hoff;
    const __nv_bfloat16* kvsrc[4] = {g_khi + hoff, g_klo + hoff,
                                     g_vhi + hoff, g_vlo + hoff};

    {
        const int r = tid >> 1, c0 = (tid & 1) * 32;
#pragma unroll
        for (int c = 0; c < 32; c += 8) {
            *(uint4*)&sQh[r * QP + c0 + c] = *(const uint4*)&Qh[(size_t)(q0 + r) * DH + c0 + c];
            *(uint4*)&sQl[r * QP + c0 + c] = *(const uint4*)&Ql[(size_t)(q0 + r) * DH + c0 + c];
        }
    }

    const int kv_r = tid >> 3, kv_c = (tid & 7) * 8;
    auto stageKV = [&](int t) {
        const int k0t = t * 64;
        const uint32_t base = smu + (F_KV0 + (t & 1) * F_KVSZ) * 2;
#pragma unroll
        for (int pl = 0; pl < 4; pl++)
#pragma unroll
            for (int half = 0; half < 2; half++) {
                const int r = kv_r + half * 32;
                cp16(base + (pl * 4608 + r * QP + kv_c) * 2,
                     kvsrc[pl] + (size_t)(k0t + r) * DH + kv_c);
            }
    };

    int kmaxi = q0 + 127;
    if (cstart - 1 > kmaxi) kmaxi = cstart - 1;
    if (kmaxi > NSEQ - 1) kmaxi = NSEQ - 1;
    const int kcnt = g_pcnt[b * (NSEQ + 1) + kmaxi + 1];
    const int ntiles = (kcnt + 63) >> 6;

    stageKV(0); cp_commit();
    if (tid < 64) scol[tid] = g_kidx[b * NSEQ + tid];

    float m0v = -1e30f, m1v = -1e30f, l0v = 0.f, l1v = 0.f;
    float oacc[8][4] = {};

    const int grow0 = q0 + wid * 16 + (lane >> 2);
    const int grow1 = grow0 + 8;
    const int visthr = (q0 > cstart - 1) ? q0 : (cstart - 1);
    const int q_ld = (wid * 16 + (lane & 15)) * QP + (lane >> 4) * 8;

    for (int t = 0; t < ntiles; t++) {
        __syncthreads();
        if (t + 1 < ntiles) {
            stageKV(t + 1);
            if (tid < 64)
                scol[((t + 1) & 1) * 64 + tid] = g_kidx[b * NSEQ + (t + 1) * 64 + tid];
            cp_commit();
            cp_wait<1>();
        } else {
            cp_wait<0>();
        }
        __syncthreads();

        const __nv_bfloat16* kb = smb + F_KV0 + (t & 1) * F_KVSZ;
        const __nv_bfloat16* sKh = kb;
        const __nv_bfloat16* sKl = kb + 4608;
        const __nv_bfloat16* sVh = kb + 9216;
        const __nv_bfloat16* sVl = kb + 13824;
        const int* sc = scol + (t & 1) * 64;

        // ---- S = Q K^T (Q fragments re-loaded per ks; no persistent regs) ----
        float sacc[8][4] = {};
#pragma unroll
        for (int ks = 0; ks < 4; ks++) {
            unsigned qh[4], ql[4];
            ldsm_x4(qh, s2u(&sQh[q_ld + ks * 16]));
            ldsm_x4(ql, s2u(&sQl[q_ld + ks * 16]));
#pragma unroll
            for (int np = 0; np < 4; np++) {
                const int row = np * 16 + ((lane >> 4) & 1) * 8 + (lane & 7);
                const int col = ks * 16 + ((lane >> 3) & 1) * 8;
                unsigned t4[4], t4l[4];
                ldsm_x4(t4, s2u(&sKh[row * QP + col]));
                ldsm_x4(t4l, s2u(&sKl[row * QP + col]));
                unsigned b0h[2] = {t4[0], t4[1]}, b1h[2] = {t4[2], t4[3]};
                unsigned b0l[2] = {t4l[0], t4l[1]}, b1l[2] = {t4l[2], t4l[3]};
                mma_bf16(sacc[2 * np], qh, b0h);
                mma_bf16(sacc[2 * np], qh, b0l);
                mma_bf16(sacc[2 * np], ql, b0h);
                mma_bf16(sacc[2 * np + 1], qh, b1h);
                mma_bf16(sacc[2 * np + 1], qh, b1l);
                mma_bf16(sacc[2 * np + 1], ql, b1h);
            }
        }

        // ---- mask (slow path only) + row max ----
        const bool fullvis = sc[63] <= visthr;
        float tmax0 = -INFINITY, tmax1 = -INFINITY;
        if (fullvis) {
#pragma unroll
            for (int nt = 0; nt < 8; nt++) {
#pragma unroll
                for (int j = 0; j < 2; j++) {
                    tmax0 = fmaxf(tmax0, sacc[nt][j]);
                    tmax1 = fmaxf(tmax1, sacc[nt][2 + j]);
                }
            }
        } else {
#pragma unroll
            for (int nt = 0; nt < 8; nt++) {
#pragma unroll
                for (int j = 0; j < 2; j++) {
                    const int lc = nt * 8 + (lane & 3) * 2 + j;
                    const int col = sc[lc];
                    float v0 = sacc[nt][j];
                    float v1 = sacc[nt][2 + j];
                    v0 = (col > grow0 && col >= cstart) ? -INFINITY : v0;
                    v1 = (col > grow1 && col >= cstart) ? -INFINITY : v1;
                    sacc[nt][j] = v0; sacc[nt][2 + j] = v1;
                    tmax0 = fmaxf(tmax0, v0); tmax1 = fmaxf(tmax1, v1);
                }
            }
        }
#pragma unroll
        for (int off = 1; off < 4; off <<= 1) {
            tmax0 = fmaxf(tmax0, __shfl_xor_sync(0xffffffffu, tmax0, off));
            tmax1 = fmaxf(tmax1, __shfl_xor_sync(0xffffffffu, tmax1, off));
        }

        // ---- online softmax update ----
        const float mn0 = fmaxf(m0v, tmax0), mn1 = fmaxf(m1v, tmax1);
        const float cr0 = __expf(m0v - mn0), cr1 = __expf(m1v - mn1);
        m0v = mn0; m1v = mn1;
        l0v *= cr0; l1v *= cr1;
#pragma unroll
        for (int nt = 0; nt < 8; nt++) {
            oacc[nt][0] *= cr0; oacc[nt][1] *= cr0;
            oacc[nt][2] *= cr1; oacc[nt][3] *= cr1;
        }
        float rs0 = 0.f, rs1 = 0.f;
#pragma unroll
        for (int nt = 0; nt < 8; nt++) {
            float p0 = __expf(sacc[nt][0] - mn0), p1 = __expf(sacc[nt][1] - mn0);
            float p2 = __expf(sacc[nt][2] - mn1), p3 = __expf(sacc[nt][3] - mn1);
            sacc[nt][0] = p0; sacc[nt][1] = p1; sacc[nt][2] = p2; sacc[nt][3] = p3;
            rs0 += p0 + p1; rs1 += p2 + p3;
        }
#pragma unroll
        for (int off = 1; off < 4; off <<= 1) {
            rs0 += __shfl_xor_sync(0xffffffffu, rs0, off);
            rs1 += __shfl_xor_sync(0xffffffffu, rs1, off);
        }
        l0v += rs0; l1v += rs1;

        // ---- O += P V ----
#pragma unroll
        for (int ks = 0; ks < 4; ks++) {
            unsigned ah[4], al[4];
            {
                const float v0 = sacc[2 * ks][0], v1 = sacc[2 * ks][1];
                const float v2 = sacc[2 * ks][2], v3 = sacc[2 * ks][3];
                const float w0 = sacc[2 * ks + 1][0], w1 = sacc[2 * ks + 1][1];
                const float w2 = sacc[2 * ks + 1][2], w3 = sacc[2 * ks + 1][3];
                __nv_bfloat162 h0 = __floats2bfloat162_rn(v0, v1);
                __nv_bfloat162 h1 = __floats2bfloat162_rn(v2, v3);
                __nv_bfloat162 h2 = __floats2bfloat162_rn(w0, w1);
                __nv_bfloat162 h3 = __floats2bfloat162_rn(w2, w3);
                ah[0] = bf2u(h0); ah[1] = bf2u(h1); ah[2] = bf2u(h2); ah[3] = bf2u(h3);
                al[0] = bf2u(__floats2bfloat162_rn(v0 - __bfloat162float(h0.x),
                                                   v1 - __bfloat162float(h0.y)));
                al[1] = bf2u(__floats2bfloat162_rn(v2 - __bfloat162float(h1.x),
                                                   v3 - __bfloat162float(h1.y)));
                al[2] = bf2u(__floats2bfloat162_rn(w0 - __bfloat162float(h2.x),
                                                   w1 - __bfloat162float(h2.y)));
                al[3] = bf2u(__floats2bfloat162_rn(w2 - __bfloat162float(h3.x),
                                                   w3 - __bfloat162float(h3.y)));
            }
#pragma unroll
            for (int np = 0; np < 4; np++) {
                const int va = (ks * 16 + (lane & 15)) * QP + np * 16 + (lane >> 4) * 8;
                unsigned t4[4], t4l[4];
                ldsm_x4t(t4, s2u(&sVh[va]));
                ldsm_x4t(t4l, s2u(&sVl[va]));
                unsigned vb0[2] = {t4[0], t4[1]}, vb1[2] = {t4[2], t4[3]};
                unsigned vl0[2] = {t4l[0], t4l[1]}, vl1[2] = {t4l[2], t4l[3]};
                mma_bf16(oacc[2 * np], ah, vb0);
                mma_bf16(oacc[2 * np], ah, vl0);
                mma_bf16(oacc[2 * np], al, vb0);
                mma_bf16(oacc[2 * np + 1], ah, vb1);
                mma_bf16(oacc[2 * np + 1], ah, vl1);
                mma_bf16(oacc[2 * np + 1], al, vb1);
            }
        }
    }

    const float inv0 = 1.f / l0v, inv1 = 1.f / l1v;
#pragma unroll
    for (int nt = 0; nt < 8; nt++) {
        const int d = nt * 8 + (lane & 3) * 2;
        const size_t o0 = ((size_t)b * NSEQ + grow0) * CDIM + h * DH + d;
        const size_t o1 = ((size_t)b * NSEQ + grow1) * CDIM + h * DH + d;
        const float v0 = oacc[nt][0] * inv0, v1 = oacc[nt][1] * inv0;
        const float w0 = oacc[nt][2] * inv1, w1 = oacc[nt][3] * inv1;
        __nv_bfloat162 h0 = __floats2bfloat162_rn(v0, v1);
        *(__nv_bfloat162*)&g_ahi[o0] = h0;
        *(__nv_bfloat162*)&g_alo[o0] = __floats2bfloat162_rn(
            v0 - __bfloat162float(h0.x), v1 - __bfloat162float(h0.y));
        __nv_bfloat162 h1 = __floats2bfloat162_rn(w0, w1);
        *(__nv_bfloat162*)&g_ahi[o1] = h1;
        *(__nv_bfloat162*)&g_alo[o1] = __floats2bfloat162_rn(
            w0 - __bfloat162float(h1.x), w1 - __bfloat162float(h1.y));
    }
}

// ---------------- launch ------------------------------------------------------
extern "C" void kernel_launch(void* const* d_in, const int* in_sizes, int n_in,
                              void* d_out, int out_size) {
    (void)n_in; (void)out_size;
    const float* x     = (const float*)d_in[0];
    const void*  mask  = d_in[1];
    const int*   cs    = (const int*)d_in[2];
    const float* wqkv  = (const float*)d_in[3];
    const float* wproj = (const float*)d_in[4];
    const float* bproj = (const float*)d_in[5];
    float* out = (float*)d_out;

    prep_kernel<<<1, 256>>>(mask, cs, in_sizes[1]);

    const int ntot4 = NX4 + NWQ4 + NWP4;
    split_all_kernel<<<(ntot4 + 255) / 256, 256>>>((const float4*)x,
        (const float4*)wqkv, (const float4*)wproj);

    cudaFuncSetAttribute(qkv_gemm_kernel,
                         cudaFuncAttributeMaxDynamicSharedMemorySize, G_SMEM);
    cudaFuncSetAttribute(proj_gemm_kernel,
                         cudaFuncAttributeMaxDynamicSharedMemorySize, G_SMEM);
    cudaFuncSetAttribute(flash_mma_kernel,
                         cudaFuncAttributeMaxDynamicSharedMemorySize, FLASH_MMA_SMEM);

    dim3 g1(QKVC / 128, MROWS / 128);
    qkv_gemm_kernel<<<g1, 128, G_SMEM>>>();

    dim3 g2(NSEQ / 128, HN, BB);
    flash_mma_kernel<<<g2, 256, FLASH_MMA_SMEM>>>();

    dim3 g3(CDIM / 128, MROWS / 128);
    proj_gemm_kernel<<<g3, 128, G_SMEM>>>(bproj, out);
}

// round 16
// speedup vs baseline: 4.4898x; 1.0083x over previous
#include <cuda_runtime.h>
#include <cuda_bf16.h>
#include <math.h>
#include <stdint.h>

#define BB    2
#define NSEQ  2048
#define CDIM  1024
#define HN    16
#define DH    64
#define MROWS (BB*NSEQ)     // 4096
#define QKVC  (3*CDIM)      // 3072

// ---------------- scratch (static device globals; no allocation) -------------
__device__ __align__(16) __nv_bfloat16 g_xhi[(size_t)MROWS*CDIM], g_xlo[(size_t)MROWS*CDIM];
__device__ __align__(16) __nv_bfloat16 g_wqhi[(size_t)CDIM*QKVC], g_wqlo[(size_t)CDIM*QKVC];
__device__ __align__(16) __nv_bfloat16 g_wphi[(size_t)CDIM*CDIM], g_wplo[(size_t)CDIM*CDIM];
__device__ __align__(16) __nv_bfloat16 g_ahi[(size_t)MROWS*CDIM], g_alo[(size_t)MROWS*CDIM];
__device__ __align__(16) __nv_bfloat16 g_qhi[(size_t)BB*HN*NSEQ*DH], g_qlo[(size_t)BB*HN*NSEQ*DH];
__device__ __align__(16) __nv_bfloat16 g_khi[(size_t)BB*HN*NSEQ*DH], g_klo[(size_t)BB*HN*NSEQ*DH];
__device__ __align__(16) __nv_bfloat16 g_vhi[(size_t)BB*HN*NSEQ*DH], g_vlo[(size_t)BB*HN*NSEQ*DH];
__device__ __align__(16) __nv_bfloat16 g_zrow[CDIM];   // zero-initialized pad row
__device__ unsigned char g_maskc[BB*NSEQ];
__device__ int g_kidx[BB*NSEQ];          // gathered j -> orig col (pad 0x7FFFFFFF), ASCENDING
__device__ int g_pcnt[BB*(NSEQ+1)];
__device__ int g_kcnt[BB];
__device__ int g_causal_d;

// ---------------- prep: mask canon + causal + per-batch key compaction -------
__global__ void prep_kernel(const void* __restrict__ mask_raw,
                            const int* __restrict__ cs_raw, int nmask) {
    __shared__ int sfmt;
    __shared__ int snz1, snz3;
    __shared__ int tsum[257];
    const unsigned char* mb = (const unsigned char*)mask_raw;
    const int tid = threadIdx.x;
    if (tid == 0) { snz1 = 0; snz3 = 0; }
    __syncthreads();
    {
        int scan = nmask < 1024 ? nmask : 1024;
        for (int i = tid; i < scan; i += 256) {
            unsigned char v = mb[i];
            if (v) { int r = i & 3; if (r == 1) snz1 = 1; else if (r == 3) snz3 = 1; }
        }
    }
    __syncthreads();
    if (tid == 0) {
        sfmt = snz1 ? 0 : (snz3 ? 2 : 1);
        int cv = cs_raw[0];
        if (cv < 0 || cv > (1 << 24)) cv = (int)__int_as_float(cv);
        g_causal_d = cv;
    }
    __syncthreads();
    int f = sfmt;
    for (int i = tid; i < nmask; i += 256) {
        unsigned char m;
        if (f == 0)      m = mb[i] != 0;
        else if (f == 1) m = ((const int*)mask_raw)[i] != 0;
        else             m = ((const float*)mask_raw)[i] != 0.0f;
        g_maskc[i] = m;
    }
    __syncthreads();
    for (int b = 0; b < BB; b++) {
        int flags[8], s = 0;
        const int base = b * NSEQ + tid * 8;
#pragma unroll
        for (int j = 0; j < 8; j++) { flags[j] = g_maskc[base + j] ? 0 : 1; s += flags[j]; }
        tsum[tid] = s;
        __syncthreads();
        if (tid == 0) {
            int acc = 0;
            for (int i = 0; i < 256; i++) { int t = tsum[i]; tsum[i] = acc; acc += t; }
            tsum[256] = acc;
            g_kcnt[b] = acc;
        }
        __syncthreads();
        int run = tsum[tid];
#pragma unroll
        for (int j = 0; j < 8; j++) {
            const int n = tid * 8 + j;
            g_pcnt[b * (NSEQ + 1) + n] = run;
            if (flags[j]) { g_kidx[b * NSEQ + run] = n; run++; }
        }
        if (tid == 255) g_pcnt[b * (NSEQ + 1) + NSEQ] = run;
        __syncthreads();
        const int cnt = tsum[256];
        for (int i = cnt + tid; i < NSEQ; i += 256) g_kidx[b * NSEQ + i] = 0x7FFFFFFF;
        __syncthreads();
    }
}

// ---------------- fused vectorized splits (x, wqkv, wproj) -------------------
#define NX4  (MROWS * CDIM / 4)
#define NWQ4 (CDIM * QKVC / 4)
#define NWP4 (CDIM * CDIM / 4)
__global__ void split_all_kernel(const float4* __restrict__ x,
                                 const float4* __restrict__ wq,
                                 const float4* __restrict__ wp) {
    int i = blockIdx.x * blockDim.x + threadIdx.x;
    const float4* src;
    __nv_bfloat162 *hi, *lo;
    if (i < NX4) {
        src = x + i; hi = (__nv_bfloat162*)g_xhi + 2 * i; lo = (__nv_bfloat162*)g_xlo + 2 * i;
    } else if (i < NX4 + NWQ4) {
        int j = i - NX4;
        src = wq + j; hi = (__nv_bfloat162*)g_wqhi + 2 * j; lo = (__nv_bfloat162*)g_wqlo + 2 * j;
    } else if (i < NX4 + NWQ4 + NWP4) {
        int j = i - NX4 - NWQ4;
        src = wp + j; hi = (__nv_bfloat162*)g_wphi + 2 * j; lo = (__nv_bfloat162*)g_wplo + 2 * j;
    } else return;
    float4 v = *src;
    __nv_bfloat162 h0 = __floats2bfloat162_rn(v.x, v.y);
    __nv_bfloat162 h1 = __floats2bfloat162_rn(v.z, v.w);
    hi[0] = h0; hi[1] = h1;
    lo[0] = __floats2bfloat162_rn(v.x - __bfloat162float(h0.x), v.y - __bfloat162float(h0.y));
    lo[1] = __floats2bfloat162_rn(v.z - __bfloat162float(h1.x), v.w - __bfloat162float(h1.y));
}

// ---------------- PTX helpers -------------------------------------------------
__device__ __forceinline__ uint32_t s2u(const void* p) {
    return (uint32_t)__cvta_generic_to_shared(p);
}
__device__ __forceinline__ void ldsm_x4(unsigned* r, uint32_t addr) {
    asm volatile("ldmatrix.sync.aligned.m8n8.x4.shared.b16 {%0,%1,%2,%3}, [%4];"
                 : "=r"(r[0]), "=r"(r[1]), "=r"(r[2]), "=r"(r[3]) : "r"(addr));
}
__device__ __forceinline__ void ldsm_x4t(unsigned* r, uint32_t addr) {
    asm volatile("ldmatrix.sync.aligned.m8n8.x4.trans.shared.b16 {%0,%1,%2,%3}, [%4];"
                 : "=r"(r[0]), "=r"(r[1]), "=r"(r[2]), "=r"(r[3]) : "r"(addr));
}
__device__ __forceinline__ void mma_bf16(float* d, const unsigned* a, const unsigned* b) {
    asm volatile("mma.sync.aligned.m16n8k16.row.col.f32.bf16.bf16.f32 "
                 "{%0,%1,%2,%3}, {%4,%5,%6,%7}, {%8,%9}, {%0,%1,%2,%3};"
                 : "+f"(d[0]), "+f"(d[1]), "+f"(d[2]), "+f"(d[3])
                 : "r"(a[0]), "r"(a[1]), "r"(a[2]), "r"(a[3]), "r"(b[0]), "r"(b[1]));
}
__device__ __forceinline__ unsigned bf2u(__nv_bfloat162 x) { return *(unsigned*)&x; }
__device__ __forceinline__ void cp16(uint32_t smem, const void* g) {
    asm volatile("cp.async.cg.shared.global [%0], [%1], 16;"
                 :: "r"(smem), "l"(__cvta_generic_to_global(g)) : "memory");
}
__device__ __forceinline__ void cp_commit() {
    asm volatile("cp.async.commit_group;" ::: "memory");
}
template<int N> __device__ __forceinline__ void cp_wait() {
    asm volatile("cp.async.wait_group %0;" :: "n"(N) : "memory");
}

// == bf16x3 GEMM core: 128x128 CTA, 4 warps x 64x64 tiles, BK=32, 3-stage ring
#define G_STG   18944
#define G_ALO   5120
#define G_BHI   10240
#define G_BLO   14592
#define G_SMEM  (3 * G_STG * 2)       // 113664 B
#define G_NT    (CDIM / 32)           // 32

// shared MMA inner block: pass-major (hh all, hl all, lh all) — no acc RAW chains
#define GEMM_MMA_BLOCK \
    do { \
        _Pragma("unroll") \
        for (int mt = 0; mt < 4; mt++) \
            _Pragma("unroll") \
            for (int nt = 0; nt < 8; nt++) mma_bf16(acc[mt][nt], ah[mt], bh[nt]); \
        _Pragma("unroll") \
        for (int mt = 0; mt < 4; mt++) \
            _Pragma("unroll") \
            for (int nt = 0; nt < 8; nt++) mma_bf16(acc[mt][nt], ah[mt], bl[nt]); \
        _Pragma("unroll") \
        for (int mt = 0; mt < 4; mt++) \
            _Pragma("unroll") \
            for (int nt = 0; nt < 8; nt++) mma_bf16(acc[mt][nt], al[mt], bh[nt]); \
    } while (0)

// --------- merged QKV GEMM: grid (24, 32); ntile<8 -> Q, else KV -------------
__global__ void __launch_bounds__(128)
qkv_gemm_kernel() {
    extern __shared__ __align__(16) char smraw[];
    const uint32_t smu = s2u(smraw);

    const int tid = threadIdx.x, lane = tid & 31, wid = tid >> 5;
    const int wm = wid >> 1, wn = wid & 1;
    const bool isQ = blockIdx.x < 8;
    const int n0 = isQ ? blockIdx.x * 128 : CDIM + (blockIdx.x - 8) * 128;
    const int m0 = blockIdx.y * 128;
    const int bb = m0 >> 11;

    if (!isQ) {
        const int j0 = m0 & (NSEQ - 1);
        if (j0 >= ((g_kcnt[bb] + 63) & ~63)) return;
    }

    const int arow = tid >> 2, acol = (tid & 3) * 8;
    const __nv_bfloat16 *pAh[4], *pAl[4];
#pragma unroll
    for (int it = 0; it < 4; it++) {
        const int r = m0 + arow + it * 32;
        if (isQ) {
            pAh[it] = g_xhi + (size_t)r * CDIM;
            pAl[it] = g_xlo + (size_t)r * CDIM;
        } else {
            const int j = r & (NSEQ - 1);
            if (j < g_kcnt[bb]) {
                const int n = g_kidx[bb * NSEQ + j];
                pAh[it] = g_xhi + ((size_t)bb * NSEQ + n) * CDIM;
                pAl[it] = g_xlo + ((size_t)bb * NSEQ + n) * CDIM;
            } else {
                pAh[it] = g_zrow;
                pAl[it] = g_zrow;
            }
        }
    }

    auto stage = [&](int kt, int s) {
        const int k0 = kt * 32;
        const uint32_t sb = smu + s * G_STG * 2;
        const int brow = tid >> 4, bcol = (tid & 15) * 8;
#pragma unroll
        for (int it = 0; it < 4; it++) {
            const int r = arow + it * 32;
            cp16(sb + (r * 40 + acol) * 2, pAh[it] + k0 + acol);
            cp16(sb + (G_ALO + r * 40 + acol) * 2, pAl[it] + k0 + acol);
            const int rb = brow + it * 8;
            cp16(sb + (G_BHI + rb * 136 + bcol) * 2, g_wqhi + (size_t)(k0 + rb) * QKVC + n0 + bcol);
            cp16(sb + (G_BLO + rb * 136 + bcol) * 2, g_wqlo + (size_t)(k0 + rb) * QKVC + n0 + bcol);
        }
    };

    float acc[4][8][4];
#pragma unroll
    for (int i = 0; i < 4; i++)
#pragma unroll
        for (int j = 0; j < 8; j++)
#pragma unroll
            for (int q = 0; q < 4; q++) acc[i][j][q] = 0.f;

    const int a_ld = (wm * 64 + (lane & 15)) * 40 + (lane >> 4) * 8;
    const int b_ld = (lane & 15) * 136 + wn * 64 + (lane >> 4) * 8;

    stage(0, 0); cp_commit();
    stage(1, 1); cp_commit();

    for (int kt = 0; kt < G_NT; kt++) {
        if (kt == G_NT - 1) cp_wait<0>(); else cp_wait<1>();
        __syncthreads();
        if (kt + 2 < G_NT) { stage(kt + 2, (kt + 2) % 3); cp_commit(); }

        const uint32_t sb = smu + (kt % 3) * G_STG * 2;
#pragma unroll
        for (int ks = 0; ks < 2; ks++) {
            unsigned ah[4][4], al[4][4], bh[8][2], bl[8][2];
            const uint32_t aBh = sb + (a_ld + ks * 16) * 2;
            const uint32_t aBl = aBh + G_ALO * 2;
            const uint32_t bBh = sb + (G_BHI + b_ld + ks * 16 * 136) * 2;
            const uint32_t bBl = bBh + (G_BLO - G_BHI) * 2;
#pragma unroll
            for (int mt = 0; mt < 4; mt++) {
                ldsm_x4(ah[mt], aBh + mt * 16 * 40 * 2);
                ldsm_x4(al[mt], aBl + mt * 16 * 40 * 2);
            }
#pragma unroll
            for (int ntp = 0; ntp < 4; ntp++) {
                unsigned t4[4];
                ldsm_x4t(t4, bBh + ntp * 16 * 2);
                bh[2 * ntp][0] = t4[0]; bh[2 * ntp][1] = t4[1];
                bh[2 * ntp + 1][0] = t4[2]; bh[2 * ntp + 1][1] = t4[3];
                ldsm_x4t(t4, bBl + ntp * 16 * 2);
                bl[2 * ntp][0] = t4[0]; bl[2 * ntp][1] = t4[1];
                bl[2 * ntp + 1][0] = t4[2]; bl[2 * ntp + 1][1] = t4[3];
            }
            GEMM_MMA_BLOCK;
        }
    }

    const int rb = m0 + wm * 64 + (lane >> 2);
    const int cb = n0 + wn * 64 + (lane & 3) * 2;
#pragma unroll
    for (int mt = 0; mt < 4; mt++)
#pragma unroll
        for (int nt = 0; nt < 8; nt++) {
            const int c = cb + nt * 8;
            if (isQ) {
                const int h = c >> 6, d = c & 63;
#pragma unroll
                for (int half = 0; half < 2; half++) {
                    const int r = rb + mt * 16 + half * 8;
                    const int bidx = r >> 11, n = r & (NSEQ - 1);
                    size_t off = (((size_t)bidx * HN + h) * NSEQ + n) * DH + d;
                    float v0 = acc[mt][nt][2 * half] * 0.125f;
                    float v1 = acc[mt][nt][2 * half + 1] * 0.125f;
                    __nv_bfloat162 hh = __floats2bfloat162_rn(v0, v1);
                    *(__nv_bfloat162*)&g_qhi[off] = hh;
                    *(__nv_bfloat162*)&g_qlo[off] = __floats2bfloat162_rn(
                        v0 - __bfloat162float(hh.x), v1 - __bfloat162float(hh.y));
                }
            } else {
                const int sec = c >> 10, h = (c & 1023) >> 6, d = c & 63;
                __nv_bfloat16* dhi = (sec == 1) ? g_khi : g_vhi;
                __nv_bfloat16* dlo = (sec == 1) ? g_klo : g_vlo;
#pragma unroll
                for (int half = 0; half < 2; half++) {
                    const int r = rb + mt * 16 + half * 8;
                    const int bidx = r >> 11, j = r & (NSEQ - 1);
                    size_t off = (((size_t)bidx * HN + h) * NSEQ + j) * DH + d;
                    float v0 = acc[mt][nt][2 * half], v1 = acc[mt][nt][2 * half + 1];
                    __nv_bfloat162 hh = __floats2bfloat162_rn(v0, v1);
                    *(__nv_bfloat162*)&dhi[off] = hh;
                    *(__nv_bfloat162*)&dlo[off] = __floats2bfloat162_rn(
                        v0 - __bfloat162float(hh.x), v1 - __bfloat162float(hh.y));
                }
            }
        }
}

// --------- proj GEMM: att(4096x1024) @ Wp + bias -> out ----------------------
__global__ void __launch_bounds__(128)
proj_gemm_kernel(const float* __restrict__ bias, float* __restrict__ out) {
    extern __shared__ __align__(16) char smraw[];
    const uint32_t smu = s2u(smraw);

    const int tid = threadIdx.x, lane = tid & 31, wid = tid >> 5;
    const int wm = wid >> 1, wn = wid & 1;
    const int m0 = blockIdx.y * 128, n0 = blockIdx.x * 128;

    auto stage = [&](int kt, int s) {
        const int k0 = kt * 32;
        const uint32_t sb = smu + s * G_STG * 2;
        const int arow = tid >> 2, acol = (tid & 3) * 8;
        const int brow = tid >> 4, bcol = (tid & 15) * 8;
#pragma unroll
        for (int it = 0; it < 4; it++) {
            const int r = arow + it * 32;
            cp16(sb + (r * 40 + acol) * 2, g_ahi + (size_t)(m0 + r) * CDIM + k0 + acol);
            cp16(sb + (G_ALO + r * 40 + acol) * 2, g_alo + (size_t)(m0 + r) * CDIM + k0 + acol);
            const int rb = brow + it * 8;
            cp16(sb + (G_BHI + rb * 136 + bcol) * 2, g_wphi + (size_t)(k0 + rb) * CDIM + n0 + bcol);
            cp16(sb + (G_BLO + rb * 136 + bcol) * 2, g_wplo + (size_t)(k0 + rb) * CDIM + n0 + bcol);
        }
    };

    float acc[4][8][4];
#pragma unroll
    for (int i = 0; i < 4; i++)
#pragma unroll
        for (int j = 0; j < 8; j++)
#pragma unroll
            for (int q = 0; q < 4; q++) acc[i][j][q] = 0.f;

    const int a_ld = (wm * 64 + (lane & 15)) * 40 + (lane >> 4) * 8;
    const int b_ld = (lane & 15) * 136 + wn * 64 + (lane >> 4) * 8;

    stage(0, 0); cp_commit();
    stage(1, 1); cp_commit();

    for (int kt = 0; kt < G_NT; kt++) {
        if (kt == G_NT - 1) cp_wait<0>(); else cp_wait<1>();
        __syncthreads();
        if (kt + 2 < G_NT) { stage(kt + 2, (kt + 2) % 3); cp_commit(); }

        const uint32_t sb = smu + (kt % 3) * G_STG * 2;
#pragma unroll
        for (int ks = 0; ks < 2; ks++) {
            unsigned ah[4][4], al[4][4], bh[8][2], bl[8][2];
            const uint32_t aBh = sb + (a_ld + ks * 16) * 2;
            const uint32_t aBl = aBh + G_ALO * 2;
            const uint32_t bBh = sb + (G_BHI + b_ld + ks * 16 * 136) * 2;
            const uint32_t bBl = bBh + (G_BLO - G_BHI) * 2;
#pragma unroll
            for (int mt = 0; mt < 4; mt++) {
                ldsm_x4(ah[mt], aBh + mt * 16 * 40 * 2);
                ldsm_x4(al[mt], aBl + mt * 16 * 40 * 2);
            }
#pragma unroll
            for (int ntp = 0; ntp < 4; ntp++) {
                unsigned t4[4];
                ldsm_x4t(t4, bBh + ntp * 16 * 2);
                bh[2 * ntp][0] = t4[0]; bh[2 * ntp][1] = t4[1];
                bh[2 * ntp + 1][0] = t4[2]; bh[2 * ntp + 1][1] = t4[3];
                ldsm_x4t(t4, bBl + ntp * 16 * 2);
                bl[2 * ntp][0] = t4[0]; bl[2 * ntp][1] = t4[1];
                bl[2 * ntp + 1][0] = t4[2]; bl[2 * ntp + 1][1] = t4[3];
            }
            GEMM_MMA_BLOCK;
        }
    }

    const int rb = m0 + wm * 64 + (lane >> 2);
    const int cb = n0 + wn * 64 + (lane & 3) * 2;
#pragma unroll
    for (int mt = 0; mt < 4; mt++)
#pragma unroll
        for (int nt = 0; nt < 8; nt++) {
            const int c = cb + nt * 8;
            const float b0 = bias[c], b1 = bias[c + 1];
#pragma unroll
            for (int half = 0; half < 2; half++) {
                const int r = rb + mt * 16 + half * 8;
                float* p = out + (size_t)r * CDIM + c;
                *(float2*)p = make_float2(acc[mt][nt][2 * half] + b0,
                                          acc[mt][nt][2 * half + 1] + b1);
            }
        }
}

// =============== Flash attention: Br=128, compacted keys, Bc=64 ==============
#define QP 72
#define F_KV0   18432
#define F_KVSZ  18432
#define F_SCOLB (55296 * 2)
#define FLASH_MMA_SMEM (F_SCOLB + 512)   // 111104 B -> 2 CTAs/SM

__global__ void __launch_bounds__(256, 2) flash_mma_kernel() {
    extern __shared__ __align__(16) char smraw[];
    __nv_bfloat16* smb = (__nv_bfloat16*)smraw;
    const uint32_t smu = s2u(smraw);
    __nv_bfloat16* sQh = smb;
    __nv_bfloat16* sQl = smb + 9216;
    int* scol = (int*)(smraw + F_SCOLB);

    const int tid = threadIdx.x, lane = tid & 31, wid = tid >> 5;
    const int qt = gridDim.x - 1 - blockIdx.x;
    const int h = blockIdx.y, b = blockIdx.z;
    const int q0 = qt * 128;
    const int cstart = g_causal_d;
    const size_t hoff = ((size_t)b * HN + h) * NSEQ * DH;

    const __nv_bfloat16 *Qh = g_qhi + hoff, *Ql = g_qlo + hoff;
    const __nv_bfloat16* kvsrc[4] = {g_khi + hoff, g_klo + hoff,
                                     g_vhi + hoff, g_vlo + hoff};

    {
        const int r = tid >> 1, c0 = (tid & 1) * 32;
#pragma unroll
        for (int c = 0; c < 32; c += 8) {
            *(uint4*)&sQh[r * QP + c0 + c] = *(const uint4*)&Qh[(size_t)(q0 + r) * DH + c0 + c];
            *(uint4*)&sQl[r * QP + c0 + c] = *(const uint4*)&Ql[(size_t)(q0 + r) * DH + c0 + c];
        }
    }

    const int kv_r = tid >> 3, kv_c = (tid & 7) * 8;
    auto stageKV = [&](int t) {
        const int k0t = t * 64;
        const uint32_t base = smu + (F_KV0 + (t & 1) * F_KVSZ) * 2;
#pragma unroll
        for (int pl = 0; pl < 4; pl++)
#pragma unroll
            for (int half = 0; half < 2; half++) {
                const int r = kv_r + half * 32;
                cp16(base + (pl * 4608 + r * QP + kv_c) * 2,
                     kvsrc[pl] + (size_t)(k0t + r) * DH + kv_c);
            }
    };

    int kmaxi = q0 + 127;
    if (cstart - 1 > kmaxi) kmaxi = cstart - 1;
    if (kmaxi > NSEQ - 1) kmaxi = NSEQ - 1;
    const int kcnt = g_pcnt[b * (NSEQ + 1) + kmaxi + 1];
    const int ntiles = (kcnt + 63) >> 6;

    stageKV(0); cp_commit();
    if (tid < 64) scol[tid] = g_kidx[b * NSEQ + tid];

    float m0v = -1e30f, m1v = -1e30f, l0v = 0.f, l1v = 0.f;
    float oacc[8][4] = {};

    const int grow0 = q0 + wid * 16 + (lane >> 2);
    const int grow1 = grow0 + 8;
    const int visthr = (q0 > cstart - 1) ? q0 : (cstart - 1);
    const int q_ld = (wid * 16 + (lane & 15)) * QP + (lane >> 4) * 8;

    for (int t = 0; t < ntiles; t++) {
        __syncthreads();
        if (t + 1 < ntiles) {
            stageKV(t + 1);
            if (tid < 64)
                scol[((t + 1) & 1) * 64 + tid] = g_kidx[b * NSEQ + (t + 1) * 64 + tid];
            cp_commit();
            cp_wait<1>();
        } else {
            cp_wait<0>();
        }
        __syncthreads();

        const __nv_bfloat16* kb = smb + F_KV0 + (t & 1) * F_KVSZ;
        const __nv_bfloat16* sKh = kb;
        const __nv_bfloat16* sKl = kb + 4608;
        const __nv_bfloat16* sVh = kb + 9216;
        const __nv_bfloat16* sVl = kb + 13824;
        const int* sc = scol + (t & 1) * 64;

        // ---- S = Q K^T (np-pairs; pass-major over 4 accs: chain distance 4) --
        float sacc[8][4] = {};
#pragma unroll
        for (int ks = 0; ks < 4; ks++) {
            unsigned qh[4], ql[4];
            ldsm_x4(qh, s2u(&sQh[q_ld + ks * 16]));
            ldsm_x4(ql, s2u(&sQl[q_ld + ks * 16]));
#pragma unroll
            for (int nph = 0; nph < 2; nph++) {
                unsigned kh[4][2], kl[4][2];
#pragma unroll
                for (int p = 0; p < 2; p++) {
                    const int np = 2 * nph + p;
                    const int row = np * 16 + ((lane >> 4) & 1) * 8 + (lane & 7);
                    const int col = ks * 16 + ((lane >> 3) & 1) * 8;
                    unsigned t4[4], t4l[4];
                    ldsm_x4(t4, s2u(&sKh[row * QP + col]));
                    ldsm_x4(t4l, s2u(&sKl[row * QP + col]));
                    kh[2 * p][0] = t4[0]; kh[2 * p][1] = t4[1];
                    kh[2 * p + 1][0] = t4[2]; kh[2 * p + 1][1] = t4[3];
                    kl[2 * p][0] = t4l[0]; kl[2 * p][1] = t4l[1];
                    kl[2 * p + 1][0] = t4l[2]; kl[2 * p + 1][1] = t4l[3];
                }
                float* sa = &sacc[4 * nph][0];
#pragma unroll
                for (int q = 0; q < 4; q++) mma_bf16(sa + 4 * q, qh, kh[q]);
#pragma unroll
                for (int q = 0; q < 4; q++) mma_bf16(sa + 4 * q, qh, kl[q]);
#pragma unroll
                for (int q = 0; q < 4; q++) mma_bf16(sa + 4 * q, ql, kh[q]);
            }
        }

        // ---- mask (slow path only) + row max ----
        const bool fullvis = sc[63] <= visthr;
        float tmax0 = -INFINITY, tmax1 = -INFINITY;
        if (fullvis) {
#pragma unroll
            for (int nt = 0; nt < 8; nt++) {
#pragma unroll
                for (int j = 0; j < 2; j++) {
                    tmax0 = fmaxf(tmax0, sacc[nt][j]);
                    tmax1 = fmaxf(tmax1, sacc[nt][2 + j]);
                }
            }
        } else {
#pragma unroll
            for (int nt = 0; nt < 8; nt++) {
#pragma unroll
                for (int j = 0; j < 2; j++) {
                    const int lc = nt * 8 + (lane & 3) * 2 + j;
                    const int col = sc[lc];
                    float v0 = sacc[nt][j];
                    float v1 = sacc[nt][2 + j];
                    v0 = (col > grow0 && col >= cstart) ? -INFINITY : v0;
                    v1 = (col > grow1 && col >= cstart) ? -INFINITY : v1;
                    sacc[nt][j] = v0; sacc[nt][2 + j] = v1;
                    tmax0 = fmaxf(tmax0, v0); tmax1 = fmaxf(tmax1, v1);
                }
            }
        }
#pragma unroll
        for (int off = 1; off < 4; off <<= 1) {
            tmax0 = fmaxf(tmax0, __shfl_xor_sync(0xffffffffu, tmax0, off));
            tmax1 = fmaxf(tmax1, __shfl_xor_sync(0xffffffffu, tmax1, off));
        }

        // ---- online softmax update ----
        const float mn0 = fmaxf(m0v, tmax0), mn1 = fmaxf(m1v, tmax1);
        const float cr0 = __expf(m0v - mn0), cr1 = __expf(m1v - mn1);
        m0v = mn0; m1v = mn1;
        l0v *= cr0; l1v *= cr1;
#pragma unroll
        for (int nt = 0; nt < 8; nt++) {
            oacc[nt][0] *= cr0; oacc[nt][1] *= cr0;
            oacc[nt][2] *= cr1; oacc[nt][3] *= cr1;
        }
        float rs0 = 0.f, rs1 = 0.f;
#pragma unroll
        for (int nt = 0; nt < 8; nt++) {
            float p0 = __expf(sacc[nt][0] - mn0), p1 = __expf(sacc[nt][1] - mn0);
            float p2 = __expf(sacc[nt][2] - mn1), p3 = __expf(sacc[nt][3] - mn1);
            sacc[nt][0] = p0; sacc[nt][1] = p1; sacc[nt][2] = p2; sacc[nt][3] = p3;
            rs0 += p0 + p1; rs1 += p2 + p3;
        }
#pragma unroll
        for (int off = 1; off < 4; off <<= 1) {
            rs0 += __shfl_xor_sync(0xffffffffu, rs0, off);
            rs1 += __shfl_xor_sync(0xffffffffu, rs1, off);
        }
        l0v += rs0; l1v += rs1;

        // ---- O += P V (np-pairs; pass-major over 4 accs) ----
#pragma unroll
        for (int ks = 0; ks < 4; ks++) {
            unsigned ah[4], al[4];
            {
                const float v0 = sacc[2 * ks][0], v1 = sacc[2 * ks][1];
                const float v2 = sacc[2 * ks][2], v3 = sacc[2 * ks][3];
                const float w0 = sacc[2 * ks + 1][0], w1 = sacc[2 * ks + 1][1];
                const float w2 = sacc[2 * ks + 1][2], w3 = sacc[2 * ks + 1][3];
                __nv_bfloat162 h0 = __floats2bfloat162_rn(v0, v1);
                __nv_bfloat162 h1 = __floats2bfloat162_rn(v2, v3);
                __nv_bfloat162 h2 = __floats2bfloat162_rn(w0, w1);
                __nv_bfloat162 h3 = __floats2bfloat162_rn(w2, w3);
                ah[0] = bf2u(h0); ah[1] = bf2u(h1); ah[2] = bf2u(h2); ah[3] = bf2u(h3);
                al[0] = bf2u(__floats2bfloat162_rn(v0 - __bfloat162float(h0.x),
                                                   v1 - __bfloat162float(h0.y)));
                al[1] = bf2u(__floats2bfloat162_rn(v2 - __bfloat162float(h1.x),
                                                   v3 - __bfloat162float(h1.y)));
                al[2] = bf2u(__floats2bfloat162_rn(w0 - __bfloat162float(h2.x),
                                                   w1 - __bfloat162float(h2.y)));
                al[3] = bf2u(__floats2bfloat162_rn(w2 - __bfloat162float(h3.x),
                                                   w3 - __bfloat162float(h3.y)));
            }
#pragma unroll
            for (int nph = 0; nph < 2; nph++) {
                unsigned vh[4][2], vl[4][2];
#pragma unroll
                for (int p = 0; p < 2; p++) {
                    const int np = 2 * nph + p;
                    const int va = (ks * 16 + (lane & 15)) * QP + np * 16 + (lane >> 4) * 8;
                    unsigned t4[4], t4l[4];
                    ldsm_x4t(t4, s2u(&sVh[va]));
                    ldsm_x4t(t4l, s2u(&sVl[va]));
                    vh[2 * p][0] = t4[0]; vh[2 * p][1] = t4[1];
                    vh[2 * p + 1][0] = t4[2]; vh[2 * p + 1][1] = t4[3];
                    vl[2 * p][0] = t4l[0]; vl[2 * p][1] = t4l[1];
                    vl[2 * p + 1][0] = t4l[2]; vl[2 * p + 1][1] = t4l[3];
                }
                float* oa = &oacc[4 * nph][0];
#pragma unroll
                for (int q = 0; q < 4; q++) mma_bf16(oa + 4 * q, ah, vh[q]);
#pragma unroll
                for (int q = 0; q < 4; q++) mma_bf16(oa + 4 * q, ah, vl[q]);
#pragma unroll
                for (int q = 0; q < 4; q++) mma_bf16(oa + 4 * q, al, vh[q]);
            }
        }
    }

    const float inv0 = 1.f / l0v, inv1 = 1.f / l1v;
#pragma unroll
    for (int nt = 0; nt < 8; nt++) {
        const int d = nt * 8 + (lane & 3) * 2;
        const size_t o0 = ((size_t)b * NSEQ + grow0) * CDIM + h * DH + d;
        const size_t o1 = ((size_t)b * NSEQ + grow1) * CDIM + h * DH + d;
        const float v0 = oacc[nt][0] * inv0, v1 = oacc[nt][1] * inv0;
        const float w0 = oacc[nt][2] * inv1, w1 = oacc[nt][3] * inv1;
        __nv_bfloat162 h0 = __floats2bfloat162_rn(v0, v1);
        *(__nv_bfloat162*)&g_ahi[o0] = h0;
        *(__nv_bfloat162*)&g_alo[o0] = __floats2bfloat162_rn(
            v0 - __bfloat162float(h0.x), v1 - __bfloat162float(h0.y));
        __nv_bfloat162 h1 = __floats2bfloat162_rn(w0, w1);
        *(__nv_bfloat162*)&g_ahi[o1] = h1;
        *(__nv_bfloat162*)&g_alo[o1] = __floats2bfloat162_rn(
            w0 - __bfloat162float(h1.x), w1 - __bfloat162float(h1.y));
    }
}

// ---------------- launch ------------------------------------------------------
extern "C" void kernel_launch(void* const* d_in, const int* in_sizes, int n_in,
                              void* d_out, int out_size) {
    (void)n_in; (void)out_size;
    const float* x     = (const float*)d_in[0];
    const void*  mask  = d_in[1];
    const int*   cs    = (const int*)d_in[2];
    const float* wqkv  = (const float*)d_in[3];
    const float* wproj = (const float*)d_in[4];
    const float* bproj = (const float*)d_in[5];
    float* out = (float*)d_out;

    prep_kernel<<<1, 256>>>(mask, cs, in_sizes[1]);

    const int ntot4 = NX4 + NWQ4 + NWP4;
    split_all_kernel<<<(ntot4 + 255) / 256, 256>>>((const float4*)x,
        (const float4*)wqkv, (const float4*)wproj);

    cudaFuncSetAttribute(qkv_gemm_kernel,
                         cudaFuncAttributeMaxDynamicSharedMemorySize, G_SMEM);
    cudaFuncSetAttribute(proj_gemm_kernel,
                         cudaFuncAttributeMaxDynamicSharedMemorySize, G_SMEM);
    cudaFuncSetAttribute(flash_mma_kernel,
                         cudaFuncAttributeMaxDynamicSharedMemorySize, FLASH_MMA_SMEM);

    dim3 g1(QKVC / 128, MROWS / 128);
    qkv_gemm_kernel<<<g1, 128, G_SMEM>>>();

    dim3 g2(NSEQ / 128, HN, BB);
    flash_mma_kernel<<<g2, 256, FLASH_MMA_SMEM>>>();

    dim3 g3(CDIM / 128, MROWS / 128);
    proj_gemm_kernel<<<g3, 128, G_SMEM>>>(bproj, out);
}

// round 17
// speedup vs baseline: 4.6288x; 1.0309x over previous
#include <cuda_runtime.h>
#include <cuda_bf16.h>
#include <math.h>
#include <stdint.h>

#define BB    2
#define NSEQ  2048
#define CDIM  1024
#define HN    16
#define DH    64
#define MROWS (BB*NSEQ)     // 4096
#define QKVC  (3*CDIM)      // 3072

// ---------------- scratch (static device globals; no allocation) -------------
__device__ __align__(16) __nv_bfloat16 g_xhi[(size_t)MROWS*CDIM], g_xlo[(size_t)MROWS*CDIM];
__device__ __align__(16) __nv_bfloat16 g_wqhi[(size_t)CDIM*QKVC], g_wqlo[(size_t)CDIM*QKVC];
__device__ __align__(16) __nv_bfloat16 g_wphi[(size_t)CDIM*CDIM], g_wplo[(size_t)CDIM*CDIM];
__device__ __align__(16) __nv_bfloat16 g_ahi[(size_t)MROWS*CDIM], g_alo[(size_t)MROWS*CDIM];
__device__ __align__(16) __nv_bfloat16 g_qhi[(size_t)BB*HN*NSEQ*DH], g_qlo[(size_t)BB*HN*NSEQ*DH];
__device__ __align__(16) __nv_bfloat16 g_khi[(size_t)BB*HN*NSEQ*DH], g_klo[(size_t)BB*HN*NSEQ*DH];
__device__ __align__(16) __nv_bfloat16 g_vhi[(size_t)BB*HN*NSEQ*DH], g_vlo[(size_t)BB*HN*NSEQ*DH];
__device__ __align__(16) __nv_bfloat16 g_zrow[CDIM];   // zero-initialized pad row
__device__ unsigned char g_maskc[BB*NSEQ];
__device__ int g_kidx[BB*NSEQ];          // gathered j -> orig col (pad 0x7FFFFFFF), ASCENDING
__device__ int g_pcnt[BB*(NSEQ+1)];
__device__ int g_kcnt[BB];
__device__ int g_causal_d;

// ---------------- prep: mask canon + causal + per-batch key compaction -------
__global__ void prep_kernel(const void* __restrict__ mask_raw,
                            const int* __restrict__ cs_raw, int nmask) {
    __shared__ int sfmt;
    __shared__ int snz1, snz3;
    __shared__ int tsum[257];
    const unsigned char* mb = (const unsigned char*)mask_raw;
    const int tid = threadIdx.x;
    if (tid == 0) { snz1 = 0; snz3 = 0; }
    __syncthreads();
    {
        int scan = nmask < 1024 ? nmask : 1024;
        for (int i = tid; i < scan; i += 256) {
            unsigned char v = mb[i];
            if (v) { int r = i & 3; if (r == 1) snz1 = 1; else if (r == 3) snz3 = 1; }
        }
    }
    __syncthreads();
    if (tid == 0) {
        sfmt = snz1 ? 0 : (snz3 ? 2 : 1);
        int cv = cs_raw[0];
        if (cv < 0 || cv > (1 << 24)) cv = (int)__int_as_float(cv);
        g_causal_d = cv;
    }
    __syncthreads();
    int f = sfmt;
    for (int i = tid; i < nmask; i += 256) {
        unsigned char m;
        if (f == 0)      m = mb[i] != 0;
        else if (f == 1) m = ((const int*)mask_raw)[i] != 0;
        else             m = ((const float*)mask_raw)[i] != 0.0f;
        g_maskc[i] = m;
    }
    __syncthreads();
    for (int b = 0; b < BB; b++) {
        int flags[8], s = 0;
        const int base = b * NSEQ + tid * 8;
#pragma unroll
        for (int j = 0; j < 8; j++) { flags[j] = g_maskc[base + j] ? 0 : 1; s += flags[j]; }
        tsum[tid] = s;
        __syncthreads();
        if (tid == 0) {
            int acc = 0;
            for (int i = 0; i < 256; i++) { int t = tsum[i]; tsum[i] = acc; acc += t; }
            tsum[256] = acc;
            g_kcnt[b] = acc;
        }
        __syncthreads();
        int run = tsum[tid];
#pragma unroll
        for (int j = 0; j < 8; j++) {
            const int n = tid * 8 + j;
            g_pcnt[b * (NSEQ + 1) + n] = run;
            if (flags[j]) { g_kidx[b * NSEQ + run] = n; run++; }
        }
        if (tid == 255) g_pcnt[b * (NSEQ + 1) + NSEQ] = run;
        __syncthreads();
        const int cnt = tsum[256];
        for (int i = cnt + tid; i < NSEQ; i += 256) g_kidx[b * NSEQ + i] = 0x7FFFFFFF;
        __syncthreads();
    }
}

// ---------------- fused vectorized splits (x, wqkv, wproj) -------------------
#define NX4  (MROWS * CDIM / 4)
#define NWQ4 (CDIM * QKVC / 4)
#define NWP4 (CDIM * CDIM / 4)
__global__ void split_all_kernel(const float4* __restrict__ x,
                                 const float4* __restrict__ wq,
                                 const float4* __restrict__ wp) {
    int i = blockIdx.x * blockDim.x + threadIdx.x;
    const float4* src;
    __nv_bfloat162 *hi, *lo;
    if (i < NX4) {
        src = x + i; hi = (__nv_bfloat162*)g_xhi + 2 * i; lo = (__nv_bfloat162*)g_xlo + 2 * i;
    } else if (i < NX4 + NWQ4) {
        int j = i - NX4;
        src = wq + j; hi = (__nv_bfloat162*)g_wqhi + 2 * j; lo = (__nv_bfloat162*)g_wqlo + 2 * j;
    } else if (i < NX4 + NWQ4 + NWP4) {
        int j = i - NX4 - NWQ4;
        src = wp + j; hi = (__nv_bfloat162*)g_wphi + 2 * j; lo = (__nv_bfloat162*)g_wplo + 2 * j;
    } else return;
    float4 v = *src;
    __nv_bfloat162 h0 = __floats2bfloat162_rn(v.x, v.y);
    __nv_bfloat162 h1 = __floats2bfloat162_rn(v.z, v.w);
    hi[0] = h0; hi[1] = h1;
    lo[0] = __floats2bfloat162_rn(v.x - __bfloat162float(h0.x), v.y - __bfloat162float(h0.y));
    lo[1] = __floats2bfloat162_rn(v.z - __bfloat162float(h1.x), v.w - __bfloat162float(h1.y));
}

// ---------------- PTX helpers -------------------------------------------------
__device__ __forceinline__ uint32_t s2u(const void* p) {
    return (uint32_t)__cvta_generic_to_shared(p);
}
__device__ __forceinline__ void ldsm_x4(unsigned* r, uint32_t addr) {
    asm volatile("ldmatrix.sync.aligned.m8n8.x4.shared.b16 {%0,%1,%2,%3}, [%4];"
                 : "=r"(r[0]), "=r"(r[1]), "=r"(r[2]), "=r"(r[3]) : "r"(addr));
}
__device__ __forceinline__ void ldsm_x4t(unsigned* r, uint32_t addr) {
    asm volatile("ldmatrix.sync.aligned.m8n8.x4.trans.shared.b16 {%0,%1,%2,%3}, [%4];"
                 : "=r"(r[0]), "=r"(r[1]), "=r"(r[2]), "=r"(r[3]) : "r"(addr));
}
__device__ __forceinline__ void mma_bf16(float* d, const unsigned* a, const unsigned* b) {
    asm volatile("mma.sync.aligned.m16n8k16.row.col.f32.bf16.bf16.f32 "
                 "{%0,%1,%2,%3}, {%4,%5,%6,%7}, {%8,%9}, {%0,%1,%2,%3};"
                 : "+f"(d[0]), "+f"(d[1]), "+f"(d[2]), "+f"(d[3])
                 : "r"(a[0]), "r"(a[1]), "r"(a[2]), "r"(a[3]), "r"(b[0]), "r"(b[1]));
}
__device__ __forceinline__ unsigned bf2u(__nv_bfloat162 x) { return *(unsigned*)&x; }
__device__ __forceinline__ void cp16(uint32_t smem, const void* g) {
    asm volatile("cp.async.cg.shared.global [%0], [%1], 16;"
                 :: "r"(smem), "l"(__cvta_generic_to_global(g)) : "memory");
}
__device__ __forceinline__ void cp_commit() {
    asm volatile("cp.async.commit_group;" ::: "memory");
}
template<int N> __device__ __forceinline__ void cp_wait() {
    asm volatile("cp.async.wait_group %0;" :: "n"(N) : "memory");
}

// == bf16x3 GEMM core: 128x128 CTA, 4 warps x 64x64 tiles, BK=32, 3-stage ring
#define G_STG   18944
#define G_ALO   5120
#define G_BHI   10240
#define G_BLO   14592
#define G_SMEM  (3 * G_STG * 2)       // 113664 B
#define G_NT    (CDIM / 32)           // 32

#define GEMM_MMA_BLOCK \
    do { \
        _Pragma("unroll") \
        for (int mt = 0; mt < 4; mt++) \
            _Pragma("unroll") \
            for (int nt = 0; nt < 8; nt++) mma_bf16(acc[mt][nt], ah[mt], bh[nt]); \
        _Pragma("unroll") \
        for (int mt = 0; mt < 4; mt++) \
            _Pragma("unroll") \
            for (int nt = 0; nt < 8; nt++) mma_bf16(acc[mt][nt], ah[mt], bl[nt]); \
        _Pragma("unroll") \
        for (int mt = 0; mt < 4; mt++) \
            _Pragma("unroll") \
            for (int nt = 0; nt < 8; nt++) mma_bf16(acc[mt][nt], al[mt], bh[nt]); \
    } while (0)

// --------- merged QKV GEMM: grid (24, 32); ntile<8 -> Q, else KV -------------
__global__ void __launch_bounds__(128)
qkv_gemm_kernel() {
    extern __shared__ __align__(16) char smraw[];
    const uint32_t smu = s2u(smraw);

    const int tid = threadIdx.x, lane = tid & 31, wid = tid >> 5;
    const int wm = wid >> 1, wn = wid & 1;
    const bool isQ = blockIdx.x < 8;
    const int n0 = isQ ? blockIdx.x * 128 : CDIM + (blockIdx.x - 8) * 128;
    const int m0 = blockIdx.y * 128;
    const int bb = m0 >> 11;

    if (!isQ) {
        const int j0 = m0 & (NSEQ - 1);
        if (j0 >= ((g_kcnt[bb] + 63) & ~63)) return;
    }

    const int arow = tid >> 2, acol = (tid & 3) * 8;
    const __nv_bfloat16 *pAh[4], *pAl[4];
#pragma unroll
    for (int it = 0; it < 4; it++) {
        const int r = m0 + arow + it * 32;
        if (isQ) {
            pAh[it] = g_xhi + (size_t)r * CDIM;
            pAl[it] = g_xlo + (size_t)r * CDIM;
        } else {
            const int j = r & (NSEQ - 1);
            if (j < g_kcnt[bb]) {
                const int n = g_kidx[bb * NSEQ + j];
                pAh[it] = g_xhi + ((size_t)bb * NSEQ + n) * CDIM;
                pAl[it] = g_xlo + ((size_t)bb * NSEQ + n) * CDIM;
            } else {
                pAh[it] = g_zrow;
                pAl[it] = g_zrow;
            }
        }
    }

    auto stage = [&](int kt, int s) {
        const int k0 = kt * 32;
        const uint32_t sb = smu + s * G_STG * 2;
        const int brow = tid >> 4, bcol = (tid & 15) * 8;
#pragma unroll
        for (int it = 0; it < 4; it++) {
            const int r = arow + it * 32;
            cp16(sb + (r * 40 + acol) * 2, pAh[it] + k0 + acol);
            cp16(sb + (G_ALO + r * 40 + acol) * 2, pAl[it] + k0 + acol);
            const int rb = brow + it * 8;
            cp16(sb + (G_BHI + rb * 136 + bcol) * 2, g_wqhi + (size_t)(k0 + rb) * QKVC + n0 + bcol);
            cp16(sb + (G_BLO + rb * 136 + bcol) * 2, g_wqlo + (size_t)(k0 + rb) * QKVC + n0 + bcol);
        }
    };

    float acc[4][8][4];
#pragma unroll
    for (int i = 0; i < 4; i++)
#pragma unroll
        for (int j = 0; j < 8; j++)
#pragma unroll
            for (int q = 0; q < 4; q++) acc[i][j][q] = 0.f;

    const int a_ld = (wm * 64 + (lane & 15)) * 40 + (lane >> 4) * 8;
    const int b_ld = (lane & 15) * 136 + wn * 64 + (lane >> 4) * 8;

    stage(0, 0); cp_commit();
    stage(1, 1); cp_commit();

    for (int kt = 0; kt < G_NT; kt++) {
        if (kt == G_NT - 1) cp_wait<0>(); else cp_wait<1>();
        __syncthreads();
        if (kt + 2 < G_NT) { stage(kt + 2, (kt + 2) % 3); cp_commit(); }

        const uint32_t sb = smu + (kt % 3) * G_STG * 2;
#pragma unroll
        for (int ks = 0; ks < 2; ks++) {
            unsigned ah[4][4], al[4][4], bh[8][2], bl[8][2];
            const uint32_t aBh = sb + (a_ld + ks * 16) * 2;
            const uint32_t aBl = aBh + G_ALO * 2;
            const uint32_t bBh = sb + (G_BHI + b_ld + ks * 16 * 136) * 2;
            const uint32_t bBl = bBh + (G_BLO - G_BHI) * 2;
#pragma unroll
            for (int mt = 0; mt < 4; mt++) {
                ldsm_x4(ah[mt], aBh + mt * 16 * 40 * 2);
                ldsm_x4(al[mt], aBl + mt * 16 * 40 * 2);
            }
#pragma unroll
            for (int ntp = 0; ntp < 4; ntp++) {
                unsigned t4[4];
                ldsm_x4t(t4, bBh + ntp * 16 * 2);
                bh[2 * ntp][0] = t4[0]; bh[2 * ntp][1] = t4[1];
                bh[2 * ntp + 1][0] = t4[2]; bh[2 * ntp + 1][1] = t4[3];
                ldsm_x4t(t4, bBl + ntp * 16 * 2);
                bl[2 * ntp][0] = t4[0]; bl[2 * ntp][1] = t4[1];
                bl[2 * ntp + 1][0] = t4[2]; bl[2 * ntp + 1][1] = t4[3];
            }
            GEMM_MMA_BLOCK;
        }
    }

    const int rb = m0 + wm * 64 + (lane >> 2);
    const int cb = n0 + wn * 64 + (lane & 3) * 2;
#pragma unroll
    for (int mt = 0; mt < 4; mt++)
#pragma unroll
        for (int nt = 0; nt < 8; nt++) {
            const int c = cb + nt * 8;
            if (isQ) {
                const int h = c >> 6, d = c & 63;
#pragma unroll
                for (int half = 0; half < 2; half++) {
                    const int r = rb + mt * 16 + half * 8;
                    const int bidx = r >> 11, n = r & (NSEQ - 1);
                    size_t off = (((size_t)bidx * HN + h) * NSEQ + n) * DH + d;
                    float v0 = acc[mt][nt][2 * half] * 0.125f;
                    float v1 = acc[mt][nt][2 * half + 1] * 0.125f;
                    __nv_bfloat162 hh = __floats2bfloat162_rn(v0, v1);
                    *(__nv_bfloat162*)&g_qhi[off] = hh;
                    *(__nv_bfloat162*)&g_qlo[off] = __floats2bfloat162_rn(
                        v0 - __bfloat162float(hh.x), v1 - __bfloat162float(hh.y));
                }
            } else {
                const int sec = c >> 10, h = (c & 1023) >> 6, d = c & 63;
                __nv_bfloat16* dhi = (sec == 1) ? g_khi : g_vhi;
                __nv_bfloat16* dlo = (sec == 1) ? g_klo : g_vlo;
#pragma unroll
                for (int half = 0; half < 2; half++) {
                    const int r = rb + mt * 16 + half * 8;
                    const int bidx = r >> 11, j = r & (NSEQ - 1);
                    size_t off = (((size_t)bidx * HN + h) * NSEQ + j) * DH + d;
                    float v0 = acc[mt][nt][2 * half], v1 = acc[mt][nt][2 * half + 1];
                    __nv_bfloat162 hh = __floats2bfloat162_rn(v0, v1);
                    *(__nv_bfloat162*)&dhi[off] = hh;
                    *(__nv_bfloat162*)&dlo[off] = __floats2bfloat162_rn(
                        v0 - __bfloat162float(hh.x), v1 - __bfloat162float(hh.y));
                }
            }
        }
}

// --------- proj GEMM: att(4096x1024) @ Wp + bias -> out ----------------------
__global__ void __launch_bounds__(128)
proj_gemm_kernel(const float* __restrict__ bias, float* __restrict__ out) {
    extern __shared__ __align__(16) char smraw[];
    const uint32_t smu = s2u(smraw);

    const int tid = threadIdx.x, lane = tid & 31, wid = tid >> 5;
    const int wm = wid >> 1, wn = wid & 1;
    const int m0 = blockIdx.y * 128, n0 = blockIdx.x * 128;

    auto stage = [&](int kt, int s) {
        const int k0 = kt * 32;
        const uint32_t sb = smu + s * G_STG * 2;
        const int arow = tid >> 2, acol = (tid & 3) * 8;
        const int brow = tid >> 4, bcol = (tid & 15) * 8;
#pragma unroll
        for (int it = 0; it < 4; it++) {
            const int r = arow + it * 32;
            cp16(sb + (r * 40 + acol) * 2, g_ahi + (size_t)(m0 + r) * CDIM + k0 + acol);
            cp16(sb + (G_ALO + r * 40 + acol) * 2, g_alo + (size_t)(m0 + r) * CDIM + k0 + acol);
            const int rb = brow + it * 8;
            cp16(sb + (G_BHI + rb * 136 + bcol) * 2, g_wphi + (size_t)(k0 + rb) * CDIM + n0 + bcol);
            cp16(sb + (G_BLO + rb * 136 + bcol) * 2, g_wplo + (size_t)(k0 + rb) * CDIM + n0 + bcol);
        }
    };

    float acc[4][8][4];
#pragma unroll
    for (int i = 0; i < 4; i++)
#pragma unroll
        for (int j = 0; j < 8; j++)
#pragma unroll
            for (int q = 0; q < 4; q++) acc[i][j][q] = 0.f;

    const int a_ld = (wm * 64 + (lane & 15)) * 40 + (lane >> 4) * 8;
    const int b_ld = (lane & 15) * 136 + wn * 64 + (lane >> 4) * 8;

    stage(0, 0); cp_commit();
    stage(1, 1); cp_commit();

    for (int kt = 0; kt < G_NT; kt++) {
        if (kt == G_NT - 1) cp_wait<0>(); else cp_wait<1>();
        __syncthreads();
        if (kt + 2 < G_NT) { stage(kt + 2, (kt + 2) % 3); cp_commit(); }

        const uint32_t sb = smu + (kt % 3) * G_STG * 2;
#pragma unroll
        for (int ks = 0; ks < 2; ks++) {
            unsigned ah[4][4], al[4][4], bh[8][2], bl[8][2];
            const uint32_t aBh = sb + (a_ld + ks * 16) * 2;
            const uint32_t aBl = aBh + G_ALO * 2;
            const uint32_t bBh = sb + (G_BHI + b_ld + ks * 16 * 136) * 2;
            const uint32_t bBl = bBh + (G_BLO - G_BHI) * 2;
#pragma unroll
            for (int mt = 0; mt < 4; mt++) {
                ldsm_x4(ah[mt], aBh + mt * 16 * 40 * 2);
                ldsm_x4(al[mt], aBl + mt * 16 * 40 * 2);
            }
#pragma unroll
            for (int ntp = 0; ntp < 4; ntp++) {
                unsigned t4[4];
                ldsm_x4t(t4, bBh + ntp * 16 * 2);
                bh[2 * ntp][0] = t4[0]; bh[2 * ntp][1] = t4[1];
                bh[2 * ntp + 1][0] = t4[2]; bh[2 * ntp + 1][1] = t4[3];
                ldsm_x4t(t4, bBl + ntp * 16 * 2);
                bl[2 * ntp][0] = t4[0]; bl[2 * ntp][1] = t4[1];
                bl[2 * ntp + 1][0] = t4[2]; bl[2 * ntp + 1][1] = t4[3];
            }
            GEMM_MMA_BLOCK;
        }
    }

    const int rb = m0 + wm * 64 + (lane >> 2);
    const int cb = n0 + wn * 64 + (lane & 3) * 2;
#pragma unroll
    for (int mt = 0; mt < 4; mt++)
#pragma unroll
        for (int nt = 0; nt < 8; nt++) {
            const int c = cb + nt * 8;
            const float b0 = bias[c], b1 = bias[c + 1];
#pragma unroll
            for (int half = 0; half < 2; half++) {
                const int r = rb + mt * 16 + half * 8;
                float* p = out + (size_t)r * CDIM + c;
                *(float2*)p = make_float2(acc[mt][nt][2 * half] + b0,
                                          acc[mt][nt][2 * half + 1] + b1);
            }
        }
}

// ====== Flash attention: Br=64, 128 threads, single-buffer KV, 4 CTAs/SM =====
#define QP 72
#define FQ_PLANE 4608            // 64*72 elems
#define F_KV0    9216            // elem offset of KV buffer
#define F_SCOLB  (27648 * 2)     // byte offset of scol (after 27648 elems)
#define FLASH_MMA_SMEM (F_SCOLB + 256)   // 55552 B -> 4 CTAs/SM

__global__ void __launch_bounds__(128, 4) flash_mma_kernel() {
    extern __shared__ __align__(16) char smraw[];
    __nv_bfloat16* smb = (__nv_bfloat16*)smraw;
    const uint32_t smu = s2u(smraw);
    __nv_bfloat16* sQh = smb;                    // [64][72]
    __nv_bfloat16* sQl = smb + FQ_PLANE;
    int* scol = (int*)(smraw + F_SCOLB);         // [64]

    const int tid = threadIdx.x, lane = tid & 31, wid = tid >> 5;
    const int qt = gridDim.x - 1 - blockIdx.x;   // heavy causal tiles first
    const int h = blockIdx.y, b = blockIdx.z;
    const int q0 = qt * 64;
    const int cstart = g_causal_d;
    const size_t hoff = ((size_t)b * HN + h) * NSEQ * DH;

    const __nv_bfloat16 *Qh = g_qhi + hoff, *Ql = g_qlo + hoff;
    const __nv_bfloat16* kvsrc[4] = {g_khi + hoff, g_klo + hoff,
                                     g_vhi + hoff, g_vlo + hoff};

    // stage Q tile (64 x 64, hi+lo): plain stores, covered by first sync
    {
        const int r = tid >> 1, c0 = (tid & 1) * 32;
#pragma unroll
        for (int c = 0; c < 32; c += 8) {
            *(uint4*)&sQh[r * QP + c0 + c] = *(const uint4*)&Qh[(size_t)(q0 + r) * DH + c0 + c];
            *(uint4*)&sQl[r * QP + c0 + c] = *(const uint4*)&Ql[(size_t)(q0 + r) * DH + c0 + c];
        }
    }

    const int kv_r = tid >> 3, kv_c = (tid & 7) * 8;   // 16 rows x 8 col-chunks
    auto stageKV = [&](int t) {
        const int k0t = t * 64;
        const uint32_t base = smu + F_KV0 * 2;
#pragma unroll
        for (int pl = 0; pl < 4; pl++)
#pragma unroll
            for (int half = 0; half < 4; half++) {
                const int r = kv_r + half * 16;
                cp16(base + (pl * 4608 + r * QP + kv_c) * 2,
                     kvsrc[pl] + (size_t)(k0t + r) * DH + kv_c);
            }
    };

    int kmaxi = q0 + 63;
    if (cstart - 1 > kmaxi) kmaxi = cstart - 1;
    if (kmaxi > NSEQ - 1) kmaxi = NSEQ - 1;
    const int kcnt = g_pcnt[b * (NSEQ + 1) + kmaxi + 1];
    const int ntiles = (kcnt + 63) >> 6;

    float m0v = -1e30f, m1v = -1e30f, l0v = 0.f, l1v = 0.f;
    float oacc[8][4] = {};

    const int grow0 = q0 + wid * 16 + (lane >> 2);
    const int grow1 = grow0 + 8;
    const int visthr = (q0 > cstart - 1) ? q0 : (cstart - 1);
    const int q_ld = (wid * 16 + (lane & 15)) * QP + (lane >> 4) * 8;

    for (int t = 0; t < ntiles; t++) {
        __syncthreads();                 // prev tile compute done; buffer free
        stageKV(t);
        if (tid < 64) scol[tid] = g_kidx[b * NSEQ + t * 64 + tid];
        cp_commit();
        cp_wait<0>();
        __syncthreads();                 // KV + scol visible (Q too on t=0)

        const __nv_bfloat16* sKh = smb + F_KV0;
        const __nv_bfloat16* sKl = smb + F_KV0 + 4608;
        const __nv_bfloat16* sVh = smb + F_KV0 + 9216;
        const __nv_bfloat16* sVl = smb + F_KV0 + 13824;
        const int* sc = scol;

        // ---- S = Q K^T (Q reloaded per ks; pass-major over 4 accs) ----
        float sacc[8][4] = {};
#pragma unroll
        for (int ks = 0; ks < 4; ks++) {
            unsigned qh[4], ql[4];
            ldsm_x4(qh, s2u(&sQh[q_ld + ks * 16]));
            ldsm_x4(ql, s2u(&sQl[q_ld + ks * 16]));
#pragma unroll
            for (int nph = 0; nph < 2; nph++) {
                unsigned kh[4][2], kl[4][2];
#pragma unroll
                for (int p = 0; p < 2; p++) {
                    const int np = 2 * nph + p;
                    const int row = np * 16 + ((lane >> 4) & 1) * 8 + (lane & 7);
                    const int col = ks * 16 + ((lane >> 3) & 1) * 8;
                    unsigned t4[4], t4l[4];
                    ldsm_x4(t4, s2u(&sKh[row * QP + col]));
                    ldsm_x4(t4l, s2u(&sKl[row * QP + col]));
                    kh[2 * p][0] = t4[0]; kh[2 * p][1] = t4[1];
                    kh[2 * p + 1][0] = t4[2]; kh[2 * p + 1][1] = t4[3];
                    kl[2 * p][0] = t4l[0]; kl[2 * p][1] = t4l[1];
                    kl[2 * p + 1][0] = t4l[2]; kl[2 * p + 1][1] = t4l[3];
                }
                float* sa = &sacc[4 * nph][0];
#pragma unroll
                for (int q = 0; q < 4; q++) mma_bf16(sa + 4 * q, qh, kh[q]);
#pragma unroll
                for (int q = 0; q < 4; q++) mma_bf16(sa + 4 * q, qh, kl[q]);
#pragma unroll
                for (int q = 0; q < 4; q++) mma_bf16(sa + 4 * q, ql, kh[q]);
            }
        }

        // ---- mask (slow path only) + row max ----
        const bool fullvis = sc[63] <= visthr;
        float tmax0 = -INFINITY, tmax1 = -INFINITY;
        if (fullvis) {
#pragma unroll
            for (int nt = 0; nt < 8; nt++) {
#pragma unroll
                for (int j = 0; j < 2; j++) {
                    tmax0 = fmaxf(tmax0, sacc[nt][j]);
                    tmax1 = fmaxf(tmax1, sacc[nt][2 + j]);
                }
            }
        } else {
#pragma unroll
            for (int nt = 0; nt < 8; nt++) {
#pragma unroll
                for (int j = 0; j < 2; j++) {
                    const int lc = nt * 8 + (lane & 3) * 2 + j;
                    const int col = sc[lc];
                    float v0 = sacc[nt][j];
                    float v1 = sacc[nt][2 + j];
                    v0 = (col > grow0 && col >= cstart) ? -INFINITY : v0;
                    v1 = (col > grow1 && col >= cstart) ? -INFINITY : v1;
                    sacc[nt][j] = v0; sacc[nt][2 + j] = v1;
                    tmax0 = fmaxf(tmax0, v0); tmax1 = fmaxf(tmax1, v1);
                }
            }
        }
#pragma unroll
        for (int off = 1; off < 4; off <<= 1) {
            tmax0 = fmaxf(tmax0, __shfl_xor_sync(0xffffffffu, tmax0, off));
            tmax1 = fmaxf(tmax1, __shfl_xor_sync(0xffffffffu, tmax1, off));
        }

        // ---- online softmax update ----
        const float mn0 = fmaxf(m0v, tmax0), mn1 = fmaxf(m1v, tmax1);
        const float cr0 = __expf(m0v - mn0), cr1 = __expf(m1v - mn1);
        m0v = mn0; m1v = mn1;
        l0v *= cr0; l1v *= cr1;
#pragma unroll
        for (int nt = 0; nt < 8; nt++) {
            oacc[nt][0] *= cr0; oacc[nt][1] *= cr0;
            oacc[nt][2] *= cr1; oacc[nt][3] *= cr1;
        }
        float rs0 = 0.f, rs1 = 0.f;
#pragma unroll
        for (int nt = 0; nt < 8; nt++) {
            float p0 = __expf(sacc[nt][0] - mn0), p1 = __expf(sacc[nt][1] - mn0);
            float p2 = __expf(sacc[nt][2] - mn1), p3 = __expf(sacc[nt][3] - mn1);
            sacc[nt][0] = p0; sacc[nt][1] = p1; sacc[nt][2] = p2; sacc[nt][3] = p3;
            rs0 += p0 + p1; rs1 += p2 + p3;
        }
#pragma unroll
        for (int off = 1; off < 4; off <<= 1) {
            rs0 += __shfl_xor_sync(0xffffffffu, rs0, off);
            rs1 += __shfl_xor_sync(0xffffffffu, rs1, off);
        }
        l0v += rs0; l1v += rs1;

        // ---- O += P V (pass-major over 4 accs) ----
#pragma unroll
        for (int ks = 0; ks < 4; ks++) {
            unsigned ah[4], al[4];
            {
                const float v0 = sacc[2 * ks][0], v1 = sacc[2 * ks][1];
                const float v2 = sacc[2 * ks][2], v3 = sacc[2 * ks][3];
                const float w0 = sacc[2 * ks + 1][0], w1 = sacc[2 * ks + 1][1];
                const float w2 = sacc[2 * ks + 1][2], w3 = sacc[2 * ks + 1][3];
                __nv_bfloat162 h0 = __floats2bfloat162_rn(v0, v1);
                __nv_bfloat162 h1 = __floats2bfloat162_rn(v2, v3);
                __nv_bfloat162 h2 = __floats2bfloat162_rn(w0, w1);
                __nv_bfloat162 h3 = __floats2bfloat162_rn(w2, w3);
                ah[0] = bf2u(h0); ah[1] = bf2u(h1); ah[2] = bf2u(h2); ah[3] = bf2u(h3);
                al[0] = bf2u(__floats2bfloat162_rn(v0 - __bfloat162float(h0.x),
                                                   v1 - __bfloat162float(h0.y)));
                al[1] = bf2u(__floats2bfloat162_rn(v2 - __bfloat162float(h1.x),
                                                   v3 - __bfloat162float(h1.y)));
                al[2] = bf2u(__floats2bfloat162_rn(w0 - __bfloat162float(h2.x),
                                                   w1 - __bfloat162float(h2.y)));
                al[3] = bf2u(__floats2bfloat162_rn(w2 - __bfloat162float(h3.x),
                                                   w3 - __bfloat162float(h3.y)));
            }
#pragma unroll
            for (int nph = 0; nph < 2; nph++) {
                unsigned vh[4][2], vl[4][2];
#pragma unroll
                for (int p = 0; p < 2; p++) {
                    const int np = 2 * nph + p;
                    const int va = (ks * 16 + (lane & 15)) * QP + np * 16 + (lane >> 4) * 8;
                    unsigned t4[4], t4l[4];
                    ldsm_x4t(t4, s2u(&sVh[va]));
                    ldsm_x4t(t4l, s2u(&sVl[va]));
                    vh[2 * p][0] = t4[0]; vh[2 * p][1] = t4[1];
                    vh[2 * p + 1][0] = t4[2]; vh[2 * p + 1][1] = t4[3];
                    vl[2 * p][0] = t4l[0]; vl[2 * p][1] = t4l[1];
                    vl[2 * p + 1][0] = t4l[2]; vl[2 * p + 1][1] = t4l[3];
                }
                float* oa = &oacc[4 * nph][0];
#pragma unroll
                for (int q = 0; q < 4; q++) mma_bf16(oa + 4 * q, ah, vh[q]);
#pragma unroll
                for (int q = 0; q < 4; q++) mma_bf16(oa + 4 * q, ah, vl[q]);
#pragma unroll
                for (int q = 0; q < 4; q++) mma_bf16(oa + 4 * q, al, vh[q]);
            }
        }
    }

    const float inv0 = 1.f / l0v, inv1 = 1.f / l1v;
#pragma unroll
    for (int nt = 0; nt < 8; nt++) {
        const int d = nt * 8 + (lane & 3) * 2;
        const size_t o0 = ((size_t)b * NSEQ + grow0) * CDIM + h * DH + d;
        const size_t o1 = ((size_t)b * NSEQ + grow1) * CDIM + h * DH + d;
        const float v0 = oacc[nt][0] * inv0, v1 = oacc[nt][1] * inv0;
        const float w0 = oacc[nt][2] * inv1, w1 = oacc[nt][3] * inv1;
        __nv_bfloat162 h0 = __floats2bfloat162_rn(v0, v1);
        *(__nv_bfloat162*)&g_ahi[o0] = h0;
        *(__nv_bfloat162*)&g_alo[o0] = __floats2bfloat162_rn(
            v0 - __bfloat162float(h0.x), v1 - __bfloat162float(h0.y));
        __nv_bfloat162 h1 = __floats2bfloat162_rn(w0, w1);
        *(__nv_bfloat162*)&g_ahi[o1] = h1;
        *(__nv_bfloat162*)&g_alo[o1] = __floats2bfloat162_rn(
            w0 - __bfloat162float(h1.x), w1 - __bfloat162float(h1.y));
    }
}

// ---------------- launch ------------------------------------------------------
extern "C" void kernel_launch(void* const* d_in, const int* in_sizes, int n_in,
                              void* d_out, int out_size) {
    (void)n_in; (void)out_size;
    const float* x     = (const float*)d_in[0];
    const void*  mask  = d_in[1];
    const int*   cs    = (const int*)d_in[2];
    const float* wqkv  = (const float*)d_in[3];
    const float* wproj = (const float*)d_in[4];
    const float* bproj = (const float*)d_in[5];
    float* out = (float*)d_out;

    prep_kernel<<<1, 256>>>(mask, cs, in_sizes[1]);

    const int ntot4 = NX4 + NWQ4 + NWP4;
    split_all_kernel<<<(ntot4 + 255) / 256, 256>>>((const float4*)x,
        (const float4*)wqkv, (const float4*)wproj);

    cudaFuncSetAttribute(qkv_gemm_kernel,
                         cudaFuncAttributeMaxDynamicSharedMemorySize, G_SMEM);
    cudaFuncSetAttribute(proj_gemm_kernel,
                         cudaFuncAttributeMaxDynamicSharedMemorySize, G_SMEM);
    cudaFuncSetAttribute(flash_mma_kernel,
                         cudaFuncAttributeMaxDynamicSharedMemorySize, FLASH_MMA_SMEM);

    dim3 g1(QKVC / 128, MROWS / 128);
    qkv_gemm_kernel<<<g1, 128, G_SMEM>>>();

    dim3 g2(NSEQ / 64, HN, BB);
    flash_mma_kernel<<<g2, 128, FLASH_MMA_SMEM>>>();

    dim3 g3(CDIM / 128, MROWS / 128);
    proj_gemm_kernel<<<g3, 128, G_SMEM>>>(bproj, out);
}